// round 5
// baseline (speedup 1.0000x reference)
#include <cuda_runtime.h>
#include <math.h>
#include <stdint.h>

// ---------------- problem dims ----------------
#define BB   4
#define N1_  9216
#define N2_  2304
#define N3_  576
#define D0_  128
#define D1_  256
#define D2_  512
#define DH_  2048

// ---------------- scratch pool (floats) ----------------
#define OFF_R1   0L
#define OFF_C1   36864L
#define OFF_R2   38912L
#define OFF_C2   48128L
#define OFF_R4   50176L
#define OFF_C4   87040L
#define OFF_RA   88064L
#define OFF_CA   97280L
#define OFF_ST1  99328L
#define OFF_ST2  1147904L
#define OFF_ST3  2196480L
#define OFF_ST4  2458624L
#define ZERO_CNT 3507200L
#define OFF_ET1  3507200L
#define OFF_ET2  22381568L
#define OFF_ET4  27100160L
#define OFF_ETA  36537344L
#define OFF_T    41255936L
#define OFF_T3   42435584L
#define OFF_A3   44794880L
#define OFF_ATT  47154176L
#define OFF_AN   48333824L
#define OFF_H    49513472L
#define OFF_AX   54232064L
#define POOL_SZ  58950656L

__device__ float g_pool[POOL_SZ];

// ---------------- helpers ----------------
__device__ __forceinline__ float to_tf32(float x) {
    float y;
    asm("cvt.rna.tf32.f32 %0, %1;" : "=f"(y) : "f"(x));
    return y;
}
__device__ __forceinline__ float4 rnd4(float4 v) {
    v.x = to_tf32(v.x); v.y = to_tf32(v.y); v.z = to_tf32(v.z); v.w = to_tf32(v.w);
    return v;
}
__device__ __forceinline__ void mma_tf32(float* d, const uint32_t* a, const uint32_t* bf) {
    asm volatile(
        "mma.sync.aligned.m16n8k8.row.col.f32.tf32.tf32.f32 "
        "{%0,%1,%2,%3}, {%4,%5,%6,%7}, {%8,%9}, {%0,%1,%2,%3};"
        : "+f"(d[0]), "+f"(d[1]), "+f"(d[2]), "+f"(d[3])
        : "r"(a[0]), "r"(a[1]), "r"(a[2]), "r"(a[3]), "r"(bf[0]), "r"(bf[1]));
}

// ================= tf32 mma.sync NT GEMM =================
// D[m][n] = sum_k A[m][k] * B[n][k], 128x128 CTA tile, BK=16,
// 256 threads = 8 warps, warp tile 64x32 (wm: 2 x 64 rows, wn: 4 x 32 cols),
// double-buffered smem (stride-20 pad, conflict-free), 2 CTAs/SM.
// EPI 0: C[m][n] = acc
// EPI 1: e = exp(acc); Et[n][m] = e; atomic rowsum[m] += sum_n e; colsum[n] += sum_m e
// EPI 2: C[m][n] = alpha*(acc + bias[n]) + (addsrc ? addsrc[m][n] : 0)
// EPI 3: C[m][n] += alpha*(acc + bias[n])
// EPI 4: atomicAdd(C[m][n], acc * mscale[m])           (split-K S-gemm, coalesced)
// AMODE: 0 alpha=1 ; 1 alpha=sigmoid(*wscal) ; 2 alpha=(1-sigmoid)/2
// KSC: B *= kscale[k] at load ; MSC: use mscale in EPI4
template<int EPI, int AMODE, bool KSC, bool MSC>
__global__ void __launch_bounds__(256, 2) tgemm(
    const float* __restrict__ A, long aStr, int lda,
    const float* __restrict__ Bm, long bStr, int ldb,
    float* __restrict__ C, long cStr, int ldc,
    int mTot, int nTot, int kTot, int splits,
    const float* __restrict__ bias,
    const float* __restrict__ addsrc,
    const float* __restrict__ wscal,
    float* __restrict__ rowsum, float* __restrict__ colsum,
    const float* __restrict__ kscale, const float* __restrict__ mscale)
{
    __shared__ float As[2][128][20];
    __shared__ float Bs[2][128][20];

    const int z = blockIdx.z;
    const int b = z / splits, sp = z % splits;
    const int Kc = kTot / splits;
    const int kbase = sp * Kc;
    const int nt = Kc >> 4;

    const float* Ab = A + (long)b * aStr;
    const float* Bb = Bm + (long)b * bStr;
    const float* ksc_b = KSC ? (kscale + (long)b * kTot) : nullptr;

    const int bm = blockIdx.y * 128;
    const int bn = blockIdx.x * 128;
    const int tid = threadIdx.x;
    const int wid = tid >> 5, lane = tid & 31;
    const int wm = wid & 1, wn = wid >> 1;        // warp tile: rows wm*64, cols wn*32
    const int lr = lane >> 2, lc = lane & 3;

    float acc[4][4][4];
#pragma unroll
    for (int i = 0; i < 4; i++)
#pragma unroll
        for (int j = 0; j < 4; j++)
#pragma unroll
            for (int r = 0; r < 4; r++) acc[i][j][r] = 0.0f;

    // ---- initial tile -> buffer 0 ----
    {
        const int k0 = kbase;
#pragma unroll
        for (int l = 0; l < 2; l++) {
            int idx = tid + (l << 8);
            int row = idx >> 2, kq = (idx & 3) << 2;
            int gr = bm + row;
            float4 va = make_float4(0.f, 0.f, 0.f, 0.f);
            if (gr < mTot) va = *(const float4*)(Ab + (long)gr * lda + k0 + kq);
            float4 vb = *(const float4*)(Bb + (long)(bn + row) * ldb + k0 + kq);
            if (KSC) {
                float4 ks = *(const float4*)(ksc_b + k0 + kq);
                vb.x *= ks.x; vb.y *= ks.y; vb.z *= ks.z; vb.w *= ks.w;
            }
            *(float4*)(&As[0][row][kq]) = rnd4(va);
            *(float4*)(&Bs[0][row][kq]) = rnd4(vb);
        }
    }
    __syncthreads();

    for (int t = 0; t < nt; t++) {
        const int cur = t & 1;
        float4 ra[2], rb[2];
        if (t + 1 < nt) {
            const int k0 = kbase + ((t + 1) << 4);
#pragma unroll
            for (int l = 0; l < 2; l++) {
                int idx = tid + (l << 8);
                int row = idx >> 2, kq = (idx & 3) << 2;
                int gr = bm + row;
                float4 va = make_float4(0.f, 0.f, 0.f, 0.f);
                if (gr < mTot) va = *(const float4*)(Ab + (long)gr * lda + k0 + kq);
                ra[l] = va;
                float4 vb = *(const float4*)(Bb + (long)(bn + row) * ldb + k0 + kq);
                if (KSC) {
                    float4 ks = *(const float4*)(ksc_b + k0 + kq);
                    vb.x *= ks.x; vb.y *= ks.y; vb.z *= ks.z; vb.w *= ks.w;
                }
                rb[l] = vb;
            }
        }
        // ---- MMA on buffer cur ----
#pragma unroll
        for (int ks = 0; ks < 2; ks++) {
            const int kb = ks << 3;
            uint32_t af[4][4];
#pragma unroll
            for (int i = 0; i < 4; i++) {
                int r0 = wm * 64 + i * 16 + lr;
                af[i][0] = __float_as_uint(As[cur][r0][kb + lc]);
                af[i][1] = __float_as_uint(As[cur][r0 + 8][kb + lc]);
                af[i][2] = __float_as_uint(As[cur][r0][kb + lc + 4]);
                af[i][3] = __float_as_uint(As[cur][r0 + 8][kb + lc + 4]);
            }
            uint32_t bf[4][2];
#pragma unroll
            for (int j = 0; j < 4; j++) {
                int n0 = wn * 32 + j * 8 + lr;
                bf[j][0] = __float_as_uint(Bs[cur][n0][kb + lc]);
                bf[j][1] = __float_as_uint(Bs[cur][n0][kb + lc + 4]);
            }
#pragma unroll
            for (int i = 0; i < 4; i++)
#pragma unroll
                for (int j = 0; j < 4; j++)
                    mma_tf32(acc[i][j], af[i], bf[j]);
        }
        if (t + 1 < nt) {
            const int nxt = (t + 1) & 1;
#pragma unroll
            for (int l = 0; l < 2; l++) {
                int idx = tid + (l << 8);
                int row = idx >> 2, kq = (idx & 3) << 2;
                *(float4*)(&As[nxt][row][kq]) = rnd4(ra[l]);
                *(float4*)(&Bs[nxt][row][kq]) = rnd4(rb[l]);
            }
        }
        __syncthreads();
    }

    // ---- epilogue ----
    float alpha = 1.0f;
    if (AMODE == 1) alpha = 1.0f / (1.0f + expf(-wscal[0]));
    if (AMODE == 2) alpha = (1.0f - 1.0f / (1.0f + expf(-wscal[0]))) * 0.5f;

    float* Cb = C + (long)b * cStr;

    if (EPI == 1) {
        float rs[4][2];
#pragma unroll
        for (int i = 0; i < 4; i++) { rs[i][0] = 0.f; rs[i][1] = 0.f; }
#pragma unroll
        for (int j = 0; j < 4; j++) {
            int col0 = bn + wn * 32 + j * 8 + lc * 2;
            float cs0 = 0.f, cs1 = 0.f;
#pragma unroll
            for (int i = 0; i < 4; i++) {
                int r0 = bm + wm * 64 + i * 16 + lr;
                float e0 = expf(acc[i][j][0]);
                float e1 = expf(acc[i][j][1]);
                float e2 = expf(acc[i][j][2]);
                float e3 = expf(acc[i][j][3]);
                Cb[(long)col0 * ldc + r0]           = e0;
                Cb[(long)(col0 + 1) * ldc + r0]     = e1;
                Cb[(long)col0 * ldc + r0 + 8]       = e2;
                Cb[(long)(col0 + 1) * ldc + r0 + 8] = e3;
                cs0 += e0 + e2; cs1 += e1 + e3;
                rs[i][0] += e0 + e1; rs[i][1] += e2 + e3;
            }
#pragma unroll
            for (int o = 4; o <= 16; o <<= 1) {
                cs0 += __shfl_xor_sync(0xffffffff, cs0, o);
                cs1 += __shfl_xor_sync(0xffffffff, cs1, o);
            }
            if (lane < 4) {
                atomicAdd(colsum + (long)b * nTot + col0, cs0);
                atomicAdd(colsum + (long)b * nTot + col0 + 1, cs1);
            }
        }
#pragma unroll
        for (int i = 0; i < 4; i++)
#pragma unroll
            for (int h = 0; h < 2; h++) {
                float v = rs[i][h];
                v += __shfl_xor_sync(0xffffffff, v, 1);
                v += __shfl_xor_sync(0xffffffff, v, 2);
                if (lc == 0) {
                    int r = bm + wm * 64 + i * 16 + lr + h * 8;
                    atomicAdd(rowsum + (long)b * mTot + r, v);
                }
            }
    } else if (EPI == 4) {
        const float* msc = MSC ? (mscale + (long)b * mTot) : nullptr;
#pragma unroll
        for (int i = 0; i < 4; i++) {
            int r0 = bm + wm * 64 + i * 16 + lr;
            float s0 = MSC ? msc[r0] : 1.0f;
            float s1 = MSC ? msc[r0 + 8] : 1.0f;
#pragma unroll
            for (int j = 0; j < 4; j++) {
                int col0 = bn + wn * 32 + j * 8 + lc * 2;
                atomicAdd(Cb + (long)r0 * ldc + col0,           acc[i][j][0] * s0);
                atomicAdd(Cb + (long)r0 * ldc + col0 + 1,       acc[i][j][1] * s0);
                atomicAdd(Cb + (long)(r0 + 8) * ldc + col0,     acc[i][j][2] * s1);
                atomicAdd(Cb + (long)(r0 + 8) * ldc + col0 + 1, acc[i][j][3] * s1);
            }
        }
    } else {
#pragma unroll
        for (int i = 0; i < 4; i++) {
#pragma unroll
            for (int h = 0; h < 2; h++) {
                int r = bm + wm * 64 + i * 16 + lr + h * 8;
                if (r >= mTot) continue;
                float* Crow = Cb + (long)r * ldc;
                const float* Srow = (EPI == 2 && addsrc) ? (addsrc + (long)b * cStr + (long)r * ldc) : nullptr;
#pragma unroll
                for (int j = 0; j < 4; j++) {
                    int col0 = bn + wn * 32 + j * 8 + lc * 2;
                    float v0 = acc[i][j][h * 2 + 0];
                    float v1 = acc[i][j][h * 2 + 1];
                    if (EPI == 2) {
                        v0 = alpha * (v0 + bias[col0]);
                        v1 = alpha * (v1 + bias[col0 + 1]);
                        if (Srow) { v0 += Srow[col0]; v1 += Srow[col0 + 1]; }
                    }
                    if (EPI == 3) {
                        float2 old = *(const float2*)(Crow + col0);
                        v0 = old.x + alpha * (v0 + bias[col0]);
                        v1 = old.y + alpha * (v1 + bias[col0 + 1]);
                    }
                    float2 o; o.x = v0; o.y = v1;
                    *(float2*)(Crow + col0) = o;
                }
            }
        }
    }
}

// ---------------- utility kernels ----------------
__global__ void zero_kernel(float* p, long n) {
    long i = (long)blockIdx.x * blockDim.x + threadIdx.x;
    long stride = (long)gridDim.x * blockDim.x;
    for (; i < n; i += stride) p[i] = 0.0f;
}
__global__ void recip_kernel(float* p, int n) {
    int i = blockIdx.x * blockDim.x + threadIdx.x;
    if (i < n) p[i] = 1.0f / p[i];
}

__global__ void ln_rows(const float* __restrict__ X, const float* __restrict__ g,
                        const float* __restrict__ bb, float* __restrict__ Y, int C)
{
    long row = blockIdx.x;
    const float* x = X + row * C;
    float s = 0.f, s2 = 0.f;
    for (int c = threadIdx.x; c < C; c += blockDim.x) { float v = x[c]; s += v; s2 += v * v; }
    __shared__ float sh1[32], sh2[32];
    int lane = threadIdx.x & 31, wid = threadIdx.x >> 5;
#pragma unroll
    for (int o = 16; o; o >>= 1) {
        s  += __shfl_down_sync(0xffffffff, s,  o);
        s2 += __shfl_down_sync(0xffffffff, s2, o);
    }
    if (!lane) { sh1[wid] = s; sh2[wid] = s2; }
    __syncthreads();
    if (threadIdx.x == 0) {
        float a = 0.f, c2 = 0.f;
        int nw = blockDim.x >> 5;
        for (int i = 0; i < nw; i++) { a += sh1[i]; c2 += sh2[i]; }
        float mean = a / C;
        float var  = c2 / C - mean * mean;
        sh1[0] = mean; sh2[0] = rsqrtf(var + 1e-5f);
    }
    __syncthreads();
    float mean = sh1[0], rstd = sh2[0];
    for (int c = threadIdx.x; c < C; c += blockDim.x) {
        float v = x[c];
        Y[row * C + c] = (v - mean) * rstd * g[c] + bb[c];
    }
}

__global__ void __launch_bounds__(256) dwconv_ln_gelu(
    const float* __restrict__ H, const float* __restrict__ Wdw,
    const float* __restrict__ bdw, const float* __restrict__ g,
    const float* __restrict__ bt, float* __restrict__ AX)
{
    const int n = blockIdx.x;
    const int b = blockIdx.y;
    const int y = n / 24, x = n % 24;
    const float* Hb = H + (long)b * 576 * 2048;
    const int tid = threadIdx.x;

    float v[8];
    float s = 0.f, s2 = 0.f;
#pragma unroll
    for (int it = 0; it < 8; it++) {
        int c = tid + it * 256;
        float a = Hb[(long)n * 2048 + c] + bdw[c];
#pragma unroll
        for (int ky = 0; ky < 3; ky++) {
            int yy = y + ky - 1;
            if (yy < 0 || yy > 23) continue;
#pragma unroll
            for (int kx = 0; kx < 3; kx++) {
                int xx = x + kx - 1;
                if (xx < 0 || xx > 23) continue;
                a += Wdw[c * 9 + ky * 3 + kx] * Hb[(long)(yy * 24 + xx) * 2048 + c];
            }
        }
        v[it] = a; s += a; s2 += a * a;
    }
    __shared__ float sh1[32], sh2[32];
    int lane = tid & 31, wid = tid >> 5;
#pragma unroll
    for (int o = 16; o; o >>= 1) {
        s  += __shfl_down_sync(0xffffffff, s,  o);
        s2 += __shfl_down_sync(0xffffffff, s2, o);
    }
    if (!lane) { sh1[wid] = s; sh2[wid] = s2; }
    __syncthreads();
    if (tid == 0) {
        float a = 0.f, c2 = 0.f;
        for (int i = 0; i < 8; i++) { a += sh1[i]; c2 += sh2[i]; }
        float mean = a / 2048.0f;
        float var  = c2 / 2048.0f - mean * mean;
        sh1[0] = mean; sh2[0] = rsqrtf(var + 1e-5f);
    }
    __syncthreads();
    float mean = sh1[0], rstd = sh2[0];
    float* out = AX + ((long)b * 576 + n) * 2048;
#pragma unroll
    for (int it = 0; it < 8; it++) {
        int c = tid + it * 256;
        float t = (v[it] - mean) * rstd * g[c] + bt[c];
        out[c] = 0.5f * t * (1.0f + erff(t * 0.70710678118654752f));
    }
}

// ---------------- host orchestration ----------------
extern "C" void kernel_launch(void* const* d_in, const int* in_sizes, int n_in,
                              void* d_out, int out_size)
{
    const float* x      = (const float*)d_in[0];
    const float* x2     = (const float*)d_in[1];
    const float* x3     = (const float*)d_in[2];
    const float* W_lin  = (const float*)d_in[3];
    const float* W_lin2 = (const float*)d_in[4];
    const float* W_lin3 = (const float*)d_in[5];
    const float* W_lin4 = (const float*)d_in[6];
    const float* w      = (const float*)d_in[7];
    const float* Wp1 = (const float*)d_in[8];  const float* bp1 = (const float*)d_in[9];
    const float* Wp2 = (const float*)d_in[10]; const float* bp2 = (const float*)d_in[11];
    const float* Wp3 = (const float*)d_in[12]; const float* bp3 = (const float*)d_in[13];
    const float* Wp4 = (const float*)d_in[14]; const float* bp4 = (const float*)d_in[15];
    const float* g_norm = (const float*)d_in[16]; const float* b_norm = (const float*)d_in[17];
    const float* Wfc1 = (const float*)d_in[18];   const float* bfc1  = (const float*)d_in[19];
    const float* Wdw  = (const float*)d_in[20];   const float* bdw   = (const float*)d_in[21];
    const float* g_ln1 = (const float*)d_in[22];  const float* b_ln1 = (const float*)d_in[23];
    const float* Wfc2 = (const float*)d_in[24];   const float* bfc2  = (const float*)d_in[25];

    float* pool = nullptr;
    cudaGetSymbolAddress((void**)&pool, g_pool);

    // 0) zero stats + S accumulators
    zero_kernel<<<1024, 256>>>(pool, ZERO_CNT);

    // 1) Et1 = exp(x @ W_lin^T)^T + softmax stats     [B,512,9216]
    tgemm<1,0,false,false><<<dim3(4,72,BB), 256>>>(
        x, (long)N1_*D0_, D0_, W_lin, 0L, D0_,
        pool+OFF_ET1, (long)D2_*N1_, N1_,
        N1_, D2_, D0_, 1,
        nullptr, nullptr, nullptr, pool+OFF_R1, pool+OFF_C1, nullptr, nullptr);

    // 2) Et2 = exp(x2 @ W_lin2^T)^T + stats           [B,512,2304]
    tgemm<1,0,false,false><<<dim3(4,18,BB), 256>>>(
        x2, (long)N2_*D1_, D1_, W_lin2, 0L, D1_,
        pool+OFF_ET2, (long)D2_*N2_, N2_,
        N2_, D2_, D1_, 1,
        nullptr, nullptr, nullptr, pool+OFF_R2, pool+OFF_C2, nullptr, nullptr);

    // 3) Et4 = exp(x @ W_lin3^T)^T + stats            [B,256,9216]
    tgemm<1,0,false,false><<<dim3(2,72,BB), 256>>>(
        x, (long)N1_*D0_, D0_, W_lin3, 0L, D0_,
        pool+OFF_ET4, (long)D1_*N1_, N1_,
        N1_, D1_, D0_, 1,
        nullptr, nullptr, nullptr, pool+OFF_R4, pool+OFF_C4, nullptr, nullptr);

    // 4) reciprocal of stats (R1,C1,R2,C2,R4,C4)
    recip_kernel<<<(88064 + 255) / 256, 256>>>(pool, 88064);

    // 5) St1[c][c3] = cinv[c] * sum_tok Et1[c][tok]*rinv[tok]*Et1[c3][tok]   split-K 8
    tgemm<4,0,true,true><<<dim3(4,4,BB*8), 256>>>(
        pool+OFF_ET1, (long)D2_*N1_, N1_, pool+OFF_ET1, (long)D2_*N1_, N1_,
        pool+OFF_ST1, (long)D2_*D2_, D2_,
        D2_, D2_, N1_, 8,
        nullptr, nullptr, nullptr, nullptr, nullptr, pool+OFF_R1, pool+OFF_C1);

    // 6) St2 (K=2304, split 4)
    tgemm<4,0,true,true><<<dim3(4,4,BB*4), 256>>>(
        pool+OFF_ET2, (long)D2_*N2_, N2_, pool+OFF_ET2, (long)D2_*N2_, N2_,
        pool+OFF_ST2, (long)D2_*D2_, D2_,
        D2_, D2_, N2_, 4,
        nullptr, nullptr, nullptr, nullptr, nullptr, pool+OFF_R2, pool+OFF_C2);

    // 7) St3 (C=256, K=9216, split 8)
    tgemm<4,0,true,true><<<dim3(2,2,BB*8), 256>>>(
        pool+OFF_ET4, (long)D1_*N1_, N1_, pool+OFF_ET4, (long)D1_*N1_, N1_,
        pool+OFF_ST3, (long)D1_*D1_, D1_,
        D1_, D1_, N1_, 8,
        nullptr, nullptr, nullptr, nullptr, nullptr, pool+OFF_R4, pool+OFF_C4);

    // 8) T = x3 @ S1   (B operand = St1 row-major)
    tgemm<0,0,false,false><<<dim3(4,5,BB), 256>>>(
        x3, (long)N3_*D2_, D2_, pool+OFF_ST1, (long)D2_*D2_, D2_,
        pool+OFF_T, (long)N3_*D2_, D2_,
        N3_, D2_, D2_, 1,
        nullptr, nullptr, nullptr, nullptr, nullptr, nullptr, nullptr);
    // 9) ATT = x3 + other*(T @ Wp1^T + bp1)
    tgemm<2,2,false,false><<<dim3(4,5,BB), 256>>>(
        pool+OFF_T, (long)N3_*D2_, D2_, Wp1, 0L, D2_,
        pool+OFF_ATT, (long)N3_*D2_, D2_,
        N3_, D2_, D2_, 1,
        bp1, x3, w, nullptr, nullptr, nullptr, nullptr);

    // 10) T = x3 @ S2 ; ATT += other*(T @ Wp2^T + bp2)
    tgemm<0,0,false,false><<<dim3(4,5,BB), 256>>>(
        x3, (long)N3_*D2_, D2_, pool+OFF_ST2, (long)D2_*D2_, D2_,
        pool+OFF_T, (long)N3_*D2_, D2_,
        N3_, D2_, D2_, 1,
        nullptr, nullptr, nullptr, nullptr, nullptr, nullptr, nullptr);
    tgemm<3,2,false,false><<<dim3(4,5,BB), 256>>>(
        pool+OFF_T, (long)N3_*D2_, D2_, Wp2, 0L, D2_,
        pool+OFF_ATT, (long)N3_*D2_, D2_,
        N3_, D2_, D2_, 1,
        bp2, nullptr, w, nullptr, nullptr, nullptr, nullptr);

    // 12) T3 = x2 @ S3   [B,2304,256]
    tgemm<0,0,false,false><<<dim3(2,18,BB), 256>>>(
        x2, (long)N2_*D1_, D1_, pool+OFF_ST3, (long)D1_*D1_, D1_,
        pool+OFF_T3, (long)N2_*D1_, D1_,
        N2_, D1_, D1_, 1,
        nullptr, nullptr, nullptr, nullptr, nullptr, nullptr, nullptr);
    // 13) A3 = T3 @ Wp3^T + bp3
    tgemm<2,0,false,false><<<dim3(2,18,BB), 256>>>(
        pool+OFF_T3, (long)N2_*D1_, D1_, Wp3, 0L, D1_,
        pool+OFF_A3, (long)N2_*D1_, D1_,
        N2_, D1_, D1_, 1,
        bp3, nullptr, nullptr, nullptr, nullptr, nullptr, nullptr);
    // 14) EtA = exp(A3 @ W_lin4^T)^T + stats   [B,512,2304]
    tgemm<1,0,false,false><<<dim3(4,18,BB), 256>>>(
        pool+OFF_A3, (long)N2_*D1_, D1_, W_lin4, 0L, D1_,
        pool+OFF_ETA, (long)D2_*N2_, N2_,
        N2_, D2_, D1_, 1,
        nullptr, nullptr, nullptr, pool+OFF_RA, pool+OFF_CA, nullptr, nullptr);
    // 15) reciprocal of RA,CA
    recip_kernel<<<(11264 + 255) / 256, 256>>>(pool + OFF_RA, 11264);
    // 16) St4 (K=2304, split 4)
    tgemm<4,0,true,true><<<dim3(4,4,BB*4), 256>>>(
        pool+OFF_ETA, (long)D2_*N2_, N2_, pool+OFF_ETA, (long)D2_*N2_, N2_,
        pool+OFF_ST4, (long)D2_*D2_, D2_,
        D2_, D2_, N2_, 4,
        nullptr, nullptr, nullptr, nullptr, nullptr, pool+OFF_RA, pool+OFF_CA);
    // 17) T = x3 @ S4 ; ATT += f*(T @ Wp4^T + bp4)
    tgemm<0,0,false,false><<<dim3(4,5,BB), 256>>>(
        x3, (long)N3_*D2_, D2_, pool+OFF_ST4, (long)D2_*D2_, D2_,
        pool+OFF_T, (long)N3_*D2_, D2_,
        N3_, D2_, D2_, 1,
        nullptr, nullptr, nullptr, nullptr, nullptr, nullptr, nullptr);
    tgemm<3,1,false,false><<<dim3(4,5,BB), 256>>>(
        pool+OFF_T, (long)N3_*D2_, D2_, Wp4, 0L, D2_,
        pool+OFF_ATT, (long)N3_*D2_, D2_,
        N3_, D2_, D2_, 1,
        bp4, nullptr, w, nullptr, nullptr, nullptr, nullptr);

    // 19) AN = LN(ATT)
    ln_rows<<<BB * N3_, 256>>>(pool + OFF_ATT, g_norm, b_norm, pool + OFF_AN, D2_);

    // 20) H = AN @ Wfc1^T + bfc1   [B,576,2048]
    tgemm<2,0,false,false><<<dim3(16,5,BB), 256>>>(
        pool+OFF_AN, (long)N3_*D2_, D2_, Wfc1, 0L, D2_,
        pool+OFF_H, (long)N3_*DH_, DH_,
        N3_, DH_, D2_, 1,
        bfc1, nullptr, nullptr, nullptr, nullptr, nullptr, nullptr);

    // 21) AX = gelu(LN(dwconv(H)+bdw+H))
    dwconv_ln_gelu<<<dim3(N3_, BB), 256>>>(pool + OFF_H, Wdw, bdw, g_ln1, b_ln1, pool + OFF_AX);

    // 22) out = ATT + AX @ Wfc2^T + bfc2
    tgemm<2,0,false,false><<<dim3(4,5,BB), 256>>>(
        pool+OFF_AX, (long)N3_*DH_, DH_, Wfc2, 0L, DH_,
        (float*)d_out, (long)N3_*D2_, D2_,
        N3_, D2_, DH_, 1,
        bfc2, pool+OFF_ATT, nullptr, nullptr, nullptr, nullptr, nullptr);
}

// round 6
// speedup vs baseline: 1.1167x; 1.1167x over previous
#include <cuda_runtime.h>
#include <math.h>
#include <stdint.h>

// ---------------- problem dims ----------------
#define BB   4
#define N1_  9216
#define N2_  2304
#define N3_  576
#define D0_  128
#define D1_  256
#define D2_  512
#define DH_  2048

// ---------------- scratch pool (floats) ----------------
#define OFF_R1   0L
#define OFF_C1   36864L
#define OFF_R2   38912L
#define OFF_C2   48128L
#define OFF_R4   50176L
#define OFF_C4   87040L
#define OFF_RA   88064L
#define OFF_CA   97280L
#define OFF_ST1  99328L
#define OFF_ST2  1147904L
#define OFF_ST3  2196480L
#define OFF_ST4  2458624L
#define ZERO_CNT 3507200L
#define OFF_ET1  3507200L
#define OFF_ET2  22381568L
#define OFF_ET4  27100160L
#define OFF_ETA  36537344L
#define OFF_T    41255936L
#define OFF_T3   42435584L
#define OFF_A3   44794880L
#define OFF_ATT  47154176L
#define OFF_AN   48333824L
#define OFF_H    49513472L
#define OFF_AX   54232064L
#define POOL_SZ  58950656L

__device__ float g_pool[POOL_SZ];

// ---------------- helpers ----------------
__device__ __forceinline__ uint32_t smem_u32(const void* p) {
    uint32_t a;
    asm("{ .reg .u64 t; cvta.to.shared.u64 t, %1; cvt.u32.u64 %0, t; }" : "=r"(a) : "l"(p));
    return a;
}
__device__ __forceinline__ float to_tf32(float x) {
    float y;
    asm("cvt.rna.tf32.f32 %0, %1;" : "=f"(y) : "f"(x));
    return y;
}
__device__ __forceinline__ float4 rnd4(float4 v) {
    v.x = to_tf32(v.x); v.y = to_tf32(v.y); v.z = to_tf32(v.z); v.w = to_tf32(v.w);
    return v;
}
__device__ __forceinline__ void mma_tf32(float* d, const uint32_t* a, const uint32_t* bf) {
    asm volatile(
        "mma.sync.aligned.m16n8k8.row.col.f32.tf32.tf32.f32 "
        "{%0,%1,%2,%3}, {%4,%5,%6,%7}, {%8,%9}, {%0,%1,%2,%3};"
        : "+f"(d[0]), "+f"(d[1]), "+f"(d[2]), "+f"(d[3])
        : "r"(a[0]), "r"(a[1]), "r"(a[2]), "r"(a[3]), "r"(bf[0]), "r"(bf[1]));
}
__device__ __forceinline__ void ldm_x4(uint32_t* r, uint32_t addr) {
    asm volatile("ldmatrix.sync.aligned.m8n8.x4.shared.b16 {%0,%1,%2,%3}, [%4];"
        : "=r"(r[0]), "=r"(r[1]), "=r"(r[2]), "=r"(r[3]) : "r"(addr));
}
__device__ __forceinline__ void ldm_x2(uint32_t* r, uint32_t addr) {
    asm volatile("ldmatrix.sync.aligned.m8n8.x2.shared.b16 {%0,%1}, [%2];"
        : "=r"(r[0]), "=r"(r[1]) : "r"(addr));
}

// ================= tf32 mma.sync NT GEMM =================
// D[m][n] = sum_k A[m][k] * B[n][k], 128x128 CTA tile, BK=16,
// 256 threads = 8 warps, warp tile 64x32, double-buffered smem
// (stride-20 pad: rows 80B = 16B-aligned, conflict-free for ldmatrix),
// fragments via ldmatrix.x4 (A) / ldmatrix.x2 (B).
// EPI 0: C[m][n] = acc
// EPI 1: e = exp(acc); Et[n][m] = e; atomic rowsum[m] += sum_n e; colsum[n] += sum_m e
// EPI 2: C[m][n] = alpha*(acc + bias[n]) + (addsrc ? addsrc[m][n] : 0)
// EPI 3: C[m][n] += alpha*(acc + bias[n])
// EPI 4: atomicAdd(C[m][n], acc * mscale[m])           (split-K S-gemm, coalesced)
// AMODE: 0 alpha=1 ; 1 alpha=sigmoid(*wscal) ; 2 alpha=(1-sigmoid)/2
// KSC: B *= kscale[k] at load ; MSC: use mscale in EPI4
template<int EPI, int AMODE, bool KSC, bool MSC>
__global__ void __launch_bounds__(256, 2) tgemm(
    const float* __restrict__ A, long aStr, int lda,
    const float* __restrict__ Bm, long bStr, int ldb,
    float* __restrict__ C, long cStr, int ldc,
    int mTot, int nTot, int kTot, int splits,
    const float* __restrict__ bias,
    const float* __restrict__ addsrc,
    const float* __restrict__ wscal,
    float* __restrict__ rowsum, float* __restrict__ colsum,
    const float* __restrict__ kscale, const float* __restrict__ mscale)
{
    __shared__ float As[2][128][20];
    __shared__ float Bs[2][128][20];

    const int z = blockIdx.z;
    const int b = z / splits, sp = z % splits;
    const int Kc = kTot / splits;
    const int kbase = sp * Kc;
    const int nt = Kc >> 4;

    const float* Ab = A + (long)b * aStr;
    const float* Bb = Bm + (long)b * bStr;
    const float* ksc_b = KSC ? (kscale + (long)b * kTot) : nullptr;

    const int bm = blockIdx.y * 128;
    const int bn = blockIdx.x * 128;
    const int tid = threadIdx.x;
    const int wid = tid >> 5, lane = tid & 31;
    const int wm = wid & 1, wn = wid >> 1;        // warp tile: rows wm*64, cols wn*32
    const int lr = lane >> 2, lc = lane & 3;

    // ldmatrix per-thread base addresses (bytes, shared space)
    const int m8 = lane >> 3;        // matrix index 0..3
    const int r8 = lane & 7;
    const uint32_t asBase = smem_u32(As) +
        (uint32_t)(((wm * 64 + (m8 & 1) * 8 + r8) * 20 + (m8 >> 1) * 4) * 4);
    const uint32_t bsBase = smem_u32(Bs) +
        (uint32_t)(((wn * 32 + r8) * 20 + ((lane >> 3) & 1) * 4) * 4);
    const uint32_t BUFB = 128 * 20 * 4;   // 10240 bytes per buffer

    float acc[4][4][4];
#pragma unroll
    for (int i = 0; i < 4; i++)
#pragma unroll
        for (int j = 0; j < 4; j++)
#pragma unroll
            for (int r = 0; r < 4; r++) acc[i][j][r] = 0.0f;

    // ---- initial tile -> buffer 0 ----
    {
        const int k0 = kbase;
#pragma unroll
        for (int l = 0; l < 2; l++) {
            int idx = tid + (l << 8);
            int row = idx >> 2, kq = (idx & 3) << 2;
            int gr = bm + row;
            float4 va = make_float4(0.f, 0.f, 0.f, 0.f);
            if (gr < mTot) va = *(const float4*)(Ab + (long)gr * lda + k0 + kq);
            float4 vb = *(const float4*)(Bb + (long)(bn + row) * ldb + k0 + kq);
            if (KSC) {
                float4 ks = *(const float4*)(ksc_b + k0 + kq);
                vb.x *= ks.x; vb.y *= ks.y; vb.z *= ks.z; vb.w *= ks.w;
            }
            *(float4*)(&As[0][row][kq]) = rnd4(va);
            *(float4*)(&Bs[0][row][kq]) = rnd4(vb);
        }
    }
    __syncthreads();

    for (int t = 0; t < nt; t++) {
        const int cur = t & 1;
        const uint32_t aCur = asBase + cur * BUFB;
        const uint32_t bCur = bsBase + cur * BUFB;
        float4 ra[2], rb[2];
        if (t + 1 < nt) {
            const int k0 = kbase + ((t + 1) << 4);
#pragma unroll
            for (int l = 0; l < 2; l++) {
                int idx = tid + (l << 8);
                int row = idx >> 2, kq = (idx & 3) << 2;
                int gr = bm + row;
                float4 va = make_float4(0.f, 0.f, 0.f, 0.f);
                if (gr < mTot) va = *(const float4*)(Ab + (long)gr * lda + k0 + kq);
                ra[l] = va;
                float4 vb = *(const float4*)(Bb + (long)(bn + row) * ldb + k0 + kq);
                if (KSC) {
                    float4 ks = *(const float4*)(ksc_b + k0 + kq);
                    vb.x *= ks.x; vb.y *= ks.y; vb.z *= ks.z; vb.w *= ks.w;
                }
                rb[l] = vb;
            }
        }
        // ---- MMA on buffer cur (fragments via ldmatrix) ----
#pragma unroll
        for (int ks = 0; ks < 2; ks++) {
            uint32_t af[4][4];
#pragma unroll
            for (int i = 0; i < 4; i++)
                ldm_x4(af[i], aCur + i * 1280 + ks * 32);
            uint32_t bf[4][2];
#pragma unroll
            for (int j = 0; j < 4; j++)
                ldm_x2(bf[j], bCur + j * 640 + ks * 32);
#pragma unroll
            for (int i = 0; i < 4; i++)
#pragma unroll
                for (int j = 0; j < 4; j++)
                    mma_tf32(acc[i][j], af[i], bf[j]);
        }
        if (t + 1 < nt) {
            const int nxt = (t + 1) & 1;
#pragma unroll
            for (int l = 0; l < 2; l++) {
                int idx = tid + (l << 8);
                int row = idx >> 2, kq = (idx & 3) << 2;
                *(float4*)(&As[nxt][row][kq]) = rnd4(ra[l]);
                *(float4*)(&Bs[nxt][row][kq]) = rnd4(rb[l]);
            }
        }
        __syncthreads();
    }

    // ---- epilogue ----
    float alpha = 1.0f;
    if (AMODE == 1) alpha = 1.0f / (1.0f + expf(-wscal[0]));
    if (AMODE == 2) alpha = (1.0f - 1.0f / (1.0f + expf(-wscal[0]))) * 0.5f;

    float* Cb = C + (long)b * cStr;

    if (EPI == 1) {
        float rs[4][2];
#pragma unroll
        for (int i = 0; i < 4; i++) { rs[i][0] = 0.f; rs[i][1] = 0.f; }
#pragma unroll
        for (int j = 0; j < 4; j++) {
            int col0 = bn + wn * 32 + j * 8 + lc * 2;
            float cs0 = 0.f, cs1 = 0.f;
#pragma unroll
            for (int i = 0; i < 4; i++) {
                int r0 = bm + wm * 64 + i * 16 + lr;
                float e0 = expf(acc[i][j][0]);
                float e1 = expf(acc[i][j][1]);
                float e2 = expf(acc[i][j][2]);
                float e3 = expf(acc[i][j][3]);
                Cb[(long)col0 * ldc + r0]           = e0;
                Cb[(long)(col0 + 1) * ldc + r0]     = e1;
                Cb[(long)col0 * ldc + r0 + 8]       = e2;
                Cb[(long)(col0 + 1) * ldc + r0 + 8] = e3;
                cs0 += e0 + e2; cs1 += e1 + e3;
                rs[i][0] += e0 + e1; rs[i][1] += e2 + e3;
            }
#pragma unroll
            for (int o = 4; o <= 16; o <<= 1) {
                cs0 += __shfl_xor_sync(0xffffffff, cs0, o);
                cs1 += __shfl_xor_sync(0xffffffff, cs1, o);
            }
            if (lane < 4) {
                atomicAdd(colsum + (long)b * nTot + col0, cs0);
                atomicAdd(colsum + (long)b * nTot + col0 + 1, cs1);
            }
        }
#pragma unroll
        for (int i = 0; i < 4; i++)
#pragma unroll
            for (int h = 0; h < 2; h++) {
                float v = rs[i][h];
                v += __shfl_xor_sync(0xffffffff, v, 1);
                v += __shfl_xor_sync(0xffffffff, v, 2);
                if (lc == 0) {
                    int r = bm + wm * 64 + i * 16 + lr + h * 8;
                    atomicAdd(rowsum + (long)b * mTot + r, v);
                }
            }
    } else if (EPI == 4) {
        const float* msc = MSC ? (mscale + (long)b * mTot) : nullptr;
#pragma unroll
        for (int i = 0; i < 4; i++) {
            int r0 = bm + wm * 64 + i * 16 + lr;
            float s0 = MSC ? msc[r0] : 1.0f;
            float s1 = MSC ? msc[r0 + 8] : 1.0f;
#pragma unroll
            for (int j = 0; j < 4; j++) {
                int col0 = bn + wn * 32 + j * 8 + lc * 2;
                atomicAdd(Cb + (long)r0 * ldc + col0,           acc[i][j][0] * s0);
                atomicAdd(Cb + (long)r0 * ldc + col0 + 1,       acc[i][j][1] * s0);
                atomicAdd(Cb + (long)(r0 + 8) * ldc + col0,     acc[i][j][2] * s1);
                atomicAdd(Cb + (long)(r0 + 8) * ldc + col0 + 1, acc[i][j][3] * s1);
            }
        }
    } else {
#pragma unroll
        for (int i = 0; i < 4; i++) {
#pragma unroll
            for (int h = 0; h < 2; h++) {
                int r = bm + wm * 64 + i * 16 + lr + h * 8;
                if (r >= mTot) continue;
                float* Crow = Cb + (long)r * ldc;
                const float* Srow = (EPI == 2 && addsrc) ? (addsrc + (long)b * cStr + (long)r * ldc) : nullptr;
#pragma unroll
                for (int j = 0; j < 4; j++) {
                    int col0 = bn + wn * 32 + j * 8 + lc * 2;
                    float v0 = acc[i][j][h * 2 + 0];
                    float v1 = acc[i][j][h * 2 + 1];
                    if (EPI == 2) {
                        v0 = alpha * (v0 + bias[col0]);
                        v1 = alpha * (v1 + bias[col0 + 1]);
                        if (Srow) { v0 += Srow[col0]; v1 += Srow[col0 + 1]; }
                    }
                    if (EPI == 3) {
                        float2 old = *(const float2*)(Crow + col0);
                        v0 = old.x + alpha * (v0 + bias[col0]);
                        v1 = old.y + alpha * (v1 + bias[col0 + 1]);
                    }
                    float2 o; o.x = v0; o.y = v1;
                    *(float2*)(Crow + col0) = o;
                }
            }
        }
    }
}

// ---------------- utility kernels ----------------
__global__ void zero_kernel(float* p, long n) {
    long i = (long)blockIdx.x * blockDim.x + threadIdx.x;
    long stride = (long)gridDim.x * blockDim.x;
    for (; i < n; i += stride) p[i] = 0.0f;
}
__global__ void recip_kernel(float* p, int n) {
    int i = blockIdx.x * blockDim.x + threadIdx.x;
    if (i < n) p[i] = 1.0f / p[i];
}

__global__ void ln_rows(const float* __restrict__ X, const float* __restrict__ g,
                        const float* __restrict__ bb, float* __restrict__ Y, int C)
{
    long row = blockIdx.x;
    const float* x = X + row * C;
    float s = 0.f, s2 = 0.f;
    for (int c = threadIdx.x; c < C; c += blockDim.x) { float v = x[c]; s += v; s2 += v * v; }
    __shared__ float sh1[32], sh2[32];
    int lane = threadIdx.x & 31, wid = threadIdx.x >> 5;
#pragma unroll
    for (int o = 16; o; o >>= 1) {
        s  += __shfl_down_sync(0xffffffff, s,  o);
        s2 += __shfl_down_sync(0xffffffff, s2, o);
    }
    if (!lane) { sh1[wid] = s; sh2[wid] = s2; }
    __syncthreads();
    if (threadIdx.x == 0) {
        float a = 0.f, c2 = 0.f;
        int nw = blockDim.x >> 5;
        for (int i = 0; i < nw; i++) { a += sh1[i]; c2 += sh2[i]; }
        float mean = a / C;
        float var  = c2 / C - mean * mean;
        sh1[0] = mean; sh2[0] = rsqrtf(var + 1e-5f);
    }
    __syncthreads();
    float mean = sh1[0], rstd = sh2[0];
    for (int c = threadIdx.x; c < C; c += blockDim.x) {
        float v = x[c];
        Y[row * C + c] = (v - mean) * rstd * g[c] + bb[c];
    }
}

__global__ void __launch_bounds__(256) dwconv_ln_gelu(
    const float* __restrict__ H, const float* __restrict__ Wdw,
    const float* __restrict__ bdw, const float* __restrict__ g,
    const float* __restrict__ bt, float* __restrict__ AX)
{
    const int n = blockIdx.x;
    const int b = blockIdx.y;
    const int y = n / 24, x = n % 24;
    const float* Hb = H + (long)b * 576 * 2048;
    const int tid = threadIdx.x;

    float v[8];
    float s = 0.f, s2 = 0.f;
#pragma unroll
    for (int it = 0; it < 8; it++) {
        int c = tid + it * 256;
        float a = Hb[(long)n * 2048 + c] + bdw[c];
#pragma unroll
        for (int ky = 0; ky < 3; ky++) {
            int yy = y + ky - 1;
            if (yy < 0 || yy > 23) continue;
#pragma unroll
            for (int kx = 0; kx < 3; kx++) {
                int xx = x + kx - 1;
                if (xx < 0 || xx > 23) continue;
                a += Wdw[c * 9 + ky * 3 + kx] * Hb[(long)(yy * 24 + xx) * 2048 + c];
            }
        }
        v[it] = a; s += a; s2 += a * a;
    }
    __shared__ float sh1[32], sh2[32];
    int lane = tid & 31, wid = tid >> 5;
#pragma unroll
    for (int o = 16; o; o >>= 1) {
        s  += __shfl_down_sync(0xffffffff, s,  o);
        s2 += __shfl_down_sync(0xffffffff, s2, o);
    }
    if (!lane) { sh1[wid] = s; sh2[wid] = s2; }
    __syncthreads();
    if (tid == 0) {
        float a = 0.f, c2 = 0.f;
        for (int i = 0; i < 8; i++) { a += sh1[i]; c2 += sh2[i]; }
        float mean = a / 2048.0f;
        float var  = c2 / 2048.0f - mean * mean;
        sh1[0] = mean; sh2[0] = rsqrtf(var + 1e-5f);
    }
    __syncthreads();
    float mean = sh1[0], rstd = sh2[0];
    float* out = AX + ((long)b * 576 + n) * 2048;
#pragma unroll
    for (int it = 0; it < 8; it++) {
        int c = tid + it * 256;
        float t = (v[it] - mean) * rstd * g[c] + bt[c];
        out[c] = 0.5f * t * (1.0f + erff(t * 0.70710678118654752f));
    }
}

// ---------------- host orchestration ----------------
extern "C" void kernel_launch(void* const* d_in, const int* in_sizes, int n_in,
                              void* d_out, int out_size)
{
    const float* x      = (const float*)d_in[0];
    const float* x2     = (const float*)d_in[1];
    const float* x3     = (const float*)d_in[2];
    const float* W_lin  = (const float*)d_in[3];
    const float* W_lin2 = (const float*)d_in[4];
    const float* W_lin3 = (const float*)d_in[5];
    const float* W_lin4 = (const float*)d_in[6];
    const float* w      = (const float*)d_in[7];
    const float* Wp1 = (const float*)d_in[8];  const float* bp1 = (const float*)d_in[9];
    const float* Wp2 = (const float*)d_in[10]; const float* bp2 = (const float*)d_in[11];
    const float* Wp3 = (const float*)d_in[12]; const float* bp3 = (const float*)d_in[13];
    const float* Wp4 = (const float*)d_in[14]; const float* bp4 = (const float*)d_in[15];
    const float* g_norm = (const float*)d_in[16]; const float* b_norm = (const float*)d_in[17];
    const float* Wfc1 = (const float*)d_in[18];   const float* bfc1  = (const float*)d_in[19];
    const float* Wdw  = (const float*)d_in[20];   const float* bdw   = (const float*)d_in[21];
    const float* g_ln1 = (const float*)d_in[22];  const float* b_ln1 = (const float*)d_in[23];
    const float* Wfc2 = (const float*)d_in[24];   const float* bfc2  = (const float*)d_in[25];

    float* pool = nullptr;
    cudaGetSymbolAddress((void**)&pool, g_pool);

    // 0) zero stats + S accumulators
    zero_kernel<<<1024, 256>>>(pool, ZERO_CNT);

    // 1) Et1 = exp(x @ W_lin^T)^T + softmax stats     [B,512,9216]
    tgemm<1,0,false,false><<<dim3(4,72,BB), 256>>>(
        x, (long)N1_*D0_, D0_, W_lin, 0L, D0_,
        pool+OFF_ET1, (long)D2_*N1_, N1_,
        N1_, D2_, D0_, 1,
        nullptr, nullptr, nullptr, pool+OFF_R1, pool+OFF_C1, nullptr, nullptr);

    // 2) Et2 = exp(x2 @ W_lin2^T)^T + stats           [B,512,2304]
    tgemm<1,0,false,false><<<dim3(4,18,BB), 256>>>(
        x2, (long)N2_*D1_, D1_, W_lin2, 0L, D1_,
        pool+OFF_ET2, (long)D2_*N2_, N2_,
        N2_, D2_, D1_, 1,
        nullptr, nullptr, nullptr, pool+OFF_R2, pool+OFF_C2, nullptr, nullptr);

    // 3) Et4 = exp(x @ W_lin3^T)^T + stats            [B,256,9216]
    tgemm<1,0,false,false><<<dim3(2,72,BB), 256>>>(
        x, (long)N1_*D0_, D0_, W_lin3, 0L, D0_,
        pool+OFF_ET4, (long)D1_*N1_, N1_,
        N1_, D1_, D0_, 1,
        nullptr, nullptr, nullptr, pool+OFF_R4, pool+OFF_C4, nullptr, nullptr);

    // 4) reciprocal of stats (R1,C1,R2,C2,R4,C4)
    recip_kernel<<<(88064 + 255) / 256, 256>>>(pool, 88064);

    // 5) St1[c][c3] = cinv[c] * sum_tok Et1[c][tok]*rinv[tok]*Et1[c3][tok]   split-K 8
    tgemm<4,0,true,true><<<dim3(4,4,BB*8), 256>>>(
        pool+OFF_ET1, (long)D2_*N1_, N1_, pool+OFF_ET1, (long)D2_*N1_, N1_,
        pool+OFF_ST1, (long)D2_*D2_, D2_,
        D2_, D2_, N1_, 8,
        nullptr, nullptr, nullptr, nullptr, nullptr, pool+OFF_R1, pool+OFF_C1);

    // 6) St2 (K=2304, split 4)
    tgemm<4,0,true,true><<<dim3(4,4,BB*4), 256>>>(
        pool+OFF_ET2, (long)D2_*N2_, N2_, pool+OFF_ET2, (long)D2_*N2_, N2_,
        pool+OFF_ST2, (long)D2_*D2_, D2_,
        D2_, D2_, N2_, 4,
        nullptr, nullptr, nullptr, nullptr, nullptr, pool+OFF_R2, pool+OFF_C2);

    // 7) St3 (C=256, K=9216, split 8)
    tgemm<4,0,true,true><<<dim3(2,2,BB*8), 256>>>(
        pool+OFF_ET4, (long)D1_*N1_, N1_, pool+OFF_ET4, (long)D1_*N1_, N1_,
        pool+OFF_ST3, (long)D1_*D1_, D1_,
        D1_, D1_, N1_, 8,
        nullptr, nullptr, nullptr, nullptr, nullptr, pool+OFF_R4, pool+OFF_C4);

    // 8) T = x3 @ S1   (B operand = St1 row-major)
    tgemm<0,0,false,false><<<dim3(4,5,BB), 256>>>(
        x3, (long)N3_*D2_, D2_, pool+OFF_ST1, (long)D2_*D2_, D2_,
        pool+OFF_T, (long)N3_*D2_, D2_,
        N3_, D2_, D2_, 1,
        nullptr, nullptr, nullptr, nullptr, nullptr, nullptr, nullptr);
    // 9) ATT = x3 + other*(T @ Wp1^T + bp1)
    tgemm<2,2,false,false><<<dim3(4,5,BB), 256>>>(
        pool+OFF_T, (long)N3_*D2_, D2_, Wp1, 0L, D2_,
        pool+OFF_ATT, (long)N3_*D2_, D2_,
        N3_, D2_, D2_, 1,
        bp1, x3, w, nullptr, nullptr, nullptr, nullptr);

    // 10) T = x3 @ S2 ; ATT += other*(T @ Wp2^T + bp2)
    tgemm<0,0,false,false><<<dim3(4,5,BB), 256>>>(
        x3, (long)N3_*D2_, D2_, pool+OFF_ST2, (long)D2_*D2_, D2_,
        pool+OFF_T, (long)N3_*D2_, D2_,
        N3_, D2_, D2_, 1,
        nullptr, nullptr, nullptr, nullptr, nullptr, nullptr, nullptr);
    tgemm<3,2,false,false><<<dim3(4,5,BB), 256>>>(
        pool+OFF_T, (long)N3_*D2_, D2_, Wp2, 0L, D2_,
        pool+OFF_ATT, (long)N3_*D2_, D2_,
        N3_, D2_, D2_, 1,
        bp2, nullptr, w, nullptr, nullptr, nullptr, nullptr);

    // 12) T3 = x2 @ S3   [B,2304,256]
    tgemm<0,0,false,false><<<dim3(2,18,BB), 256>>>(
        x2, (long)N2_*D1_, D1_, pool+OFF_ST3, (long)D1_*D1_, D1_,
        pool+OFF_T3, (long)N2_*D1_, D1_,
        N2_, D1_, D1_, 1,
        nullptr, nullptr, nullptr, nullptr, nullptr, nullptr, nullptr);
    // 13) A3 = T3 @ Wp3^T + bp3
    tgemm<2,0,false,false><<<dim3(2,18,BB), 256>>>(
        pool+OFF_T3, (long)N2_*D1_, D1_, Wp3, 0L, D1_,
        pool+OFF_A3, (long)N2_*D1_, D1_,
        N2_, D1_, D1_, 1,
        bp3, nullptr, nullptr, nullptr, nullptr, nullptr, nullptr);
    // 14) EtA = exp(A3 @ W_lin4^T)^T + stats   [B,512,2304]
    tgemm<1,0,false,false><<<dim3(4,18,BB), 256>>>(
        pool+OFF_A3, (long)N2_*D1_, D1_, W_lin4, 0L, D1_,
        pool+OFF_ETA, (long)D2_*N2_, N2_,
        N2_, D2_, D1_, 1,
        nullptr, nullptr, nullptr, pool+OFF_RA, pool+OFF_CA, nullptr, nullptr);
    // 15) reciprocal of RA,CA
    recip_kernel<<<(11264 + 255) / 256, 256>>>(pool + OFF_RA, 11264);
    // 16) St4 (K=2304, split 4)
    tgemm<4,0,true,true><<<dim3(4,4,BB*4), 256>>>(
        pool+OFF_ETA, (long)D2_*N2_, N2_, pool+OFF_ETA, (long)D2_*N2_, N2_,
        pool+OFF_ST4, (long)D2_*D2_, D2_,
        D2_, D2_, N2_, 4,
        nullptr, nullptr, nullptr, nullptr, nullptr, pool+OFF_RA, pool+OFF_CA);
    // 17) T = x3 @ S4 ; ATT += f*(T @ Wp4^T + bp4)
    tgemm<0,0,false,false><<<dim3(4,5,BB), 256>>>(
        x3, (long)N3_*D2_, D2_, pool+OFF_ST4, (long)D2_*D2_, D2_,
        pool+OFF_T, (long)N3_*D2_, D2_,
        N3_, D2_, D2_, 1,
        nullptr, nullptr, nullptr, nullptr, nullptr, nullptr, nullptr);
    tgemm<3,1,false,false><<<dim3(4,5,BB), 256>>>(
        pool+OFF_T, (long)N3_*D2_, D2_, Wp4, 0L, D2_,
        pool+OFF_ATT, (long)N3_*D2_, D2_,
        N3_, D2_, D2_, 1,
        bp4, nullptr, w, nullptr, nullptr, nullptr, nullptr);

    // 19) AN = LN(ATT)
    ln_rows<<<BB * N3_, 256>>>(pool + OFF_ATT, g_norm, b_norm, pool + OFF_AN, D2_);

    // 20) H = AN @ Wfc1^T + bfc1   [B,576,2048]
    tgemm<2,0,false,false><<<dim3(16,5,BB), 256>>>(
        pool+OFF_AN, (long)N3_*D2_, D2_, Wfc1, 0L, D2_,
        pool+OFF_H, (long)N3_*DH_, DH_,
        N3_, DH_, D2_, 1,
        bfc1, nullptr, nullptr, nullptr, nullptr, nullptr, nullptr);

    // 21) AX = gelu(LN(dwconv(H)+bdw+H))
    dwconv_ln_gelu<<<dim3(N3_, BB), 256>>>(pool + OFF_H, Wdw, bdw, g_ln1, b_ln1, pool + OFF_AX);

    // 22) out = ATT + AX @ Wfc2^T + bfc2
    tgemm<2,0,false,false><<<dim3(4,5,BB), 256>>>(
        pool+OFF_AX, (long)N3_*DH_, DH_, Wfc2, 0L, DH_,
        (float*)d_out, (long)N3_*D2_, D2_,
        N3_, D2_, DH_, 1,
        bfc2, pool+OFF_ATT, nullptr, nullptr, nullptr, nullptr, nullptr);
}

// round 7
// speedup vs baseline: 1.1307x; 1.0125x over previous
#include <cuda_runtime.h>
#include <math.h>
#include <stdint.h>

// ---------------- problem dims ----------------
#define BB   4
#define N1_  9216
#define N2_  2304
#define N3_  576
#define D0_  128
#define D1_  256
#define D2_  512
#define DH_  2048

// ---------------- scratch pool (floats) ----------------
#define OFF_R1   0L
#define OFF_C1   36864L
#define OFF_R2   38912L
#define OFF_C2   48128L
#define OFF_R4   50176L
#define OFF_C4   87040L
#define OFF_RA   88064L
#define OFF_CA   97280L
#define OFF_ST12 99328L            // [B][1024][512]  (St1 rows 0-511, St2 rows 512-1023)
#define OFF_ST3  2196480L          // [B][256][256]
#define OFF_ST4  2458624L          // [B][512][512]
#define ZERO_CNT 3507200L
#define OFF_ET1  3507200L
#define OFF_ET2  22381568L
#define OFF_ET4  27100160L
#define OFF_ETA  36537344L         // also reused earlier as T12 [B][576][1024]
#define OFF_T    41255936L         // Wp12 (512x1024) + bsum(512) early; T [B][576][512] later
#define OFF_T3   42435584L
#define OFF_A3   44794880L
#define OFF_ATT  47154176L
#define OFF_AN   48333824L
#define OFF_H    49513472L
#define OFF_AX   54232064L
#define POOL_SZ  58950656L

#define OFF_T12   OFF_ETA
#define OFF_WP12  OFF_T
#define OFF_BSUM  (OFF_T + 524288L)

__device__ float g_pool[POOL_SZ];

// ---------------- helpers ----------------
__device__ __forceinline__ uint32_t smem_u32(const void* p) {
    uint32_t a;
    asm("{ .reg .u64 t; cvta.to.shared.u64 t, %1; cvt.u32.u64 %0, t; }" : "=r"(a) : "l"(p));
    return a;
}
__device__ __forceinline__ float to_tf32(float x) {
    float y;
    asm("cvt.rna.tf32.f32 %0, %1;" : "=f"(y) : "f"(x));
    return y;
}
__device__ __forceinline__ float4 rnd4(float4 v) {
    v.x = to_tf32(v.x); v.y = to_tf32(v.y); v.z = to_tf32(v.z); v.w = to_tf32(v.w);
    return v;
}
__device__ __forceinline__ void mma_tf32(float* d, const uint32_t* a, const uint32_t* bf) {
    asm volatile(
        "mma.sync.aligned.m16n8k8.row.col.f32.tf32.tf32.f32 "
        "{%0,%1,%2,%3}, {%4,%5,%6,%7}, {%8,%9}, {%0,%1,%2,%3};"
        : "+f"(d[0]), "+f"(d[1]), "+f"(d[2]), "+f"(d[3])
        : "r"(a[0]), "r"(a[1]), "r"(a[2]), "r"(a[3]), "r"(bf[0]), "r"(bf[1]));
}
__device__ __forceinline__ void ldm_x4(uint32_t* r, uint32_t addr) {
    asm volatile("ldmatrix.sync.aligned.m8n8.x4.shared.b16 {%0,%1,%2,%3}, [%4];"
        : "=r"(r[0]), "=r"(r[1]), "=r"(r[2]), "=r"(r[3]) : "r"(addr));
}
__device__ __forceinline__ void ldm_x2(uint32_t* r, uint32_t addr) {
    asm volatile("ldmatrix.sync.aligned.m8n8.x2.shared.b16 {%0,%1}, [%2];"
        : "=r"(r[0]), "=r"(r[1]) : "r"(addr));
}

// ================= tf32 mma.sync NT GEMM =================
// D[m][n] = sum_k A[m][k] * B[n][k], 128x128 CTA tile, BK=16,
// 256 threads = 8 warps, warp tile 64x32, double-buffered smem,
// fragments via ldmatrix. 2 CTAs/SM.
// EPI 0: C[m][n] = acc
// EPI 1: e = exp(acc); Et[n][m] = e (smem-staged coalesced); rowsum/colsum atomics
// EPI 2: C[m][n] = alpha*(acc + bias[n]) + (addsrc ? addsrc[m][n] : 0)
// EPI 3: C[m][n] += alpha*(acc + bias[n])
// EPI 5: symmetric split-K: triangular tile decode from blockIdx.x;
//        atomicAdd(C[m][n], acc*mscale[m]); if offdiag also atomicAdd(C[n][m], acc*mscale[n])
// AMODE: 0 alpha=1 ; 1 alpha=sigmoid(*wscal) ; 2 alpha=(1-sigmoid)/2
// KSC: B *= kscale[k] at load
template<int EPI, int AMODE, bool KSC>
__global__ void __launch_bounds__(256, 2) tgemm(
    const float* __restrict__ A, long aStr, int lda,
    const float* __restrict__ Bm, long bStr, int ldb,
    float* __restrict__ C, long cStr, int ldc,
    int mTot, int nTot, int kTot, int splits,
    const float* __restrict__ bias,
    const float* __restrict__ addsrc,
    const float* __restrict__ wscal,
    float* __restrict__ rowsum, float* __restrict__ colsum,
    const float* __restrict__ kscale, const float* __restrict__ mscale)
{
    __shared__ float sm[2][2][128][20];   // [buf-set A/B][dbl][row][k+pad]
    float (*As)[128][20] = sm[0];
    float (*Bs)[128][20] = sm[1];

    const int z = blockIdx.z;
    const int b = z / splits, sp = z % splits;
    const int Kc = kTot / splits;
    const int kbase = sp * Kc;
    const int nt = Kc >> 4;

    const float* Ab = A + (long)b * aStr;
    const float* Bb = Bm + (long)b * bStr;
    const float* ksc_b = KSC ? (kscale + (long)b * kTot) : nullptr;

    int bxq, byq;
    if (EPI == 5) {
        int q = blockIdx.x;
        const int T = nTot >> 7;
        int by = 0;
        while (q >= T - by) { q -= (T - by); by++; }
        byq = by; bxq = by + q;
    } else {
        bxq = blockIdx.x; byq = blockIdx.y;
    }
    const int bm = byq * 128;
    const int bn = bxq * 128;

    const int tid = threadIdx.x;
    const int wid = tid >> 5, lane = tid & 31;
    const int wm = wid & 1, wn = wid >> 1;        // warp tile: rows wm*64, cols wn*32
    const int lr = lane >> 2, lc = lane & 3;

    // ldmatrix per-thread base addresses (bytes)
    const int m8 = lane >> 3;
    const int r8 = lane & 7;
    const uint32_t asBase = smem_u32(As) +
        (uint32_t)(((wm * 64 + (m8 & 1) * 8 + r8) * 20 + (m8 >> 1) * 4) * 4);
    const uint32_t bsBase = smem_u32(Bs) +
        (uint32_t)(((wn * 32 + r8) * 20 + ((lane >> 3) & 1) * 4) * 4);
    const uint32_t BUFB = 128 * 20 * 4;

    float acc[4][4][4];
#pragma unroll
    for (int i = 0; i < 4; i++)
#pragma unroll
        for (int j = 0; j < 4; j++)
#pragma unroll
            for (int r = 0; r < 4; r++) acc[i][j][r] = 0.0f;

    // ---- initial tile -> buffer 0 ----
    {
        const int k0 = kbase;
#pragma unroll
        for (int l = 0; l < 2; l++) {
            int idx = tid + (l << 8);
            int row = idx >> 2, kq = (idx & 3) << 2;
            int gr = bm + row;
            float4 va = make_float4(0.f, 0.f, 0.f, 0.f);
            if (gr < mTot) va = *(const float4*)(Ab + (long)gr * lda + k0 + kq);
            float4 vb = *(const float4*)(Bb + (long)(bn + row) * ldb + k0 + kq);
            if (KSC) {
                float4 ks = *(const float4*)(ksc_b + k0 + kq);
                vb.x *= ks.x; vb.y *= ks.y; vb.z *= ks.z; vb.w *= ks.w;
            }
            *(float4*)(&As[0][row][kq]) = rnd4(va);
            *(float4*)(&Bs[0][row][kq]) = rnd4(vb);
        }
    }
    __syncthreads();

    for (int t = 0; t < nt; t++) {
        const int cur = t & 1;
        const uint32_t aCur = asBase + cur * BUFB;
        const uint32_t bCur = bsBase + cur * BUFB;
        float4 ra[2], rb[2];
        if (t + 1 < nt) {
            const int k0 = kbase + ((t + 1) << 4);
#pragma unroll
            for (int l = 0; l < 2; l++) {
                int idx = tid + (l << 8);
                int row = idx >> 2, kq = (idx & 3) << 2;
                int gr = bm + row;
                float4 va = make_float4(0.f, 0.f, 0.f, 0.f);
                if (gr < mTot) va = *(const float4*)(Ab + (long)gr * lda + k0 + kq);
                ra[l] = va;
                float4 vb = *(const float4*)(Bb + (long)(bn + row) * ldb + k0 + kq);
                if (KSC) {
                    float4 ks = *(const float4*)(ksc_b + k0 + kq);
                    vb.x *= ks.x; vb.y *= ks.y; vb.z *= ks.z; vb.w *= ks.w;
                }
                rb[l] = vb;
            }
        }
#pragma unroll
        for (int ks = 0; ks < 2; ks++) {
            uint32_t af[4][4];
#pragma unroll
            for (int i = 0; i < 4; i++)
                ldm_x4(af[i], aCur + i * 1280 + ks * 32);
            uint32_t bf[4][2];
#pragma unroll
            for (int j = 0; j < 4; j++)
                ldm_x2(bf[j], bCur + j * 640 + ks * 32);
#pragma unroll
            for (int i = 0; i < 4; i++)
#pragma unroll
                for (int j = 0; j < 4; j++)
                    mma_tf32(acc[i][j], af[i], bf[j]);
        }
        if (t + 1 < nt) {
            const int nxt = (t + 1) & 1;
#pragma unroll
            for (int l = 0; l < 2; l++) {
                int idx = tid + (l << 8);
                int row = idx >> 2, kq = (idx & 3) << 2;
                *(float4*)(&As[nxt][row][kq]) = rnd4(ra[l]);
                *(float4*)(&Bs[nxt][row][kq]) = rnd4(rb[l]);
            }
        }
        __syncthreads();
    }

    // ---- epilogue ----
    float alpha = 1.0f;
    if (AMODE == 1) alpha = 1.0f / (1.0f + expf(-wscal[0]));
    if (AMODE == 2) alpha = (1.0f - 1.0f / (1.0f + expf(-wscal[0]))) * 0.5f;

    float* Cb = C + (long)b * cStr;

    if (EPI == 1) {
        // exp in place + rowsum/colsum reductions
        float rs[4][2];
#pragma unroll
        for (int i = 0; i < 4; i++) { rs[i][0] = 0.f; rs[i][1] = 0.f; }
#pragma unroll
        for (int j = 0; j < 4; j++) {
            int col0 = bn + wn * 32 + j * 8 + lc * 2;
            float cs0 = 0.f, cs1 = 0.f;
#pragma unroll
            for (int i = 0; i < 4; i++) {
                float e0 = expf(acc[i][j][0]);
                float e1 = expf(acc[i][j][1]);
                float e2 = expf(acc[i][j][2]);
                float e3 = expf(acc[i][j][3]);
                acc[i][j][0] = e0; acc[i][j][1] = e1;
                acc[i][j][2] = e2; acc[i][j][3] = e3;
                cs0 += e0 + e2; cs1 += e1 + e3;
                rs[i][0] += e0 + e1; rs[i][1] += e2 + e3;
            }
#pragma unroll
            for (int o = 4; o <= 16; o <<= 1) {
                cs0 += __shfl_xor_sync(0xffffffff, cs0, o);
                cs1 += __shfl_xor_sync(0xffffffff, cs1, o);
            }
            if (lane < 4) {
                atomicAdd(colsum + (long)b * nTot + col0, cs0);
                atomicAdd(colsum + (long)b * nTot + col0 + 1, cs1);
            }
        }
#pragma unroll
        for (int i = 0; i < 4; i++)
#pragma unroll
            for (int h = 0; h < 2; h++) {
                float v = rs[i][h];
                v += __shfl_xor_sync(0xffffffff, v, 1);
                v += __shfl_xor_sync(0xffffffff, v, 2);
                if (lc == 0) {
                    int r = bm + wm * 64 + i * 16 + lr + h * 8;
                    atomicAdd(rowsum + (long)b * mTot + r, v);
                }
            }
        // smem-staged transposed store (two 64-col halves), coalesced float4 writes
        float* stg = &sm[0][0][0][0];
#pragma unroll
        for (int h2 = 0; h2 < 2; h2++) {
            __syncthreads();
            if ((wn >> 1) == h2) {
                int snb = wn * 32 - h2 * 64;
#pragma unroll
                for (int j = 0; j < 4; j++) {
                    int sn = snb + j * 8 + lc * 2;
#pragma unroll
                    for (int i = 0; i < 4; i++) {
                        int ml = wm * 64 + i * 16 + lr;
                        stg[sn * 132 + ml]           = acc[i][j][0];
                        stg[(sn + 1) * 132 + ml]     = acc[i][j][1];
                        stg[sn * 132 + ml + 8]       = acc[i][j][2];
                        stg[(sn + 1) * 132 + ml + 8] = acc[i][j][3];
                    }
                }
            }
            __syncthreads();
#pragma unroll
            for (int it = 0; it < 8; it++) {
                int id = tid + (it << 8);
                int row = id >> 5, m4 = (id & 31) << 2;
                float4 v = *(float4*)&stg[row * 132 + m4];
                *(float4*)(Cb + (long)(bn + h2 * 64 + row) * ldc + bm + m4) = v;
            }
        }
    } else if (EPI == 5) {
        const float* msc = mscale + (long)b * mTot;
#pragma unroll
        for (int i = 0; i < 4; i++) {
            int r0 = bm + wm * 64 + i * 16 + lr;
            float s0 = msc[r0];
            float s1 = msc[r0 + 8];
#pragma unroll
            for (int j = 0; j < 4; j++) {
                int col0 = bn + wn * 32 + j * 8 + lc * 2;
                atomicAdd(Cb + (long)r0 * ldc + col0,           acc[i][j][0] * s0);
                atomicAdd(Cb + (long)r0 * ldc + col0 + 1,       acc[i][j][1] * s0);
                atomicAdd(Cb + (long)(r0 + 8) * ldc + col0,     acc[i][j][2] * s1);
                atomicAdd(Cb + (long)(r0 + 8) * ldc + col0 + 1, acc[i][j][3] * s1);
            }
        }
        if (bxq != byq) {
            // transposed block: C[n][m] += acc * mscale[n]
#pragma unroll
            for (int j = 0; j < 4; j++) {
                int n0 = bn + wn * 32 + j * 8 + lc * 2;
                float sn0 = msc[n0];
                float sn1 = msc[n0 + 1];
#pragma unroll
                for (int i = 0; i < 4; i++) {
                    int r0 = bm + wm * 64 + i * 16 + lr;
                    atomicAdd(Cb + (long)n0 * ldc + r0,           acc[i][j][0] * sn0);
                    atomicAdd(Cb + (long)(n0 + 1) * ldc + r0,     acc[i][j][1] * sn1);
                    atomicAdd(Cb + (long)n0 * ldc + r0 + 8,       acc[i][j][2] * sn0);
                    atomicAdd(Cb + (long)(n0 + 1) * ldc + r0 + 8, acc[i][j][3] * sn1);
                }
            }
        }
    } else {
#pragma unroll
        for (int i = 0; i < 4; i++) {
#pragma unroll
            for (int h = 0; h < 2; h++) {
                int r = bm + wm * 64 + i * 16 + lr + h * 8;
                if (r >= mTot) continue;
                float* Crow = Cb + (long)r * ldc;
                const float* Srow = (EPI == 2 && addsrc) ? (addsrc + (long)b * (long)mTot * ldc + (long)r * ldc) : nullptr;
#pragma unroll
                for (int j = 0; j < 4; j++) {
                    int col0 = bn + wn * 32 + j * 8 + lc * 2;
                    float v0 = acc[i][j][h * 2 + 0];
                    float v1 = acc[i][j][h * 2 + 1];
                    if (EPI == 2) {
                        v0 = alpha * (v0 + bias[col0]);
                        v1 = alpha * (v1 + bias[col0 + 1]);
                        if (Srow) { v0 += Srow[col0]; v1 += Srow[col0 + 1]; }
                    }
                    if (EPI == 3) {
                        float2 old = *(const float2*)(Crow + col0);
                        v0 = old.x + alpha * (v0 + bias[col0]);
                        v1 = old.y + alpha * (v1 + bias[col0 + 1]);
                    }
                    float2 o; o.x = v0; o.y = v1;
                    *(float2*)(Crow + col0) = o;
                }
            }
        }
    }
}

// ---------------- utility kernels ----------------
__global__ void zero_kernel(float* p, long n) {
    long i = (long)blockIdx.x * blockDim.x + threadIdx.x;
    long stride = (long)gridDim.x * blockDim.x;
    for (; i < n; i += stride) p[i] = 0.0f;
}
__global__ void recip_kernel(float* p, int n) {
    int i = blockIdx.x * blockDim.x + threadIdx.x;
    if (i < n) p[i] = 1.0f / p[i];
}
// W12[n][k] = k<512 ? Wp1[n][k] : Wp2[n][k-512]; bsum = bp1+bp2
__global__ void concat_w(const float* __restrict__ W1, const float* __restrict__ W2,
                         const float* __restrict__ b1, const float* __restrict__ b2,
                         float* __restrict__ W12, float* __restrict__ bsum) {
    int i = blockIdx.x * 256 + threadIdx.x;
    if (i < 512 * 1024) {
        int n = i >> 10, k = i & 1023;
        W12[i] = (k < 512) ? W1[n * 512 + k] : W2[n * 512 + k - 512];
    }
    if (i < 512) bsum[i] = b1[i] + b2[i];
}

__global__ void ln_rows(const float* __restrict__ X, const float* __restrict__ g,
                        const float* __restrict__ bb, float* __restrict__ Y, int C)
{
    long row = blockIdx.x;
    const float* x = X + row * C;
    float s = 0.f, s2 = 0.f;
    for (int c = threadIdx.x; c < C; c += blockDim.x) { float v = x[c]; s += v; s2 += v * v; }
    __shared__ float sh1[32], sh2[32];
    int lane = threadIdx.x & 31, wid = threadIdx.x >> 5;
#pragma unroll
    for (int o = 16; o; o >>= 1) {
        s  += __shfl_down_sync(0xffffffff, s,  o);
        s2 += __shfl_down_sync(0xffffffff, s2, o);
    }
    if (!lane) { sh1[wid] = s; sh2[wid] = s2; }
    __syncthreads();
    if (threadIdx.x == 0) {
        float a = 0.f, c2 = 0.f;
        int nw = blockDim.x >> 5;
        for (int i = 0; i < nw; i++) { a += sh1[i]; c2 += sh2[i]; }
        float mean = a / C;
        float var  = c2 / C - mean * mean;
        sh1[0] = mean; sh2[0] = rsqrtf(var + 1e-5f);
    }
    __syncthreads();
    float mean = sh1[0], rstd = sh2[0];
    for (int c = threadIdx.x; c < C; c += blockDim.x) {
        float v = x[c];
        Y[row * C + c] = (v - mean) * rstd * g[c] + bb[c];
    }
}

__global__ void __launch_bounds__(256) dwconv_ln_gelu(
    const float* __restrict__ H, const float* __restrict__ Wdw,
    const float* __restrict__ bdw, const float* __restrict__ g,
    const float* __restrict__ bt, float* __restrict__ AX)
{
    const int n = blockIdx.x;
    const int b = blockIdx.y;
    const int y = n / 24, x = n % 24;
    const float* Hb = H + (long)b * 576 * 2048;
    const int tid = threadIdx.x;

    float v[8];
    float s = 0.f, s2 = 0.f;
#pragma unroll
    for (int it = 0; it < 8; it++) {
        int c = tid + it * 256;
        float a = Hb[(long)n * 2048 + c] + bdw[c];
#pragma unroll
        for (int ky = 0; ky < 3; ky++) {
            int yy = y + ky - 1;
            if (yy < 0 || yy > 23) continue;
#pragma unroll
            for (int kx = 0; kx < 3; kx++) {
                int xx = x + kx - 1;
                if (xx < 0 || xx > 23) continue;
                a += Wdw[c * 9 + ky * 3 + kx] * Hb[(long)(yy * 24 + xx) * 2048 + c];
            }
        }
        v[it] = a; s += a; s2 += a * a;
    }
    __shared__ float sh1[32], sh2[32];
    int lane = tid & 31, wid = tid >> 5;
#pragma unroll
    for (int o = 16; o; o >>= 1) {
        s  += __shfl_down_sync(0xffffffff, s,  o);
        s2 += __shfl_down_sync(0xffffffff, s2, o);
    }
    if (!lane) { sh1[wid] = s; sh2[wid] = s2; }
    __syncthreads();
    if (tid == 0) {
        float a = 0.f, c2 = 0.f;
        for (int i = 0; i < 8; i++) { a += sh1[i]; c2 += sh2[i]; }
        float mean = a / 2048.0f;
        float var  = c2 / 2048.0f - mean * mean;
        sh1[0] = mean; sh2[0] = rsqrtf(var + 1e-5f);
    }
    __syncthreads();
    float mean = sh1[0], rstd = sh2[0];
    float* out = AX + ((long)b * 576 + n) * 2048;
#pragma unroll
    for (int it = 0; it < 8; it++) {
        int c = tid + it * 256;
        float t = (v[it] - mean) * rstd * g[c] + bt[c];
        out[c] = 0.5f * t * (1.0f + erff(t * 0.70710678118654752f));
    }
}

// ---------------- host orchestration ----------------
extern "C" void kernel_launch(void* const* d_in, const int* in_sizes, int n_in,
                              void* d_out, int out_size)
{
    const float* x      = (const float*)d_in[0];
    const float* x2     = (const float*)d_in[1];
    const float* x3     = (const float*)d_in[2];
    const float* W_lin  = (const float*)d_in[3];
    const float* W_lin2 = (const float*)d_in[4];
    const float* W_lin3 = (const float*)d_in[5];
    const float* W_lin4 = (const float*)d_in[6];
    const float* w      = (const float*)d_in[7];
    const float* Wp1 = (const float*)d_in[8];  const float* bp1 = (const float*)d_in[9];
    const float* Wp2 = (const float*)d_in[10]; const float* bp2 = (const float*)d_in[11];
    const float* Wp3 = (const float*)d_in[12]; const float* bp3 = (const float*)d_in[13];
    const float* Wp4 = (const float*)d_in[14]; const float* bp4 = (const float*)d_in[15];
    const float* g_norm = (const float*)d_in[16]; const float* b_norm = (const float*)d_in[17];
    const float* Wfc1 = (const float*)d_in[18];   const float* bfc1  = (const float*)d_in[19];
    const float* Wdw  = (const float*)d_in[20];   const float* bdw   = (const float*)d_in[21];
    const float* g_ln1 = (const float*)d_in[22];  const float* b_ln1 = (const float*)d_in[23];
    const float* Wfc2 = (const float*)d_in[24];   const float* bfc2  = (const float*)d_in[25];

    float* pool = nullptr;
    cudaGetSymbolAddress((void**)&pool, g_pool);

    // 0) zero stats + S accumulators; build Wp12/bsum
    zero_kernel<<<1024, 256>>>(pool, ZERO_CNT);
    concat_w<<<2048, 256>>>(Wp1, Wp2, bp1, bp2, pool + OFF_WP12, pool + OFF_BSUM);

    // 1) Et1 = exp(x @ W_lin^T)^T + softmax stats     [B,512,9216]
    tgemm<1,0,false><<<dim3(4,72,BB), 256>>>(
        x, (long)N1_*D0_, D0_, W_lin, 0L, D0_,
        pool+OFF_ET1, (long)D2_*N1_, N1_,
        N1_, D2_, D0_, 1,
        nullptr, nullptr, nullptr, pool+OFF_R1, pool+OFF_C1, nullptr, nullptr);

    // 2) Et2 = exp(x2 @ W_lin2^T)^T + stats           [B,512,2304]
    tgemm<1,0,false><<<dim3(4,18,BB), 256>>>(
        x2, (long)N2_*D1_, D1_, W_lin2, 0L, D1_,
        pool+OFF_ET2, (long)D2_*N2_, N2_,
        N2_, D2_, D1_, 1,
        nullptr, nullptr, nullptr, pool+OFF_R2, pool+OFF_C2, nullptr, nullptr);

    // 3) Et4 = exp(x @ W_lin3^T)^T + stats            [B,256,9216]
    tgemm<1,0,false><<<dim3(2,72,BB), 256>>>(
        x, (long)N1_*D0_, D0_, W_lin3, 0L, D0_,
        pool+OFF_ET4, (long)D1_*N1_, N1_,
        N1_, D1_, D0_, 1,
        nullptr, nullptr, nullptr, pool+OFF_R4, pool+OFF_C4, nullptr, nullptr);

    // 4) reciprocal of stats (R1,C1,R2,C2,R4,C4)
    recip_kernel<<<(88064 + 255) / 256, 256>>>(pool, 88064);

    // 5) St1 (symmetric, triangular 10 tiles, split-K 8) -> St12 rows 0-511
    tgemm<5,0,true><<<dim3(10,1,BB*8), 256>>>(
        pool+OFF_ET1, (long)D2_*N1_, N1_, pool+OFF_ET1, (long)D2_*N1_, N1_,
        pool+OFF_ST12, (long)2*D2_*D2_, D2_,
        D2_, D2_, N1_, 8,
        nullptr, nullptr, nullptr, nullptr, nullptr, pool+OFF_R1, pool+OFF_C1);

    // 6) St2 (symmetric, split 4) -> St12 rows 512-1023
    tgemm<5,0,true><<<dim3(10,1,BB*4), 256>>>(
        pool+OFF_ET2, (long)D2_*N2_, N2_, pool+OFF_ET2, (long)D2_*N2_, N2_,
        pool+OFF_ST12 + (long)D2_*D2_, (long)2*D2_*D2_, D2_,
        D2_, D2_, N2_, 4,
        nullptr, nullptr, nullptr, nullptr, nullptr, pool+OFF_R2, pool+OFF_C2);

    // 7) St3 (symmetric, 3 tiles, split 8)
    tgemm<5,0,true><<<dim3(3,1,BB*8), 256>>>(
        pool+OFF_ET4, (long)D1_*N1_, N1_, pool+OFF_ET4, (long)D1_*N1_, N1_,
        pool+OFF_ST3, (long)D1_*D1_, D1_,
        D1_, D1_, N1_, 8,
        nullptr, nullptr, nullptr, nullptr, nullptr, pool+OFF_R4, pool+OFF_C4);

    // 8) T12 = x3 @ [St1;St2]^T   [B,576,1024]
    tgemm<0,0,false><<<dim3(8,5,BB), 256>>>(
        x3, (long)N3_*D2_, D2_, pool+OFF_ST12, (long)2*D2_*D2_, D2_,
        pool+OFF_T12, (long)N3_*2*D2_, 2*D2_,
        N3_, 2*D2_, D2_, 1,
        nullptr, nullptr, nullptr, nullptr, nullptr, nullptr, nullptr);
    // 9) ATT = x3 + other*(T12 @ Wp12^T + bsum)
    tgemm<2,2,false><<<dim3(4,5,BB), 256>>>(
        pool+OFF_T12, (long)N3_*2*D2_, 2*D2_, pool+OFF_WP12, 0L, 2*D2_,
        pool+OFF_ATT, (long)N3_*D2_, D2_,
        N3_, D2_, 2*D2_, 1,
        pool+OFF_BSUM, x3, w, nullptr, nullptr, nullptr, nullptr);

    // 12) T3 = x2 @ St3   [B,2304,256]
    tgemm<0,0,false><<<dim3(2,18,BB), 256>>>(
        x2, (long)N2_*D1_, D1_, pool+OFF_ST3, (long)D1_*D1_, D1_,
        pool+OFF_T3, (long)N2_*D1_, D1_,
        N2_, D1_, D1_, 1,
        nullptr, nullptr, nullptr, nullptr, nullptr, nullptr, nullptr);
    // 13) A3 = T3 @ Wp3^T + bp3
    tgemm<2,0,false><<<dim3(2,18,BB), 256>>>(
        pool+OFF_T3, (long)N2_*D1_, D1_, Wp3, 0L, D1_,
        pool+OFF_A3, (long)N2_*D1_, D1_,
        N2_, D1_, D1_, 1,
        bp3, nullptr, nullptr, nullptr, nullptr, nullptr, nullptr);
    // 14) EtA = exp(A3 @ W_lin4^T)^T + stats   [B,512,2304]
    tgemm<1,0,false><<<dim3(4,18,BB), 256>>>(
        pool+OFF_A3, (long)N2_*D1_, D1_, W_lin4, 0L, D1_,
        pool+OFF_ETA, (long)D2_*N2_, N2_,
        N2_, D2_, D1_, 1,
        nullptr, nullptr, nullptr, pool+OFF_RA, pool+OFF_CA, nullptr, nullptr);
    // 15) reciprocal of RA,CA
    recip_kernel<<<(11264 + 255) / 256, 256>>>(pool + OFF_RA, 11264);
    // 16) St4 (symmetric, split 4)
    tgemm<5,0,true><<<dim3(10,1,BB*4), 256>>>(
        pool+OFF_ETA, (long)D2_*N2_, N2_, pool+OFF_ETA, (long)D2_*N2_, N2_,
        pool+OFF_ST4, (long)D2_*D2_, D2_,
        D2_, D2_, N2_, 4,
        nullptr, nullptr, nullptr, nullptr, nullptr, pool+OFF_RA, pool+OFF_CA);
    // 17) T = x3 @ St4 ; ATT += f*(T @ Wp4^T + bp4)
    tgemm<0,0,false><<<dim3(4,5,BB), 256>>>(
        x3, (long)N3_*D2_, D2_, pool+OFF_ST4, (long)D2_*D2_, D2_,
        pool+OFF_T, (long)N3_*D2_, D2_,
        N3_, D2_, D2_, 1,
        nullptr, nullptr, nullptr, nullptr, nullptr, nullptr, nullptr);
    tgemm<3,1,false><<<dim3(4,5,BB), 256>>>(
        pool+OFF_T, (long)N3_*D2_, D2_, Wp4, 0L, D2_,
        pool+OFF_ATT, (long)N3_*D2_, D2_,
        N3_, D2_, D2_, 1,
        bp4, nullptr, w, nullptr, nullptr, nullptr, nullptr);

    // 19) AN = LN(ATT)
    ln_rows<<<BB * N3_, 256>>>(pool + OFF_ATT, g_norm, b_norm, pool + OFF_AN, D2_);

    // 20) H = AN @ Wfc1^T + bfc1   [B,576,2048]
    tgemm<2,0,false><<<dim3(16,5,BB), 256>>>(
        pool+OFF_AN, (long)N3_*D2_, D2_, Wfc1, 0L, D2_,
        pool+OFF_H, (long)N3_*DH_, DH_,
        N3_, DH_, D2_, 1,
        bfc1, nullptr, nullptr, nullptr, nullptr, nullptr, nullptr);

    // 21) AX = gelu(LN(dwconv(H)+bdw+H))
    dwconv_ln_gelu<<<dim3(N3_, BB), 256>>>(pool + OFF_H, Wdw, bdw, g_ln1, b_ln1, pool + OFF_AX);

    // 22) out = ATT + AX @ Wfc2^T + bfc2
    tgemm<2,0,false><<<dim3(4,5,BB), 256>>>(
        pool+OFF_AX, (long)N3_*DH_, DH_, Wfc2, 0L, DH_,
        (float*)d_out, (long)N3_*D2_, D2_,
        N3_, D2_, DH_, 1,
        bfc2, pool+OFF_ATT, nullptr, nullptr, nullptr, nullptr, nullptr);
}

// round 8
// speedup vs baseline: 1.1643x; 1.0297x over previous
#include <cuda_runtime.h>
#include <math.h>
#include <stdint.h>

// ---------------- problem dims ----------------
#define BB   4
#define N1_  9216
#define N2_  2304
#define N3_  576
#define D0_  128
#define D1_  256
#define D2_  512
#define DH_  2048

// ---------------- scratch pool (floats) ----------------
#define OFF_R1   0L
#define OFF_C1   36864L
#define OFF_R2   38912L
#define OFF_C2   48128L
#define OFF_R4   50176L
#define OFF_C4   87040L
#define OFF_RA   88064L
#define OFF_CA   97280L
#define OFF_ST12 99328L            // [B][1024][512]
#define OFF_ST3  2196480L          // [B][256][256]
#define OFF_ST4  2458624L          // [B][512][512]
#define ZERO_CNT 3507200L
#define OFF_ET1  3507200L
#define OFF_ET2  22381568L
#define OFF_ET4  27100160L
#define OFF_ETA  36537344L         // reused earlier as T12 [B][576][1024]
#define OFF_T    41255936L         // Wp12 (512x1024)+bsum early; T later
#define OFF_T3   42435584L
#define OFF_A3   44794880L
#define OFF_ATT  47154176L
#define OFF_AN   48333824L
#define OFF_H    49513472L
#define OFF_AX   54232064L
// tf32-rounded operand copies
#define OFF_XR   58950656L
#define OFF_X2R  63669248L
#define OFF_X3R  66028544L
#define OFF_WL   67208192L
#define OFF_WL2  67273728L
#define OFF_WL3  67404800L
#define OFF_WL4  67437568L
#define OFF_WP3R 67568640L
#define OFF_WP4R 67634176L
#define OFF_WF1  67896320L
#define OFF_WF2  68944896L
#define POOL_SZ  69993472L

#define OFF_T12   OFF_ETA
#define OFF_WP12  OFF_T
#define OFF_BSUM  (OFF_T + 524288L)

__device__ float g_pool[POOL_SZ];

// ---------------- helpers ----------------
__device__ __forceinline__ uint32_t smem_u32(const void* p) {
    uint32_t a;
    asm("{ .reg .u64 t; cvta.to.shared.u64 t, %1; cvt.u32.u64 %0, t; }" : "=r"(a) : "l"(p));
    return a;
}
__device__ __forceinline__ float to_tf32(float x) {
    float y;
    asm("cvt.rna.tf32.f32 %0, %1;" : "=f"(y) : "f"(x));
    return y;
}
__device__ __forceinline__ float4 rnd4(float4 v) {
    v.x = to_tf32(v.x); v.y = to_tf32(v.y); v.z = to_tf32(v.z); v.w = to_tf32(v.w);
    return v;
}
__device__ __forceinline__ void mma_tf32(float* d, const uint32_t* a, const uint32_t* bf) {
    asm volatile(
        "mma.sync.aligned.m16n8k8.row.col.f32.tf32.tf32.f32 "
        "{%0,%1,%2,%3}, {%4,%5,%6,%7}, {%8,%9}, {%0,%1,%2,%3};"
        : "+f"(d[0]), "+f"(d[1]), "+f"(d[2]), "+f"(d[3])
        : "r"(a[0]), "r"(a[1]), "r"(a[2]), "r"(a[3]), "r"(bf[0]), "r"(bf[1]));
}
__device__ __forceinline__ void ldm_x4(uint32_t* r, uint32_t addr) {
    asm volatile("ldmatrix.sync.aligned.m8n8.x4.shared.b16 {%0,%1,%2,%3}, [%4];"
        : "=r"(r[0]), "=r"(r[1]), "=r"(r[2]), "=r"(r[3]) : "r"(addr));
}
__device__ __forceinline__ void ldm_x2(uint32_t* r, uint32_t addr) {
    asm volatile("ldmatrix.sync.aligned.m8n8.x2.shared.b16 {%0,%1}, [%2];"
        : "=r"(r[0]), "=r"(r[1]) : "r"(addr));
}
__device__ __forceinline__ void cpa16(uint32_t dst, const float* src, bool valid) {
    int sz = valid ? 16 : 0;
    asm volatile("cp.async.cg.shared.global [%0], [%1], 16, %2;"
        :: "r"(dst), "l"(src), "r"(sz) : "memory");
}
#define CP_COMMIT() asm volatile("cp.async.commit_group;" ::: "memory")
#define CP_WAIT1()  asm volatile("cp.async.wait_group 1;" ::: "memory")

// ================= tf32 mma.sync NT GEMM (cp.async mainloop) =================
// D[m][n] = sum_k A[m][k] * B[n][k], 128x128 CTA tile, BK=16, 256 thr / 8 warps,
// warp tile 64x32, 2-stage cp.async pipeline (prefetch distance 2), ldmatrix frags.
// All GEMM operands must be PRE-ROUNDED to tf32 (hardware truncates raw fp32).
// EPI 0: C[m][n] = acc                          (RND: round stores)
// EPI 1: e = tf32(exp(acc)); Et[n][m]=e (smem-staged); rowsum/colsum atomics
// EPI 2: C = alpha*(acc+bias) + addsrc?         (RND optional)
// EPI 3: C += alpha*(acc+bias)
// EPI 5: symmetric split-K triangular; atomicAdd C[m][n]+=acc*mscale[m]; offdiag also C[n][m]
// AMODE: 0 alpha=1 ; 1 alpha=sigmoid(*wscal) ; 2 alpha=(1-sigmoid)/2
// KSC: B-fragment *= kscale[k] (applied post-ldmatrix, re-rounded)
template<int EPI, int AMODE, bool KSC, bool RND>
__global__ void __launch_bounds__(256, 2) tgemm(
    const float* __restrict__ A, long aStr, int lda,
    const float* __restrict__ Bm, long bStr, int ldb,
    float* __restrict__ C, long cStr, int ldc,
    int mTot, int nTot, int kTot, int splits,
    const float* __restrict__ bias,
    const float* __restrict__ addsrc,
    const float* __restrict__ wscal,
    float* __restrict__ rowsum, float* __restrict__ colsum,
    const float* __restrict__ kscale, const float* __restrict__ mscale)
{
    __shared__ float sm[2][2][128][20];   // [op A/B][stage][row][k+pad]

    const int z = blockIdx.z;
    const int b = z / splits, sp = z % splits;
    const int Kc = kTot / splits;
    const int kbase = sp * Kc;
    const int nt = Kc >> 4;

    const float* Ab = A + (long)b * aStr;
    const float* Bb = Bm + (long)b * bStr;
    const float* ksc_b = KSC ? (kscale + (long)b * kTot) : nullptr;

    int bxq, byq;
    if (EPI == 5) {
        int q = blockIdx.x;
        const int T = nTot >> 7;
        int by = 0;
        while (q >= T - by) { q -= (T - by); by++; }
        byq = by; bxq = by + q;
    } else {
        bxq = blockIdx.x; byq = blockIdx.y;
    }
    const int bm = byq * 128;
    const int bn = bxq * 128;

    const int tid = threadIdx.x;
    const int wid = tid >> 5, lane = tid & 31;
    const int wm = wid & 1, wn = wid >> 1;
    const int lr = lane >> 2, lc = lane & 3;

    const uint32_t smBase = smem_u32(sm);
    // ldmatrix per-thread addresses
    const int m8 = lane >> 3;
    const int r8 = lane & 7;
    const uint32_t asBase = smBase +
        (uint32_t)(((wm * 64 + (m8 & 1) * 8 + r8) * 20 + (m8 >> 1) * 4) * 4);
    const uint32_t bsBase = smBase + 20480u +
        (uint32_t)(((wn * 32 + r8) * 20 + ((lane >> 3) & 1) * 4) * 4);
    const uint32_t BUFB = 10240u;

    // per-thread copy slots
    const int cr0 = tid >> 2,        ck0 = (tid & 3) << 2;
    const int cr1 = (tid + 256) >> 2, ck1 = ((tid + 256) & 3) << 2;
    const uint32_t coff0 = (uint32_t)((cr0 * 20 + ck0) * 4);
    const uint32_t coff1 = (uint32_t)((cr1 * 20 + ck1) * 4);

    auto issue_copy = [&](int tt) {
        const int k0 = kbase + (tt << 4);
        const uint32_t aS = smBase + (uint32_t)(tt & 1) * BUFB;
        const uint32_t bS = smBase + 20480u + (uint32_t)(tt & 1) * BUFB;
        cpa16(aS + coff0, Ab + (long)(bm + cr0) * lda + k0 + ck0, (bm + cr0) < mTot);
        cpa16(bS + coff0, Bb + (long)(bn + cr0) * ldb + k0 + ck0, true);
        cpa16(aS + coff1, Ab + (long)(bm + cr1) * lda + k0 + ck1, (bm + cr1) < mTot);
        cpa16(bS + coff1, Bb + (long)(bn + cr1) * ldb + k0 + ck1, true);
    };

    float acc[4][4][4];
#pragma unroll
    for (int i = 0; i < 4; i++)
#pragma unroll
        for (int j = 0; j < 4; j++)
#pragma unroll
            for (int r = 0; r < 4; r++) acc[i][j][r] = 0.0f;

    issue_copy(0); CP_COMMIT();
    issue_copy(1); CP_COMMIT();

    for (int t = 0; t < nt; t++) {
        CP_WAIT1();
        __syncthreads();
        const int cur = t & 1;
        const uint32_t aCur = asBase + cur * BUFB;
        const uint32_t bCur = bsBase + cur * BUFB;
        float sc[4];
        if (KSC) {
            const int k0t = kbase + (t << 4);
            sc[0] = ksc_b[k0t + lc];
            sc[1] = ksc_b[k0t + 4 + lc];
            sc[2] = ksc_b[k0t + 8 + lc];
            sc[3] = ksc_b[k0t + 12 + lc];
        }
#pragma unroll
        for (int ks = 0; ks < 2; ks++) {
            uint32_t af[4][4];
#pragma unroll
            for (int i = 0; i < 4; i++)
                ldm_x4(af[i], aCur + i * 1280 + ks * 32);
            uint32_t bf[4][2];
#pragma unroll
            for (int j = 0; j < 4; j++) {
                ldm_x2(bf[j], bCur + j * 640 + ks * 32);
                if (KSC) {
                    bf[j][0] = __float_as_uint(to_tf32(__uint_as_float(bf[j][0]) * sc[ks * 2]));
                    bf[j][1] = __float_as_uint(to_tf32(__uint_as_float(bf[j][1]) * sc[ks * 2 + 1]));
                }
            }
#pragma unroll
            for (int i = 0; i < 4; i++)
#pragma unroll
                for (int j = 0; j < 4; j++)
                    mma_tf32(acc[i][j], af[i], bf[j]);
        }
        __syncthreads();
        if (t + 2 < nt) issue_copy(t + 2);
        CP_COMMIT();
    }

    // ---- epilogue ----
    float alpha = 1.0f;
    if (AMODE == 1) alpha = 1.0f / (1.0f + expf(-wscal[0]));
    if (AMODE == 2) alpha = (1.0f - 1.0f / (1.0f + expf(-wscal[0]))) * 0.5f;

    float* Cb = C + (long)b * cStr;

    if (EPI == 1) {
        float rs[4][2];
#pragma unroll
        for (int i = 0; i < 4; i++) { rs[i][0] = 0.f; rs[i][1] = 0.f; }
#pragma unroll
        for (int j = 0; j < 4; j++) {
            int col0 = bn + wn * 32 + j * 8 + lc * 2;
            float cs0 = 0.f, cs1 = 0.f;
#pragma unroll
            for (int i = 0; i < 4; i++) {
                float e0 = to_tf32(expf(acc[i][j][0]));
                float e1 = to_tf32(expf(acc[i][j][1]));
                float e2 = to_tf32(expf(acc[i][j][2]));
                float e3 = to_tf32(expf(acc[i][j][3]));
                acc[i][j][0] = e0; acc[i][j][1] = e1;
                acc[i][j][2] = e2; acc[i][j][3] = e3;
                cs0 += e0 + e2; cs1 += e1 + e3;
                rs[i][0] += e0 + e1; rs[i][1] += e2 + e3;
            }
#pragma unroll
            for (int o = 4; o <= 16; o <<= 1) {
                cs0 += __shfl_xor_sync(0xffffffff, cs0, o);
                cs1 += __shfl_xor_sync(0xffffffff, cs1, o);
            }
            if (lane < 4) {
                atomicAdd(colsum + (long)b * nTot + col0, cs0);
                atomicAdd(colsum + (long)b * nTot + col0 + 1, cs1);
            }
        }
#pragma unroll
        for (int i = 0; i < 4; i++)
#pragma unroll
            for (int h = 0; h < 2; h++) {
                float v = rs[i][h];
                v += __shfl_xor_sync(0xffffffff, v, 1);
                v += __shfl_xor_sync(0xffffffff, v, 2);
                if (lc == 0) {
                    int r = bm + wm * 64 + i * 16 + lr + h * 8;
                    atomicAdd(rowsum + (long)b * mTot + r, v);
                }
            }
        // smem-staged transposed store, coalesced float4 writes
        float* stg = &sm[0][0][0][0];
#pragma unroll
        for (int h2 = 0; h2 < 2; h2++) {
            __syncthreads();
            if ((wn >> 1) == h2) {
                int snb = wn * 32 - h2 * 64;
#pragma unroll
                for (int j = 0; j < 4; j++) {
                    int sn = snb + j * 8 + lc * 2;
#pragma unroll
                    for (int i = 0; i < 4; i++) {
                        int ml = wm * 64 + i * 16 + lr;
                        stg[sn * 132 + ml]           = acc[i][j][0];
                        stg[(sn + 1) * 132 + ml]     = acc[i][j][1];
                        stg[sn * 132 + ml + 8]       = acc[i][j][2];
                        stg[(sn + 1) * 132 + ml + 8] = acc[i][j][3];
                    }
                }
            }
            __syncthreads();
#pragma unroll
            for (int it = 0; it < 8; it++) {
                int id = tid + (it << 8);
                int row = id >> 5, m4 = (id & 31) << 2;
                float4 v = *(float4*)&stg[row * 132 + m4];
                *(float4*)(Cb + (long)(bn + h2 * 64 + row) * ldc + bm + m4) = v;
            }
        }
    } else if (EPI == 5) {
        const float* msc = mscale + (long)b * mTot;
#pragma unroll
        for (int i = 0; i < 4; i++) {
            int r0 = bm + wm * 64 + i * 16 + lr;
            float s0 = msc[r0];
            float s1 = msc[r0 + 8];
#pragma unroll
            for (int j = 0; j < 4; j++) {
                int col0 = bn + wn * 32 + j * 8 + lc * 2;
                atomicAdd(Cb + (long)r0 * ldc + col0,           acc[i][j][0] * s0);
                atomicAdd(Cb + (long)r0 * ldc + col0 + 1,       acc[i][j][1] * s0);
                atomicAdd(Cb + (long)(r0 + 8) * ldc + col0,     acc[i][j][2] * s1);
                atomicAdd(Cb + (long)(r0 + 8) * ldc + col0 + 1, acc[i][j][3] * s1);
            }
        }
        if (bxq != byq) {
#pragma unroll
            for (int j = 0; j < 4; j++) {
                int n0 = bn + wn * 32 + j * 8 + lc * 2;
                float sn0 = msc[n0];
                float sn1 = msc[n0 + 1];
#pragma unroll
                for (int i = 0; i < 4; i++) {
                    int r0 = bm + wm * 64 + i * 16 + lr;
                    atomicAdd(Cb + (long)n0 * ldc + r0,           acc[i][j][0] * sn0);
                    atomicAdd(Cb + (long)(n0 + 1) * ldc + r0,     acc[i][j][1] * sn1);
                    atomicAdd(Cb + (long)n0 * ldc + r0 + 8,       acc[i][j][2] * sn0);
                    atomicAdd(Cb + (long)(n0 + 1) * ldc + r0 + 8, acc[i][j][3] * sn1);
                }
            }
        }
    } else {
#pragma unroll
        for (int i = 0; i < 4; i++) {
#pragma unroll
            for (int h = 0; h < 2; h++) {
                int r = bm + wm * 64 + i * 16 + lr + h * 8;
                if (r >= mTot) continue;
                float* Crow = Cb + (long)r * ldc;
                const float* Srow = (EPI == 2 && addsrc) ? (addsrc + (long)b * (long)mTot * ldc + (long)r * ldc) : nullptr;
#pragma unroll
                for (int j = 0; j < 4; j++) {
                    int col0 = bn + wn * 32 + j * 8 + lc * 2;
                    float v0 = acc[i][j][h * 2 + 0];
                    float v1 = acc[i][j][h * 2 + 1];
                    if (EPI == 2) {
                        v0 = alpha * (v0 + bias[col0]);
                        v1 = alpha * (v1 + bias[col0 + 1]);
                        if (Srow) { v0 += Srow[col0]; v1 += Srow[col0 + 1]; }
                    }
                    if (EPI == 3) {
                        float2 old = *(const float2*)(Crow + col0);
                        v0 = old.x + alpha * (v0 + bias[col0]);
                        v1 = old.y + alpha * (v1 + bias[col0 + 1]);
                    }
                    if (RND) { v0 = to_tf32(v0); v1 = to_tf32(v1); }
                    float2 o; o.x = v0; o.y = v1;
                    *(float2*)(Crow + col0) = o;
                }
            }
        }
    }
}

// ---------------- utility kernels ----------------
__global__ void zero_kernel(float* p, long n) {
    long i = (long)blockIdx.x * blockDim.x + threadIdx.x;
    long stride = (long)gridDim.x * blockDim.x;
    for (; i < n; i += stride) p[i] = 0.0f;
}
__global__ void recip_kernel(float* p, int n) {
    int i = blockIdx.x * blockDim.x + threadIdx.x;
    if (i < n) p[i] = 1.0f / p[i];
}
// W12[n][k] = tf32(k<512 ? Wp1[n][k] : Wp2[n][k-512]); bsum = bp1+bp2
__global__ void concat_w(const float* __restrict__ W1, const float* __restrict__ W2,
                         const float* __restrict__ b1, const float* __restrict__ b2,
                         float* __restrict__ W12, float* __restrict__ bsum) {
    int i = blockIdx.x * 256 + threadIdx.x;
    if (i < 512 * 1024) {
        int n = i >> 10, k = i & 1023;
        W12[i] = to_tf32((k < 512) ? W1[n * 512 + k] : W2[n * 512 + k - 512]);
    }
    if (i < 512) bsum[i] = b1[i] + b2[i];
}

struct RoundArgs {
    const float* src[11];
    float* dst[11];
    long n[11];
};
__global__ void round_multi(RoundArgs a, int nseg) {
    int seg = blockIdx.y;
    if (seg >= nseg) return;
    const float4* s = (const float4*)a.src[seg];
    float4* d = (float4*)a.dst[seg];
    long n4 = a.n[seg] >> 2;
    for (long i = (long)blockIdx.x * blockDim.x + threadIdx.x; i < n4;
         i += (long)gridDim.x * blockDim.x)
        d[i] = rnd4(s[i]);
}

__global__ void ln_rows(const float* __restrict__ X, const float* __restrict__ g,
                        const float* __restrict__ bb, float* __restrict__ Y, int C)
{
    long row = blockIdx.x;
    const float* x = X + row * C;
    float s = 0.f, s2 = 0.f;
    for (int c = threadIdx.x; c < C; c += blockDim.x) { float v = x[c]; s += v; s2 += v * v; }
    __shared__ float sh1[32], sh2[32];
    int lane = threadIdx.x & 31, wid = threadIdx.x >> 5;
#pragma unroll
    for (int o = 16; o; o >>= 1) {
        s  += __shfl_down_sync(0xffffffff, s,  o);
        s2 += __shfl_down_sync(0xffffffff, s2, o);
    }
    if (!lane) { sh1[wid] = s; sh2[wid] = s2; }
    __syncthreads();
    if (threadIdx.x == 0) {
        float a = 0.f, c2 = 0.f;
        int nw = blockDim.x >> 5;
        for (int i = 0; i < nw; i++) { a += sh1[i]; c2 += sh2[i]; }
        float mean = a / C;
        float var  = c2 / C - mean * mean;
        sh1[0] = mean; sh2[0] = rsqrtf(var + 1e-5f);
    }
    __syncthreads();
    float mean = sh1[0], rstd = sh2[0];
    for (int c = threadIdx.x; c < C; c += blockDim.x) {
        float v = x[c];
        Y[row * C + c] = to_tf32((v - mean) * rstd * g[c] + bb[c]);
    }
}

__global__ void __launch_bounds__(256) dwconv_ln_gelu(
    const float* __restrict__ H, const float* __restrict__ Wdw,
    const float* __restrict__ bdw, const float* __restrict__ g,
    const float* __restrict__ bt, float* __restrict__ AX)
{
    const int n = blockIdx.x;
    const int b = blockIdx.y;
    const int y = n / 24, x = n % 24;
    const float* Hb = H + (long)b * 576 * 2048;
    const int tid = threadIdx.x;

    float v[8];
    float s = 0.f, s2 = 0.f;
#pragma unroll
    for (int it = 0; it < 8; it++) {
        int c = tid + it * 256;
        float a = Hb[(long)n * 2048 + c] + bdw[c];
#pragma unroll
        for (int ky = 0; ky < 3; ky++) {
            int yy = y + ky - 1;
            if (yy < 0 || yy > 23) continue;
#pragma unroll
            for (int kx = 0; kx < 3; kx++) {
                int xx = x + kx - 1;
                if (xx < 0 || xx > 23) continue;
                a += Wdw[c * 9 + ky * 3 + kx] * Hb[(long)(yy * 24 + xx) * 2048 + c];
            }
        }
        v[it] = a; s += a; s2 += a * a;
    }
    __shared__ float sh1[32], sh2[32];
    int lane = tid & 31, wid = tid >> 5;
#pragma unroll
    for (int o = 16; o; o >>= 1) {
        s  += __shfl_down_sync(0xffffffff, s,  o);
        s2 += __shfl_down_sync(0xffffffff, s2, o);
    }
    if (!lane) { sh1[wid] = s; sh2[wid] = s2; }
    __syncthreads();
    if (tid == 0) {
        float a = 0.f, c2 = 0.f;
        for (int i = 0; i < 8; i++) { a += sh1[i]; c2 += sh2[i]; }
        float mean = a / 2048.0f;
        float var  = c2 / 2048.0f - mean * mean;
        sh1[0] = mean; sh2[0] = rsqrtf(var + 1e-5f);
    }
    __syncthreads();
    float mean = sh1[0], rstd = sh2[0];
    float* out = AX + ((long)b * 576 + n) * 2048;
#pragma unroll
    for (int it = 0; it < 8; it++) {
        int c = tid + it * 256;
        float t = (v[it] - mean) * rstd * g[c] + bt[c];
        out[c] = to_tf32(0.5f * t * (1.0f + erff(t * 0.70710678118654752f)));
    }
}

// ---------------- host orchestration ----------------
extern "C" void kernel_launch(void* const* d_in, const int* in_sizes, int n_in,
                              void* d_out, int out_size)
{
    const float* x      = (const float*)d_in[0];
    const float* x2     = (const float*)d_in[1];
    const float* x3     = (const float*)d_in[2];
    const float* W_lin  = (const float*)d_in[3];
    const float* W_lin2 = (const float*)d_in[4];
    const float* W_lin3 = (const float*)d_in[5];
    const float* W_lin4 = (const float*)d_in[6];
    const float* w      = (const float*)d_in[7];
    const float* Wp1 = (const float*)d_in[8];  const float* bp1 = (const float*)d_in[9];
    const float* Wp2 = (const float*)d_in[10]; const float* bp2 = (const float*)d_in[11];
    const float* Wp3 = (const float*)d_in[12]; const float* bp3 = (const float*)d_in[13];
    const float* Wp4 = (const float*)d_in[14]; const float* bp4 = (const float*)d_in[15];
    const float* g_norm = (const float*)d_in[16]; const float* b_norm = (const float*)d_in[17];
    const float* Wfc1 = (const float*)d_in[18];   const float* bfc1  = (const float*)d_in[19];
    const float* Wdw  = (const float*)d_in[20];   const float* bdw   = (const float*)d_in[21];
    const float* g_ln1 = (const float*)d_in[22];  const float* b_ln1 = (const float*)d_in[23];
    const float* Wfc2 = (const float*)d_in[24];   const float* bfc2  = (const float*)d_in[25];

    float* pool = nullptr;
    cudaGetSymbolAddress((void**)&pool, g_pool);

    // 0) zero stats + S accumulators; build Wp12/bsum; pre-round all GEMM operands
    zero_kernel<<<1024, 256>>>(pool, ZERO_CNT);
    concat_w<<<2048, 256>>>(Wp1, Wp2, bp1, bp2, pool + OFF_WP12, pool + OFF_BSUM);
    {
        RoundArgs ra;
        const float* srcs[11] = { x, x2, x3, W_lin, W_lin2, W_lin3, W_lin4, Wp3, Wp4, Wfc1, Wfc2 };
        long offs[11] = { OFF_XR, OFF_X2R, OFF_X3R, OFF_WL, OFF_WL2, OFF_WL3, OFF_WL4,
                          OFF_WP3R, OFF_WP4R, OFF_WF1, OFF_WF2 };
        long ns[11] = { (long)BB*N1_*D0_, (long)BB*N2_*D1_, (long)BB*N3_*D2_,
                        (long)D2_*D0_, (long)D2_*D1_, (long)D1_*D0_, (long)D2_*D1_,
                        (long)D1_*D1_, (long)D2_*D2_, (long)DH_*D2_, (long)D2_*DH_ };
        for (int i = 0; i < 11; i++) { ra.src[i] = srcs[i]; ra.dst[i] = pool + offs[i]; ra.n[i] = ns[i]; }
        round_multi<<<dim3(512, 11), 256>>>(ra, 11);
    }
    const float* xr  = pool + OFF_XR;
    const float* x2r = pool + OFF_X2R;
    const float* x3r = pool + OFF_X3R;

    // 1) Et1 = tf32(exp(xr @ WL^T))^T + stats     [B,512,9216]
    tgemm<1,0,false,false><<<dim3(4,72,BB), 256>>>(
        xr, (long)N1_*D0_, D0_, pool+OFF_WL, 0L, D0_,
        pool+OFF_ET1, (long)D2_*N1_, N1_,
        N1_, D2_, D0_, 1,
        nullptr, nullptr, nullptr, pool+OFF_R1, pool+OFF_C1, nullptr, nullptr);

    // 2) Et2   [B,512,2304]
    tgemm<1,0,false,false><<<dim3(4,18,BB), 256>>>(
        x2r, (long)N2_*D1_, D1_, pool+OFF_WL2, 0L, D1_,
        pool+OFF_ET2, (long)D2_*N2_, N2_,
        N2_, D2_, D1_, 1,
        nullptr, nullptr, nullptr, pool+OFF_R2, pool+OFF_C2, nullptr, nullptr);

    // 3) Et4   [B,256,9216]
    tgemm<1,0,false,false><<<dim3(2,72,BB), 256>>>(
        xr, (long)N1_*D0_, D0_, pool+OFF_WL3, 0L, D0_,
        pool+OFF_ET4, (long)D1_*N1_, N1_,
        N1_, D1_, D0_, 1,
        nullptr, nullptr, nullptr, pool+OFF_R4, pool+OFF_C4, nullptr, nullptr);

    // 4) reciprocal of stats (R1,C1,R2,C2,R4,C4)
    recip_kernel<<<(88064 + 255) / 256, 256>>>(pool, 88064);

    // 5) St1 (symmetric triangular, split-K 8) -> St12 rows 0-511
    tgemm<5,0,true,false><<<dim3(10,1,BB*8), 256>>>(
        pool+OFF_ET1, (long)D2_*N1_, N1_, pool+OFF_ET1, (long)D2_*N1_, N1_,
        pool+OFF_ST12, (long)2*D2_*D2_, D2_,
        D2_, D2_, N1_, 8,
        nullptr, nullptr, nullptr, nullptr, nullptr, pool+OFF_R1, pool+OFF_C1);

    // 6) St2 (split 4) -> St12 rows 512-1023
    tgemm<5,0,true,false><<<dim3(10,1,BB*4), 256>>>(
        pool+OFF_ET2, (long)D2_*N2_, N2_, pool+OFF_ET2, (long)D2_*N2_, N2_,
        pool+OFF_ST12 + (long)D2_*D2_, (long)2*D2_*D2_, D2_,
        D2_, D2_, N2_, 4,
        nullptr, nullptr, nullptr, nullptr, nullptr, pool+OFF_R2, pool+OFF_C2);

    // 7) St3 (3 tiles, split 8)
    tgemm<5,0,true,false><<<dim3(3,1,BB*8), 256>>>(
        pool+OFF_ET4, (long)D1_*N1_, N1_, pool+OFF_ET4, (long)D1_*N1_, N1_,
        pool+OFF_ST3, (long)D1_*D1_, D1_,
        D1_, D1_, N1_, 8,
        nullptr, nullptr, nullptr, nullptr, nullptr, pool+OFF_R4, pool+OFF_C4);

    // 7b) round St12+St3 in place (tf32 operands for consumer GEMMs)
    {
        RoundArgs ra;
        ra.src[0] = pool + OFF_ST12; ra.dst[0] = pool + OFF_ST12; ra.n[0] = (long)BB*2*D2_*D2_;
        ra.src[1] = pool + OFF_ST3;  ra.dst[1] = pool + OFF_ST3;  ra.n[1] = (long)BB*D1_*D1_;
        round_multi<<<dim3(512, 2), 256>>>(ra, 2);
    }

    // 8) T12 = x3 @ [St1;St2]^T   [B,576,1024]
    tgemm<0,0,false,true><<<dim3(8,5,BB), 256>>>(
        x3r, (long)N3_*D2_, D2_, pool+OFF_ST12, (long)2*D2_*D2_, D2_,
        pool+OFF_T12, (long)N3_*2*D2_, 2*D2_,
        N3_, 2*D2_, D2_, 1,
        nullptr, nullptr, nullptr, nullptr, nullptr, nullptr, nullptr);
    // 9) ATT = x3 + other*(T12 @ Wp12^T + bsum)
    tgemm<2,2,false,false><<<dim3(4,5,BB), 256>>>(
        pool+OFF_T12, (long)N3_*2*D2_, 2*D2_, pool+OFF_WP12, 0L, 2*D2_,
        pool+OFF_ATT, (long)N3_*D2_, D2_,
        N3_, D2_, 2*D2_, 1,
        pool+OFF_BSUM, x3, w, nullptr, nullptr, nullptr, nullptr);

    // 12) T3 = x2 @ St3   [B,2304,256]
    tgemm<0,0,false,true><<<dim3(2,18,BB), 256>>>(
        x2r, (long)N2_*D1_, D1_, pool+OFF_ST3, (long)D1_*D1_, D1_,
        pool+OFF_T3, (long)N2_*D1_, D1_,
        N2_, D1_, D1_, 1,
        nullptr, nullptr, nullptr, nullptr, nullptr, nullptr, nullptr);
    // 13) A3 = T3 @ Wp3^T + bp3 (rounded output, feeds EtA GEMM)
    tgemm<2,0,false,true><<<dim3(2,18,BB), 256>>>(
        pool+OFF_T3, (long)N2_*D1_, D1_, pool+OFF_WP3R, 0L, D1_,
        pool+OFF_A3, (long)N2_*D1_, D1_,
        N2_, D1_, D1_, 1,
        bp3, nullptr, nullptr, nullptr, nullptr, nullptr, nullptr);
    // 14) EtA = tf32(exp(A3 @ WL4^T))^T + stats   [B,512,2304]
    tgemm<1,0,false,false><<<dim3(4,18,BB), 256>>>(
        pool+OFF_A3, (long)N2_*D1_, D1_, pool+OFF_WL4, 0L, D1_,
        pool+OFF_ETA, (long)D2_*N2_, N2_,
        N2_, D2_, D1_, 1,
        nullptr, nullptr, nullptr, pool+OFF_RA, pool+OFF_CA, nullptr, nullptr);
    // 15) reciprocal of RA,CA
    recip_kernel<<<(11264 + 255) / 256, 256>>>(pool + OFF_RA, 11264);
    // 16) St4 (symmetric, split 4)
    tgemm<5,0,true,false><<<dim3(10,1,BB*4), 256>>>(
        pool+OFF_ETA, (long)D2_*N2_, N2_, pool+OFF_ETA, (long)D2_*N2_, N2_,
        pool+OFF_ST4, (long)D2_*D2_, D2_,
        D2_, D2_, N2_, 4,
        nullptr, nullptr, nullptr, nullptr, nullptr, pool+OFF_RA, pool+OFF_CA);
    // 16b) round St4 in place
    {
        RoundArgs ra;
        ra.src[0] = pool + OFF_ST4; ra.dst[0] = pool + OFF_ST4; ra.n[0] = (long)BB*D2_*D2_;
        round_multi<<<dim3(512, 1), 256>>>(ra, 1);
    }
    // 17) T = x3 @ St4 ; ATT += f*(T @ Wp4^T + bp4)
    tgemm<0,0,false,true><<<dim3(4,5,BB), 256>>>(
        x3r, (long)N3_*D2_, D2_, pool+OFF_ST4, (long)D2_*D2_, D2_,
        pool+OFF_T, (long)N3_*D2_, D2_,
        N3_, D2_, D2_, 1,
        nullptr, nullptr, nullptr, nullptr, nullptr, nullptr, nullptr);
    tgemm<3,1,false,false><<<dim3(4,5,BB), 256>>>(
        pool+OFF_T, (long)N3_*D2_, D2_, pool+OFF_WP4R, 0L, D2_,
        pool+OFF_ATT, (long)N3_*D2_, D2_,
        N3_, D2_, D2_, 1,
        bp4, nullptr, w, nullptr, nullptr, nullptr, nullptr);

    // 19) AN = tf32(LN(ATT))
    ln_rows<<<BB * N3_, 256>>>(pool + OFF_ATT, g_norm, b_norm, pool + OFF_AN, D2_);

    // 20) H = AN @ Wfc1^T + bfc1   [B,576,2048] (fp32 out, feeds dwconv only)
    tgemm<2,0,false,false><<<dim3(16,5,BB), 256>>>(
        pool+OFF_AN, (long)N3_*D2_, D2_, pool+OFF_WF1, 0L, D2_,
        pool+OFF_H, (long)N3_*DH_, DH_,
        N3_, DH_, D2_, 1,
        bfc1, nullptr, nullptr, nullptr, nullptr, nullptr, nullptr);

    // 21) AX = tf32(gelu(LN(dwconv(H)+bdw+H)))
    dwconv_ln_gelu<<<dim3(N3_, BB), 256>>>(pool + OFF_H, Wdw, bdw, g_ln1, b_ln1, pool + OFF_AX);

    // 22) out = ATT + AX @ Wfc2^T + bfc2
    tgemm<2,0,false,false><<<dim3(4,5,BB), 256>>>(
        pool+OFF_AX, (long)N3_*DH_, DH_, pool+OFF_WF2, 0L, DH_,
        (float*)d_out, (long)N3_*D2_, D2_,
        N3_, D2_, DH_, 1,
        bfc2, pool+OFF_ATT, nullptr, nullptr, nullptr, nullptr, nullptr);
}

// round 9
// speedup vs baseline: 1.3325x; 1.1444x over previous
#include <cuda_runtime.h>
#include <math.h>
#include <stdint.h>

// ---------------- problem dims ----------------
#define BB   4
#define N1_  9216
#define N2_  2304
#define N3_  576
#define D0_  128
#define D1_  256
#define D2_  512
#define DH_  2048

// ---------------- scratch pool (floats) ----------------
#define OFF_R1   0L
#define OFF_C1   36864L
#define OFF_R2   38912L
#define OFF_C2   48128L
#define OFF_R4   50176L
#define OFF_C4   87040L
#define OFF_RA   88064L
#define OFF_CA   97280L
#define OFF_ST12 99328L            // [B][1024][512]
#define OFF_ST3  2196480L          // [B][256][256]
#define OFF_ST4  2458624L          // [B][512][512]
#define ZERO_CNT 3507200L
#define OFF_ET1  3507200L
#define OFF_ET2  22381568L
#define OFF_ET4  27100160L
#define OFF_ETA  36537344L         // reused earlier as T12 [B][576][1024]
#define OFF_T    41255936L         // Wp12 (512x1024)+bsum early; T later
#define OFF_T3   42435584L
#define OFF_A3   44794880L
#define OFF_ATT  47154176L
#define OFF_AN   48333824L
#define OFF_H    49513472L
#define OFF_AX   54232064L
// tf32-rounded operand copies
#define OFF_XR   58950656L
#define OFF_X2R  63669248L
#define OFF_X3R  66028544L
#define OFF_WL   67208192L
#define OFF_WL2  67273728L
#define OFF_WL3  67404800L
#define OFF_WL4  67437568L
#define OFF_WP3R 67568640L
#define OFF_WP4R 67634176L
#define OFF_WF1  67896320L
#define OFF_WF2  68944896L
#define POOL_SZ  69993472L

#define OFF_T12   OFF_ETA
#define OFF_WP12  OFF_T
#define OFF_BSUM  (OFF_T + 524288L)

__device__ float g_pool[POOL_SZ];

#define SMEM_DYN 61440   // 3 stages x (A,B) x 10240 bytes

// ---------------- helpers ----------------
__device__ __forceinline__ uint32_t smem_u32(const void* p) {
    uint32_t a;
    asm("{ .reg .u64 t; cvta.to.shared.u64 t, %1; cvt.u32.u64 %0, t; }" : "=r"(a) : "l"(p));
    return a;
}
__device__ __forceinline__ float to_tf32(float x) {
    float y;
    asm("cvt.rna.tf32.f32 %0, %1;" : "=f"(y) : "f"(x));
    return y;
}
__device__ __forceinline__ float4 rnd4(float4 v) {
    v.x = to_tf32(v.x); v.y = to_tf32(v.y); v.z = to_tf32(v.z); v.w = to_tf32(v.w);
    return v;
}
__device__ __forceinline__ void mma_tf32(float* d, const uint32_t* a, const uint32_t* bf) {
    asm volatile(
        "mma.sync.aligned.m16n8k8.row.col.f32.tf32.tf32.f32 "
        "{%0,%1,%2,%3}, {%4,%5,%6,%7}, {%8,%9}, {%0,%1,%2,%3};"
        : "+f"(d[0]), "+f"(d[1]), "+f"(d[2]), "+f"(d[3])
        : "r"(a[0]), "r"(a[1]), "r"(a[2]), "r"(a[3]), "r"(bf[0]), "r"(bf[1]));
}
__device__ __forceinline__ void ldm_x4(uint32_t* r, uint32_t addr) {
    asm volatile("ldmatrix.sync.aligned.m8n8.x4.shared.b16 {%0,%1,%2,%3}, [%4];"
        : "=r"(r[0]), "=r"(r[1]), "=r"(r[2]), "=r"(r[3]) : "r"(addr));
}
__device__ __forceinline__ void ldm_x2(uint32_t* r, uint32_t addr) {
    asm volatile("ldmatrix.sync.aligned.m8n8.x2.shared.b16 {%0,%1}, [%2];"
        : "=r"(r[0]), "=r"(r[1]) : "r"(addr));
}
__device__ __forceinline__ void cpa16(uint32_t dst, const float* src, bool valid) {
    int sz = valid ? 16 : 0;
    asm volatile("cp.async.cg.shared.global [%0], [%1], 16, %2;"
        :: "r"(dst), "l"(src), "r"(sz) : "memory");
}
#define CP_COMMIT() asm volatile("cp.async.commit_group;" ::: "memory")
#define CP_WAIT1()  asm volatile("cp.async.wait_group 1;" ::: "memory")

// ================= tf32 mma.sync NT GEMM (3-stage cp.async, 1 sync/tile) =============
// D[m][n] = sum_k A[m][k]*B[n][k], 128x128 CTA tile, BK=16, 256 thr / 8 warps,
// warp tile 64x32, 3-stage cp.async pipeline, ldmatrix fragments.
// Operands must be PRE-ROUNDED to tf32.
// EPI 0: C = acc (RND rounds)     EPI 1: exp + transposed store + stats
// EPI 2: C = alpha*(acc+bias)+addsrc?   EPI 3: C += alpha*(acc+bias)
// EPI 5: symmetric triangular split-K atomics (x mscale)
// EPI 6: atomicAdd(C, alpha*acc)  (plain split-K accumulate; bias prefilled)
// AMODE: 0 alpha=1 ; 1 sigmoid(*w) ; 2 (1-sigmoid)/2
template<int EPI, int AMODE, bool KSC, bool RND>
__global__ void __launch_bounds__(256, 2) tgemm(
    const float* __restrict__ A, long aStr, int lda,
    const float* __restrict__ Bm, long bStr, int ldb,
    float* __restrict__ C, long cStr, int ldc,
    int mTot, int nTot, int kTot, int splits,
    const float* __restrict__ bias,
    const float* __restrict__ addsrc,
    const float* __restrict__ wscal,
    float* __restrict__ rowsum, float* __restrict__ colsum,
    const float* __restrict__ kscale, const float* __restrict__ mscale)
{
    extern __shared__ float dynsm[];

    const int z = blockIdx.z;
    const int b = z / splits, sp = z % splits;
    const int Kc = kTot / splits;
    const int kbase = sp * Kc;
    const int nt = Kc >> 4;

    const float* Ab = A + (long)b * aStr;
    const float* Bb = Bm + (long)b * bStr;
    const float* ksc_b = KSC ? (kscale + (long)b * kTot) : nullptr;

    int bxq, byq;
    if (EPI == 5) {
        int q = blockIdx.x;
        const int T = nTot >> 7;
        int by = 0;
        while (q >= T - by) { q -= (T - by); by++; }
        byq = by; bxq = by + q;
    } else {
        bxq = blockIdx.x; byq = blockIdx.y;
    }
    const int bm = byq * 128;
    const int bn = bxq * 128;

    const int tid = threadIdx.x;
    const int wid = tid >> 5, lane = tid & 31;
    const int wm = wid & 1, wn = wid >> 1;
    const int lr = lane >> 2, lc = lane & 3;

    const uint32_t smBase = smem_u32(dynsm);
    const uint32_t BUFB = 10240u;
    // ldmatrix per-thread addresses (A at stage*BUFB, B at 30720+stage*BUFB)
    const int m8 = lane >> 3;
    const int r8 = lane & 7;
    const uint32_t asBase = smBase +
        (uint32_t)(((wm * 64 + (m8 & 1) * 8 + r8) * 20 + (m8 >> 1) * 4) * 4);
    const uint32_t bsBase = smBase + 30720u +
        (uint32_t)(((wn * 32 + r8) * 20 + ((lane >> 3) & 1) * 4) * 4);

    // per-thread copy slots
    const int cr0 = tid >> 2,        ck0 = (tid & 3) << 2;
    const int cr1 = (tid + 256) >> 2, ck1 = ((tid + 256) & 3) << 2;
    const uint32_t coff0 = (uint32_t)((cr0 * 20 + ck0) * 4);
    const uint32_t coff1 = (uint32_t)((cr1 * 20 + ck1) * 4);

    auto issue_copy = [&](int tt, uint32_t stOff) {
        const int k0 = kbase + (tt << 4);
        const uint32_t aS = smBase + stOff;
        const uint32_t bS = smBase + 30720u + stOff;
        cpa16(aS + coff0, Ab + (long)(bm + cr0) * lda + k0 + ck0, (bm + cr0) < mTot);
        cpa16(bS + coff0, Bb + (long)(bn + cr0) * ldb + k0 + ck0, true);
        cpa16(aS + coff1, Ab + (long)(bm + cr1) * lda + k0 + ck1, (bm + cr1) < mTot);
        cpa16(bS + coff1, Bb + (long)(bn + cr1) * ldb + k0 + ck1, true);
    };

    float acc[4][4][4];
#pragma unroll
    for (int i = 0; i < 4; i++)
#pragma unroll
        for (int j = 0; j < 4; j++)
#pragma unroll
            for (int r = 0; r < 4; r++) acc[i][j][r] = 0.0f;

    issue_copy(0, 0);       CP_COMMIT();
    issue_copy(1, BUFB);    CP_COMMIT();

    uint32_t curOff = 0, nxtOff = BUFB, thrOff = 2 * BUFB;

    for (int t = 0; t < nt; t++) {
        CP_WAIT1();
        __syncthreads();
        if (t + 2 < nt) issue_copy(t + 2, thrOff);
        CP_COMMIT();

        const uint32_t aCur = asBase + curOff;
        const uint32_t bCur = bsBase + curOff;
        float sc[4];
        if (KSC) {
            const int k0t = kbase + (t << 4);
            sc[0] = ksc_b[k0t + lc];
            sc[1] = ksc_b[k0t + 4 + lc];
            sc[2] = ksc_b[k0t + 8 + lc];
            sc[3] = ksc_b[k0t + 12 + lc];
        }
#pragma unroll
        for (int ks = 0; ks < 2; ks++) {
            uint32_t af[4][4];
#pragma unroll
            for (int i = 0; i < 4; i++)
                ldm_x4(af[i], aCur + i * 1280 + ks * 32);
            uint32_t bf[4][2];
#pragma unroll
            for (int j = 0; j < 4; j++) {
                ldm_x2(bf[j], bCur + j * 640 + ks * 32);
                if (KSC) {
                    bf[j][0] = __float_as_uint(to_tf32(__uint_as_float(bf[j][0]) * sc[ks * 2]));
                    bf[j][1] = __float_as_uint(to_tf32(__uint_as_float(bf[j][1]) * sc[ks * 2 + 1]));
                }
            }
#pragma unroll
            for (int i = 0; i < 4; i++)
#pragma unroll
                for (int j = 0; j < 4; j++)
                    mma_tf32(acc[i][j], af[i], bf[j]);
        }
        uint32_t tmp = curOff; curOff = nxtOff; nxtOff = thrOff; thrOff = tmp;
    }
    __syncthreads();

    // ---- epilogue ----
    float alpha = 1.0f;
    if (AMODE == 1) alpha = 1.0f / (1.0f + expf(-wscal[0]));
    if (AMODE == 2) alpha = (1.0f - 1.0f / (1.0f + expf(-wscal[0]))) * 0.5f;

    float* Cb = C + (long)b * cStr;

    if (EPI == 1) {
        float rs[4][2];
#pragma unroll
        for (int i = 0; i < 4; i++) { rs[i][0] = 0.f; rs[i][1] = 0.f; }
#pragma unroll
        for (int j = 0; j < 4; j++) {
            int col0 = bn + wn * 32 + j * 8 + lc * 2;
            float cs0 = 0.f, cs1 = 0.f;
#pragma unroll
            for (int i = 0; i < 4; i++) {
                float e0 = to_tf32(expf(acc[i][j][0]));
                float e1 = to_tf32(expf(acc[i][j][1]));
                float e2 = to_tf32(expf(acc[i][j][2]));
                float e3 = to_tf32(expf(acc[i][j][3]));
                acc[i][j][0] = e0; acc[i][j][1] = e1;
                acc[i][j][2] = e2; acc[i][j][3] = e3;
                cs0 += e0 + e2; cs1 += e1 + e3;
                rs[i][0] += e0 + e1; rs[i][1] += e2 + e3;
            }
#pragma unroll
            for (int o = 4; o <= 16; o <<= 1) {
                cs0 += __shfl_xor_sync(0xffffffff, cs0, o);
                cs1 += __shfl_xor_sync(0xffffffff, cs1, o);
            }
            if (lane < 4) {
                atomicAdd(colsum + (long)b * nTot + col0, cs0);
                atomicAdd(colsum + (long)b * nTot + col0 + 1, cs1);
            }
        }
#pragma unroll
        for (int i = 0; i < 4; i++)
#pragma unroll
            for (int h = 0; h < 2; h++) {
                float v = rs[i][h];
                v += __shfl_xor_sync(0xffffffff, v, 1);
                v += __shfl_xor_sync(0xffffffff, v, 2);
                if (lc == 0) {
                    int r = bm + wm * 64 + i * 16 + lr + h * 8;
                    atomicAdd(rowsum + (long)b * mTot + r, v);
                }
            }
        // smem-staged transposed store, coalesced float4 writes
        float* stg = dynsm;
#pragma unroll
        for (int h2 = 0; h2 < 2; h2++) {
            __syncthreads();
            if ((wn >> 1) == h2) {
                int snb = wn * 32 - h2 * 64;
#pragma unroll
                for (int j = 0; j < 4; j++) {
                    int sn = snb + j * 8 + lc * 2;
#pragma unroll
                    for (int i = 0; i < 4; i++) {
                        int ml = wm * 64 + i * 16 + lr;
                        stg[sn * 132 + ml]           = acc[i][j][0];
                        stg[(sn + 1) * 132 + ml]     = acc[i][j][1];
                        stg[sn * 132 + ml + 8]       = acc[i][j][2];
                        stg[(sn + 1) * 132 + ml + 8] = acc[i][j][3];
                    }
                }
            }
            __syncthreads();
#pragma unroll
            for (int it = 0; it < 8; it++) {
                int id = tid + (it << 8);
                int row = id >> 5, m4 = (id & 31) << 2;
                float4 v = *(float4*)&stg[row * 132 + m4];
                *(float4*)(Cb + (long)(bn + h2 * 64 + row) * ldc + bm + m4) = v;
            }
        }
    } else if (EPI == 5) {
        const float* msc = mscale + (long)b * mTot;
#pragma unroll
        for (int i = 0; i < 4; i++) {
            int r0 = bm + wm * 64 + i * 16 + lr;
            float s0 = msc[r0];
            float s1 = msc[r0 + 8];
#pragma unroll
            for (int j = 0; j < 4; j++) {
                int col0 = bn + wn * 32 + j * 8 + lc * 2;
                atomicAdd(Cb + (long)r0 * ldc + col0,           acc[i][j][0] * s0);
                atomicAdd(Cb + (long)r0 * ldc + col0 + 1,       acc[i][j][1] * s0);
                atomicAdd(Cb + (long)(r0 + 8) * ldc + col0,     acc[i][j][2] * s1);
                atomicAdd(Cb + (long)(r0 + 8) * ldc + col0 + 1, acc[i][j][3] * s1);
            }
        }
        if (bxq != byq) {
#pragma unroll
            for (int j = 0; j < 4; j++) {
                int n0 = bn + wn * 32 + j * 8 + lc * 2;
                float sn0 = msc[n0];
                float sn1 = msc[n0 + 1];
#pragma unroll
                for (int i = 0; i < 4; i++) {
                    int r0 = bm + wm * 64 + i * 16 + lr;
                    atomicAdd(Cb + (long)n0 * ldc + r0,           acc[i][j][0] * sn0);
                    atomicAdd(Cb + (long)(n0 + 1) * ldc + r0,     acc[i][j][1] * sn1);
                    atomicAdd(Cb + (long)n0 * ldc + r0 + 8,       acc[i][j][2] * sn0);
                    atomicAdd(Cb + (long)(n0 + 1) * ldc + r0 + 8, acc[i][j][3] * sn1);
                }
            }
        }
    } else if (EPI == 6) {
#pragma unroll
        for (int i = 0; i < 4; i++) {
#pragma unroll
            for (int h = 0; h < 2; h++) {
                int r = bm + wm * 64 + i * 16 + lr + h * 8;
                if (r >= mTot) continue;
                float* Crow = Cb + (long)r * ldc;
#pragma unroll
                for (int j = 0; j < 4; j++) {
                    int col0 = bn + wn * 32 + j * 8 + lc * 2;
                    atomicAdd(Crow + col0,     alpha * acc[i][j][h * 2 + 0]);
                    atomicAdd(Crow + col0 + 1, alpha * acc[i][j][h * 2 + 1]);
                }
            }
        }
    } else {
#pragma unroll
        for (int i = 0; i < 4; i++) {
#pragma unroll
            for (int h = 0; h < 2; h++) {
                int r = bm + wm * 64 + i * 16 + lr + h * 8;
                if (r >= mTot) continue;
                float* Crow = Cb + (long)r * ldc;
                const float* Srow = (EPI == 2 && addsrc) ? (addsrc + (long)b * (long)mTot * ldc + (long)r * ldc) : nullptr;
#pragma unroll
                for (int j = 0; j < 4; j++) {
                    int col0 = bn + wn * 32 + j * 8 + lc * 2;
                    float v0 = acc[i][j][h * 2 + 0];
                    float v1 = acc[i][j][h * 2 + 1];
                    if (EPI == 2) {
                        v0 = alpha * (v0 + bias[col0]);
                        v1 = alpha * (v1 + bias[col0 + 1]);
                        if (Srow) { v0 += Srow[col0]; v1 += Srow[col0 + 1]; }
                    }
                    if (EPI == 3) {
                        float2 old = *(const float2*)(Crow + col0);
                        v0 = old.x + alpha * (v0 + bias[col0]);
                        v1 = old.y + alpha * (v1 + bias[col0 + 1]);
                    }
                    if (RND) { v0 = to_tf32(v0); v1 = to_tf32(v1); }
                    float2 o; o.x = v0; o.y = v1;
                    *(float2*)(Crow + col0) = o;
                }
            }
        }
    }
}

// ---------------- utility kernels ----------------
__global__ void zero_kernel(float* p, long n) {
    long i = (long)blockIdx.x * blockDim.x + threadIdx.x;
    long stride = (long)gridDim.x * blockDim.x;
    for (; i < n; i += stride) p[i] = 0.0f;
}
__global__ void recip_kernel(float* p, int n) {
    int i = blockIdx.x * blockDim.x + threadIdx.x;
    if (i < n) p[i] = 1.0f / p[i];
}
// W12[n][k] = tf32(k<512 ? Wp1[n][k] : Wp2[n][k-512]); bsum = bp1+bp2
__global__ void concat_w(const float* __restrict__ W1, const float* __restrict__ W2,
                         const float* __restrict__ b1, const float* __restrict__ b2,
                         float* __restrict__ W12, float* __restrict__ bsum) {
    int i = blockIdx.x * 256 + threadIdx.x;
    if (i < 512 * 1024) {
        int n = i >> 10, k = i & 1023;
        W12[i] = to_tf32((k < 512) ? W1[n * 512 + k] : W2[n * 512 + k - 512]);
    }
    if (i < 512) bsum[i] = b1[i] + b2[i];
}
// ATT = x3 + other*bsum[col] + f*bp4[col]  (bias prefill for EPI6 accumulations)
__global__ void prefill_att(const float* __restrict__ x3, const float* __restrict__ bsum,
                            const float* __restrict__ bp4, const float* __restrict__ wscal,
                            float* __restrict__ ATT) {
    long i = (long)blockIdx.x * blockDim.x + threadIdx.x;
    if (i >= (long)BB * N3_ * D2_) return;
    float f = 1.0f / (1.0f + expf(-wscal[0]));
    float other = (1.0f - f) * 0.5f;
    int col = (int)(i & (D2_ - 1));
    ATT[i] = x3[i] + other * bsum[col] + f * bp4[col];
}
// out = ATT + bfc2[col]
__global__ void prefill_out(const float* __restrict__ ATT, const float* __restrict__ bfc2,
                            float* __restrict__ out) {
    long i = (long)blockIdx.x * blockDim.x + threadIdx.x;
    if (i >= (long)BB * N3_ * D2_) return;
    int col = (int)(i & (D2_ - 1));
    out[i] = ATT[i] + bfc2[col];
}

struct RoundArgs {
    const float* src[11];
    float* dst[11];
    long n[11];
};
__global__ void round_multi(RoundArgs a, int nseg) {
    int seg = blockIdx.y;
    if (seg >= nseg) return;
    const float4* s = (const float4*)a.src[seg];
    float4* d = (float4*)a.dst[seg];
    long n4 = a.n[seg] >> 2;
    for (long i = (long)blockIdx.x * blockDim.x + threadIdx.x; i < n4;
         i += (long)gridDim.x * blockDim.x)
        d[i] = rnd4(s[i]);
}

__global__ void ln_rows(const float* __restrict__ X, const float* __restrict__ g,
                        const float* __restrict__ bb, float* __restrict__ Y, int C)
{
    long row = blockIdx.x;
    const float* x = X + row * C;
    float s = 0.f, s2 = 0.f;
    for (int c = threadIdx.x; c < C; c += blockDim.x) { float v = x[c]; s += v; s2 += v * v; }
    __shared__ float sh1[32], sh2[32];
    int lane = threadIdx.x & 31, wid = threadIdx.x >> 5;
#pragma unroll
    for (int o = 16; o; o >>= 1) {
        s  += __shfl_down_sync(0xffffffff, s,  o);
        s2 += __shfl_down_sync(0xffffffff, s2, o);
    }
    if (!lane) { sh1[wid] = s; sh2[wid] = s2; }
    __syncthreads();
    if (threadIdx.x == 0) {
        float a = 0.f, c2 = 0.f;
        int nw = blockDim.x >> 5;
        for (int i = 0; i < nw; i++) { a += sh1[i]; c2 += sh2[i]; }
        float mean = a / C;
        float var  = c2 / C - mean * mean;
        sh1[0] = mean; sh2[0] = rsqrtf(var + 1e-5f);
    }
    __syncthreads();
    float mean = sh1[0], rstd = sh2[0];
    for (int c = threadIdx.x; c < C; c += blockDim.x) {
        float v = x[c];
        Y[row * C + c] = to_tf32((v - mean) * rstd * g[c] + bb[c]);
    }
}

__global__ void __launch_bounds__(256) dwconv_ln_gelu(
    const float* __restrict__ H, const float* __restrict__ Wdw,
    const float* __restrict__ bdw, const float* __restrict__ g,
    const float* __restrict__ bt, float* __restrict__ AX)
{
    const int n = blockIdx.x;
    const int b = blockIdx.y;
    const int y = n / 24, x = n % 24;
    const float* Hb = H + (long)b * 576 * 2048;
    const int tid = threadIdx.x;

    float v[8];
    float s = 0.f, s2 = 0.f;
#pragma unroll
    for (int it = 0; it < 8; it++) {
        int c = tid + it * 256;
        float a = Hb[(long)n * 2048 + c] + bdw[c];
#pragma unroll
        for (int ky = 0; ky < 3; ky++) {
            int yy = y + ky - 1;
            if (yy < 0 || yy > 23) continue;
#pragma unroll
            for (int kx = 0; kx < 3; kx++) {
                int xx = x + kx - 1;
                if (xx < 0 || xx > 23) continue;
                a += Wdw[c * 9 + ky * 3 + kx] * Hb[(long)(yy * 24 + xx) * 2048 + c];
            }
        }
        v[it] = a; s += a; s2 += a * a;
    }
    __shared__ float sh1[32], sh2[32];
    int lane = tid & 31, wid = tid >> 5;
#pragma unroll
    for (int o = 16; o; o >>= 1) {
        s  += __shfl_down_sync(0xffffffff, s,  o);
        s2 += __shfl_down_sync(0xffffffff, s2, o);
    }
    if (!lane) { sh1[wid] = s; sh2[wid] = s2; }
    __syncthreads();
    if (tid == 0) {
        float a = 0.f, c2 = 0.f;
        for (int i = 0; i < 8; i++) { a += sh1[i]; c2 += sh2[i]; }
        float mean = a / 2048.0f;
        float var  = c2 / 2048.0f - mean * mean;
        sh1[0] = mean; sh2[0] = rsqrtf(var + 1e-5f);
    }
    __syncthreads();
    float mean = sh1[0], rstd = sh2[0];
    float* out = AX + ((long)b * 576 + n) * 2048;
#pragma unroll
    for (int it = 0; it < 8; it++) {
        int c = tid + it * 256;
        float t = (v[it] - mean) * rstd * g[c] + bt[c];
        out[c] = to_tf32(0.5f * t * (1.0f + erff(t * 0.70710678118654752f)));
    }
}

// ---------------- host orchestration ----------------
#define SET_SMEM(k) cudaFuncSetAttribute(k, cudaFuncAttributeMaxDynamicSharedMemorySize, SMEM_DYN)

extern "C" void kernel_launch(void* const* d_in, const int* in_sizes, int n_in,
                              void* d_out, int out_size)
{
    const float* x      = (const float*)d_in[0];
    const float* x2     = (const float*)d_in[1];
    const float* x3     = (const float*)d_in[2];
    const float* W_lin  = (const float*)d_in[3];
    const float* W_lin2 = (const float*)d_in[4];
    const float* W_lin3 = (const float*)d_in[5];
    const float* W_lin4 = (const float*)d_in[6];
    const float* w      = (const float*)d_in[7];
    const float* Wp1 = (const float*)d_in[8];  const float* bp1 = (const float*)d_in[9];
    const float* Wp2 = (const float*)d_in[10]; const float* bp2 = (const float*)d_in[11];
    const float* Wp3 = (const float*)d_in[12]; const float* bp3 = (const float*)d_in[13];
    const float* Wp4 = (const float*)d_in[14]; const float* bp4 = (const float*)d_in[15];
    const float* g_norm = (const float*)d_in[16]; const float* b_norm = (const float*)d_in[17];
    const float* Wfc1 = (const float*)d_in[18];   const float* bfc1  = (const float*)d_in[19];
    const float* Wdw  = (const float*)d_in[20];   const float* bdw   = (const float*)d_in[21];
    const float* g_ln1 = (const float*)d_in[22];  const float* b_ln1 = (const float*)d_in[23];
    const float* Wfc2 = (const float*)d_in[24];   const float* bfc2  = (const float*)d_in[25];

    float* pool = nullptr;
    cudaGetSymbolAddress((void**)&pool, g_pool);

    SET_SMEM((tgemm<1,0,false,false>));
    SET_SMEM((tgemm<5,0,true,false>));
    SET_SMEM((tgemm<0,0,false,true>));
    SET_SMEM((tgemm<2,0,false,true>));
    SET_SMEM((tgemm<2,0,false,false>));
    SET_SMEM((tgemm<6,2,false,false>));
    SET_SMEM((tgemm<6,1,false,false>));
    SET_SMEM((tgemm<6,0,false,false>));

    // 0) zero + weight prep + operand rounding
    zero_kernel<<<1024, 256>>>(pool, ZERO_CNT);
    concat_w<<<2048, 256>>>(Wp1, Wp2, bp1, bp2, pool + OFF_WP12, pool + OFF_BSUM);
    {
        RoundArgs ra;
        const float* srcs[11] = { x, x2, x3, W_lin, W_lin2, W_lin3, W_lin4, Wp3, Wp4, Wfc1, Wfc2 };
        long offs[11] = { OFF_XR, OFF_X2R, OFF_X3R, OFF_WL, OFF_WL2, OFF_WL3, OFF_WL4,
                          OFF_WP3R, OFF_WP4R, OFF_WF1, OFF_WF2 };
        long ns[11] = { (long)BB*N1_*D0_, (long)BB*N2_*D1_, (long)BB*N3_*D2_,
                        (long)D2_*D0_, (long)D2_*D1_, (long)D1_*D0_, (long)D2_*D1_,
                        (long)D1_*D1_, (long)D2_*D2_, (long)DH_*D2_, (long)D2_*DH_ };
        for (int i = 0; i < 11; i++) { ra.src[i] = srcs[i]; ra.dst[i] = pool + offs[i]; ra.n[i] = ns[i]; }
        round_multi<<<dim3(512, 11), 256>>>(ra, 11);
    }
    const float* xr  = pool + OFF_XR;
    const float* x2r = pool + OFF_X2R;
    const float* x3r = pool + OFF_X3R;

    // 1) Et1 [B,512,9216]
    tgemm<1,0,false,false><<<dim3(4,72,BB), 256, SMEM_DYN>>>(
        xr, (long)N1_*D0_, D0_, pool+OFF_WL, 0L, D0_,
        pool+OFF_ET1, (long)D2_*N1_, N1_,
        N1_, D2_, D0_, 1,
        nullptr, nullptr, nullptr, pool+OFF_R1, pool+OFF_C1, nullptr, nullptr);
    // 2) Et2 [B,512,2304]
    tgemm<1,0,false,false><<<dim3(4,18,BB), 256, SMEM_DYN>>>(
        x2r, (long)N2_*D1_, D1_, pool+OFF_WL2, 0L, D1_,
        pool+OFF_ET2, (long)D2_*N2_, N2_,
        N2_, D2_, D1_, 1,
        nullptr, nullptr, nullptr, pool+OFF_R2, pool+OFF_C2, nullptr, nullptr);
    // 3) Et4 [B,256,9216]
    tgemm<1,0,false,false><<<dim3(2,72,BB), 256, SMEM_DYN>>>(
        xr, (long)N1_*D0_, D0_, pool+OFF_WL3, 0L, D0_,
        pool+OFF_ET4, (long)D1_*N1_, N1_,
        N1_, D1_, D0_, 1,
        nullptr, nullptr, nullptr, pool+OFF_R4, pool+OFF_C4, nullptr, nullptr);

    // 4) reciprocals + ATT prefill
    recip_kernel<<<(88064 + 255) / 256, 256>>>(pool, 88064);
    prefill_att<<<(BB*N3_*D2_ + 255)/256, 256>>>(x3, pool+OFF_BSUM, bp4, w, pool+OFF_ATT);

    // 5) St1 (symmetric triangular, split-K 8)
    tgemm<5,0,true,false><<<dim3(10,1,BB*8), 256, SMEM_DYN>>>(
        pool+OFF_ET1, (long)D2_*N1_, N1_, pool+OFF_ET1, (long)D2_*N1_, N1_,
        pool+OFF_ST12, (long)2*D2_*D2_, D2_,
        D2_, D2_, N1_, 8,
        nullptr, nullptr, nullptr, nullptr, nullptr, pool+OFF_R1, pool+OFF_C1);
    // 6) St2 (split 4)
    tgemm<5,0,true,false><<<dim3(10,1,BB*4), 256, SMEM_DYN>>>(
        pool+OFF_ET2, (long)D2_*N2_, N2_, pool+OFF_ET2, (long)D2_*N2_, N2_,
        pool+OFF_ST12 + (long)D2_*D2_, (long)2*D2_*D2_, D2_,
        D2_, D2_, N2_, 4,
        nullptr, nullptr, nullptr, nullptr, nullptr, pool+OFF_R2, pool+OFF_C2);
    // 7) St3 (split 8)
    tgemm<5,0,true,false><<<dim3(3,1,BB*8), 256, SMEM_DYN>>>(
        pool+OFF_ET4, (long)D1_*N1_, N1_, pool+OFF_ET4, (long)D1_*N1_, N1_,
        pool+OFF_ST3, (long)D1_*D1_, D1_,
        D1_, D1_, N1_, 8,
        nullptr, nullptr, nullptr, nullptr, nullptr, pool+OFF_R4, pool+OFF_C4);
    // 7b) round St12+St3 in place
    {
        RoundArgs ra;
        ra.src[0] = pool + OFF_ST12; ra.dst[0] = pool + OFF_ST12; ra.n[0] = (long)BB*2*D2_*D2_;
        ra.src[1] = pool + OFF_ST3;  ra.dst[1] = pool + OFF_ST3;  ra.n[1] = (long)BB*D1_*D1_;
        round_multi<<<dim3(512, 2), 256>>>(ra, 2);
    }

    // 8) T12 = x3 @ [St1;St2]^T   [B,576,1024]
    tgemm<0,0,false,true><<<dim3(8,5,BB), 256, SMEM_DYN>>>(
        x3r, (long)N3_*D2_, D2_, pool+OFF_ST12, (long)2*D2_*D2_, D2_,
        pool+OFF_T12, (long)N3_*2*D2_, 2*D2_,
        N3_, 2*D2_, D2_, 1,
        nullptr, nullptr, nullptr, nullptr, nullptr, nullptr, nullptr);
    // 9) ATT += other * (T12 @ Wp12^T)   (bias prefilled; split-K 2)
    tgemm<6,2,false,false><<<dim3(4,5,BB*2), 256, SMEM_DYN>>>(
        pool+OFF_T12, (long)N3_*2*D2_, 2*D2_, pool+OFF_WP12, 0L, 2*D2_,
        pool+OFF_ATT, (long)N3_*D2_, D2_,
        N3_, D2_, 2*D2_, 2,
        nullptr, nullptr, w, nullptr, nullptr, nullptr, nullptr);

    // 12) T3 = x2 @ St3   [B,2304,256]
    tgemm<0,0,false,true><<<dim3(2,18,BB), 256, SMEM_DYN>>>(
        x2r, (long)N2_*D1_, D1_, pool+OFF_ST3, (long)D1_*D1_, D1_,
        pool+OFF_T3, (long)N2_*D1_, D1_,
        N2_, D1_, D1_, 1,
        nullptr, nullptr, nullptr, nullptr, nullptr, nullptr, nullptr);
    // 13) A3 = T3 @ Wp3^T + bp3
    tgemm<2,0,false,true><<<dim3(2,18,BB), 256, SMEM_DYN>>>(
        pool+OFF_T3, (long)N2_*D1_, D1_, pool+OFF_WP3R, 0L, D1_,
        pool+OFF_A3, (long)N2_*D1_, D1_,
        N2_, D1_, D1_, 1,
        bp3, nullptr, nullptr, nullptr, nullptr, nullptr, nullptr);
    // 14) EtA [B,512,2304]
    tgemm<1,0,false,false><<<dim3(4,18,BB), 256, SMEM_DYN>>>(
        pool+OFF_A3, (long)N2_*D1_, D1_, pool+OFF_WL4, 0L, D1_,
        pool+OFF_ETA, (long)D2_*N2_, N2_,
        N2_, D2_, D1_, 1,
        nullptr, nullptr, nullptr, pool+OFF_RA, pool+OFF_CA, nullptr, nullptr);
    // 15) reciprocals RA,CA
    recip_kernel<<<(11264 + 255) / 256, 256>>>(pool + OFF_RA, 11264);
    // 16) St4 (split 4)
    tgemm<5,0,true,false><<<dim3(10,1,BB*4), 256, SMEM_DYN>>>(
        pool+OFF_ETA, (long)D2_*N2_, N2_, pool+OFF_ETA, (long)D2_*N2_, N2_,
        pool+OFF_ST4, (long)D2_*D2_, D2_,
        D2_, D2_, N2_, 4,
        nullptr, nullptr, nullptr, nullptr, nullptr, pool+OFF_RA, pool+OFF_CA);
    // 16b) round St4 in place
    {
        RoundArgs ra;
        ra.src[0] = pool + OFF_ST4; ra.dst[0] = pool + OFF_ST4; ra.n[0] = (long)BB*D2_*D2_;
        round_multi<<<dim3(512, 1), 256>>>(ra, 1);
    }
    // 17) T = x3 @ St4 ; ATT += f * (T @ Wp4^T)   (bias prefilled; split-K 2)
    tgemm<0,0,false,true><<<dim3(4,5,BB), 256, SMEM_DYN>>>(
        x3r, (long)N3_*D2_, D2_, pool+OFF_ST4, (long)D2_*D2_, D2_,
        pool+OFF_T, (long)N3_*D2_, D2_,
        N3_, D2_, D2_, 1,
        nullptr, nullptr, nullptr, nullptr, nullptr, nullptr, nullptr);
    tgemm<6,1,false,false><<<dim3(4,5,BB*2), 256, SMEM_DYN>>>(
        pool+OFF_T, (long)N3_*D2_, D2_, pool+OFF_WP4R, 0L, D2_,
        pool+OFF_ATT, (long)N3_*D2_, D2_,
        N3_, D2_, D2_, 2,
        nullptr, nullptr, w, nullptr, nullptr, nullptr, nullptr);

    // 19) AN = tf32(LN(ATT))
    ln_rows<<<BB * N3_, 256>>>(pool + OFF_ATT, g_norm, b_norm, pool + OFF_AN, D2_);

    // 20) H = AN @ Wfc1^T + bfc1   [B,576,2048]
    tgemm<2,0,false,false><<<dim3(16,5,BB), 256, SMEM_DYN>>>(
        pool+OFF_AN, (long)N3_*D2_, D2_, pool+OFF_WF1, 0L, D2_,
        pool+OFF_H, (long)N3_*DH_, DH_,
        N3_, DH_, D2_, 1,
        bfc1, nullptr, nullptr, nullptr, nullptr, nullptr, nullptr);

    // 21) AX = tf32(gelu(LN(dwconv(H)+bdw+H)))
    dwconv_ln_gelu<<<dim3(N3_, BB), 256>>>(pool + OFF_H, Wdw, bdw, g_ln1, b_ln1, pool + OFF_AX);

    // 22) out = ATT + bfc2 (prefill), then += AX @ Wfc2^T  (split-K 4)
    prefill_out<<<(BB*N3_*D2_ + 255)/256, 256>>>(pool + OFF_ATT, bfc2, (float*)d_out);
    tgemm<6,0,false,false><<<dim3(4,5,BB*4), 256, SMEM_DYN>>>(
        pool+OFF_AX, (long)N3_*DH_, DH_, pool+OFF_WF2, 0L, DH_,
        (float*)d_out, (long)N3_*D2_, D2_,
        N3_, D2_, DH_, 4,
        nullptr, nullptr, nullptr, nullptr, nullptr, nullptr, nullptr);
}

// round 10
// speedup vs baseline: 1.4361x; 1.0778x over previous
#include <cuda_runtime.h>
#include <math.h>
#include <stdint.h>

// ---------------- problem dims ----------------
#define BB   4
#define N1_  9216
#define N2_  2304
#define N3_  576
#define D0_  128
#define D1_  256
#define D2_  512
#define DH_  2048

// ---------------- scratch pool (floats) ----------------
#define OFF_R1   0L
#define OFF_C1   36864L
#define OFF_R2   38912L
#define OFF_C2   48128L
#define OFF_R4   50176L
#define OFF_C4   87040L
#define OFF_RA   88064L
#define OFF_CA   97280L
#define OFF_ST12 99328L            // [B][1024][512]
#define OFF_ST3  2196480L          // [B][256][256]
#define OFF_ST4  2458624L          // [B][512][512]
#define ZERO_CNT 3507200L
#define OFF_ET1  3507200L
#define OFF_ET2  22381568L
#define OFF_ET4  27100160L
#define OFF_ETA  36537344L         // reused earlier as T12 [B][576][1024]
#define OFF_T    41255936L         // Wp12 (512x1024)+bsum early; T later
#define OFF_T3   42435584L
#define OFF_A3   44794880L
#define OFF_ATT  47154176L
#define OFF_AN   48333824L
#define OFF_H    49513472L
#define OFF_AX   54232064L
// tf32-rounded operand copies
#define OFF_XR   58950656L
#define OFF_X2R  63669248L
#define OFF_X3R  66028544L
#define OFF_WL   67208192L
#define OFF_WL2  67273728L
#define OFF_WL3  67404800L
#define OFF_WL4  67437568L
#define OFF_WP3R 67568640L
#define OFF_WP4R 67634176L
#define OFF_WF1  67896320L
#define OFF_WF2  68944896L
#define POOL_SZ  69993472L

#define OFF_T12   OFF_ETA
#define OFF_WP12  OFF_T
#define OFF_BSUM  (OFF_T + 524288L)

__device__ float g_pool[POOL_SZ];

// 3 stages x (A,B) x (128 rows x 36 floats) = 3*2*18432 bytes
#define STAGEB  18432u
#define BOFF    55296u
#define SMEM_DYN 110592

// ---------------- helpers ----------------
__device__ __forceinline__ uint32_t smem_u32(const void* p) {
    uint32_t a;
    asm("{ .reg .u64 t; cvta.to.shared.u64 t, %1; cvt.u32.u64 %0, t; }" : "=r"(a) : "l"(p));
    return a;
}
__device__ __forceinline__ float to_tf32(float x) {
    float y;
    asm("cvt.rna.tf32.f32 %0, %1;" : "=f"(y) : "f"(x));
    return y;
}
__device__ __forceinline__ float4 rnd4(float4 v) {
    v.x = to_tf32(v.x); v.y = to_tf32(v.y); v.z = to_tf32(v.z); v.w = to_tf32(v.w);
    return v;
}
__device__ __forceinline__ void mma_tf32(float* d, const uint32_t* a, const uint32_t* bf) {
    asm volatile(
        "mma.sync.aligned.m16n8k8.row.col.f32.tf32.tf32.f32 "
        "{%0,%1,%2,%3}, {%4,%5,%6,%7}, {%8,%9}, {%0,%1,%2,%3};"
        : "+f"(d[0]), "+f"(d[1]), "+f"(d[2]), "+f"(d[3])
        : "r"(a[0]), "r"(a[1]), "r"(a[2]), "r"(a[3]), "r"(bf[0]), "r"(bf[1]));
}
__device__ __forceinline__ void ldm_x4(uint32_t* r, uint32_t addr) {
    asm volatile("ldmatrix.sync.aligned.m8n8.x4.shared.b16 {%0,%1,%2,%3}, [%4];"
        : "=r"(r[0]), "=r"(r[1]), "=r"(r[2]), "=r"(r[3]) : "r"(addr));
}
__device__ __forceinline__ void ldm_x2(uint32_t* r, uint32_t addr) {
    asm volatile("ldmatrix.sync.aligned.m8n8.x2.shared.b16 {%0,%1}, [%2];"
        : "=r"(r[0]), "=r"(r[1]) : "r"(addr));
}
__device__ __forceinline__ void cpa16(uint32_t dst, const float* src, bool valid) {
    int sz = valid ? 16 : 0;
    asm volatile("cp.async.cg.shared.global [%0], [%1], 16, %2;"
        :: "r"(dst), "l"(src), "r"(sz) : "memory");
}
#define CP_COMMIT() asm volatile("cp.async.commit_group;" ::: "memory")
#define CP_WAIT1()  asm volatile("cp.async.wait_group 1;" ::: "memory")

// ================= tf32 mma.sync NT GEMM (3-stage cp.async, BK=32, 1 sync/tile) ======
// D[m][n] = sum_k A[m][k]*B[n][k], 128x128 CTA tile, BK=32, 256 thr / 8 warps,
// warp tile 64x32, 3-stage cp.async pipeline, ldmatrix fragments.
// Operands must be PRE-ROUNDED to tf32.
// EPI 0: C = acc (RND rounds)     EPI 1: exp + transposed store + stats
// EPI 2: C = alpha*(acc+bias)+addsrc?   EPI 3: C += alpha*(acc+bias)
// EPI 5: symmetric triangular split-K atomics (x mscale)
// EPI 6: atomicAdd(C, alpha*acc)  (plain split-K accumulate; bias prefilled)
// AMODE: 0 alpha=1 ; 1 sigmoid(*w) ; 2 (1-sigmoid)/2
template<int EPI, int AMODE, bool KSC, bool RND>
__global__ void __launch_bounds__(256, 2) tgemm(
    const float* __restrict__ A, long aStr, int lda,
    const float* __restrict__ Bm, long bStr, int ldb,
    float* __restrict__ C, long cStr, int ldc,
    int mTot, int nTot, int kTot, int splits,
    const float* __restrict__ bias,
    const float* __restrict__ addsrc,
    const float* __restrict__ wscal,
    float* __restrict__ rowsum, float* __restrict__ colsum,
    const float* __restrict__ kscale, const float* __restrict__ mscale)
{
    extern __shared__ float dynsm[];

    const int z = blockIdx.z;
    const int b = z / splits, sp = z % splits;
    const int Kc = kTot / splits;
    const int kbase = sp * Kc;
    const int nt = Kc >> 5;

    const float* Ab = A + (long)b * aStr;
    const float* Bb = Bm + (long)b * bStr;
    const float* ksc_b = KSC ? (kscale + (long)b * kTot) : nullptr;

    int bxq, byq;
    if (EPI == 5) {
        int q = blockIdx.x;
        const int T = nTot >> 7;
        int by = 0;
        while (q >= T - by) { q -= (T - by); by++; }
        byq = by; bxq = by + q;
    } else {
        bxq = blockIdx.x; byq = blockIdx.y;
    }
    const int bm = byq * 128;
    const int bn = bxq * 128;

    const int tid = threadIdx.x;
    const int wid = tid >> 5, lane = tid & 31;
    const int wm = wid & 1, wn = wid >> 1;
    const int lr = lane >> 2, lc = lane & 3;

    const uint32_t smBase = smem_u32(dynsm);
    // ldmatrix per-thread addresses (A at stage*STAGEB, B at BOFF+stage*STAGEB)
    const int m8 = lane >> 3;
    const int r8 = lane & 7;
    const uint32_t asBase = smBase +
        (uint32_t)(((wm * 64 + (m8 & 1) * 8 + r8) * 36 + (m8 >> 1) * 4) * 4);
    const uint32_t bsBase = smBase + BOFF +
        (uint32_t)(((wn * 32 + r8) * 36 + ((lane >> 3) & 1) * 4) * 4);

    auto issue_copy = [&](int tt, uint32_t stOff) {
        const int k0 = kbase + (tt << 5);
        const uint32_t aS = smBase + stOff;
        const uint32_t bS = smBase + BOFF + stOff;
#pragma unroll
        for (int l = 0; l < 4; l++) {
            int c = tid + (l << 8);
            int row = c >> 3, kq = (c & 7) << 2;
            uint32_t off = (uint32_t)((row * 36 + kq) * 4);
            cpa16(aS + off, Ab + (long)(bm + row) * lda + k0 + kq, (bm + row) < mTot);
            cpa16(bS + off, Bb + (long)(bn + row) * ldb + k0 + kq, true);
        }
    };

    float acc[4][4][4];
#pragma unroll
    for (int i = 0; i < 4; i++)
#pragma unroll
        for (int j = 0; j < 4; j++)
#pragma unroll
            for (int r = 0; r < 4; r++) acc[i][j][r] = 0.0f;

    issue_copy(0, 0);        CP_COMMIT();
    if (nt > 1) { issue_copy(1, STAGEB); }
    CP_COMMIT();

    uint32_t curOff = 0, nxtOff = STAGEB, thrOff = 2 * STAGEB;

    for (int t = 0; t < nt; t++) {
        CP_WAIT1();
        __syncthreads();
        if (t + 2 < nt) issue_copy(t + 2, thrOff);
        CP_COMMIT();

        const uint32_t aCur = asBase + curOff;
        const uint32_t bCur = bsBase + curOff;
        float sc[8];
        if (KSC) {
            const int k0t = kbase + (t << 5);
#pragma unroll
            for (int ks = 0; ks < 4; ks++) {
                sc[2 * ks]     = ksc_b[k0t + ks * 8 + lc];
                sc[2 * ks + 1] = ksc_b[k0t + ks * 8 + 4 + lc];
            }
        }
#pragma unroll
        for (int ks = 0; ks < 4; ks++) {
            uint32_t af[4][4];
#pragma unroll
            for (int i = 0; i < 4; i++)
                ldm_x4(af[i], aCur + i * 2304 + ks * 32);
            uint32_t bf[4][2];
#pragma unroll
            for (int j = 0; j < 4; j++) {
                ldm_x2(bf[j], bCur + j * 1152 + ks * 32);
                if (KSC) {
                    bf[j][0] = __float_as_uint(to_tf32(__uint_as_float(bf[j][0]) * sc[2 * ks]));
                    bf[j][1] = __float_as_uint(to_tf32(__uint_as_float(bf[j][1]) * sc[2 * ks + 1]));
                }
            }
#pragma unroll
            for (int i = 0; i < 4; i++)
#pragma unroll
                for (int j = 0; j < 4; j++)
                    mma_tf32(acc[i][j], af[i], bf[j]);
        }
        uint32_t tmp = curOff; curOff = nxtOff; nxtOff = thrOff; thrOff = tmp;
    }
    __syncthreads();

    // ---- epilogue ----
    float alpha = 1.0f;
    if (AMODE == 1) alpha = 1.0f / (1.0f + expf(-wscal[0]));
    if (AMODE == 2) alpha = (1.0f - 1.0f / (1.0f + expf(-wscal[0]))) * 0.5f;

    float* Cb = C + (long)b * cStr;

    if (EPI == 1) {
        float rs[4][2];
#pragma unroll
        for (int i = 0; i < 4; i++) { rs[i][0] = 0.f; rs[i][1] = 0.f; }
#pragma unroll
        for (int j = 0; j < 4; j++) {
            int col0 = bn + wn * 32 + j * 8 + lc * 2;
            float cs0 = 0.f, cs1 = 0.f;
#pragma unroll
            for (int i = 0; i < 4; i++) {
                float e0 = to_tf32(expf(acc[i][j][0]));
                float e1 = to_tf32(expf(acc[i][j][1]));
                float e2 = to_tf32(expf(acc[i][j][2]));
                float e3 = to_tf32(expf(acc[i][j][3]));
                acc[i][j][0] = e0; acc[i][j][1] = e1;
                acc[i][j][2] = e2; acc[i][j][3] = e3;
                cs0 += e0 + e2; cs1 += e1 + e3;
                rs[i][0] += e0 + e1; rs[i][1] += e2 + e3;
            }
#pragma unroll
            for (int o = 4; o <= 16; o <<= 1) {
                cs0 += __shfl_xor_sync(0xffffffff, cs0, o);
                cs1 += __shfl_xor_sync(0xffffffff, cs1, o);
            }
            if (lane < 4) {
                atomicAdd(colsum + (long)b * nTot + col0, cs0);
                atomicAdd(colsum + (long)b * nTot + col0 + 1, cs1);
            }
        }
#pragma unroll
        for (int i = 0; i < 4; i++)
#pragma unroll
            for (int h = 0; h < 2; h++) {
                float v = rs[i][h];
                v += __shfl_xor_sync(0xffffffff, v, 1);
                v += __shfl_xor_sync(0xffffffff, v, 2);
                if (lc == 0) {
                    int r = bm + wm * 64 + i * 16 + lr + h * 8;
                    atomicAdd(rowsum + (long)b * mTot + r, v);
                }
            }
        // smem-staged transposed store, coalesced float4 writes
        float* stg = dynsm;
#pragma unroll
        for (int h2 = 0; h2 < 2; h2++) {
            __syncthreads();
            if ((wn >> 1) == h2) {
                int snb = wn * 32 - h2 * 64;
#pragma unroll
                for (int j = 0; j < 4; j++) {
                    int sn = snb + j * 8 + lc * 2;
#pragma unroll
                    for (int i = 0; i < 4; i++) {
                        int ml = wm * 64 + i * 16 + lr;
                        stg[sn * 132 + ml]           = acc[i][j][0];
                        stg[(sn + 1) * 132 + ml]     = acc[i][j][1];
                        stg[sn * 132 + ml + 8]       = acc[i][j][2];
                        stg[(sn + 1) * 132 + ml + 8] = acc[i][j][3];
                    }
                }
            }
            __syncthreads();
#pragma unroll
            for (int it = 0; it < 8; it++) {
                int id = tid + (it << 8);
                int row = id >> 5, m4 = (id & 31) << 2;
                float4 v = *(float4*)&stg[row * 132 + m4];
                *(float4*)(Cb + (long)(bn + h2 * 64 + row) * ldc + bm + m4) = v;
            }
        }
    } else if (EPI == 5) {
        const float* msc = mscale + (long)b * mTot;
#pragma unroll
        for (int i = 0; i < 4; i++) {
            int r0 = bm + wm * 64 + i * 16 + lr;
            float s0 = msc[r0];
            float s1 = msc[r0 + 8];
#pragma unroll
            for (int j = 0; j < 4; j++) {
                int col0 = bn + wn * 32 + j * 8 + lc * 2;
                atomicAdd(Cb + (long)r0 * ldc + col0,           acc[i][j][0] * s0);
                atomicAdd(Cb + (long)r0 * ldc + col0 + 1,       acc[i][j][1] * s0);
                atomicAdd(Cb + (long)(r0 + 8) * ldc + col0,     acc[i][j][2] * s1);
                atomicAdd(Cb + (long)(r0 + 8) * ldc + col0 + 1, acc[i][j][3] * s1);
            }
        }
        if (bxq != byq) {
#pragma unroll
            for (int j = 0; j < 4; j++) {
                int n0 = bn + wn * 32 + j * 8 + lc * 2;
                float sn0 = msc[n0];
                float sn1 = msc[n0 + 1];
#pragma unroll
                for (int i = 0; i < 4; i++) {
                    int r0 = bm + wm * 64 + i * 16 + lr;
                    atomicAdd(Cb + (long)n0 * ldc + r0,           acc[i][j][0] * sn0);
                    atomicAdd(Cb + (long)(n0 + 1) * ldc + r0,     acc[i][j][1] * sn1);
                    atomicAdd(Cb + (long)n0 * ldc + r0 + 8,       acc[i][j][2] * sn0);
                    atomicAdd(Cb + (long)(n0 + 1) * ldc + r0 + 8, acc[i][j][3] * sn1);
                }
            }
        }
    } else if (EPI == 6) {
#pragma unroll
        for (int i = 0; i < 4; i++) {
#pragma unroll
            for (int h = 0; h < 2; h++) {
                int r = bm + wm * 64 + i * 16 + lr + h * 8;
                if (r >= mTot) continue;
                float* Crow = Cb + (long)r * ldc;
#pragma unroll
                for (int j = 0; j < 4; j++) {
                    int col0 = bn + wn * 32 + j * 8 + lc * 2;
                    atomicAdd(Crow + col0,     alpha * acc[i][j][h * 2 + 0]);
                    atomicAdd(Crow + col0 + 1, alpha * acc[i][j][h * 2 + 1]);
                }
            }
        }
    } else {
#pragma unroll
        for (int i = 0; i < 4; i++) {
#pragma unroll
            for (int h = 0; h < 2; h++) {
                int r = bm + wm * 64 + i * 16 + lr + h * 8;
                if (r >= mTot) continue;
                float* Crow = Cb + (long)r * ldc;
                const float* Srow = (EPI == 2 && addsrc) ? (addsrc + (long)b * (long)mTot * ldc + (long)r * ldc) : nullptr;
#pragma unroll
                for (int j = 0; j < 4; j++) {
                    int col0 = bn + wn * 32 + j * 8 + lc * 2;
                    float v0 = acc[i][j][h * 2 + 0];
                    float v1 = acc[i][j][h * 2 + 1];
                    if (EPI == 2) {
                        v0 = alpha * (v0 + bias[col0]);
                        v1 = alpha * (v1 + bias[col0 + 1]);
                        if (Srow) { v0 += Srow[col0]; v1 += Srow[col0 + 1]; }
                    }
                    if (EPI == 3) {
                        float2 old = *(const float2*)(Crow + col0);
                        v0 = old.x + alpha * (v0 + bias[col0]);
                        v1 = old.y + alpha * (v1 + bias[col0 + 1]);
                    }
                    if (RND) { v0 = to_tf32(v0); v1 = to_tf32(v1); }
                    float2 o; o.x = v0; o.y = v1;
                    *(float2*)(Crow + col0) = o;
                }
            }
        }
    }
}

// ---------------- utility kernels ----------------
__global__ void zero_kernel(float* p, long n) {
    long i = (long)blockIdx.x * blockDim.x + threadIdx.x;
    long stride = (long)gridDim.x * blockDim.x;
    for (; i < n; i += stride) p[i] = 0.0f;
}
__global__ void recip_kernel(float* p, int n) {
    int i = blockIdx.x * blockDim.x + threadIdx.x;
    if (i < n) p[i] = 1.0f / p[i];
}
// W12[n][k] = tf32(k<512 ? Wp1[n][k] : Wp2[n][k-512]); bsum = bp1+bp2
__global__ void concat_w(const float* __restrict__ W1, const float* __restrict__ W2,
                         const float* __restrict__ b1, const float* __restrict__ b2,
                         float* __restrict__ W12, float* __restrict__ bsum) {
    int i = blockIdx.x * 256 + threadIdx.x;
    if (i < 512 * 1024) {
        int n = i >> 10, k = i & 1023;
        W12[i] = to_tf32((k < 512) ? W1[n * 512 + k] : W2[n * 512 + k - 512]);
    }
    if (i < 512) bsum[i] = b1[i] + b2[i];
}
// ATT = x3 + other*bsum[col] + f*bp4[col]
__global__ void prefill_att(const float* __restrict__ x3, const float* __restrict__ bsum,
                            const float* __restrict__ bp4, const float* __restrict__ wscal,
                            float* __restrict__ ATT) {
    long i = (long)blockIdx.x * blockDim.x + threadIdx.x;
    if (i >= (long)BB * N3_ * D2_) return;
    float f = 1.0f / (1.0f + expf(-wscal[0]));
    float other = (1.0f - f) * 0.5f;
    int col = (int)(i & (D2_ - 1));
    ATT[i] = x3[i] + other * bsum[col] + f * bp4[col];
}
// out = ATT + bfc2[col]
__global__ void prefill_out(const float* __restrict__ ATT, const float* __restrict__ bfc2,
                            float* __restrict__ out) {
    long i = (long)blockIdx.x * blockDim.x + threadIdx.x;
    if (i >= (long)BB * N3_ * D2_) return;
    int col = (int)(i & (D2_ - 1));
    out[i] = ATT[i] + bfc2[col];
}

struct RoundArgs {
    const float* src[11];
    float* dst[11];
    long n[11];
};
__global__ void round_multi(RoundArgs a, int nseg) {
    int seg = blockIdx.y;
    if (seg >= nseg) return;
    const float4* s = (const float4*)a.src[seg];
    float4* d = (float4*)a.dst[seg];
    long n4 = a.n[seg] >> 2;
    for (long i = (long)blockIdx.x * blockDim.x + threadIdx.x; i < n4;
         i += (long)gridDim.x * blockDim.x)
        d[i] = rnd4(s[i]);
}

__global__ void ln_rows(const float* __restrict__ X, const float* __restrict__ g,
                        const float* __restrict__ bb, float* __restrict__ Y, int C)
{
    long row = blockIdx.x;
    const float* x = X + row * C;
    float s = 0.f, s2 = 0.f;
    for (int c = threadIdx.x; c < C; c += blockDim.x) { float v = x[c]; s += v; s2 += v * v; }
    __shared__ float sh1[32], sh2[32];
    int lane = threadIdx.x & 31, wid = threadIdx.x >> 5;
#pragma unroll
    for (int o = 16; o; o >>= 1) {
        s  += __shfl_down_sync(0xffffffff, s,  o);
        s2 += __shfl_down_sync(0xffffffff, s2, o);
    }
    if (!lane) { sh1[wid] = s; sh2[wid] = s2; }
    __syncthreads();
    if (threadIdx.x == 0) {
        float a = 0.f, c2 = 0.f;
        int nw = blockDim.x >> 5;
        for (int i = 0; i < nw; i++) { a += sh1[i]; c2 += sh2[i]; }
        float mean = a / C;
        float var  = c2 / C - mean * mean;
        sh1[0] = mean; sh2[0] = rsqrtf(var + 1e-5f);
    }
    __syncthreads();
    float mean = sh1[0], rstd = sh2[0];
    for (int c = threadIdx.x; c < C; c += blockDim.x) {
        float v = x[c];
        Y[row * C + c] = to_tf32((v - mean) * rstd * g[c] + bb[c]);
    }
}

__global__ void __launch_bounds__(256) dwconv_ln_gelu(
    const float* __restrict__ H, const float* __restrict__ Wdw,
    const float* __restrict__ bdw, const float* __restrict__ g,
    const float* __restrict__ bt, float* __restrict__ AX)
{
    const int n = blockIdx.x;
    const int b = blockIdx.y;
    const int y = n / 24, x = n % 24;
    const float* Hb = H + (long)b * 576 * 2048;
    const int tid = threadIdx.x;

    float v[8];
    float s = 0.f, s2 = 0.f;
#pragma unroll
    for (int it = 0; it < 8; it++) {
        int c = tid + it * 256;
        float a = Hb[(long)n * 2048 + c] + bdw[c];
#pragma unroll
        for (int ky = 0; ky < 3; ky++) {
            int yy = y + ky - 1;
            if (yy < 0 || yy > 23) continue;
#pragma unroll
            for (int kx = 0; kx < 3; kx++) {
                int xx = x + kx - 1;
                if (xx < 0 || xx > 23) continue;
                a += Wdw[c * 9 + ky * 3 + kx] * Hb[(long)(yy * 24 + xx) * 2048 + c];
            }
        }
        v[it] = a; s += a; s2 += a * a;
    }
    __shared__ float sh1[32], sh2[32];
    int lane = tid & 31, wid = tid >> 5;
#pragma unroll
    for (int o = 16; o; o >>= 1) {
        s  += __shfl_down_sync(0xffffffff, s,  o);
        s2 += __shfl_down_sync(0xffffffff, s2, o);
    }
    if (!lane) { sh1[wid] = s; sh2[wid] = s2; }
    __syncthreads();
    if (tid == 0) {
        float a = 0.f, c2 = 0.f;
        for (int i = 0; i < 8; i++) { a += sh1[i]; c2 += sh2[i]; }
        float mean = a / 2048.0f;
        float var  = c2 / 2048.0f - mean * mean;
        sh1[0] = mean; sh2[0] = rsqrtf(var + 1e-5f);
    }
    __syncthreads();
    float mean = sh1[0], rstd = sh2[0];
    float* out = AX + ((long)b * 576 + n) * 2048;
#pragma unroll
    for (int it = 0; it < 8; it++) {
        int c = tid + it * 256;
        float t = (v[it] - mean) * rstd * g[c] + bt[c];
        out[c] = to_tf32(0.5f * t * (1.0f + erff(t * 0.70710678118654752f)));
    }
}

// ---------------- host orchestration ----------------
#define SET_SMEM(k) cudaFuncSetAttribute(k, cudaFuncAttributeMaxDynamicSharedMemorySize, SMEM_DYN)

extern "C" void kernel_launch(void* const* d_in, const int* in_sizes, int n_in,
                              void* d_out, int out_size)
{
    const float* x      = (const float*)d_in[0];
    const float* x2     = (const float*)d_in[1];
    const float* x3     = (const float*)d_in[2];
    const float* W_lin  = (const float*)d_in[3];
    const float* W_lin2 = (const float*)d_in[4];
    const float* W_lin3 = (const float*)d_in[5];
    const float* W_lin4 = (const float*)d_in[6];
    const float* w      = (const float*)d_in[7];
    const float* Wp1 = (const float*)d_in[8];  const float* bp1 = (const float*)d_in[9];
    const float* Wp2 = (const float*)d_in[10]; const float* bp2 = (const float*)d_in[11];
    const float* Wp3 = (const float*)d_in[12]; const float* bp3 = (const float*)d_in[13];
    const float* Wp4 = (const float*)d_in[14]; const float* bp4 = (const float*)d_in[15];
    const float* g_norm = (const float*)d_in[16]; const float* b_norm = (const float*)d_in[17];
    const float* Wfc1 = (const float*)d_in[18];   const float* bfc1  = (const float*)d_in[19];
    const float* Wdw  = (const float*)d_in[20];   const float* bdw   = (const float*)d_in[21];
    const float* g_ln1 = (const float*)d_in[22];  const float* b_ln1 = (const float*)d_in[23];
    const float* Wfc2 = (const float*)d_in[24];   const float* bfc2  = (const float*)d_in[25];

    float* pool = nullptr;
    cudaGetSymbolAddress((void**)&pool, g_pool);

    SET_SMEM((tgemm<1,0,false,false>));
    SET_SMEM((tgemm<5,0,true,false>));
    SET_SMEM((tgemm<0,0,false,true>));
    SET_SMEM((tgemm<2,0,false,true>));
    SET_SMEM((tgemm<2,0,false,false>));
    SET_SMEM((tgemm<6,2,false,false>));
    SET_SMEM((tgemm<6,1,false,false>));
    SET_SMEM((tgemm<6,0,false,false>));

    // 0) zero + weight prep + operand rounding
    zero_kernel<<<1024, 256>>>(pool, ZERO_CNT);
    concat_w<<<2048, 256>>>(Wp1, Wp2, bp1, bp2, pool + OFF_WP12, pool + OFF_BSUM);
    {
        RoundArgs ra;
        const float* srcs[11] = { x, x2, x3, W_lin, W_lin2, W_lin3, W_lin4, Wp3, Wp4, Wfc1, Wfc2 };
        long offs[11] = { OFF_XR, OFF_X2R, OFF_X3R, OFF_WL, OFF_WL2, OFF_WL3, OFF_WL4,
                          OFF_WP3R, OFF_WP4R, OFF_WF1, OFF_WF2 };
        long ns[11] = { (long)BB*N1_*D0_, (long)BB*N2_*D1_, (long)BB*N3_*D2_,
                        (long)D2_*D0_, (long)D2_*D1_, (long)D1_*D0_, (long)D2_*D1_,
                        (long)D1_*D1_, (long)D2_*D2_, (long)DH_*D2_, (long)D2_*DH_ };
        for (int i = 0; i < 11; i++) { ra.src[i] = srcs[i]; ra.dst[i] = pool + offs[i]; ra.n[i] = ns[i]; }
        round_multi<<<dim3(512, 11), 256>>>(ra, 11);
    }
    const float* xr  = pool + OFF_XR;
    const float* x2r = pool + OFF_X2R;
    const float* x3r = pool + OFF_X3R;

    // 1) Et1 [B,512,9216]
    tgemm<1,0,false,false><<<dim3(4,72,BB), 256, SMEM_DYN>>>(
        xr, (long)N1_*D0_, D0_, pool+OFF_WL, 0L, D0_,
        pool+OFF_ET1, (long)D2_*N1_, N1_,
        N1_, D2_, D0_, 1,
        nullptr, nullptr, nullptr, pool+OFF_R1, pool+OFF_C1, nullptr, nullptr);
    // 2) Et2 [B,512,2304]
    tgemm<1,0,false,false><<<dim3(4,18,BB), 256, SMEM_DYN>>>(
        x2r, (long)N2_*D1_, D1_, pool+OFF_WL2, 0L, D1_,
        pool+OFF_ET2, (long)D2_*N2_, N2_,
        N2_, D2_, D1_, 1,
        nullptr, nullptr, nullptr, pool+OFF_R2, pool+OFF_C2, nullptr, nullptr);
    // 3) Et4 [B,256,9216]
    tgemm<1,0,false,false><<<dim3(2,72,BB), 256, SMEM_DYN>>>(
        xr, (long)N1_*D0_, D0_, pool+OFF_WL3, 0L, D0_,
        pool+OFF_ET4, (long)D1_*N1_, N1_,
        N1_, D1_, D0_, 1,
        nullptr, nullptr, nullptr, pool+OFF_R4, pool+OFF_C4, nullptr, nullptr);

    // 4) reciprocals + ATT prefill
    recip_kernel<<<(88064 + 255) / 256, 256>>>(pool, 88064);
    prefill_att<<<(BB*N3_*D2_ + 255)/256, 256>>>(x3, pool+OFF_BSUM, bp4, w, pool+OFF_ATT);

    // 5) St1 (symmetric triangular, split-K 8)
    tgemm<5,0,true,false><<<dim3(10,1,BB*8), 256, SMEM_DYN>>>(
        pool+OFF_ET1, (long)D2_*N1_, N1_, pool+OFF_ET1, (long)D2_*N1_, N1_,
        pool+OFF_ST12, (long)2*D2_*D2_, D2_,
        D2_, D2_, N1_, 8,
        nullptr, nullptr, nullptr, nullptr, nullptr, pool+OFF_R1, pool+OFF_C1);
    // 6) St2 (split 4)
    tgemm<5,0,true,false><<<dim3(10,1,BB*4), 256, SMEM_DYN>>>(
        pool+OFF_ET2, (long)D2_*N2_, N2_, pool+OFF_ET2, (long)D2_*N2_, N2_,
        pool+OFF_ST12 + (long)D2_*D2_, (long)2*D2_*D2_, D2_,
        D2_, D2_, N2_, 4,
        nullptr, nullptr, nullptr, nullptr, nullptr, pool+OFF_R2, pool+OFF_C2);
    // 7) St3 (split 8)
    tgemm<5,0,true,false><<<dim3(3,1,BB*8), 256, SMEM_DYN>>>(
        pool+OFF_ET4, (long)D1_*N1_, N1_, pool+OFF_ET4, (long)D1_*N1_, N1_,
        pool+OFF_ST3, (long)D1_*D1_, D1_,
        D1_, D1_, N1_, 8,
        nullptr, nullptr, nullptr, nullptr, nullptr, pool+OFF_R4, pool+OFF_C4);
    // 7b) round St12+St3 in place
    {
        RoundArgs ra;
        ra.src[0] = pool + OFF_ST12; ra.dst[0] = pool + OFF_ST12; ra.n[0] = (long)BB*2*D2_*D2_;
        ra.src[1] = pool + OFF_ST3;  ra.dst[1] = pool + OFF_ST3;  ra.n[1] = (long)BB*D1_*D1_;
        round_multi<<<dim3(512, 2), 256>>>(ra, 2);
    }

    // 8) T12 = x3 @ [St1;St2]^T   [B,576,1024]
    tgemm<0,0,false,true><<<dim3(8,5,BB), 256, SMEM_DYN>>>(
        x3r, (long)N3_*D2_, D2_, pool+OFF_ST12, (long)2*D2_*D2_, D2_,
        pool+OFF_T12, (long)N3_*2*D2_, 2*D2_,
        N3_, 2*D2_, D2_, 1,
        nullptr, nullptr, nullptr, nullptr, nullptr, nullptr, nullptr);
    // 9) ATT += other * (T12 @ Wp12^T)   (bias prefilled; split-K 2)
    tgemm<6,2,false,false><<<dim3(4,5,BB*2), 256, SMEM_DYN>>>(
        pool+OFF_T12, (long)N3_*2*D2_, 2*D2_, pool+OFF_WP12, 0L, 2*D2_,
        pool+OFF_ATT, (long)N3_*D2_, D2_,
        N3_, D2_, 2*D2_, 2,
        nullptr, nullptr, w, nullptr, nullptr, nullptr, nullptr);

    // 12) T3 = x2 @ St3   [B,2304,256]
    tgemm<0,0,false,true><<<dim3(2,18,BB), 256, SMEM_DYN>>>(
        x2r, (long)N2_*D1_, D1_, pool+OFF_ST3, (long)D1_*D1_, D1_,
        pool+OFF_T3, (long)N2_*D1_, D1_,
        N2_, D1_, D1_, 1,
        nullptr, nullptr, nullptr, nullptr, nullptr, nullptr, nullptr);
    // 13) A3 = T3 @ Wp3^T + bp3
    tgemm<2,0,false,true><<<dim3(2,18,BB), 256, SMEM_DYN>>>(
        pool+OFF_T3, (long)N2_*D1_, D1_, pool+OFF_WP3R, 0L, D1_,
        pool+OFF_A3, (long)N2_*D1_, D1_,
        N2_, D1_, D1_, 1,
        bp3, nullptr, nullptr, nullptr, nullptr, nullptr, nullptr);
    // 14) EtA [B,512,2304]
    tgemm<1,0,false,false><<<dim3(4,18,BB), 256, SMEM_DYN>>>(
        pool+OFF_A3, (long)N2_*D1_, D1_, pool+OFF_WL4, 0L, D1_,
        pool+OFF_ETA, (long)D2_*N2_, N2_,
        N2_, D2_, D1_, 1,
        nullptr, nullptr, nullptr, pool+OFF_RA, pool+OFF_CA, nullptr, nullptr);
    // 15) reciprocals RA,CA
    recip_kernel<<<(11264 + 255) / 256, 256>>>(pool + OFF_RA, 11264);
    // 16) St4 (split 4)
    tgemm<5,0,true,false><<<dim3(10,1,BB*4), 256, SMEM_DYN>>>(
        pool+OFF_ETA, (long)D2_*N2_, N2_, pool+OFF_ETA, (long)D2_*N2_, N2_,
        pool+OFF_ST4, (long)D2_*D2_, D2_,
        D2_, D2_, N2_, 4,
        nullptr, nullptr, nullptr, nullptr, nullptr, pool+OFF_RA, pool+OFF_CA);
    // 16b) round St4 in place
    {
        RoundArgs ra;
        ra.src[0] = pool + OFF_ST4; ra.dst[0] = pool + OFF_ST4; ra.n[0] = (long)BB*D2_*D2_;
        round_multi<<<dim3(512, 1), 256>>>(ra, 1);
    }
    // 17) T = x3 @ St4 ; ATT += f * (T @ Wp4^T)   (bias prefilled; split-K 2)
    tgemm<0,0,false,true><<<dim3(4,5,BB), 256, SMEM_DYN>>>(
        x3r, (long)N3_*D2_, D2_, pool+OFF_ST4, (long)D2_*D2_, D2_,
        pool+OFF_T, (long)N3_*D2_, D2_,
        N3_, D2_, D2_, 1,
        nullptr, nullptr, nullptr, nullptr, nullptr, nullptr, nullptr);
    tgemm<6,1,false,false><<<dim3(4,5,BB*2), 256, SMEM_DYN>>>(
        pool+OFF_T, (long)N3_*D2_, D2_, pool+OFF_WP4R, 0L, D2_,
        pool+OFF_ATT, (long)N3_*D2_, D2_,
        N3_, D2_, D2_, 2,
        nullptr, nullptr, w, nullptr, nullptr, nullptr, nullptr);

    // 19) AN = tf32(LN(ATT))
    ln_rows<<<BB * N3_, 256>>>(pool + OFF_ATT, g_norm, b_norm, pool + OFF_AN, D2_);

    // 20) H = AN @ Wfc1^T + bfc1   [B,576,2048]
    tgemm<2,0,false,false><<<dim3(16,5,BB), 256, SMEM_DYN>>>(
        pool+OFF_AN, (long)N3_*D2_, D2_, pool+OFF_WF1, 0L, D2_,
        pool+OFF_H, (long)N3_*DH_, DH_,
        N3_, DH_, D2_, 1,
        bfc1, nullptr, nullptr, nullptr, nullptr, nullptr, nullptr);

    // 21) AX = tf32(gelu(LN(dwconv(H)+bdw+H)))
    dwconv_ln_gelu<<<dim3(N3_, BB), 256>>>(pool + OFF_H, Wdw, bdw, g_ln1, b_ln1, pool + OFF_AX);

    // 22) out = ATT + bfc2 (prefill), then += AX @ Wfc2^T  (split-K 4)
    prefill_out<<<(BB*N3_*D2_ + 255)/256, 256>>>(pool + OFF_ATT, bfc2, (float*)d_out);
    tgemm<6,0,false,false><<<dim3(4,5,BB*4), 256, SMEM_DYN>>>(
        pool+OFF_AX, (long)N3_*DH_, DH_, pool+OFF_WF2, 0L, DH_,
        (float*)d_out, (long)N3_*D2_, D2_,
        N3_, D2_, DH_, 4,
        nullptr, nullptr, nullptr, nullptr, nullptr, nullptr, nullptr);
}

// round 11
// speedup vs baseline: 1.6906x; 1.1772x over previous
#include <cuda_runtime.h>
#include <math.h>
#include <stdint.h>

// ---------------- problem dims ----------------
#define BB   4
#define N1_  9216
#define N2_  2304
#define N3_  576
#define D0_  128
#define D1_  256
#define D2_  512
#define DH_  2048

// ---------------- scratch pool (floats) ----------------
#define OFF_R1   0L
#define OFF_C1   36864L
#define OFF_R2   38912L
#define OFF_C2   48128L
#define OFF_R4   50176L
#define OFF_C4   87040L
#define OFF_RA   88064L
#define OFF_CA   97280L
#define OFF_ST12 99328L            // [B][1024][512]
#define OFF_ST3  2196480L          // [B][256][256]
#define OFF_ST4  2458624L          // [B][512][512]
#define ZERO_CNT 3507200L
#define OFF_ET1  3507200L
#define OFF_ET2  22381568L
#define OFF_ET4  27100160L
#define OFF_ETA  36537344L         // reused earlier as T12 [B][576][1024]
#define OFF_T    41255936L         // Wp12 (512x1024)+bsum early; T later
#define OFF_T3   42435584L
#define OFF_A3   44794880L
#define OFF_ATT  47154176L
#define OFF_AN   48333824L
#define OFF_H    49513472L
#define OFF_AX   54232064L
// tf32-rounded operand copies
#define OFF_XR   58950656L
#define OFF_X2R  63669248L
#define OFF_X3R  66028544L
#define OFF_WL   67208192L
#define OFF_WL2  67273728L
#define OFF_WL3  67404800L
#define OFF_WL4  67437568L
#define OFF_WP3R 67568640L
#define OFF_WP4R 67634176L
#define OFF_WF1  67896320L
#define OFF_WF2  68944896L
#define POOL_SZ  69993472L

#define OFF_T12   OFF_ETA
#define OFF_WP12  OFF_T
#define OFF_BSUM  (OFF_T + 524288L)

__device__ float g_pool[POOL_SZ];

// 3 stages x (A,B) x (128 rows x 36 floats)
#define STAGEB  18432u
#define BOFF    55296u
#define SMEM_DYN 110592

// ---------------- job table ----------------
struct Job {
    const float *A, *Bm;
    float *C;
    long aStr, bStr, cStr;
    int lda, ldb, ldc;
    int mTot, nTot, kTot, splits, gx, gy;
    const float *kscale, *mscale;
    float *rowsum, *colsum;
};
struct Jobs { Job j[3]; int off[4]; };

// ---------------- helpers ----------------
__device__ __forceinline__ uint32_t smem_u32(const void* p) {
    uint32_t a;
    asm("{ .reg .u64 t; cvta.to.shared.u64 t, %1; cvt.u32.u64 %0, t; }" : "=r"(a) : "l"(p));
    return a;
}
__device__ __forceinline__ float to_tf32(float x) {
    float y;
    asm("cvt.rna.tf32.f32 %0, %1;" : "=f"(y) : "f"(x));
    return y;
}
__device__ __forceinline__ float4 rnd4(float4 v) {
    v.x = to_tf32(v.x); v.y = to_tf32(v.y); v.z = to_tf32(v.z); v.w = to_tf32(v.w);
    return v;
}
__device__ __forceinline__ void mma_tf32(float* d, const uint32_t* a, const uint32_t* bf) {
    asm volatile(
        "mma.sync.aligned.m16n8k8.row.col.f32.tf32.tf32.f32 "
        "{%0,%1,%2,%3}, {%4,%5,%6,%7}, {%8,%9}, {%0,%1,%2,%3};"
        : "+f"(d[0]), "+f"(d[1]), "+f"(d[2]), "+f"(d[3])
        : "r"(a[0]), "r"(a[1]), "r"(a[2]), "r"(a[3]), "r"(bf[0]), "r"(bf[1]));
}
__device__ __forceinline__ void ldm_x4(uint32_t* r, uint32_t addr) {
    asm volatile("ldmatrix.sync.aligned.m8n8.x4.shared.b16 {%0,%1,%2,%3}, [%4];"
        : "=r"(r[0]), "=r"(r[1]), "=r"(r[2]), "=r"(r[3]) : "r"(addr));
}
__device__ __forceinline__ void cpa16(uint32_t dst, const float* src, bool valid) {
    int sz = valid ? 16 : 0;
    asm volatile("cp.async.cg.shared.global [%0], [%1], 16, %2;"
        :: "r"(dst), "l"(src), "r"(sz) : "memory");
}
#define CP_COMMIT() asm volatile("cp.async.commit_group;" ::: "memory")
#define CP_WAIT1()  asm volatile("cp.async.wait_group 1;" ::: "memory")

// ================= tf32 mma.sync NT GEMM (job-batched, 3-stage cp.async, BK=32) ======
// D[m][n] = sum_k A[m][k]*B[n][k] per job; 128x128 CTA tile, BK=32, 256 thr / 8 warps,
// warp tile 64x32, ldmatrix x4 for A and paired-B fragments. Operands pre-rounded tf32.
// EPI 0: C = acc (RND rounds)     EPI 1: exp + transposed store + rowsum/colsum atomics
// EPI 2: C = alpha*(acc+bias)     EPI 5: symmetric triangular split-K atomics (x mscale)
// EPI 6: atomicAdd(C, alpha*acc)
// AMODE: 0 alpha=1 ; 1 sigmoid(*w) ; 2 (1-sigmoid)/2
template<int EPI, int AMODE, bool KSC, bool RND>
__global__ void __launch_bounds__(256, 2) tgemm(
    Jobs jobs, const float* __restrict__ bias, const float* __restrict__ wscal)
{
    extern __shared__ float dynsm[];

    int q = blockIdx.x;
    int ji = 0;
    if (q >= jobs.off[1]) ji = 1;
    if (q >= jobs.off[2]) ji = 2;
    q -= jobs.off[ji];
    const Job J = jobs.j[ji];

    const int b = blockIdx.z;
    const int Kc = J.kTot / J.splits;
    int sp, bxq, byq;
    if (EPI == 5) {
        sp = q / J.gx;
        int tri = q % J.gx;
        const int T = J.nTot >> 7;
        int by = 0;
        while (tri >= T - by) { tri -= (T - by); by++; }
        byq = by; bxq = by + tri;
    } else {
        const int gxy = J.gx * J.gy;
        sp = q / gxy;
        int r = q % gxy;
        bxq = r % J.gx; byq = r / J.gx;
    }
    const int kbase = sp * Kc;
    const int nt = Kc >> 5;
    const int bm = byq * 128;
    const int bn = bxq * 128;

    const float* Ab = J.A + (long)b * J.aStr;
    const float* Bb = J.Bm + (long)b * J.bStr;
    const float* ksc_b = KSC ? (J.kscale + (long)b * J.kTot) : nullptr;
    const int lda = J.lda, ldb = J.ldb;
    const int mTot = J.mTot;

    const int tid = threadIdx.x;
    const int wid = tid >> 5, lane = tid & 31;
    const int wm = wid & 1, wn = wid >> 1;
    const int lr = lane >> 2, lc = lane & 3;

    const uint32_t smBase = smem_u32(dynsm);
    const int g8 = lane >> 3;
    const int r8 = lane & 7;
    // A x4 fragment base: matrices (r0,k0),(r8,k0),(r0,k4),(r8,k4)
    const uint32_t asBase = smBase +
        (uint32_t)(((wm * 64 + (g8 & 1) * 8 + r8) * 36 + (g8 >> 1) * 4) * 4);
    // B paired-x4 base: matrices (j2*16+0..8,k0),(+0..8,k4),(+8..16,k0),(+8..16,k4)
    const uint32_t bsBase = smBase + BOFF +
        (uint32_t)(((wn * 32 + (g8 >> 1) * 8 + r8) * 36 + (g8 & 1) * 4) * 4);

    auto issue_copy = [&](int tt, uint32_t stOff) {
        const int k0 = kbase + (tt << 5);
        const uint32_t aS = smBase + stOff;
        const uint32_t bS = smBase + BOFF + stOff;
#pragma unroll
        for (int l = 0; l < 4; l++) {
            int c = tid + (l << 8);
            int row = c >> 3, kq = (c & 7) << 2;
            uint32_t off = (uint32_t)((row * 36 + kq) * 4);
            cpa16(aS + off, Ab + (long)(bm + row) * lda + k0 + kq, (bm + row) < mTot);
            cpa16(bS + off, Bb + (long)(bn + row) * ldb + k0 + kq, true);
        }
    };

    float acc[4][4][4];
#pragma unroll
    for (int i = 0; i < 4; i++)
#pragma unroll
        for (int j = 0; j < 4; j++)
#pragma unroll
            for (int r = 0; r < 4; r++) acc[i][j][r] = 0.0f;

    issue_copy(0, 0);        CP_COMMIT();
    if (nt > 1) { issue_copy(1, STAGEB); }
    CP_COMMIT();

    uint32_t curOff = 0, nxtOff = STAGEB, thrOff = 2 * STAGEB;

    for (int t = 0; t < nt; t++) {
        CP_WAIT1();
        __syncthreads();
        if (t + 2 < nt) issue_copy(t + 2, thrOff);
        CP_COMMIT();

        const uint32_t aCur = asBase + curOff;
        const uint32_t bCur = bsBase + curOff;
        float sc[8];
        if (KSC) {
            const int k0t = kbase + (t << 5);
#pragma unroll
            for (int ks = 0; ks < 4; ks++) {
                sc[2 * ks]     = ksc_b[k0t + ks * 8 + lc];
                sc[2 * ks + 1] = ksc_b[k0t + ks * 8 + 4 + lc];
            }
        }
#pragma unroll
        for (int ks = 0; ks < 4; ks++) {
            uint32_t af[4][4];
#pragma unroll
            for (int i = 0; i < 4; i++)
                ldm_x4(af[i], aCur + i * 2304 + ks * 32);
            uint32_t bf[4][2];
#pragma unroll
            for (int j2 = 0; j2 < 2; j2++) {
                uint32_t r4[4];
                ldm_x4(r4, bCur + j2 * 2304 + ks * 32);
                if (KSC) {
                    r4[0] = __float_as_uint(to_tf32(__uint_as_float(r4[0]) * sc[2 * ks]));
                    r4[1] = __float_as_uint(to_tf32(__uint_as_float(r4[1]) * sc[2 * ks + 1]));
                    r4[2] = __float_as_uint(to_tf32(__uint_as_float(r4[2]) * sc[2 * ks]));
                    r4[3] = __float_as_uint(to_tf32(__uint_as_float(r4[3]) * sc[2 * ks + 1]));
                }
                bf[2 * j2][0] = r4[0]; bf[2 * j2][1] = r4[1];
                bf[2 * j2 + 1][0] = r4[2]; bf[2 * j2 + 1][1] = r4[3];
            }
#pragma unroll
            for (int i = 0; i < 4; i++)
#pragma unroll
                for (int j = 0; j < 4; j++)
                    mma_tf32(acc[i][j], af[i], bf[j]);
        }
        uint32_t tmp = curOff; curOff = nxtOff; nxtOff = thrOff; thrOff = tmp;
    }
    __syncthreads();

    // ---- epilogue ----
    float alpha = 1.0f;
    if (AMODE == 1) alpha = 1.0f / (1.0f + expf(-wscal[0]));
    if (AMODE == 2) alpha = (1.0f - 1.0f / (1.0f + expf(-wscal[0]))) * 0.5f;

    float* Cb = J.C + (long)b * J.cStr;
    const int ldc = J.ldc;

    if (EPI == 1) {
        float rs[4][2];
#pragma unroll
        for (int i = 0; i < 4; i++) { rs[i][0] = 0.f; rs[i][1] = 0.f; }
#pragma unroll
        for (int j = 0; j < 4; j++) {
            int col0 = bn + wn * 32 + j * 8 + lc * 2;
            float cs0 = 0.f, cs1 = 0.f;
#pragma unroll
            for (int i = 0; i < 4; i++) {
                float e0 = to_tf32(expf(acc[i][j][0]));
                float e1 = to_tf32(expf(acc[i][j][1]));
                float e2 = to_tf32(expf(acc[i][j][2]));
                float e3 = to_tf32(expf(acc[i][j][3]));
                acc[i][j][0] = e0; acc[i][j][1] = e1;
                acc[i][j][2] = e2; acc[i][j][3] = e3;
                cs0 += e0 + e2; cs1 += e1 + e3;
                rs[i][0] += e0 + e1; rs[i][1] += e2 + e3;
            }
#pragma unroll
            for (int o = 4; o <= 16; o <<= 1) {
                cs0 += __shfl_xor_sync(0xffffffff, cs0, o);
                cs1 += __shfl_xor_sync(0xffffffff, cs1, o);
            }
            if (lane < 4) {
                atomicAdd(J.colsum + (long)b * J.nTot + col0, cs0);
                atomicAdd(J.colsum + (long)b * J.nTot + col0 + 1, cs1);
            }
        }
#pragma unroll
        for (int i = 0; i < 4; i++)
#pragma unroll
            for (int h = 0; h < 2; h++) {
                float v = rs[i][h];
                v += __shfl_xor_sync(0xffffffff, v, 1);
                v += __shfl_xor_sync(0xffffffff, v, 2);
                if (lc == 0) {
                    int r = bm + wm * 64 + i * 16 + lr + h * 8;
                    atomicAdd(J.rowsum + (long)b * mTot + r, v);
                }
            }
        // smem-staged transposed store, coalesced float4 writes
        float* stg = dynsm;
#pragma unroll
        for (int h2 = 0; h2 < 2; h2++) {
            __syncthreads();
            if ((wn >> 1) == h2) {
                int snb = wn * 32 - h2 * 64;
#pragma unroll
                for (int j = 0; j < 4; j++) {
                    int sn = snb + j * 8 + lc * 2;
#pragma unroll
                    for (int i = 0; i < 4; i++) {
                        int ml = wm * 64 + i * 16 + lr;
                        stg[sn * 132 + ml]           = acc[i][j][0];
                        stg[(sn + 1) * 132 + ml]     = acc[i][j][1];
                        stg[sn * 132 + ml + 8]       = acc[i][j][2];
                        stg[(sn + 1) * 132 + ml + 8] = acc[i][j][3];
                    }
                }
            }
            __syncthreads();
#pragma unroll
            for (int it = 0; it < 8; it++) {
                int id = tid + (it << 8);
                int row = id >> 5, m4 = (id & 31) << 2;
                float4 v = *(float4*)&stg[row * 132 + m4];
                *(float4*)(Cb + (long)(bn + h2 * 64 + row) * ldc + bm + m4) = v;
            }
        }
    } else if (EPI == 5) {
        const float* msc = J.mscale + (long)b * mTot;
#pragma unroll
        for (int i = 0; i < 4; i++) {
            int r0 = bm + wm * 64 + i * 16 + lr;
            float s0 = msc[r0];
            float s1 = msc[r0 + 8];
#pragma unroll
            for (int j = 0; j < 4; j++) {
                int col0 = bn + wn * 32 + j * 8 + lc * 2;
                atomicAdd(Cb + (long)r0 * ldc + col0,           acc[i][j][0] * s0);
                atomicAdd(Cb + (long)r0 * ldc + col0 + 1,       acc[i][j][1] * s0);
                atomicAdd(Cb + (long)(r0 + 8) * ldc + col0,     acc[i][j][2] * s1);
                atomicAdd(Cb + (long)(r0 + 8) * ldc + col0 + 1, acc[i][j][3] * s1);
            }
        }
        if (bxq != byq) {
#pragma unroll
            for (int j = 0; j < 4; j++) {
                int n0 = bn + wn * 32 + j * 8 + lc * 2;
                float sn0 = msc[n0];
                float sn1 = msc[n0 + 1];
#pragma unroll
                for (int i = 0; i < 4; i++) {
                    int r0 = bm + wm * 64 + i * 16 + lr;
                    atomicAdd(Cb + (long)n0 * ldc + r0,           acc[i][j][0] * sn0);
                    atomicAdd(Cb + (long)(n0 + 1) * ldc + r0,     acc[i][j][1] * sn1);
                    atomicAdd(Cb + (long)n0 * ldc + r0 + 8,       acc[i][j][2] * sn0);
                    atomicAdd(Cb + (long)(n0 + 1) * ldc + r0 + 8, acc[i][j][3] * sn1);
                }
            }
        }
    } else if (EPI == 6) {
#pragma unroll
        for (int i = 0; i < 4; i++) {
#pragma unroll
            for (int h = 0; h < 2; h++) {
                int r = bm + wm * 64 + i * 16 + lr + h * 8;
                if (r >= mTot) continue;
                float* Crow = Cb + (long)r * ldc;
#pragma unroll
                for (int j = 0; j < 4; j++) {
                    int col0 = bn + wn * 32 + j * 8 + lc * 2;
                    atomicAdd(Crow + col0,     alpha * acc[i][j][h * 2 + 0]);
                    atomicAdd(Crow + col0 + 1, alpha * acc[i][j][h * 2 + 1]);
                }
            }
        }
    } else {
#pragma unroll
        for (int i = 0; i < 4; i++) {
#pragma unroll
            for (int h = 0; h < 2; h++) {
                int r = bm + wm * 64 + i * 16 + lr + h * 8;
                if (r >= mTot) continue;
                float* Crow = Cb + (long)r * ldc;
#pragma unroll
                for (int j = 0; j < 4; j++) {
                    int col0 = bn + wn * 32 + j * 8 + lc * 2;
                    float v0 = acc[i][j][h * 2 + 0];
                    float v1 = acc[i][j][h * 2 + 1];
                    if (EPI == 2) {
                        v0 = alpha * (v0 + bias[col0]);
                        v1 = alpha * (v1 + bias[col0 + 1]);
                    }
                    if (RND) { v0 = to_tf32(v0); v1 = to_tf32(v1); }
                    float2 o; o.x = v0; o.y = v1;
                    *(float2*)(Crow + col0) = o;
                }
            }
        }
    }
}

// ---------------- utility kernels ----------------
__global__ void zero_kernel(float* p, long n) {
    long i = (long)blockIdx.x * blockDim.x + threadIdx.x;
    long stride = (long)gridDim.x * blockDim.x;
    for (; i < n; i += stride) p[i] = 0.0f;
}
__global__ void recip_kernel(float* p, int n) {
    int i = blockIdx.x * blockDim.x + threadIdx.x;
    if (i < n) p[i] = 1.0f / p[i];
}
__global__ void concat_w(const float* __restrict__ W1, const float* __restrict__ W2,
                         const float* __restrict__ b1, const float* __restrict__ b2,
                         float* __restrict__ W12, float* __restrict__ bsum) {
    int i = blockIdx.x * 256 + threadIdx.x;
    if (i < 512 * 1024) {
        int n = i >> 10, k = i & 1023;
        W12[i] = to_tf32((k < 512) ? W1[n * 512 + k] : W2[n * 512 + k - 512]);
    }
    if (i < 512) bsum[i] = b1[i] + b2[i];
}
__global__ void prefill_att(const float* __restrict__ x3, const float* __restrict__ bsum,
                            const float* __restrict__ bp4, const float* __restrict__ wscal,
                            float* __restrict__ ATT) {
    long i = (long)blockIdx.x * blockDim.x + threadIdx.x;
    if (i >= (long)BB * N3_ * D2_) return;
    float f = 1.0f / (1.0f + expf(-wscal[0]));
    float other = (1.0f - f) * 0.5f;
    int col = (int)(i & (D2_ - 1));
    ATT[i] = x3[i] + other * bsum[col] + f * bp4[col];
}
__global__ void prefill_out(const float* __restrict__ ATT, const float* __restrict__ bfc2,
                            float* __restrict__ out) {
    long i = (long)blockIdx.x * blockDim.x + threadIdx.x;
    if (i >= (long)BB * N3_ * D2_) return;
    int col = (int)(i & (D2_ - 1));
    out[i] = ATT[i] + bfc2[col];
}

struct RoundArgs {
    const float* src[11];
    float* dst[11];
    long n[11];
};
__global__ void round_multi(RoundArgs a, int nseg) {
    int seg = blockIdx.y;
    if (seg >= nseg) return;
    const float4* s = (const float4*)a.src[seg];
    float4* d = (float4*)a.dst[seg];
    long n4 = a.n[seg] >> 2;
    for (long i = (long)blockIdx.x * blockDim.x + threadIdx.x; i < n4;
         i += (long)gridDim.x * blockDim.x)
        d[i] = rnd4(s[i]);
}

__global__ void ln_rows(const float* __restrict__ X, const float* __restrict__ g,
                        const float* __restrict__ bb, float* __restrict__ Y, int C)
{
    long row = blockIdx.x;
    const float* x = X + row * C;
    float s = 0.f, s2 = 0.f;
    for (int c = threadIdx.x; c < C; c += blockDim.x) { float v = x[c]; s += v; s2 += v * v; }
    __shared__ float sh1[32], sh2[32];
    int lane = threadIdx.x & 31, wid = threadIdx.x >> 5;
#pragma unroll
    for (int o = 16; o; o >>= 1) {
        s  += __shfl_down_sync(0xffffffff, s,  o);
        s2 += __shfl_down_sync(0xffffffff, s2, o);
    }
    if (!lane) { sh1[wid] = s; sh2[wid] = s2; }
    __syncthreads();
    if (threadIdx.x == 0) {
        float a = 0.f, c2 = 0.f;
        int nw = blockDim.x >> 5;
        for (int i = 0; i < nw; i++) { a += sh1[i]; c2 += sh2[i]; }
        float mean = a / C;
        float var  = c2 / C - mean * mean;
        sh1[0] = mean; sh2[0] = rsqrtf(var + 1e-5f);
    }
    __syncthreads();
    float mean = sh1[0], rstd = sh2[0];
    for (int c = threadIdx.x; c < C; c += blockDim.x) {
        float v = x[c];
        Y[row * C + c] = to_tf32((v - mean) * rstd * g[c] + bb[c]);
    }
}

__global__ void __launch_bounds__(256) dwconv_ln_gelu(
    const float* __restrict__ H, const float* __restrict__ Wdw,
    const float* __restrict__ bdw, const float* __restrict__ g,
    const float* __restrict__ bt, float* __restrict__ AX)
{
    const int n = blockIdx.x;
    const int b = blockIdx.y;
    const int y = n / 24, x = n % 24;
    const float* Hb = H + (long)b * 576 * 2048;
    const int tid = threadIdx.x;

    float v[8];
    float s = 0.f, s2 = 0.f;
#pragma unroll
    for (int it = 0; it < 8; it++) {
        int c = tid + it * 256;
        float a = Hb[(long)n * 2048 + c] + bdw[c];
#pragma unroll
        for (int ky = 0; ky < 3; ky++) {
            int yy = y + ky - 1;
            if (yy < 0 || yy > 23) continue;
#pragma unroll
            for (int kx = 0; kx < 3; kx++) {
                int xx = x + kx - 1;
                if (xx < 0 || xx > 23) continue;
                a += Wdw[c * 9 + ky * 3 + kx] * Hb[(long)(yy * 24 + xx) * 2048 + c];
            }
        }
        v[it] = a; s += a; s2 += a * a;
    }
    __shared__ float sh1[32], sh2[32];
    int lane = tid & 31, wid = tid >> 5;
#pragma unroll
    for (int o = 16; o; o >>= 1) {
        s  += __shfl_down_sync(0xffffffff, s,  o);
        s2 += __shfl_down_sync(0xffffffff, s2, o);
    }
    if (!lane) { sh1[wid] = s; sh2[wid] = s2; }
    __syncthreads();
    if (tid == 0) {
        float a = 0.f, c2 = 0.f;
        for (int i = 0; i < 8; i++) { a += sh1[i]; c2 += sh2[i]; }
        float mean = a / 2048.0f;
        float var  = c2 / 2048.0f - mean * mean;
        sh1[0] = mean; sh2[0] = rsqrtf(var + 1e-5f);
    }
    __syncthreads();
    float mean = sh1[0], rstd = sh2[0];
    float* out = AX + ((long)b * 576 + n) * 2048;
#pragma unroll
    for (int it = 0; it < 8; it++) {
        int c = tid + it * 256;
        float t = (v[it] - mean) * rstd * g[c] + bt[c];
        out[c] = to_tf32(0.5f * t * (1.0f + erff(t * 0.70710678118654752f)));
    }
}

// ---------------- host orchestration ----------------
#define SET_SMEM(k) cudaFuncSetAttribute(k, cudaFuncAttributeMaxDynamicSharedMemorySize, SMEM_DYN)

static Job mk_job(const float* A, long aStr, int lda,
                  const float* B, long bStr, int ldb,
                  float* C, long cStr, int ldc,
                  int m, int n, int k, int splits, int gx, int gy,
                  const float* ksc = nullptr, const float* msc = nullptr,
                  float* rsum = nullptr, float* csum = nullptr) {
    Job J;
    J.A = A; J.Bm = B; J.C = C;
    J.aStr = aStr; J.bStr = bStr; J.cStr = cStr;
    J.lda = lda; J.ldb = ldb; J.ldc = ldc;
    J.mTot = m; J.nTot = n; J.kTot = k; J.splits = splits; J.gx = gx; J.gy = gy;
    J.kscale = ksc; J.mscale = msc; J.rowsum = rsum; J.colsum = csum;
    return J;
}

extern "C" void kernel_launch(void* const* d_in, const int* in_sizes, int n_in,
                              void* d_out, int out_size)
{
    const float* x      = (const float*)d_in[0];
    const float* x2     = (const float*)d_in[1];
    const float* x3     = (const float*)d_in[2];
    const float* W_lin  = (const float*)d_in[3];
    const float* W_lin2 = (const float*)d_in[4];
    const float* W_lin3 = (const float*)d_in[5];
    const float* W_lin4 = (const float*)d_in[6];
    const float* w      = (const float*)d_in[7];
    const float* Wp1 = (const float*)d_in[8];  const float* bp1 = (const float*)d_in[9];
    const float* Wp2 = (const float*)d_in[10]; const float* bp2 = (const float*)d_in[11];
    const float* Wp3 = (const float*)d_in[12]; const float* bp3 = (const float*)d_in[13];
    const float* Wp4 = (const float*)d_in[14]; const float* bp4 = (const float*)d_in[15];
    const float* g_norm = (const float*)d_in[16]; const float* b_norm = (const float*)d_in[17];
    const float* Wfc1 = (const float*)d_in[18];   const float* bfc1  = (const float*)d_in[19];
    const float* Wdw  = (const float*)d_in[20];   const float* bdw   = (const float*)d_in[21];
    const float* g_ln1 = (const float*)d_in[22];  const float* b_ln1 = (const float*)d_in[23];
    const float* Wfc2 = (const float*)d_in[24];   const float* bfc2  = (const float*)d_in[25];

    float* pool = nullptr;
    cudaGetSymbolAddress((void**)&pool, g_pool);

    SET_SMEM((tgemm<1,0,false,false>));
    SET_SMEM((tgemm<5,0,true,false>));
    SET_SMEM((tgemm<0,0,false,true>));
    SET_SMEM((tgemm<2,0,false,true>));
    SET_SMEM((tgemm<2,0,false,false>));
    SET_SMEM((tgemm<6,2,false,false>));
    SET_SMEM((tgemm<6,1,false,false>));
    SET_SMEM((tgemm<6,0,false,false>));

    // 0) zero + weight prep + operand rounding
    zero_kernel<<<1024, 256>>>(pool, ZERO_CNT);
    concat_w<<<2048, 256>>>(Wp1, Wp2, bp1, bp2, pool + OFF_WP12, pool + OFF_BSUM);
    {
        RoundArgs ra;
        const float* srcs[11] = { x, x2, x3, W_lin, W_lin2, W_lin3, W_lin4, Wp3, Wp4, Wfc1, Wfc2 };
        long offs[11] = { OFF_XR, OFF_X2R, OFF_X3R, OFF_WL, OFF_WL2, OFF_WL3, OFF_WL4,
                          OFF_WP3R, OFF_WP4R, OFF_WF1, OFF_WF2 };
        long ns[11] = { (long)BB*N1_*D0_, (long)BB*N2_*D1_, (long)BB*N3_*D2_,
                        (long)D2_*D0_, (long)D2_*D1_, (long)D1_*D0_, (long)D2_*D1_,
                        (long)D1_*D1_, (long)D2_*D2_, (long)DH_*D2_, (long)D2_*DH_ };
        for (int i = 0; i < 11; i++) { ra.src[i] = srcs[i]; ra.dst[i] = pool + offs[i]; ra.n[i] = ns[i]; }
        round_multi<<<dim3(512, 11), 256>>>(ra, 11);
    }
    const float* xr  = pool + OFF_XR;
    const float* x2r = pool + OFF_X2R;
    const float* x3r = pool + OFF_X3R;

    // 1-3) Et1+Et2+Et4 in one launch (EPI1, 3 jobs)
    {
        Jobs js;
        js.j[0] = mk_job(xr, (long)N1_*D0_, D0_, pool+OFF_WL, 0L, D0_,
                         pool+OFF_ET1, (long)D2_*N1_, N1_, N1_, D2_, D0_, 1, 4, 72,
                         nullptr, nullptr, pool+OFF_R1, pool+OFF_C1);
        js.j[1] = mk_job(x2r, (long)N2_*D1_, D1_, pool+OFF_WL2, 0L, D1_,
                         pool+OFF_ET2, (long)D2_*N2_, N2_, N2_, D2_, D1_, 1, 4, 18,
                         nullptr, nullptr, pool+OFF_R2, pool+OFF_C2);
        js.j[2] = mk_job(xr, (long)N1_*D0_, D0_, pool+OFF_WL3, 0L, D0_,
                         pool+OFF_ET4, (long)D1_*N1_, N1_, N1_, D1_, D0_, 1, 2, 72,
                         nullptr, nullptr, pool+OFF_R4, pool+OFF_C4);
        js.off[0] = 0; js.off[1] = 288; js.off[2] = 360; js.off[3] = 504;
        tgemm<1,0,false,false><<<dim3(504,1,BB), 256, SMEM_DYN>>>(js, nullptr, nullptr);
    }

    // 4) reciprocals + ATT prefill
    recip_kernel<<<(88064 + 255) / 256, 256>>>(pool, 88064);
    prefill_att<<<(BB*N3_*D2_ + 255)/256, 256>>>(x3, pool+OFF_BSUM, bp4, w, pool+OFF_ATT);

    // 5-7) St1+St2+St3 in one launch (EPI5, 3 jobs)
    {
        Jobs js;
        js.j[0] = mk_job(pool+OFF_ET1, (long)D2_*N1_, N1_, pool+OFF_ET1, (long)D2_*N1_, N1_,
                         pool+OFF_ST12, (long)2*D2_*D2_, D2_, D2_, D2_, N1_, 8, 10, 1,
                         pool+OFF_R1, pool+OFF_C1);
        js.j[1] = mk_job(pool+OFF_ET2, (long)D2_*N2_, N2_, pool+OFF_ET2, (long)D2_*N2_, N2_,
                         pool+OFF_ST12 + (long)D2_*D2_, (long)2*D2_*D2_, D2_, D2_, D2_, N2_, 4, 10, 1,
                         pool+OFF_R2, pool+OFF_C2);
        js.j[2] = mk_job(pool+OFF_ET4, (long)D1_*N1_, N1_, pool+OFF_ET4, (long)D1_*N1_, N1_,
                         pool+OFF_ST3, (long)D1_*D1_, D1_, D1_, D1_, N1_, 8, 3, 1,
                         pool+OFF_R4, pool+OFF_C4);
        js.off[0] = 0; js.off[1] = 80; js.off[2] = 120; js.off[3] = 144;
        tgemm<5,0,true,false><<<dim3(144,1,BB), 256, SMEM_DYN>>>(js, nullptr, nullptr);
    }
    // 7b) round St12+St3 in place
    {
        RoundArgs ra;
        ra.src[0] = pool + OFF_ST12; ra.dst[0] = pool + OFF_ST12; ra.n[0] = (long)BB*2*D2_*D2_;
        ra.src[1] = pool + OFF_ST3;  ra.dst[1] = pool + OFF_ST3;  ra.n[1] = (long)BB*D1_*D1_;
        round_multi<<<dim3(512, 2), 256>>>(ra, 2);
    }

    // 8+12) T12 and T3 in one launch (EPI0 RND, 2 jobs)
    {
        Jobs js;
        js.j[0] = mk_job(x3r, (long)N3_*D2_, D2_, pool+OFF_ST12, (long)2*D2_*D2_, D2_,
                         pool+OFF_T12, (long)N3_*2*D2_, 2*D2_, N3_, 2*D2_, D2_, 1, 8, 5);
        js.j[1] = mk_job(x2r, (long)N2_*D1_, D1_, pool+OFF_ST3, (long)D1_*D1_, D1_,
                         pool+OFF_T3, (long)N2_*D1_, D1_, N2_, D1_, D1_, 1, 2, 18);
        js.j[2] = js.j[1];
        js.off[0] = 0; js.off[1] = 40; js.off[2] = 76; js.off[3] = 76;
        tgemm<0,0,false,true><<<dim3(76,1,BB), 256, SMEM_DYN>>>(js, nullptr, nullptr);
    }

    // 9) ATT += other*(T12 @ Wp12^T)  (split-K 2)
    {
        Jobs js;
        js.j[0] = mk_job(pool+OFF_T12, (long)N3_*2*D2_, 2*D2_, pool+OFF_WP12, 0L, 2*D2_,
                         pool+OFF_ATT, (long)N3_*D2_, D2_, N3_, D2_, 2*D2_, 2, 4, 5);
        js.j[1] = js.j[0]; js.j[2] = js.j[0];
        js.off[0] = 0; js.off[1] = 40; js.off[2] = 40; js.off[3] = 40;
        tgemm<6,2,false,false><<<dim3(40,1,BB), 256, SMEM_DYN>>>(js, nullptr, w);
    }
    // 13) A3 = T3 @ Wp3^T + bp3
    {
        Jobs js;
        js.j[0] = mk_job(pool+OFF_T3, (long)N2_*D1_, D1_, pool+OFF_WP3R, 0L, D1_,
                         pool+OFF_A3, (long)N2_*D1_, D1_, N2_, D1_, D1_, 1, 2, 18);
        js.j[1] = js.j[0]; js.j[2] = js.j[0];
        js.off[0] = 0; js.off[1] = 36; js.off[2] = 36; js.off[3] = 36;
        tgemm<2,0,false,true><<<dim3(36,1,BB), 256, SMEM_DYN>>>(js, bp3, nullptr);
    }
    // 14) EtA (EPI1, 1 job)
    {
        Jobs js;
        js.j[0] = mk_job(pool+OFF_A3, (long)N2_*D1_, D1_, pool+OFF_WL4, 0L, D1_,
                         pool+OFF_ETA, (long)D2_*N2_, N2_, N2_, D2_, D1_, 1, 4, 18,
                         nullptr, nullptr, pool+OFF_RA, pool+OFF_CA);
        js.j[1] = js.j[0]; js.j[2] = js.j[0];
        js.off[0] = 0; js.off[1] = 72; js.off[2] = 72; js.off[3] = 72;
        tgemm<1,0,false,false><<<dim3(72,1,BB), 256, SMEM_DYN>>>(js, nullptr, nullptr);
    }
    // 15) reciprocals RA,CA
    recip_kernel<<<(11264 + 255) / 256, 256>>>(pool + OFF_RA, 11264);
    // 16) St4 (EPI5, 1 job)
    {
        Jobs js;
        js.j[0] = mk_job(pool+OFF_ETA, (long)D2_*N2_, N2_, pool+OFF_ETA, (long)D2_*N2_, N2_,
                         pool+OFF_ST4, (long)D2_*D2_, D2_, D2_, D2_, N2_, 4, 10, 1,
                         pool+OFF_RA, pool+OFF_CA);
        js.j[1] = js.j[0]; js.j[2] = js.j[0];
        js.off[0] = 0; js.off[1] = 40; js.off[2] = 40; js.off[3] = 40;
        tgemm<5,0,true,false><<<dim3(40,1,BB), 256, SMEM_DYN>>>(js, nullptr, nullptr);
    }
    // 16b) round St4 in place
    {
        RoundArgs ra;
        ra.src[0] = pool + OFF_ST4; ra.dst[0] = pool + OFF_ST4; ra.n[0] = (long)BB*D2_*D2_;
        round_multi<<<dim3(512, 1), 256>>>(ra, 1);
    }
    // 17a) T = x3 @ St4
    {
        Jobs js;
        js.j[0] = mk_job(x3r, (long)N3_*D2_, D2_, pool+OFF_ST4, (long)D2_*D2_, D2_,
                         pool+OFF_T, (long)N3_*D2_, D2_, N3_, D2_, D2_, 1, 4, 5);
        js.j[1] = js.j[0]; js.j[2] = js.j[0];
        js.off[0] = 0; js.off[1] = 20; js.off[2] = 20; js.off[3] = 20;
        tgemm<0,0,false,true><<<dim3(20,1,BB), 256, SMEM_DYN>>>(js, nullptr, nullptr);
    }
    // 17b) ATT += f*(T @ Wp4^T)  (split-K 2)
    {
        Jobs js;
        js.j[0] = mk_job(pool+OFF_T, (long)N3_*D2_, D2_, pool+OFF_WP4R, 0L, D2_,
                         pool+OFF_ATT, (long)N3_*D2_, D2_, N3_, D2_, D2_, 2, 4, 5);
        js.j[1] = js.j[0]; js.j[2] = js.j[0];
        js.off[0] = 0; js.off[1] = 40; js.off[2] = 40; js.off[3] = 40;
        tgemm<6,1,false,false><<<dim3(40,1,BB), 256, SMEM_DYN>>>(js, nullptr, w);
    }

    // 19) AN = tf32(LN(ATT))
    ln_rows<<<BB * N3_, 256>>>(pool + OFF_ATT, g_norm, b_norm, pool + OFF_AN, D2_);

    // 20) H = AN @ Wfc1^T + bfc1
    {
        Jobs js;
        js.j[0] = mk_job(pool+OFF_AN, (long)N3_*D2_, D2_, pool+OFF_WF1, 0L, D2_,
                         pool+OFF_H, (long)N3_*DH_, DH_, N3_, DH_, D2_, 1, 16, 5);
        js.j[1] = js.j[0]; js.j[2] = js.j[0];
        js.off[0] = 0; js.off[1] = 80; js.off[2] = 80; js.off[3] = 80;
        tgemm<2,0,false,false><<<dim3(80,1,BB), 256, SMEM_DYN>>>(js, bfc1, nullptr);
    }

    // 21) AX = tf32(gelu(LN(dwconv(H)+bdw+H)))
    dwconv_ln_gelu<<<dim3(N3_, BB), 256>>>(pool + OFF_H, Wdw, bdw, g_ln1, b_ln1, pool + OFF_AX);

    // 22) out = ATT + bfc2 (prefill), then += AX @ Wfc2^T  (split-K 4)
    prefill_out<<<(BB*N3_*D2_ + 255)/256, 256>>>(pool + OFF_ATT, bfc2, (float*)d_out);
    {
        Jobs js;
        js.j[0] = mk_job(pool+OFF_AX, (long)N3_*DH_, DH_, pool+OFF_WF2, 0L, DH_,
                         (float*)d_out, (long)N3_*D2_, D2_, N3_, D2_, DH_, 4, 4, 5);
        js.j[1] = js.j[0]; js.j[2] = js.j[0];
        js.off[0] = 0; js.off[1] = 80; js.off[2] = 80; js.off[3] = 80;
        tgemm<6,0,false,false><<<dim3(80,1,BB), 256, SMEM_DYN>>>(js, nullptr, nullptr);
    }
}

// round 12
// speedup vs baseline: 1.7816x; 1.0539x over previous
#include <cuda_runtime.h>
#include <math.h>
#include <stdint.h>

// ---------------- problem dims ----------------
#define BB   4
#define N1_  9216
#define N2_  2304
#define N3_  576
#define D0_  128
#define D1_  256
#define D2_  512
#define DH_  2048

// ---------------- scratch pool (floats) ----------------
#define OFF_R1   0L
#define OFF_C1   36864L
#define OFF_R2   38912L
#define OFF_C2   48128L
#define OFF_R4   50176L
#define OFF_C4   87040L
#define OFF_RA   88064L
#define OFF_CA   97280L
#define OFF_ST12 99328L            // [B][1024][512]
#define OFF_ST3  2196480L          // [B][256][256]
#define OFF_ST4  2458624L          // [B][512][512]
#define ZERO_CNT 3507200L
#define OFF_ET1  3507200L
#define OFF_ET2  22381568L
#define OFF_ET4  27100160L
#define OFF_ETA  36537344L         // reused earlier as T12 [B][576][1024]
#define OFF_T    41255936L         // Wp12 (512x1024)+bsum early; T later
#define OFF_T3   42435584L
#define OFF_A3   44794880L
#define OFF_ATT  47154176L
#define OFF_AN   48333824L
#define OFF_H    49513472L
#define OFF_AX   54232064L
// tf32-rounded operand copies
#define OFF_XR   58950656L
#define OFF_X2R  63669248L
#define OFF_X3R  66028544L
#define OFF_WL   67208192L
#define OFF_WL2  67273728L
#define OFF_WL3  67404800L
#define OFF_WL4  67437568L
#define OFF_WP3R 67568640L
#define OFF_WP4R 67634176L
#define OFF_WF1  67896320L
#define OFF_WF2  68944896L
#define POOL_SZ  69993472L

#define OFF_T12   OFF_ETA
#define OFF_WP12  OFF_T
#define OFF_BSUM  (OFF_T + 524288L)

__device__ float g_pool[POOL_SZ];

// 3 stages x (A,B) x (128 rows x 36 floats)
#define STAGEB  18432u
#define BOFF    55296u
#define SMEM_DYN 110592

// ---------------- job table ----------------
struct Job {
    const float *A, *Bm;
    float *C;
    long aStr, bStr, cStr;
    int lda, ldb, ldc;
    int mTot, nTot, kTot, splits, gx, gy, amode;
    const float *kscale, *mscale;
    float *rowsum, *colsum;
};
struct Jobs { Job j[3]; int off[4]; };

// ---------------- helpers ----------------
__device__ __forceinline__ uint32_t smem_u32(const void* p) {
    uint32_t a;
    asm("{ .reg .u64 t; cvta.to.shared.u64 t, %1; cvt.u32.u64 %0, t; }" : "=r"(a) : "l"(p));
    return a;
}
__device__ __forceinline__ float to_tf32(float x) {
    float y;
    asm("cvt.rna.tf32.f32 %0, %1;" : "=f"(y) : "f"(x));
    return y;
}
__device__ __forceinline__ float4 rnd4(float4 v) {
    v.x = to_tf32(v.x); v.y = to_tf32(v.y); v.z = to_tf32(v.z); v.w = to_tf32(v.w);
    return v;
}
__device__ __forceinline__ void mma_tf32(float* d, const uint32_t* a, const uint32_t* bf) {
    asm volatile(
        "mma.sync.aligned.m16n8k8.row.col.f32.tf32.tf32.f32 "
        "{%0,%1,%2,%3}, {%4,%5,%6,%7}, {%8,%9}, {%0,%1,%2,%3};"
        : "+f"(d[0]), "+f"(d[1]), "+f"(d[2]), "+f"(d[3])
        : "r"(a[0]), "r"(a[1]), "r"(a[2]), "r"(a[3]), "r"(bf[0]), "r"(bf[1]));
}
__device__ __forceinline__ void ldm_x4(uint32_t* r, uint32_t addr) {
    asm volatile("ldmatrix.sync.aligned.m8n8.x4.shared.b16 {%0,%1,%2,%3}, [%4];"
        : "=r"(r[0]), "=r"(r[1]), "=r"(r[2]), "=r"(r[3]) : "r"(addr));
}
__device__ __forceinline__ void cpa16(uint32_t dst, const float* src, bool valid) {
    int sz = valid ? 16 : 0;
    asm volatile("cp.async.cg.shared.global [%0], [%1], 16, %2;"
        :: "r"(dst), "l"(src), "r"(sz) : "memory");
}
#define CP_COMMIT() asm volatile("cp.async.commit_group;" ::: "memory")
#define CP_WAIT1()  asm volatile("cp.async.wait_group 1;" ::: "memory")

// ================= tf32 mma.sync NT GEMM (job-batched, 3-stage cp.async, BK=32) ======
// D[m][n] = sum_k A[m][k]*B[n][k] per job; 128x128 CTA tile, BK=32, 256 thr / 8 warps,
// warp tile 64x32, ldmatrix x4 for A and paired-B fragments.
// EPI 0: C = acc (RND rounds)     EPI 1: exp + transposed store + rowsum/colsum atomics
// EPI 2: C = alpha*(acc+bias)     EPI 5: symmetric triangular split-K atomics (x mscale)
// EPI 6: atomicAdd(C, alpha*acc)
// amode (runtime per job): 0 alpha=1 ; 1 sigmoid(*w) ; 2 (1-sigmoid)/2
template<int EPI, bool KSC, bool RND>
__global__ void __launch_bounds__(256, 2) tgemm(
    Jobs jobs, const float* __restrict__ bias, const float* __restrict__ wscal)
{
    extern __shared__ float dynsm[];

    int q = blockIdx.x;
    int ji = 0;
    if (q >= jobs.off[1]) ji = 1;
    if (q >= jobs.off[2]) ji = 2;
    q -= jobs.off[ji];
    const Job J = jobs.j[ji];

    const int b = blockIdx.z;
    const int Kc = J.kTot / J.splits;
    int sp, bxq, byq;
    if (EPI == 5) {
        sp = q / J.gx;
        int tri = q % J.gx;
        const int T = J.nTot >> 7;
        int by = 0;
        while (tri >= T - by) { tri -= (T - by); by++; }
        byq = by; bxq = by + tri;
    } else {
        const int gxy = J.gx * J.gy;
        sp = q / gxy;
        int r = q % gxy;
        bxq = r % J.gx; byq = r / J.gx;
    }
    const int kbase = sp * Kc;
    const int nt = Kc >> 5;
    const int bm = byq * 128;
    const int bn = bxq * 128;

    const float* Ab = J.A + (long)b * J.aStr;
    const float* Bb = J.Bm + (long)b * J.bStr;
    const float* ksc_b = KSC ? (J.kscale + (long)b * J.kTot) : nullptr;
    const int lda = J.lda, ldb = J.ldb;
    const int mTot = J.mTot;

    const int tid = threadIdx.x;
    const int wid = tid >> 5, lane = tid & 31;
    const int wm = wid & 1, wn = wid >> 1;
    const int lr = lane >> 2, lc = lane & 3;

    const uint32_t smBase = smem_u32(dynsm);
    const int g8 = lane >> 3;
    const int r8 = lane & 7;
    const uint32_t asBase = smBase +
        (uint32_t)(((wm * 64 + (g8 & 1) * 8 + r8) * 36 + (g8 >> 1) * 4) * 4);
    const uint32_t bsBase = smBase + BOFF +
        (uint32_t)(((wn * 32 + (g8 >> 1) * 8 + r8) * 36 + (g8 & 1) * 4) * 4);

    auto issue_copy = [&](int tt, uint32_t stOff) {
        const int k0 = kbase + (tt << 5);
        const uint32_t aS = smBase + stOff;
        const uint32_t bS = smBase + BOFF + stOff;
#pragma unroll
        for (int l = 0; l < 4; l++) {
            int c = tid + (l << 8);
            int row = c >> 3, kq = (c & 7) << 2;
            uint32_t off = (uint32_t)((row * 36 + kq) * 4);
            cpa16(aS + off, Ab + (long)(bm + row) * lda + k0 + kq, (bm + row) < mTot);
            cpa16(bS + off, Bb + (long)(bn + row) * ldb + k0 + kq, true);
        }
    };

    float acc[4][4][4];
#pragma unroll
    for (int i = 0; i < 4; i++)
#pragma unroll
        for (int j = 0; j < 4; j++)
#pragma unroll
            for (int r = 0; r < 4; r++) acc[i][j][r] = 0.0f;

    issue_copy(0, 0);        CP_COMMIT();
    if (nt > 1) { issue_copy(1, STAGEB); }
    CP_COMMIT();

    uint32_t curOff = 0, nxtOff = STAGEB, thrOff = 2 * STAGEB;

    for (int t = 0; t < nt; t++) {
        CP_WAIT1();
        __syncthreads();
        if (t + 2 < nt) issue_copy(t + 2, thrOff);
        CP_COMMIT();

        const uint32_t aCur = asBase + curOff;
        const uint32_t bCur = bsBase + curOff;
        float sc[8];
        if (KSC) {
            const int k0t = kbase + (t << 5);
#pragma unroll
            for (int ks = 0; ks < 4; ks++) {
                sc[2 * ks]     = ksc_b[k0t + ks * 8 + lc];
                sc[2 * ks + 1] = ksc_b[k0t + ks * 8 + 4 + lc];
            }
        }
#pragma unroll
        for (int ks = 0; ks < 4; ks++) {
            uint32_t af[4][4];
#pragma unroll
            for (int i = 0; i < 4; i++)
                ldm_x4(af[i], aCur + i * 2304 + ks * 32);
            uint32_t bf[4][2];
#pragma unroll
            for (int j2 = 0; j2 < 2; j2++) {
                uint32_t r4[4];
                ldm_x4(r4, bCur + j2 * 2304 + ks * 32);
                if (KSC) {
                    r4[0] = __float_as_uint(to_tf32(__uint_as_float(r4[0]) * sc[2 * ks]));
                    r4[1] = __float_as_uint(to_tf32(__uint_as_float(r4[1]) * sc[2 * ks + 1]));
                    r4[2] = __float_as_uint(to_tf32(__uint_as_float(r4[2]) * sc[2 * ks]));
                    r4[3] = __float_as_uint(to_tf32(__uint_as_float(r4[3]) * sc[2 * ks + 1]));
                }
                bf[2 * j2][0] = r4[0]; bf[2 * j2][1] = r4[1];
                bf[2 * j2 + 1][0] = r4[2]; bf[2 * j2 + 1][1] = r4[3];
            }
#pragma unroll
            for (int i = 0; i < 4; i++)
#pragma unroll
                for (int j = 0; j < 4; j++)
                    mma_tf32(acc[i][j], af[i], bf[j]);
        }
        uint32_t tmp = curOff; curOff = nxtOff; nxtOff = thrOff; thrOff = tmp;
    }
    __syncthreads();

    // ---- epilogue ----
    float alpha = 1.0f;
    if (J.amode != 0) {
        float f = 1.0f / (1.0f + expf(-wscal[0]));
        alpha = (J.amode == 1) ? f : (1.0f - f) * 0.5f;
    }

    float* Cb = J.C + (long)b * J.cStr;
    const int ldc = J.ldc;

    if (EPI == 1) {
        float rs[4][2];
#pragma unroll
        for (int i = 0; i < 4; i++) { rs[i][0] = 0.f; rs[i][1] = 0.f; }
#pragma unroll
        for (int j = 0; j < 4; j++) {
            int col0 = bn + wn * 32 + j * 8 + lc * 2;
            float cs0 = 0.f, cs1 = 0.f;
#pragma unroll
            for (int i = 0; i < 4; i++) {
                float e0 = to_tf32(expf(acc[i][j][0]));
                float e1 = to_tf32(expf(acc[i][j][1]));
                float e2 = to_tf32(expf(acc[i][j][2]));
                float e3 = to_tf32(expf(acc[i][j][3]));
                acc[i][j][0] = e0; acc[i][j][1] = e1;
                acc[i][j][2] = e2; acc[i][j][3] = e3;
                cs0 += e0 + e2; cs1 += e1 + e3;
                rs[i][0] += e0 + e1; rs[i][1] += e2 + e3;
            }
#pragma unroll
            for (int o = 4; o <= 16; o <<= 1) {
                cs0 += __shfl_xor_sync(0xffffffff, cs0, o);
                cs1 += __shfl_xor_sync(0xffffffff, cs1, o);
            }
            if (lane < 4) {
                atomicAdd(J.colsum + (long)b * J.nTot + col0, cs0);
                atomicAdd(J.colsum + (long)b * J.nTot + col0 + 1, cs1);
            }
        }
#pragma unroll
        for (int i = 0; i < 4; i++)
#pragma unroll
            for (int h = 0; h < 2; h++) {
                float v = rs[i][h];
                v += __shfl_xor_sync(0xffffffff, v, 1);
                v += __shfl_xor_sync(0xffffffff, v, 2);
                if (lc == 0) {
                    int r = bm + wm * 64 + i * 16 + lr + h * 8;
                    atomicAdd(J.rowsum + (long)b * mTot + r, v);
                }
            }
        float* stg = dynsm;
#pragma unroll
        for (int h2 = 0; h2 < 2; h2++) {
            __syncthreads();
            if ((wn >> 1) == h2) {
                int snb = wn * 32 - h2 * 64;
#pragma unroll
                for (int j = 0; j < 4; j++) {
                    int sn = snb + j * 8 + lc * 2;
#pragma unroll
                    for (int i = 0; i < 4; i++) {
                        int ml = wm * 64 + i * 16 + lr;
                        stg[sn * 132 + ml]           = acc[i][j][0];
                        stg[(sn + 1) * 132 + ml]     = acc[i][j][1];
                        stg[sn * 132 + ml + 8]       = acc[i][j][2];
                        stg[(sn + 1) * 132 + ml + 8] = acc[i][j][3];
                    }
                }
            }
            __syncthreads();
#pragma unroll
            for (int it = 0; it < 8; it++) {
                int id = tid + (it << 8);
                int row = id >> 5, m4 = (id & 31) << 2;
                float4 v = *(float4*)&stg[row * 132 + m4];
                *(float4*)(Cb + (long)(bn + h2 * 64 + row) * ldc + bm + m4) = v;
            }
        }
    } else if (EPI == 5) {
        const float* msc = J.mscale + (long)b * mTot;
#pragma unroll
        for (int i = 0; i < 4; i++) {
            int r0 = bm + wm * 64 + i * 16 + lr;
            float s0 = msc[r0];
            float s1 = msc[r0 + 8];
#pragma unroll
            for (int j = 0; j < 4; j++) {
                int col0 = bn + wn * 32 + j * 8 + lc * 2;
                atomicAdd(Cb + (long)r0 * ldc + col0,           acc[i][j][0] * s0);
                atomicAdd(Cb + (long)r0 * ldc + col0 + 1,       acc[i][j][1] * s0);
                atomicAdd(Cb + (long)(r0 + 8) * ldc + col0,     acc[i][j][2] * s1);
                atomicAdd(Cb + (long)(r0 + 8) * ldc + col0 + 1, acc[i][j][3] * s1);
            }
        }
        if (bxq != byq) {
#pragma unroll
            for (int j = 0; j < 4; j++) {
                int n0 = bn + wn * 32 + j * 8 + lc * 2;
                float sn0 = msc[n0];
                float sn1 = msc[n0 + 1];
#pragma unroll
                for (int i = 0; i < 4; i++) {
                    int r0 = bm + wm * 64 + i * 16 + lr;
                    atomicAdd(Cb + (long)n0 * ldc + r0,           acc[i][j][0] * sn0);
                    atomicAdd(Cb + (long)(n0 + 1) * ldc + r0,     acc[i][j][1] * sn1);
                    atomicAdd(Cb + (long)n0 * ldc + r0 + 8,       acc[i][j][2] * sn0);
                    atomicAdd(Cb + (long)(n0 + 1) * ldc + r0 + 8, acc[i][j][3] * sn1);
                }
            }
        }
    } else if (EPI == 6) {
#pragma unroll
        for (int i = 0; i < 4; i++) {
#pragma unroll
            for (int h = 0; h < 2; h++) {
                int r = bm + wm * 64 + i * 16 + lr + h * 8;
                if (r >= mTot) continue;
                float* Crow = Cb + (long)r * ldc;
#pragma unroll
                for (int j = 0; j < 4; j++) {
                    int col0 = bn + wn * 32 + j * 8 + lc * 2;
                    atomicAdd(Crow + col0,     alpha * acc[i][j][h * 2 + 0]);
                    atomicAdd(Crow + col0 + 1, alpha * acc[i][j][h * 2 + 1]);
                }
            }
        }
    } else {
#pragma unroll
        for (int i = 0; i < 4; i++) {
#pragma unroll
            for (int h = 0; h < 2; h++) {
                int r = bm + wm * 64 + i * 16 + lr + h * 8;
                if (r >= mTot) continue;
                float* Crow = Cb + (long)r * ldc;
#pragma unroll
                for (int j = 0; j < 4; j++) {
                    int col0 = bn + wn * 32 + j * 8 + lc * 2;
                    float v0 = acc[i][j][h * 2 + 0];
                    float v1 = acc[i][j][h * 2 + 1];
                    if (EPI == 2) {
                        v0 = alpha * (v0 + bias[col0]);
                        v1 = alpha * (v1 + bias[col0 + 1]);
                    }
                    if (RND) { v0 = to_tf32(v0); v1 = to_tf32(v1); }
                    float2 o; o.x = v0; o.y = v1;
                    *(float2*)(Crow + col0) = o;
                }
            }
        }
    }
}

// ---------------- fused utility kernels ----------------
struct PrepArgs {
    const float* src[11];
    float* dst[11];
    long n[11];
    const float *W1, *W2, *b1, *b2;
    float *W12, *bsum, *zero;
    long zn;
};
// seg 0-10: tf32 round copies; seg 11: zero; seg 12: W12 concat; seg 13: bsum
__global__ void prep(PrepArgs a) {
    int seg = blockIdx.y;
    long i0 = (long)blockIdx.x * blockDim.x + threadIdx.x;
    long stride = (long)gridDim.x * blockDim.x;
    if (seg < 11) {
        const float4* s = (const float4*)a.src[seg];
        float4* d = (float4*)a.dst[seg];
        long n4 = a.n[seg] >> 2;
        for (long i = i0; i < n4; i += stride) d[i] = rnd4(s[i]);
    } else if (seg == 11) {
        float4* z = (float4*)a.zero;
        long n4 = a.zn >> 2;
        float4 v = make_float4(0.f, 0.f, 0.f, 0.f);
        for (long i = i0; i < n4; i += stride) z[i] = v;
    } else if (seg == 12) {
        float4* d = (float4*)a.W12;
        for (long i = i0; i < 131072L; i += stride) {
            long base = i << 2;
            int n = (int)(base >> 10), k = (int)(base & 1023);
            float4 v = (k < 512) ? *(const float4*)(a.W1 + (long)n * 512 + k)
                                 : *(const float4*)(a.W2 + (long)n * 512 + k - 512);
            d[i] = rnd4(v);
        }
    } else {
        for (long i = i0; i < 512; i += stride) a.bsum[i] = a.b1[i] + a.b2[i];
    }
}

// seg0: recip stats[0..nstats); seg1: ATT = x3 + other*bsum + f*bp4; seg2: A3 = bp3
__global__ void fuse2(float* stats, int nstats,
                      const float* __restrict__ x3, const float* __restrict__ bsum,
                      const float* __restrict__ bp4, const float* __restrict__ wscal,
                      float* __restrict__ ATT,
                      const float* __restrict__ bp3, float* __restrict__ A3)
{
    int seg = blockIdx.y;
    long i0 = (long)blockIdx.x * blockDim.x + threadIdx.x;
    long stride = (long)gridDim.x * blockDim.x;
    if (seg == 0) {
        for (long i = i0; i < nstats; i += stride) stats[i] = 1.0f / stats[i];
    } else if (seg == 1) {
        float f = 1.0f / (1.0f + expf(-wscal[0]));
        float other = (1.0f - f) * 0.5f;
        for (long i = i0; i < (long)BB * N3_ * D2_; i += stride) {
            int col = (int)(i & (D2_ - 1));
            ATT[i] = x3[i] + other * bsum[col] + f * bp4[col];
        }
    } else {
        for (long i = i0; i < (long)BB * N2_ * D1_; i += stride)
            A3[i] = bp3[(int)(i & (D1_ - 1))];
    }
}

__global__ void recip_kernel(float* p, int n) {
    int i = blockIdx.x * blockDim.x + threadIdx.x;
    if (i < n) p[i] = 1.0f / p[i];
}

// LN over last dim + fused out-prefill: Y = tf32(LN(X)); outp = X + bfc2
__global__ void ln_rows(const float* __restrict__ X, const float* __restrict__ g,
                        const float* __restrict__ bb, float* __restrict__ Y, int C,
                        const float* __restrict__ bfc2, float* __restrict__ outp)
{
    long row = blockIdx.x;
    const float* x = X + row * C;
    float s = 0.f, s2 = 0.f;
    for (int c = threadIdx.x; c < C; c += blockDim.x) { float v = x[c]; s += v; s2 += v * v; }
    __shared__ float sh1[32], sh2[32];
    int lane = threadIdx.x & 31, wid = threadIdx.x >> 5;
#pragma unroll
    for (int o = 16; o; o >>= 1) {
        s  += __shfl_down_sync(0xffffffff, s,  o);
        s2 += __shfl_down_sync(0xffffffff, s2, o);
    }
    if (!lane) { sh1[wid] = s; sh2[wid] = s2; }
    __syncthreads();
    if (threadIdx.x == 0) {
        float a = 0.f, c2 = 0.f;
        int nw = blockDim.x >> 5;
        for (int i = 0; i < nw; i++) { a += sh1[i]; c2 += sh2[i]; }
        float mean = a / C;
        float var  = c2 / C - mean * mean;
        sh1[0] = mean; sh2[0] = rsqrtf(var + 1e-5f);
    }
    __syncthreads();
    float mean = sh1[0], rstd = sh2[0];
    for (int c = threadIdx.x; c < C; c += blockDim.x) {
        float v = x[c];
        Y[row * C + c] = to_tf32((v - mean) * rstd * g[c] + bb[c]);
        outp[row * C + c] = v + bfc2[c];
    }
}

__global__ void __launch_bounds__(256) dwconv_ln_gelu(
    const float* __restrict__ H, const float* __restrict__ Wdw,
    const float* __restrict__ bdw, const float* __restrict__ g,
    const float* __restrict__ bt, float* __restrict__ AX)
{
    const int n = blockIdx.x;
    const int b = blockIdx.y;
    const int y = n / 24, x = n % 24;
    const float* Hb = H + (long)b * 576 * 2048;
    const int tid = threadIdx.x;

    float v[8];
    float s = 0.f, s2 = 0.f;
#pragma unroll
    for (int it = 0; it < 8; it++) {
        int c = tid + it * 256;
        float a = Hb[(long)n * 2048 + c] + bdw[c];
#pragma unroll
        for (int ky = 0; ky < 3; ky++) {
            int yy = y + ky - 1;
            if (yy < 0 || yy > 23) continue;
#pragma unroll
            for (int kx = 0; kx < 3; kx++) {
                int xx = x + kx - 1;
                if (xx < 0 || xx > 23) continue;
                a += Wdw[c * 9 + ky * 3 + kx] * Hb[(long)(yy * 24 + xx) * 2048 + c];
            }
        }
        v[it] = a; s += a; s2 += a * a;
    }
    __shared__ float sh1[32], sh2[32];
    int lane = tid & 31, wid = tid >> 5;
#pragma unroll
    for (int o = 16; o; o >>= 1) {
        s  += __shfl_down_sync(0xffffffff, s,  o);
        s2 += __shfl_down_sync(0xffffffff, s2, o);
    }
    if (!lane) { sh1[wid] = s; sh2[wid] = s2; }
    __syncthreads();
    if (tid == 0) {
        float a = 0.f, c2 = 0.f;
        for (int i = 0; i < 8; i++) { a += sh1[i]; c2 += sh2[i]; }
        float mean = a / 2048.0f;
        float var  = c2 / 2048.0f - mean * mean;
        sh1[0] = mean; sh2[0] = rsqrtf(var + 1e-5f);
    }
    __syncthreads();
    float mean = sh1[0], rstd = sh2[0];
    float* out = AX + ((long)b * 576 + n) * 2048;
#pragma unroll
    for (int it = 0; it < 8; it++) {
        int c = tid + it * 256;
        float t = (v[it] - mean) * rstd * g[c] + bt[c];
        out[c] = to_tf32(0.5f * t * (1.0f + erff(t * 0.70710678118654752f)));
    }
}

// ---------------- host orchestration ----------------
#define SET_SMEM(k) cudaFuncSetAttribute(k, cudaFuncAttributeMaxDynamicSharedMemorySize, SMEM_DYN)

static Job mk_job(const float* A, long aStr, int lda,
                  const float* B, long bStr, int ldb,
                  float* C, long cStr, int ldc,
                  int m, int n, int k, int splits, int gx, int gy, int amode,
                  const float* ksc = nullptr, const float* msc = nullptr,
                  float* rsum = nullptr, float* csum = nullptr) {
    Job J;
    J.A = A; J.Bm = B; J.C = C;
    J.aStr = aStr; J.bStr = bStr; J.cStr = cStr;
    J.lda = lda; J.ldb = ldb; J.ldc = ldc;
    J.mTot = m; J.nTot = n; J.kTot = k; J.splits = splits; J.gx = gx; J.gy = gy;
    J.amode = amode;
    J.kscale = ksc; J.mscale = msc; J.rowsum = rsum; J.colsum = csum;
    return J;
}

extern "C" void kernel_launch(void* const* d_in, const int* in_sizes, int n_in,
                              void* d_out, int out_size)
{
    const float* x      = (const float*)d_in[0];
    const float* x2     = (const float*)d_in[1];
    const float* x3     = (const float*)d_in[2];
    const float* W_lin  = (const float*)d_in[3];
    const float* W_lin2 = (const float*)d_in[4];
    const float* W_lin3 = (const float*)d_in[5];
    const float* W_lin4 = (const float*)d_in[6];
    const float* w      = (const float*)d_in[7];
    const float* Wp1 = (const float*)d_in[8];  const float* bp1 = (const float*)d_in[9];
    const float* Wp2 = (const float*)d_in[10]; const float* bp2 = (const float*)d_in[11];
    const float* Wp3 = (const float*)d_in[12]; const float* bp3 = (const float*)d_in[13];
    const float* Wp4 = (const float*)d_in[14]; const float* bp4 = (const float*)d_in[15];
    const float* g_norm = (const float*)d_in[16]; const float* b_norm = (const float*)d_in[17];
    const float* Wfc1 = (const float*)d_in[18];   const float* bfc1  = (const float*)d_in[19];
    const float* Wdw  = (const float*)d_in[20];   const float* bdw   = (const float*)d_in[21];
    const float* g_ln1 = (const float*)d_in[22];  const float* b_ln1 = (const float*)d_in[23];
    const float* Wfc2 = (const float*)d_in[24];   const float* bfc2  = (const float*)d_in[25];

    float* pool = nullptr;
    cudaGetSymbolAddress((void**)&pool, g_pool);

    SET_SMEM((tgemm<1,false,false>));
    SET_SMEM((tgemm<5,true,false>));
    SET_SMEM((tgemm<0,false,true>));
    SET_SMEM((tgemm<2,false,false>));
    SET_SMEM((tgemm<6,false,false>));

    // 0) fused prologue: rounding copies + zero + W12 concat + bsum
    {
        PrepArgs pa;
        const float* srcs[11] = { x, x2, x3, W_lin, W_lin2, W_lin3, W_lin4, Wp3, Wp4, Wfc1, Wfc2 };
        long offs[11] = { OFF_XR, OFF_X2R, OFF_X3R, OFF_WL, OFF_WL2, OFF_WL3, OFF_WL4,
                          OFF_WP3R, OFF_WP4R, OFF_WF1, OFF_WF2 };
        long ns[11] = { (long)BB*N1_*D0_, (long)BB*N2_*D1_, (long)BB*N3_*D2_,
                        (long)D2_*D0_, (long)D2_*D1_, (long)D1_*D0_, (long)D2_*D1_,
                        (long)D1_*D1_, (long)D2_*D2_, (long)DH_*D2_, (long)D2_*DH_ };
        for (int i = 0; i < 11; i++) { pa.src[i] = srcs[i]; pa.dst[i] = pool + offs[i]; pa.n[i] = ns[i]; }
        pa.W1 = Wp1; pa.W2 = Wp2; pa.b1 = bp1; pa.b2 = bp2;
        pa.W12 = pool + OFF_WP12; pa.bsum = pool + OFF_BSUM;
        pa.zero = pool; pa.zn = ZERO_CNT;
        prep<<<dim3(512, 14), 256>>>(pa);
    }
    const float* xr  = pool + OFF_XR;
    const float* x2r = pool + OFF_X2R;
    const float* x3r = pool + OFF_X3R;

    // 1-3) Et1+Et2+Et4 (EPI1, 3 jobs)
    {
        Jobs js;
        js.j[0] = mk_job(xr, (long)N1_*D0_, D0_, pool+OFF_WL, 0L, D0_,
                         pool+OFF_ET1, (long)D2_*N1_, N1_, N1_, D2_, D0_, 1, 4, 72, 0,
                         nullptr, nullptr, pool+OFF_R1, pool+OFF_C1);
        js.j[1] = mk_job(x2r, (long)N2_*D1_, D1_, pool+OFF_WL2, 0L, D1_,
                         pool+OFF_ET2, (long)D2_*N2_, N2_, N2_, D2_, D1_, 1, 4, 18, 0,
                         nullptr, nullptr, pool+OFF_R2, pool+OFF_C2);
        js.j[2] = mk_job(xr, (long)N1_*D0_, D0_, pool+OFF_WL3, 0L, D0_,
                         pool+OFF_ET4, (long)D1_*N1_, N1_, N1_, D1_, D0_, 1, 2, 72, 0,
                         nullptr, nullptr, pool+OFF_R4, pool+OFF_C4);
        js.off[0] = 0; js.off[1] = 288; js.off[2] = 360; js.off[3] = 504;
        tgemm<1,false,false><<<dim3(504,1,BB), 256, SMEM_DYN>>>(js, nullptr, nullptr);
    }

    // 4) fused: reciprocals + ATT prefill + A3 prefill (bp3)
    fuse2<<<dim3(1024, 3), 256>>>(pool, 88064, x3, pool+OFF_BSUM, bp4, w,
                                  pool+OFF_ATT, bp3, pool+OFF_A3);

    // 5-7) St1+St2+St3 (EPI5, 3 jobs)
    {
        Jobs js;
        js.j[0] = mk_job(pool+OFF_ET1, (long)D2_*N1_, N1_, pool+OFF_ET1, (long)D2_*N1_, N1_,
                         pool+OFF_ST12, (long)2*D2_*D2_, D2_, D2_, D2_, N1_, 8, 10, 1, 0,
                         pool+OFF_R1, pool+OFF_C1);
        js.j[1] = mk_job(pool+OFF_ET2, (long)D2_*N2_, N2_, pool+OFF_ET2, (long)D2_*N2_, N2_,
                         pool+OFF_ST12 + (long)D2_*D2_, (long)2*D2_*D2_, D2_, D2_, D2_, N2_, 4, 10, 1, 0,
                         pool+OFF_R2, pool+OFF_C2);
        js.j[2] = mk_job(pool+OFF_ET4, (long)D1_*N1_, N1_, pool+OFF_ET4, (long)D1_*N1_, N1_,
                         pool+OFF_ST3, (long)D1_*D1_, D1_, D1_, D1_, N1_, 8, 3, 1, 0,
                         pool+OFF_R4, pool+OFF_C4);
        js.off[0] = 0; js.off[1] = 80; js.off[2] = 120; js.off[3] = 144;
        tgemm<5,true,false><<<dim3(144,1,BB), 256, SMEM_DYN>>>(js, nullptr, nullptr);
    }

    // 8+12) T12 and T3 (EPI0 RND, 2 jobs) — St operands enter truncated (no round pass)
    {
        Jobs js;
        js.j[0] = mk_job(x3r, (long)N3_*D2_, D2_, pool+OFF_ST12, (long)2*D2_*D2_, D2_,
                         pool+OFF_T12, (long)N3_*2*D2_, 2*D2_, N3_, 2*D2_, D2_, 1, 8, 5, 0);
        js.j[1] = mk_job(x2r, (long)N2_*D1_, D1_, pool+OFF_ST3, (long)D1_*D1_, D1_,
                         pool+OFF_T3, (long)N2_*D1_, D1_, N2_, D1_, D1_, 1, 2, 18, 0);
        js.j[2] = js.j[1];
        js.off[0] = 0; js.off[1] = 40; js.off[2] = 76; js.off[3] = 76;
        tgemm<0,false,true><<<dim3(76,1,BB), 256, SMEM_DYN>>>(js, nullptr, nullptr);
    }

    // 9+13) ATT += other*(T12@Wp12^T)  AND  A3 += T3@Wp3^T  (EPI6, per-job alpha)
    {
        Jobs js;
        js.j[0] = mk_job(pool+OFF_T12, (long)N3_*2*D2_, 2*D2_, pool+OFF_WP12, 0L, 2*D2_,
                         pool+OFF_ATT, (long)N3_*D2_, D2_, N3_, D2_, 2*D2_, 2, 4, 5, 2);
        js.j[1] = mk_job(pool+OFF_T3, (long)N2_*D1_, D1_, pool+OFF_WP3R, 0L, D1_,
                         pool+OFF_A3, (long)N2_*D1_, D1_, N2_, D1_, D1_, 1, 2, 18, 0);
        js.j[2] = js.j[1];
        js.off[0] = 0; js.off[1] = 40; js.off[2] = 76; js.off[3] = 76;
        tgemm<6,false,false><<<dim3(76,1,BB), 256, SMEM_DYN>>>(js, nullptr, w);
    }

    // 14) EtA (EPI1)
    {
        Jobs js;
        js.j[0] = mk_job(pool+OFF_A3, (long)N2_*D1_, D1_, pool+OFF_WL4, 0L, D1_,
                         pool+OFF_ETA, (long)D2_*N2_, N2_, N2_, D2_, D1_, 1, 4, 18, 0,
                         nullptr, nullptr, pool+OFF_RA, pool+OFF_CA);
        js.j[1] = js.j[0]; js.j[2] = js.j[0];
        js.off[0] = 0; js.off[1] = 72; js.off[2] = 72; js.off[3] = 72;
        tgemm<1,false,false><<<dim3(72,1,BB), 256, SMEM_DYN>>>(js, nullptr, nullptr);
    }
    // 15) reciprocals RA,CA
    recip_kernel<<<(11264 + 255) / 256, 256>>>(pool + OFF_RA, 11264);
    // 16) St4 (EPI5)
    {
        Jobs js;
        js.j[0] = mk_job(pool+OFF_ETA, (long)D2_*N2_, N2_, pool+OFF_ETA, (long)D2_*N2_, N2_,
                         pool+OFF_ST4, (long)D2_*D2_, D2_, D2_, D2_, N2_, 4, 10, 1, 0,
                         pool+OFF_RA, pool+OFF_CA);
        js.j[1] = js.j[0]; js.j[2] = js.j[0];
        js.off[0] = 0; js.off[1] = 40; js.off[2] = 40; js.off[3] = 40;
        tgemm<5,true,false><<<dim3(40,1,BB), 256, SMEM_DYN>>>(js, nullptr, nullptr);
    }
    // 17a) T = x3 @ St4 (St4 truncated)
    {
        Jobs js;
        js.j[0] = mk_job(x3r, (long)N3_*D2_, D2_, pool+OFF_ST4, (long)D2_*D2_, D2_,
                         pool+OFF_T, (long)N3_*D2_, D2_, N3_, D2_, D2_, 1, 4, 5, 0);
        js.j[1] = js.j[0]; js.j[2] = js.j[0];
        js.off[0] = 0; js.off[1] = 20; js.off[2] = 20; js.off[3] = 20;
        tgemm<0,false,true><<<dim3(20,1,BB), 256, SMEM_DYN>>>(js, nullptr, nullptr);
    }
    // 17b) ATT += f*(T @ Wp4^T)  (EPI6, split-K 2)
    {
        Jobs js;
        js.j[0] = mk_job(pool+OFF_T, (long)N3_*D2_, D2_, pool+OFF_WP4R, 0L, D2_,
                         pool+OFF_ATT, (long)N3_*D2_, D2_, N3_, D2_, D2_, 2, 4, 5, 1);
        js.j[1] = js.j[0]; js.j[2] = js.j[0];
        js.off[0] = 0; js.off[1] = 40; js.off[2] = 40; js.off[3] = 40;
        tgemm<6,false,false><<<dim3(40,1,BB), 256, SMEM_DYN>>>(js, nullptr, w);
    }

    // 19) AN = tf32(LN(ATT)) + out prefill (ATT + bfc2)
    ln_rows<<<BB * N3_, 256>>>(pool + OFF_ATT, g_norm, b_norm, pool + OFF_AN, D2_,
                               bfc2, (float*)d_out);

    // 20) H = AN @ Wfc1^T + bfc1
    {
        Jobs js;
        js.j[0] = mk_job(pool+OFF_AN, (long)N3_*D2_, D2_, pool+OFF_WF1, 0L, D2_,
                         pool+OFF_H, (long)N3_*DH_, DH_, N3_, DH_, D2_, 1, 16, 5, 0);
        js.j[1] = js.j[0]; js.j[2] = js.j[0];
        js.off[0] = 0; js.off[1] = 80; js.off[2] = 80; js.off[3] = 80;
        tgemm<2,false,false><<<dim3(80,1,BB), 256, SMEM_DYN>>>(js, bfc1, nullptr);
    }

    // 21) AX = tf32(gelu(LN(dwconv(H)+bdw+H)))
    dwconv_ln_gelu<<<dim3(N3_, BB), 256>>>(pool + OFF_H, Wdw, bdw, g_ln1, b_ln1, pool + OFF_AX);

    // 22) out += AX @ Wfc2^T  (EPI6, split-K 4)
    {
        Jobs js;
        js.j[0] = mk_job(pool+OFF_AX, (long)N3_*DH_, DH_, pool+OFF_WF2, 0L, DH_,
                         (float*)d_out, (long)N3_*D2_, D2_, N3_, D2_, DH_, 4, 4, 5, 0);
        js.j[1] = js.j[0]; js.j[2] = js.j[0];
        js.off[0] = 0; js.off[1] = 80; js.off[2] = 80; js.off[3] = 80;
        tgemm<6,false,false><<<dim3(80,1,BB), 256, SMEM_DYN>>>(js, nullptr, nullptr);
    }
}

// round 14
// speedup vs baseline: 2.1535x; 1.2088x over previous
#include <cuda_runtime.h>
#include <cuda_fp16.h>
#include <math.h>
#include <stdint.h>

// ---------------- problem dims ----------------
#define BB   4
#define N1_  9216
#define N2_  2304
#define N3_  576
#define D0_  128
#define D1_  256
#define D2_  512
#define DH_  2048

// ---------------- scratch pool (floats) ----------------
#define OFF_R1   0L
#define OFF_C1   36864L
#define OFF_R2   38912L
#define OFF_C2   48128L
#define OFF_R4   50176L
#define OFF_C4   87040L
#define OFF_RA   88064L
#define OFF_CA   97280L
#define OFF_ST12 99328L            // [B][1024][512] fp32
#define OFF_ST3  2196480L          // [B][256][256]  fp32
#define OFF_ST4  2458624L          // [B][512][512]  fp32
#define ZERO_CNT 3507200L
#define OFF_ET1  3507200L          // fp16 [B][512][9216]
#define OFF_ET2  22381568L         // fp16
#define OFF_ET4  27100160L         // fp16
#define OFF_ETA  36537344L         // fp16; earlier reused as T12 [B][576][1024] fp32
#define OFF_T    41255936L         // Wp12+bsum early; T later
#define OFF_T3   42435584L
#define OFF_A3   44794880L
#define OFF_ATT  47154176L
#define OFF_AN   48333824L
#define OFF_H    49513472L
#define OFF_AX   54232064L
// tf32-rounded operand copies
#define OFF_XR   58950656L
#define OFF_X2R  63669248L
#define OFF_X3R  66028544L
#define OFF_WL   67208192L
#define OFF_WL2  67273728L
#define OFF_WL3  67404800L
#define OFF_WL4  67437568L
#define OFF_WP3R 67568640L
#define OFF_WP4R 67634176L
#define OFF_WF1  67896320L
#define OFF_WF2  68944896L
// fp16 scaled row-recip arrays (stored in float slots, used as half*)
#define OFF_R1H  69993472L
#define OFF_R2H  70011904L
#define OFF_R4H  70016512L
#define OFF_RAH  70034944L
#define POOL_SZ  70039552L

#define OFF_T12   OFF_ETA
#define OFF_WP12  OFF_T
#define OFF_BSUM  (OFF_T + 524288L)

__device__ float g_pool[POOL_SZ];

// float kernel: 3 stages x (A,B) x (128 rows x 36 floats)
// half kernel:  3 stages x (A,B) x (128 rows x 72 halves)  -> same byte counts
#define STAGEB  18432u
#define BOFF    55296u
#define SMEM_DYN 110592

// ---------------- job table ----------------
struct Job {
    const float *A, *Bm;
    float *C;
    long aStr, bStr, cStr;   // element units of their respective dtypes
    int lda, ldb, ldc;
    int mTot, nTot, kTot, splits, gx, gy, amode;
    const float *kscale, *mscale;
    float *rowsum, *colsum;
};
struct Jobs { Job j[3]; int off[4]; };

// ---------------- helpers ----------------
__device__ __forceinline__ uint32_t smem_u32(const void* p) {
    uint32_t a;
    asm("{ .reg .u64 t; cvta.to.shared.u64 t, %1; cvt.u32.u64 %0, t; }" : "=r"(a) : "l"(p));
    return a;
}
__device__ __forceinline__ float to_tf32(float x) {
    float y;
    asm("cvt.rna.tf32.f32 %0, %1;" : "=f"(y) : "f"(x));
    return y;
}
__device__ __forceinline__ float4 rnd4(float4 v) {
    v.x = to_tf32(v.x); v.y = to_tf32(v.y); v.z = to_tf32(v.z); v.w = to_tf32(v.w);
    return v;
}
__device__ __forceinline__ void mma_tf32(float* d, const uint32_t* a, const uint32_t* bf) {
    asm volatile(
        "mma.sync.aligned.m16n8k8.row.col.f32.tf32.tf32.f32 "
        "{%0,%1,%2,%3}, {%4,%5,%6,%7}, {%8,%9}, {%0,%1,%2,%3};"
        : "+f"(d[0]), "+f"(d[1]), "+f"(d[2]), "+f"(d[3])
        : "r"(a[0]), "r"(a[1]), "r"(a[2]), "r"(a[3]), "r"(bf[0]), "r"(bf[1]));
}
__device__ __forceinline__ void mma_f16(float* d, const uint32_t* a, const uint32_t* bf) {
    asm volatile(
        "mma.sync.aligned.m16n8k16.row.col.f32.f16.f16.f32 "
        "{%0,%1,%2,%3}, {%4,%5,%6,%7}, {%8,%9}, {%0,%1,%2,%3};"
        : "+f"(d[0]), "+f"(d[1]), "+f"(d[2]), "+f"(d[3])
        : "r"(a[0]), "r"(a[1]), "r"(a[2]), "r"(a[3]), "r"(bf[0]), "r"(bf[1]));
}
__device__ __forceinline__ void ldm_x4(uint32_t* r, uint32_t addr) {
    asm volatile("ldmatrix.sync.aligned.m8n8.x4.shared.b16 {%0,%1,%2,%3}, [%4];"
        : "=r"(r[0]), "=r"(r[1]), "=r"(r[2]), "=r"(r[3]) : "r"(addr));
}
__device__ __forceinline__ void cpa16(uint32_t dst, const void* src, bool valid) {
    int sz = valid ? 16 : 0;
    asm volatile("cp.async.cg.shared.global [%0], [%1], 16, %2;"
        :: "r"(dst), "l"(src), "r"(sz) : "memory");
}
__device__ __forceinline__ uint32_t h2mul(uint32_t a, __half2 s) {
    __half2 v = __hmul2(*(__half2*)&a, s);
    return *(uint32_t*)&v;
}
#define CP_COMMIT() asm volatile("cp.async.commit_group;" ::: "memory")
#define CP_WAIT1()  asm volatile("cp.async.wait_group 1;" ::: "memory")

// ================= fp32/tf32 NT GEMM (job-batched, 3-stage cp.async, BK=32) ======
// EPI 0: C = acc (RND rounds)   EPI 1: exp -> fp16; Et[n][m] (half; cStr in HALF units)
// EPI 2: C = alpha*(acc+bias)   EPI 6: atomicAdd(C, alpha*acc)
// amode runtime: 0 alpha=1 ; 1 sigmoid(*w) ; 2 (1-sigmoid)/2
template<int EPI, bool RND>
__global__ void __launch_bounds__(256, 2) tgemm(
    Jobs jobs, const float* __restrict__ bias, const float* __restrict__ wscal)
{
    extern __shared__ float dynsm[];

    int q = blockIdx.x;
    int ji = 0;
    if (q >= jobs.off[1]) ji = 1;
    if (q >= jobs.off[2]) ji = 2;
    q -= jobs.off[ji];
    const Job J = jobs.j[ji];

    const int b = blockIdx.z;
    const int Kc = J.kTot / J.splits;
    const int gxy = J.gx * J.gy;
    int sp = q / gxy;
    int r0q = q % gxy;
    int bxq = r0q % J.gx, byq = r0q / J.gx;
    const int kbase = sp * Kc;
    const int nt = Kc >> 5;
    const int bm = byq * 128;
    const int bn = bxq * 128;

    const float* Ab = J.A + (long)b * J.aStr;
    const float* Bb = J.Bm + (long)b * J.bStr;
    const int lda = J.lda, ldb = J.ldb;
    const int mTot = J.mTot;

    const int tid = threadIdx.x;
    const int wid = tid >> 5, lane = tid & 31;
    const int wm = wid & 1, wn = wid >> 1;
    const int lr = lane >> 2, lc = lane & 3;

    const uint32_t smBase = smem_u32(dynsm);
    const int g8 = lane >> 3;
    const int r8 = lane & 7;
    const uint32_t asBase = smBase +
        (uint32_t)(((wm * 64 + (g8 & 1) * 8 + r8) * 36 + (g8 >> 1) * 4) * 4);
    const uint32_t bsBase = smBase + BOFF +
        (uint32_t)(((wn * 32 + (g8 >> 1) * 8 + r8) * 36 + (g8 & 1) * 4) * 4);

    auto issue_copy = [&](int tt, uint32_t stOff) {
        const int k0 = kbase + (tt << 5);
        const uint32_t aS = smBase + stOff;
        const uint32_t bS = smBase + BOFF + stOff;
#pragma unroll
        for (int l = 0; l < 4; l++) {
            int c = tid + (l << 8);
            int row = c >> 3, kq = (c & 7) << 2;
            uint32_t off = (uint32_t)((row * 36 + kq) * 4);
            cpa16(aS + off, Ab + (long)(bm + row) * lda + k0 + kq, (bm + row) < mTot);
            cpa16(bS + off, Bb + (long)(bn + row) * ldb + k0 + kq, true);
        }
    };

    float acc[4][4][4];
#pragma unroll
    for (int i = 0; i < 4; i++)
#pragma unroll
        for (int j = 0; j < 4; j++)
#pragma unroll
            for (int r = 0; r < 4; r++) acc[i][j][r] = 0.0f;

    issue_copy(0, 0);        CP_COMMIT();
    if (nt > 1) { issue_copy(1, STAGEB); }
    CP_COMMIT();

    uint32_t curOff = 0, nxtOff = STAGEB, thrOff = 2 * STAGEB;

    for (int t = 0; t < nt; t++) {
        CP_WAIT1();
        __syncthreads();
        if (t + 2 < nt) issue_copy(t + 2, thrOff);
        CP_COMMIT();

        const uint32_t aCur = asBase + curOff;
        const uint32_t bCur = bsBase + curOff;
#pragma unroll
        for (int ks = 0; ks < 4; ks++) {
            uint32_t af[4][4];
#pragma unroll
            for (int i = 0; i < 4; i++)
                ldm_x4(af[i], aCur + i * 2304 + ks * 32);
            uint32_t bf[4][2];
#pragma unroll
            for (int j2 = 0; j2 < 2; j2++) {
                uint32_t r4[4];
                ldm_x4(r4, bCur + j2 * 2304 + ks * 32);
                bf[2 * j2][0] = r4[0]; bf[2 * j2][1] = r4[1];
                bf[2 * j2 + 1][0] = r4[2]; bf[2 * j2 + 1][1] = r4[3];
            }
#pragma unroll
            for (int i = 0; i < 4; i++)
#pragma unroll
                for (int j = 0; j < 4; j++)
                    mma_tf32(acc[i][j], af[i], bf[j]);
        }
        uint32_t tmp = curOff; curOff = nxtOff; nxtOff = thrOff; thrOff = tmp;
    }
    __syncthreads();

    // ---- epilogue ----
    float alpha = 1.0f;
    if (J.amode != 0) {
        float f = 1.0f / (1.0f + expf(-wscal[0]));
        alpha = (J.amode == 1) ? f : (1.0f - f) * 0.5f;
    }

    float* Cb = J.C + (long)b * J.cStr;
    const int ldc = J.ldc;

    if (EPI == 1) {
        float rs[4][2];
#pragma unroll
        for (int i = 0; i < 4; i++) { rs[i][0] = 0.f; rs[i][1] = 0.f; }
#pragma unroll
        for (int j = 0; j < 4; j++) {
            int col0 = bn + wn * 32 + j * 8 + lc * 2;
            float cs0 = 0.f, cs1 = 0.f;
#pragma unroll
            for (int i = 0; i < 4; i++) {
                float e0 = __half2float(__float2half_rn(expf(acc[i][j][0])));
                float e1 = __half2float(__float2half_rn(expf(acc[i][j][1])));
                float e2 = __half2float(__float2half_rn(expf(acc[i][j][2])));
                float e3 = __half2float(__float2half_rn(expf(acc[i][j][3])));
                acc[i][j][0] = e0; acc[i][j][1] = e1;
                acc[i][j][2] = e2; acc[i][j][3] = e3;
                cs0 += e0 + e2; cs1 += e1 + e3;
                rs[i][0] += e0 + e1; rs[i][1] += e2 + e3;
            }
#pragma unroll
            for (int o = 4; o <= 16; o <<= 1) {
                cs0 += __shfl_xor_sync(0xffffffff, cs0, o);
                cs1 += __shfl_xor_sync(0xffffffff, cs1, o);
            }
            if (lane < 4) {
                atomicAdd(J.colsum + (long)b * J.nTot + col0, cs0);
                atomicAdd(J.colsum + (long)b * J.nTot + col0 + 1, cs1);
            }
        }
#pragma unroll
        for (int i = 0; i < 4; i++)
#pragma unroll
            for (int h = 0; h < 2; h++) {
                float v = rs[i][h];
                v += __shfl_xor_sync(0xffffffff, v, 1);
                v += __shfl_xor_sync(0xffffffff, v, 2);
                if (lc == 0) {
                    int r = bm + wm * 64 + i * 16 + lr + h * 8;
                    atomicAdd(J.rowsum + (long)b * mTot + r, v);
                }
            }
        // smem-staged transposed store, coalesced 8B half4 writes.
        // NOTE: batch stride cStr is in HALF units here (consumer hgemm_s matches).
        float* stg = dynsm;
        __half* Ch = (__half*)J.C + (long)b * J.cStr;
#pragma unroll
        for (int h2 = 0; h2 < 2; h2++) {
            __syncthreads();
            if ((wn >> 1) == h2) {
                int snb = wn * 32 - h2 * 64;
#pragma unroll
                for (int j = 0; j < 4; j++) {
                    int sn = snb + j * 8 + lc * 2;
#pragma unroll
                    for (int i = 0; i < 4; i++) {
                        int ml = wm * 64 + i * 16 + lr;
                        stg[sn * 132 + ml]           = acc[i][j][0];
                        stg[(sn + 1) * 132 + ml]     = acc[i][j][1];
                        stg[sn * 132 + ml + 8]       = acc[i][j][2];
                        stg[(sn + 1) * 132 + ml + 8] = acc[i][j][3];
                    }
                }
            }
            __syncthreads();
#pragma unroll
            for (int it = 0; it < 8; it++) {
                int id = tid + (it << 8);
                int row = id >> 5, m4 = (id & 31) << 2;
                float4 v = *(float4*)&stg[row * 132 + m4];
                __half2 h0 = __floats2half2_rn(v.x, v.y);
                __half2 h1 = __floats2half2_rn(v.z, v.w);
                uint2 o;
                o.x = *(uint32_t*)&h0; o.y = *(uint32_t*)&h1;
                *(uint2*)(Ch + (long)(bn + h2 * 64 + row) * ldc + bm + m4) = o;
            }
        }
    } else if (EPI == 6) {
#pragma unroll
        for (int i = 0; i < 4; i++) {
#pragma unroll
            for (int h = 0; h < 2; h++) {
                int r = bm + wm * 64 + i * 16 + lr + h * 8;
                if (r >= mTot) continue;
                float* Crow = Cb + (long)r * ldc;
#pragma unroll
                for (int j = 0; j < 4; j++) {
                    int col0 = bn + wn * 32 + j * 8 + lc * 2;
                    atomicAdd(Crow + col0,     alpha * acc[i][j][h * 2 + 0]);
                    atomicAdd(Crow + col0 + 1, alpha * acc[i][j][h * 2 + 1]);
                }
            }
        }
    } else {
#pragma unroll
        for (int i = 0; i < 4; i++) {
#pragma unroll
            for (int h = 0; h < 2; h++) {
                int r = bm + wm * 64 + i * 16 + lr + h * 8;
                if (r >= mTot) continue;
                float* Crow = Cb + (long)r * ldc;
#pragma unroll
                for (int j = 0; j < 4; j++) {
                    int col0 = bn + wn * 32 + j * 8 + lc * 2;
                    float v0 = acc[i][j][h * 2 + 0];
                    float v1 = acc[i][j][h * 2 + 1];
                    if (EPI == 2) {
                        v0 = alpha * (v0 + bias[col0]);
                        v1 = alpha * (v1 + bias[col0 + 1]);
                    }
                    if (RND) { v0 = to_tf32(v0); v1 = to_tf32(v1); }
                    float2 o; o.x = v0; o.y = v1;
                    *(float2*)(Crow + col0) = o;
                }
            }
        }
    }
}

// ================= fp16 symmetric S-GEMM (BK=64, m16n8k16) =================
// St[c][c'] += cinv'[c] * sum_k E[c][k] * (rinv'[k] * E[c'][k]);  E fp16,
// rinv' = 1024*rinv (fp16), cinv' = cinv/1024 (fp32 mscale).
// A/B strides in HALF units. Triangular decode; off-diag tiles emit transpose too.
__global__ void __launch_bounds__(256, 2) hgemm_s(Jobs jobs)
{
    extern __shared__ float dynsm[];

    int q = blockIdx.x;
    int ji = 0;
    if (q >= jobs.off[1]) ji = 1;
    if (q >= jobs.off[2]) ji = 2;
    q -= jobs.off[ji];
    const Job J = jobs.j[ji];

    const int b = blockIdx.z;
    const int Kc = J.kTot / J.splits;
    int sp = q / J.gx;
    int tri = q % J.gx;
    const int T = J.nTot >> 7;
    int by = 0;
    while (tri >= T - by) { tri -= (T - by); by++; }
    const int byq = by, bxq = by + tri;
    const int kbase = sp * Kc;
    const int nt = Kc >> 6;
    const int bm = byq * 128;
    const int bn = bxq * 128;

    const __half* Ab = (const __half*)J.A + (long)b * J.aStr;
    const __half* Bb = (const __half*)J.Bm + (long)b * J.bStr;
    const __half2* ksc2 = (const __half2*)((const __half*)J.kscale + (long)b * J.kTot);
    const int lda = J.lda, ldb = J.ldb;

    const int tid = threadIdx.x;
    const int wid = tid >> 5, lane = tid & 31;
    const int wm = wid & 1, wn = wid >> 1;
    const int lr = lane >> 2, lc = lane & 3;

    const uint32_t smBase = smem_u32(dynsm);
    const int g8 = lane >> 3;
    const int r8 = lane & 7;
    // rows stride 72 halves (144B); A frag matrices (m,k0),(m+8,k0),(m,k8),(m+8,k8)
    const uint32_t asBase = smBase +
        (uint32_t)(((wm * 64 + (g8 & 1) * 8 + r8) * 72 + (g8 >> 1) * 8) * 2);
    // B paired frag matrices (n,k0),(n,k8),(n+8,k0),(n+8,k8)
    const uint32_t bsBase = smBase + BOFF +
        (uint32_t)(((wn * 32 + (g8 >> 1) * 8 + r8) * 72 + (g8 & 1) * 8) * 2);

    auto issue_copy = [&](int tt, uint32_t stOff) {
        const int k0 = kbase + (tt << 6);
        const uint32_t aS = smBase + stOff;
        const uint32_t bS = smBase + BOFF + stOff;
#pragma unroll
        for (int l = 0; l < 4; l++) {
            int c = tid + (l << 8);
            int row = c >> 3, kq = (c & 7) << 3;      // 8 halves per 16B chunk
            uint32_t off = (uint32_t)(row * 144 + kq * 2);
            cpa16(aS + off, Ab + (long)(bm + row) * lda + k0 + kq, true);
            cpa16(bS + off, Bb + (long)(bn + row) * ldb + k0 + kq, true);
        }
    };

    float acc[4][4][4];
#pragma unroll
    for (int i = 0; i < 4; i++)
#pragma unroll
        for (int j = 0; j < 4; j++)
#pragma unroll
            for (int r = 0; r < 4; r++) acc[i][j][r] = 0.0f;

    issue_copy(0, 0);        CP_COMMIT();
    if (nt > 1) { issue_copy(1, STAGEB); }
    CP_COMMIT();

    uint32_t curOff = 0, nxtOff = STAGEB, thrOff = 2 * STAGEB;

    for (int t = 0; t < nt; t++) {
        CP_WAIT1();
        __syncthreads();
        if (t + 2 < nt) issue_copy(t + 2, thrOff);
        CP_COMMIT();

        const uint32_t aCur = asBase + curOff;
        const uint32_t bCur = bsBase + curOff;
        const int kh = (kbase + (t << 6)) >> 1;    // half2 index base
#pragma unroll
        for (int ks = 0; ks < 4; ks++) {
            uint32_t af[4][4];
#pragma unroll
            for (int i = 0; i < 4; i++)
                ldm_x4(af[i], aCur + i * 2304 + ks * 32);
            __half2 slo = ksc2[kh + ks * 8 + lc];
            __half2 shi = ksc2[kh + ks * 8 + 4 + lc];
            uint32_t bf[4][2];
#pragma unroll
            for (int j2 = 0; j2 < 2; j2++) {
                uint32_t r4[4];
                ldm_x4(r4, bCur + j2 * 2304 + ks * 32);
                r4[0] = h2mul(r4[0], slo);
                r4[1] = h2mul(r4[1], shi);
                r4[2] = h2mul(r4[2], slo);
                r4[3] = h2mul(r4[3], shi);
                bf[2 * j2][0] = r4[0]; bf[2 * j2][1] = r4[1];
                bf[2 * j2 + 1][0] = r4[2]; bf[2 * j2 + 1][1] = r4[3];
            }
#pragma unroll
            for (int i = 0; i < 4; i++)
#pragma unroll
                for (int j = 0; j < 4; j++)
                    mma_f16(acc[i][j], af[i], bf[j]);
        }
        uint32_t tmp = curOff; curOff = nxtOff; nxtOff = thrOff; thrOff = tmp;
    }
    __syncthreads();

    // ---- EPI5 epilogue ----
    float* Cb = J.C + (long)b * J.cStr;
    const int ldc = J.ldc;
    const float* msc = J.mscale + (long)b * J.mTot;
#pragma unroll
    for (int i = 0; i < 4; i++) {
        int r0 = bm + wm * 64 + i * 16 + lr;
        float s0 = msc[r0];
        float s1 = msc[r0 + 8];
#pragma unroll
        for (int j = 0; j < 4; j++) {
            int col0 = bn + wn * 32 + j * 8 + lc * 2;
            atomicAdd(Cb + (long)r0 * ldc + col0,           acc[i][j][0] * s0);
            atomicAdd(Cb + (long)r0 * ldc + col0 + 1,       acc[i][j][1] * s0);
            atomicAdd(Cb + (long)(r0 + 8) * ldc + col0,     acc[i][j][2] * s1);
            atomicAdd(Cb + (long)(r0 + 8) * ldc + col0 + 1, acc[i][j][3] * s1);
        }
    }
    if (bxq != byq) {
#pragma unroll
        for (int j = 0; j < 4; j++) {
            int n0 = bn + wn * 32 + j * 8 + lc * 2;
            float sn0 = msc[n0];
            float sn1 = msc[n0 + 1];
#pragma unroll
            for (int i = 0; i < 4; i++) {
                int r0 = bm + wm * 64 + i * 16 + lr;
                atomicAdd(Cb + (long)n0 * ldc + r0,           acc[i][j][0] * sn0);
                atomicAdd(Cb + (long)(n0 + 1) * ldc + r0,     acc[i][j][1] * sn1);
                atomicAdd(Cb + (long)n0 * ldc + r0 + 8,       acc[i][j][2] * sn0);
                atomicAdd(Cb + (long)(n0 + 1) * ldc + r0 + 8, acc[i][j][3] * sn1);
            }
        }
    }
}

// ---------------- fused utility kernels ----------------
struct PrepArgs {
    const float* src[11];
    float* dst[11];
    long n[11];
    const float *W1, *W2, *b1, *b2;
    float *W12, *bsum, *zero;
    long zn;
};
__global__ void prep(PrepArgs a) {
    int seg = blockIdx.y;
    long i0 = (long)blockIdx.x * blockDim.x + threadIdx.x;
    long stride = (long)gridDim.x * blockDim.x;
    if (seg < 11) {
        const float4* s = (const float4*)a.src[seg];
        float4* d = (float4*)a.dst[seg];
        long n4 = a.n[seg] >> 2;
        for (long i = i0; i < n4; i += stride) d[i] = rnd4(s[i]);
    } else if (seg == 11) {
        float4* z = (float4*)a.zero;
        long n4 = a.zn >> 2;
        float4 v = make_float4(0.f, 0.f, 0.f, 0.f);
        for (long i = i0; i < n4; i += stride) z[i] = v;
    } else if (seg == 12) {
        float4* d = (float4*)a.W12;
        for (long i = i0; i < 131072L; i += stride) {
            long base = i << 2;
            int n = (int)(base >> 10), k = (int)(base & 1023);
            float4 v = (k < 512) ? *(const float4*)(a.W1 + (long)n * 512 + k)
                                 : *(const float4*)(a.W2 + (long)n * 512 + k - 512);
            d[i] = rnd4(v);
        }
    } else {
        for (long i = i0; i < 512; i += stride) a.bsum[i] = a.b1[i] + a.b2[i];
    }
}

// seg0: stats recips (R->fp16*1024, C->fp32/1024); seg1: ATT prefill; seg2: A3 = bp3
__global__ void fuse2(float* stats,
                      __half* r1h, __half* r2h, __half* r4h,
                      const float* __restrict__ x3, const float* __restrict__ bsum,
                      const float* __restrict__ bp4, const float* __restrict__ wscal,
                      float* __restrict__ ATT,
                      const float* __restrict__ bp3, float* __restrict__ A3)
{
    int seg = blockIdx.y;
    long i0 = (long)blockIdx.x * blockDim.x + threadIdx.x;
    long stride = (long)gridDim.x * blockDim.x;
    if (seg == 0) {
        for (long i = i0; i < 88064; i += stride) {
            float r = 1.0f / stats[i];
            if (i < 36864)       r1h[i] = __float2half(r * 1024.0f);
            else if (i < 38912)  stats[i] = r * 0.0009765625f;
            else if (i < 48128)  r2h[i - 38912] = __float2half(r * 1024.0f);
            else if (i < 50176)  stats[i] = r * 0.0009765625f;
            else if (i < 87040)  r4h[i - 50176] = __float2half(r * 1024.0f);
            else                 stats[i] = r * 0.0009765625f;
        }
    } else if (seg == 1) {
        float f = 1.0f / (1.0f + expf(-wscal[0]));
        float other = (1.0f - f) * 0.5f;
        for (long i = i0; i < (long)BB * N3_ * D2_; i += stride) {
            int col = (int)(i & (D2_ - 1));
            ATT[i] = x3[i] + other * bsum[col] + f * bp4[col];
        }
    } else {
        for (long i = i0; i < (long)BB * N2_ * D1_; i += stride)
            A3[i] = bp3[(int)(i & (D1_ - 1))];
    }
}

// RA -> fp16 1024/x ; CA -> fp32 (1/x)/1024
__global__ void recip2(float* ra, __half* rah, int nr, float* ca, int nc) {
    int i = blockIdx.x * blockDim.x + threadIdx.x;
    if (i < nr) rah[i] = __float2half(1024.0f / ra[i]);
    else if (i < nr + nc) { int j = i - nr; ca[j] = (1.0f / ca[j]) * 0.0009765625f; }
}

// LN over last dim + fused out-prefill
__global__ void ln_rows(const float* __restrict__ X, const float* __restrict__ g,
                        const float* __restrict__ bb, float* __restrict__ Y, int C,
                        const float* __restrict__ bfc2, float* __restrict__ outp)
{
    long row = blockIdx.x;
    const float* x = X + row * C;
    float s = 0.f, s2 = 0.f;
    for (int c = threadIdx.x; c < C; c += blockDim.x) { float v = x[c]; s += v; s2 += v * v; }
    __shared__ float sh1[32], sh2[32];
    int lane = threadIdx.x & 31, wid = threadIdx.x >> 5;
#pragma unroll
    for (int o = 16; o; o >>= 1) {
        s  += __shfl_down_sync(0xffffffff, s,  o);
        s2 += __shfl_down_sync(0xffffffff, s2, o);
    }
    if (!lane) { sh1[wid] = s; sh2[wid] = s2; }
    __syncthreads();
    if (threadIdx.x == 0) {
        float a = 0.f, c2 = 0.f;
        int nw = blockDim.x >> 5;
        for (int i = 0; i < nw; i++) { a += sh1[i]; c2 += sh2[i]; }
        float mean = a / C;
        float var  = c2 / C - mean * mean;
        sh1[0] = mean; sh2[0] = rsqrtf(var + 1e-5f);
    }
    __syncthreads();
    float mean = sh1[0], rstd = sh2[0];
    for (int c = threadIdx.x; c < C; c += blockDim.x) {
        float v = x[c];
        Y[row * C + c] = to_tf32((v - mean) * rstd * g[c] + bb[c]);
        outp[row * C + c] = v + bfc2[c];
    }
}

__global__ void __launch_bounds__(256) dwconv_ln_gelu(
    const float* __restrict__ H, const float* __restrict__ Wdw,
    const float* __restrict__ bdw, const float* __restrict__ g,
    const float* __restrict__ bt, float* __restrict__ AX)
{
    const int n = blockIdx.x;
    const int b = blockIdx.y;
    const int y = n / 24, x = n % 24;
    const float* Hb = H + (long)b * 576 * 2048;
    const int tid = threadIdx.x;

    float v[8];
    float s = 0.f, s2 = 0.f;
#pragma unroll
    for (int it = 0; it < 8; it++) {
        int c = tid + it * 256;
        float a = Hb[(long)n * 2048 + c] + bdw[c];
#pragma unroll
        for (int ky = 0; ky < 3; ky++) {
            int yy = y + ky - 1;
            if (yy < 0 || yy > 23) continue;
#pragma unroll
            for (int kx = 0; kx < 3; kx++) {
                int xx = x + kx - 1;
                if (xx < 0 || xx > 23) continue;
                a += Wdw[c * 9 + ky * 3 + kx] * Hb[(long)(yy * 24 + xx) * 2048 + c];
            }
        }
        v[it] = a; s += a; s2 += a * a;
    }
    __shared__ float sh1[32], sh2[32];
    int lane = tid & 31, wid = tid >> 5;
#pragma unroll
    for (int o = 16; o; o >>= 1) {
        s  += __shfl_down_sync(0xffffffff, s,  o);
        s2 += __shfl_down_sync(0xffffffff, s2, o);
    }
    if (!lane) { sh1[wid] = s; sh2[wid] = s2; }
    __syncthreads();
    if (tid == 0) {
        float a = 0.f, c2 = 0.f;
        for (int i = 0; i < 8; i++) { a += sh1[i]; c2 += sh2[i]; }
        float mean = a / 2048.0f;
        float var  = c2 / 2048.0f - mean * mean;
        sh1[0] = mean; sh2[0] = rsqrtf(var + 1e-5f);
    }
    __syncthreads();
    float mean = sh1[0], rstd = sh2[0];
    float* out = AX + ((long)b * 576 + n) * 2048;
#pragma unroll
    for (int it = 0; it < 8; it++) {
        int c = tid + it * 256;
        float t = (v[it] - mean) * rstd * g[c] + bt[c];
        out[c] = to_tf32(0.5f * t * (1.0f + erff(t * 0.70710678118654752f)));
    }
}

// ---------------- host orchestration ----------------
#define SET_SMEM(k) cudaFuncSetAttribute(k, cudaFuncAttributeMaxDynamicSharedMemorySize, SMEM_DYN)

static Job mk_job(const float* A, long aStr, int lda,
                  const float* B, long bStr, int ldb,
                  float* C, long cStr, int ldc,
                  int m, int n, int k, int splits, int gx, int gy, int amode,
                  const float* ksc = nullptr, const float* msc = nullptr,
                  float* rsum = nullptr, float* csum = nullptr) {
    Job J;
    J.A = A; J.Bm = B; J.C = C;
    J.aStr = aStr; J.bStr = bStr; J.cStr = cStr;
    J.lda = lda; J.ldb = ldb; J.ldc = ldc;
    J.mTot = m; J.nTot = n; J.kTot = k; J.splits = splits; J.gx = gx; J.gy = gy;
    J.amode = amode;
    J.kscale = ksc; J.mscale = msc; J.rowsum = rsum; J.colsum = csum;
    return J;
}

extern "C" void kernel_launch(void* const* d_in, const int* in_sizes, int n_in,
                              void* d_out, int out_size)
{
    const float* x      = (const float*)d_in[0];
    const float* x2     = (const float*)d_in[1];
    const float* x3     = (const float*)d_in[2];
    const float* W_lin  = (const float*)d_in[3];
    const float* W_lin2 = (const float*)d_in[4];
    const float* W_lin3 = (const float*)d_in[5];
    const float* W_lin4 = (const float*)d_in[6];
    const float* w      = (const float*)d_in[7];
    const float* Wp1 = (const float*)d_in[8];  const float* bp1 = (const float*)d_in[9];
    const float* Wp2 = (const float*)d_in[10]; const float* bp2 = (const float*)d_in[11];
    const float* Wp3 = (const float*)d_in[12]; const float* bp3 = (const float*)d_in[13];
    const float* Wp4 = (const float*)d_in[14]; const float* bp4 = (const float*)d_in[15];
    const float* g_norm = (const float*)d_in[16]; const float* b_norm = (const float*)d_in[17];
    const float* Wfc1 = (const float*)d_in[18];   const float* bfc1  = (const float*)d_in[19];
    const float* Wdw  = (const float*)d_in[20];   const float* bdw   = (const float*)d_in[21];
    const float* g_ln1 = (const float*)d_in[22];  const float* b_ln1 = (const float*)d_in[23];
    const float* Wfc2 = (const float*)d_in[24];   const float* bfc2  = (const float*)d_in[25];

    float* pool = nullptr;
    cudaGetSymbolAddress((void**)&pool, g_pool);

    SET_SMEM((tgemm<1,false>));
    SET_SMEM((tgemm<0,true>));
    SET_SMEM((tgemm<2,false>));
    SET_SMEM((tgemm<6,false>));
    SET_SMEM(hgemm_s);

    // 0) fused prologue
    {
        PrepArgs pa;
        const float* srcs[11] = { x, x2, x3, W_lin, W_lin2, W_lin3, W_lin4, Wp3, Wp4, Wfc1, Wfc2 };
        long offs[11] = { OFF_XR, OFF_X2R, OFF_X3R, OFF_WL, OFF_WL2, OFF_WL3, OFF_WL4,
                          OFF_WP3R, OFF_WP4R, OFF_WF1, OFF_WF2 };
        long ns[11] = { (long)BB*N1_*D0_, (long)BB*N2_*D1_, (long)BB*N3_*D2_,
                        (long)D2_*D0_, (long)D2_*D1_, (long)D1_*D0_, (long)D2_*D1_,
                        (long)D1_*D1_, (long)D2_*D2_, (long)DH_*D2_, (long)D2_*DH_ };
        for (int i = 0; i < 11; i++) { pa.src[i] = srcs[i]; pa.dst[i] = pool + offs[i]; pa.n[i] = ns[i]; }
        pa.W1 = Wp1; pa.W2 = Wp2; pa.b1 = bp1; pa.b2 = bp2;
        pa.W12 = pool + OFF_WP12; pa.bsum = pool + OFF_BSUM;
        pa.zero = pool; pa.zn = ZERO_CNT;
        prep<<<dim3(512, 14), 256>>>(pa);
    }
    const float* xr  = pool + OFF_XR;
    const float* x2r = pool + OFF_X2R;
    const float* x3r = pool + OFF_X3R;

    // 1-3) Et1+Et2+Et4 (EPI1: exp -> fp16 transposed; cStr in HALF units)
    {
        Jobs js;
        js.j[0] = mk_job(xr, (long)N1_*D0_, D0_, pool+OFF_WL, 0L, D0_,
                         pool+OFF_ET1, (long)D2_*N1_, N1_, N1_, D2_, D0_, 1, 4, 72, 0,
                         nullptr, nullptr, pool+OFF_R1, pool+OFF_C1);
        js.j[1] = mk_job(x2r, (long)N2_*D1_, D1_, pool+OFF_WL2, 0L, D1_,
                         pool+OFF_ET2, (long)D2_*N2_, N2_, N2_, D2_, D1_, 1, 4, 18, 0,
                         nullptr, nullptr, pool+OFF_R2, pool+OFF_C2);
        js.j[2] = mk_job(xr, (long)N1_*D0_, D0_, pool+OFF_WL3, 0L, D0_,
                         pool+OFF_ET4, (long)D1_*N1_, N1_, N1_, D1_, D0_, 1, 2, 72, 0,
                         nullptr, nullptr, pool+OFF_R4, pool+OFF_C4);
        js.off[0] = 0; js.off[1] = 288; js.off[2] = 360; js.off[3] = 504;
        tgemm<1,false><<<dim3(504,1,BB), 256, SMEM_DYN>>>(js, nullptr, nullptr);
    }

    // 4) fused: recips (fp16 scaled R, fp32 /1024 C) + ATT prefill + A3 prefill
    fuse2<<<dim3(1024, 3), 256>>>(pool,
        (__half*)(pool + OFF_R1H), (__half*)(pool + OFF_R2H), (__half*)(pool + OFF_R4H),
        x3, pool+OFF_BSUM, bp4, w, pool+OFF_ATT, bp3, pool+OFF_A3);

    // 5-7) St1+St2+St3 (fp16 symmetric, strides in HALF units)
    {
        Jobs js;
        js.j[0] = mk_job(pool+OFF_ET1, (long)D2_*N1_, N1_, pool+OFF_ET1, (long)D2_*N1_, N1_,
                         pool+OFF_ST12, (long)2*D2_*D2_, D2_, D2_, D2_, N1_, 8, 10, 1, 0,
                         (const float*)(pool+OFF_R1H), pool+OFF_C1);
        js.j[1] = mk_job(pool+OFF_ET2, (long)D2_*N2_, N2_, pool+OFF_ET2, (long)D2_*N2_, N2_,
                         pool+OFF_ST12 + (long)D2_*D2_, (long)2*D2_*D2_, D2_, D2_, D2_, N2_, 4, 10, 1, 0,
                         (const float*)(pool+OFF_R2H), pool+OFF_C2);
        js.j[2] = mk_job(pool+OFF_ET4, (long)D1_*N1_, N1_, pool+OFF_ET4, (long)D1_*N1_, N1_,
                         pool+OFF_ST3, (long)D1_*D1_, D1_, D1_, D1_, N1_, 8, 3, 1, 0,
                         (const float*)(pool+OFF_R4H), pool+OFF_C4);
        js.off[0] = 0; js.off[1] = 80; js.off[2] = 120; js.off[3] = 144;
        hgemm_s<<<dim3(144,1,BB), 256, SMEM_DYN>>>(js);
    }

    // 8+12) T12 and T3 (EPI0 RND; St operands truncate in MMA)
    {
        Jobs js;
        js.j[0] = mk_job(x3r, (long)N3_*D2_, D2_, pool+OFF_ST12, (long)2*D2_*D2_, D2_,
                         pool+OFF_T12, (long)N3_*2*D2_, 2*D2_, N3_, 2*D2_, D2_, 1, 8, 5, 0);
        js.j[1] = mk_job(x2r, (long)N2_*D1_, D1_, pool+OFF_ST3, (long)D1_*D1_, D1_,
                         pool+OFF_T3, (long)N2_*D1_, D1_, N2_, D1_, D1_, 1, 2, 18, 0);
        js.j[2] = js.j[1];
        js.off[0] = 0; js.off[1] = 40; js.off[2] = 76; js.off[3] = 76;
        tgemm<0,true><<<dim3(76,1,BB), 256, SMEM_DYN>>>(js, nullptr, nullptr);
    }

    // 9+13) ATT += other*(T12@Wp12^T)  AND  A3 += T3@Wp3^T  (EPI6)
    {
        Jobs js;
        js.j[0] = mk_job(pool+OFF_T12, (long)N3_*2*D2_, 2*D2_, pool+OFF_WP12, 0L, 2*D2_,
                         pool+OFF_ATT, (long)N3_*D2_, D2_, N3_, D2_, 2*D2_, 2, 4, 5, 2);
        js.j[1] = mk_job(pool+OFF_T3, (long)N2_*D1_, D1_, pool+OFF_WP3R, 0L, D1_,
                         pool+OFF_A3, (long)N2_*D1_, D1_, N2_, D1_, D1_, 1, 2, 18, 0);
        js.j[2] = js.j[1];
        js.off[0] = 0; js.off[1] = 40; js.off[2] = 76; js.off[3] = 76;
        tgemm<6,false><<<dim3(76,1,BB), 256, SMEM_DYN>>>(js, nullptr, w);
    }

    // 14) EtA (EPI1 -> fp16; cStr in HALF units)
    {
        Jobs js;
        js.j[0] = mk_job(pool+OFF_A3, (long)N2_*D1_, D1_, pool+OFF_WL4, 0L, D1_,
                         pool+OFF_ETA, (long)D2_*N2_, N2_, N2_, D2_, D1_, 1, 4, 18, 0,
                         nullptr, nullptr, pool+OFF_RA, pool+OFF_CA);
        js.j[1] = js.j[0]; js.j[2] = js.j[0];
        js.off[0] = 0; js.off[1] = 72; js.off[2] = 72; js.off[3] = 72;
        tgemm<1,false><<<dim3(72,1,BB), 256, SMEM_DYN>>>(js, nullptr, nullptr);
    }
    // 15) RA->fp16*1024, CA->fp32/1024
    recip2<<<(11264 + 255) / 256, 256>>>(pool + OFF_RA, (__half*)(pool + OFF_RAH),
                                         BB * N2_, pool + OFF_CA, BB * D2_);
    // 16) St4 (fp16 symmetric)
    {
        Jobs js;
        js.j[0] = mk_job(pool+OFF_ETA, (long)D2_*N2_, N2_, pool+OFF_ETA, (long)D2_*N2_, N2_,
                         pool+OFF_ST4, (long)D2_*D2_, D2_, D2_, D2_, N2_, 4, 10, 1, 0,
                         (const float*)(pool+OFF_RAH), pool+OFF_CA);
        js.j[1] = js.j[0]; js.j[2] = js.j[0];
        js.off[0] = 0; js.off[1] = 40; js.off[2] = 40; js.off[3] = 40;
        hgemm_s<<<dim3(40,1,BB), 256, SMEM_DYN>>>(js);
    }
    // 17a) T = x3 @ St4
    {
        Jobs js;
        js.j[0] = mk_job(x3r, (long)N3_*D2_, D2_, pool+OFF_ST4, (long)D2_*D2_, D2_,
                         pool+OFF_T, (long)N3_*D2_, D2_, N3_, D2_, D2_, 1, 4, 5, 0);
        js.j[1] = js.j[0]; js.j[2] = js.j[0];
        js.off[0] = 0; js.off[1] = 20; js.off[2] = 20; js.off[3] = 20;
        tgemm<0,true><<<dim3(20,1,BB), 256, SMEM_DYN>>>(js, nullptr, nullptr);
    }
    // 17b) ATT += f*(T @ Wp4^T)  (EPI6, split-K 2)
    {
        Jobs js;
        js.j[0] = mk_job(pool+OFF_T, (long)N3_*D2_, D2_, pool+OFF_WP4R, 0L, D2_,
                         pool+OFF_ATT, (long)N3_*D2_, D2_, N3_, D2_, D2_, 2, 4, 5, 1);
        js.j[1] = js.j[0]; js.j[2] = js.j[0];
        js.off[0] = 0; js.off[1] = 40; js.off[2] = 40; js.off[3] = 40;
        tgemm<6,false><<<dim3(40,1,BB), 256, SMEM_DYN>>>(js, nullptr, w);
    }

    // 19) AN = tf32(LN(ATT)) + out prefill
    ln_rows<<<BB * N3_, 256>>>(pool + OFF_ATT, g_norm, b_norm, pool + OFF_AN, D2_,
                               bfc2, (float*)d_out);

    // 20) H = AN @ Wfc1^T + bfc1
    {
        Jobs js;
        js.j[0] = mk_job(pool+OFF_AN, (long)N3_*D2_, D2_, pool+OFF_WF1, 0L, D2_,
                         pool+OFF_H, (long)N3_*DH_, DH_, N3_, DH_, D2_, 1, 16, 5, 0);
        js.j[1] = js.j[0]; js.j[2] = js.j[0];
        js.off[0] = 0; js.off[1] = 80; js.off[2] = 80; js.off[3] = 80;
        tgemm<2,false><<<dim3(80,1,BB), 256, SMEM_DYN>>>(js, bfc1, nullptr);
    }

    // 21) AX = tf32(gelu(LN(dwconv(H)+bdw+H)))
    dwconv_ln_gelu<<<dim3(N3_, BB), 256>>>(pool + OFF_H, Wdw, bdw, g_ln1, b_ln1, pool + OFF_AX);

    // 22) out += AX @ Wfc2^T  (EPI6, split-K 4)
    {
        Jobs js;
        js.j[0] = mk_job(pool+OFF_AX, (long)N3_*DH_, DH_, pool+OFF_WF2, 0L, DH_,
                         (float*)d_out, (long)N3_*D2_, D2_, N3_, D2_, DH_, 4, 4, 5, 0);
        js.j[1] = js.j[0]; js.j[2] = js.j[0];
        js.off[0] = 0; js.off[1] = 80; js.off[2] = 80; js.off[3] = 80;
        tgemm<6,false><<<dim3(80,1,BB), 256, SMEM_DYN>>>(js, nullptr, nullptr);
    }
}

// round 15
// speedup vs baseline: 2.3171x; 1.0759x over previous
#include <cuda_runtime.h>
#include <cuda_fp16.h>
#include <math.h>
#include <stdint.h>

// ---------------- problem dims ----------------
#define BB   4
#define N1_  9216
#define N2_  2304
#define N3_  576
#define D0_  128
#define D1_  256
#define D2_  512
#define DH_  2048

// ---------------- scratch pool (floats) ----------------
#define OFF_R1   0L
#define OFF_C1   36864L
#define OFF_R2   38912L
#define OFF_C2   48128L
#define OFF_R4   50176L
#define OFF_C4   87040L
#define OFF_RA   88064L
#define OFF_CA   97280L
#define OFF_ST12 99328L            // [B][1024][512] fp32
#define OFF_ST3  2196480L          // [B][256][256]  fp32
#define OFF_ST4  2458624L          // [B][512][512]  fp32
#define ZERO_CNT 3507200L
#define OFF_ET1  3507200L          // fp16 [B][512][9216]
#define OFF_ET2  22381568L         // fp16
#define OFF_ET4  27100160L         // fp16
#define OFF_ETA  36537344L         // fp16; earlier reused as T12 [B][576][1024] fp32
#define OFF_T    41255936L         // Wp12+bsum early; T later
#define OFF_T3   42435584L
#define OFF_A3   44794880L
#define OFF_ATT  47154176L
#define OFF_AN   48333824L
#define OFF_H    49513472L
#define OFF_AX   54232064L
// fp16 operand copies (in old XR slot) + tf32 copies
#define OFF_XH   58950656L         // fp16 x: BB*N1*D0 halves = 2359296 float slots
#define OFF_X2H  61309952L         // fp16 x2: 1179648 float slots
#define OFF_X2R  63669248L
#define OFF_X3R  66028544L
#define OFF_WLH  67208192L         // fp16 W_lin
#define OFF_WL2H 67273728L         // fp16 W_lin2
#define OFF_WL3H 67404800L         // fp16 W_lin3
#define OFF_WL4  67437568L         // tf32 (EtA path)
#define OFF_WP3R 67568640L
#define OFF_WP4R 67634176L
#define OFF_WF1  67896320L
#define OFF_WF2  68944896L
// fp16 scaled row-recip arrays
#define OFF_R1H  69993472L
#define OFF_R2H  70011904L
#define OFF_R4H  70016512L
#define OFF_RAH  70034944L
#define POOL_SZ  70039552L

#define OFF_T12   OFF_ETA
#define OFF_WP12  OFF_T
#define OFF_BSUM  (OFF_T + 524288L)

__device__ float g_pool[POOL_SZ];

// float kernel: 3 stages x (A,B) x (128 rows x 36 floats)
// half kernel:  3 stages x (A,B) x (128 rows x 72 halves)  -> same byte counts
#define STAGEB  18432u
#define BOFF    55296u
#define SMEM_DYN 110592

// ---------------- job table ----------------
struct Job {
    const float *A, *Bm;
    float *C;
    long aStr, bStr, cStr;   // element units of their respective dtypes
    int lda, ldb, ldc;
    int mTot, nTot, kTot, splits, gx, gy, amode;
    const float *kscale, *mscale;
    float *rowsum, *colsum;
};
struct Jobs { Job j[3]; int off[4]; };

// ---------------- helpers ----------------
__device__ __forceinline__ uint32_t smem_u32(const void* p) {
    uint32_t a;
    asm("{ .reg .u64 t; cvta.to.shared.u64 t, %1; cvt.u32.u64 %0, t; }" : "=r"(a) : "l"(p));
    return a;
}
__device__ __forceinline__ float to_tf32(float x) {
    float y;
    asm("cvt.rna.tf32.f32 %0, %1;" : "=f"(y) : "f"(x));
    return y;
}
__device__ __forceinline__ float4 rnd4(float4 v) {
    v.x = to_tf32(v.x); v.y = to_tf32(v.y); v.z = to_tf32(v.z); v.w = to_tf32(v.w);
    return v;
}
__device__ __forceinline__ void mma_tf32(float* d, const uint32_t* a, const uint32_t* bf) {
    asm volatile(
        "mma.sync.aligned.m16n8k8.row.col.f32.tf32.tf32.f32 "
        "{%0,%1,%2,%3}, {%4,%5,%6,%7}, {%8,%9}, {%0,%1,%2,%3};"
        : "+f"(d[0]), "+f"(d[1]), "+f"(d[2]), "+f"(d[3])
        : "r"(a[0]), "r"(a[1]), "r"(a[2]), "r"(a[3]), "r"(bf[0]), "r"(bf[1]));
}
__device__ __forceinline__ void mma_f16(float* d, const uint32_t* a, const uint32_t* bf) {
    asm volatile(
        "mma.sync.aligned.m16n8k16.row.col.f32.f16.f16.f32 "
        "{%0,%1,%2,%3}, {%4,%5,%6,%7}, {%8,%9}, {%0,%1,%2,%3};"
        : "+f"(d[0]), "+f"(d[1]), "+f"(d[2]), "+f"(d[3])
        : "r"(a[0]), "r"(a[1]), "r"(a[2]), "r"(a[3]), "r"(bf[0]), "r"(bf[1]));
}
__device__ __forceinline__ void ldm_x4(uint32_t* r, uint32_t addr) {
    asm volatile("ldmatrix.sync.aligned.m8n8.x4.shared.b16 {%0,%1,%2,%3}, [%4];"
        : "=r"(r[0]), "=r"(r[1]), "=r"(r[2]), "=r"(r[3]) : "r"(addr));
}
__device__ __forceinline__ void cpa16(uint32_t dst, const void* src, bool valid) {
    int sz = valid ? 16 : 0;
    asm volatile("cp.async.cg.shared.global [%0], [%1], 16, %2;"
        :: "r"(dst), "l"(src), "r"(sz) : "memory");
}
__device__ __forceinline__ uint32_t h2mul(uint32_t a, __half2 s) {
    __half2 v = __hmul2(*(__half2*)&a, s);
    return *(uint32_t*)&v;
}
#define CP_COMMIT() asm volatile("cp.async.commit_group;" ::: "memory")
#define CP_WAIT1()  asm volatile("cp.async.wait_group 1;" ::: "memory")

// ================= fp32/tf32 NT GEMM (job-batched, 3-stage cp.async, BK=32) ======
// EPI 0: C = acc (RND rounds)   EPI 1: exp -> fp16; Et[n][m] (half; cStr in HALF units)
// EPI 2: C = alpha*(acc+bias)   EPI 6: atomicAdd(C, alpha*acc)
template<int EPI, bool RND>
__global__ void __launch_bounds__(256, 2) tgemm(
    Jobs jobs, const float* __restrict__ bias, const float* __restrict__ wscal)
{
    extern __shared__ float dynsm[];

    int q = blockIdx.x;
    int ji = 0;
    if (q >= jobs.off[1]) ji = 1;
    if (q >= jobs.off[2]) ji = 2;
    q -= jobs.off[ji];
    const Job J = jobs.j[ji];

    const int b = blockIdx.z;
    const int Kc = J.kTot / J.splits;
    const int gxy = J.gx * J.gy;
    int sp = q / gxy;
    int r0q = q % gxy;
    int bxq = r0q % J.gx, byq = r0q / J.gx;
    const int kbase = sp * Kc;
    const int nt = Kc >> 5;
    const int bm = byq * 128;
    const int bn = bxq * 128;

    const float* Ab = J.A + (long)b * J.aStr;
    const float* Bb = J.Bm + (long)b * J.bStr;
    const int lda = J.lda, ldb = J.ldb;
    const int mTot = J.mTot;

    const int tid = threadIdx.x;
    const int wid = tid >> 5, lane = tid & 31;
    const int wm = wid & 1, wn = wid >> 1;
    const int lr = lane >> 2, lc = lane & 3;

    const uint32_t smBase = smem_u32(dynsm);
    const int g8 = lane >> 3;
    const int r8 = lane & 7;
    const uint32_t asBase = smBase +
        (uint32_t)(((wm * 64 + (g8 & 1) * 8 + r8) * 36 + (g8 >> 1) * 4) * 4);
    const uint32_t bsBase = smBase + BOFF +
        (uint32_t)(((wn * 32 + (g8 >> 1) * 8 + r8) * 36 + (g8 & 1) * 4) * 4);

    auto issue_copy = [&](int tt, uint32_t stOff) {
        const int k0 = kbase + (tt << 5);
        const uint32_t aS = smBase + stOff;
        const uint32_t bS = smBase + BOFF + stOff;
#pragma unroll
        for (int l = 0; l < 4; l++) {
            int c = tid + (l << 8);
            int row = c >> 3, kq = (c & 7) << 2;
            uint32_t off = (uint32_t)((row * 36 + kq) * 4);
            cpa16(aS + off, Ab + (long)(bm + row) * lda + k0 + kq, (bm + row) < mTot);
            cpa16(bS + off, Bb + (long)(bn + row) * ldb + k0 + kq, true);
        }
    };

    float acc[4][4][4];
#pragma unroll
    for (int i = 0; i < 4; i++)
#pragma unroll
        for (int j = 0; j < 4; j++)
#pragma unroll
            for (int r = 0; r < 4; r++) acc[i][j][r] = 0.0f;

    issue_copy(0, 0);        CP_COMMIT();
    if (nt > 1) { issue_copy(1, STAGEB); }
    CP_COMMIT();

    uint32_t curOff = 0, nxtOff = STAGEB, thrOff = 2 * STAGEB;

    for (int t = 0; t < nt; t++) {
        CP_WAIT1();
        __syncthreads();
        if (t + 2 < nt) issue_copy(t + 2, thrOff);
        CP_COMMIT();

        const uint32_t aCur = asBase + curOff;
        const uint32_t bCur = bsBase + curOff;
#pragma unroll
        for (int ks = 0; ks < 4; ks++) {
            uint32_t af[4][4];
#pragma unroll
            for (int i = 0; i < 4; i++)
                ldm_x4(af[i], aCur + i * 2304 + ks * 32);
            uint32_t bf[4][2];
#pragma unroll
            for (int j2 = 0; j2 < 2; j2++) {
                uint32_t r4[4];
                ldm_x4(r4, bCur + j2 * 2304 + ks * 32);
                bf[2 * j2][0] = r4[0]; bf[2 * j2][1] = r4[1];
                bf[2 * j2 + 1][0] = r4[2]; bf[2 * j2 + 1][1] = r4[3];
            }
#pragma unroll
            for (int i = 0; i < 4; i++)
#pragma unroll
                for (int j = 0; j < 4; j++)
                    mma_tf32(acc[i][j], af[i], bf[j]);
        }
        uint32_t tmp = curOff; curOff = nxtOff; nxtOff = thrOff; thrOff = tmp;
    }
    __syncthreads();

    float alpha = 1.0f;
    if (J.amode != 0) {
        float f = 1.0f / (1.0f + expf(-wscal[0]));
        alpha = (J.amode == 1) ? f : (1.0f - f) * 0.5f;
    }

    float* Cb = J.C + (long)b * J.cStr;
    const int ldc = J.ldc;

    if (EPI == 1) {
        float rs[4][2];
#pragma unroll
        for (int i = 0; i < 4; i++) { rs[i][0] = 0.f; rs[i][1] = 0.f; }
#pragma unroll
        for (int j = 0; j < 4; j++) {
            int col0 = bn + wn * 32 + j * 8 + lc * 2;
            float cs0 = 0.f, cs1 = 0.f;
#pragma unroll
            for (int i = 0; i < 4; i++) {
                float e0 = __half2float(__float2half_rn(expf(acc[i][j][0])));
                float e1 = __half2float(__float2half_rn(expf(acc[i][j][1])));
                float e2 = __half2float(__float2half_rn(expf(acc[i][j][2])));
                float e3 = __half2float(__float2half_rn(expf(acc[i][j][3])));
                acc[i][j][0] = e0; acc[i][j][1] = e1;
                acc[i][j][2] = e2; acc[i][j][3] = e3;
                cs0 += e0 + e2; cs1 += e1 + e3;
                rs[i][0] += e0 + e1; rs[i][1] += e2 + e3;
            }
#pragma unroll
            for (int o = 4; o <= 16; o <<= 1) {
                cs0 += __shfl_xor_sync(0xffffffff, cs0, o);
                cs1 += __shfl_xor_sync(0xffffffff, cs1, o);
            }
            if (lane < 4) {
                atomicAdd(J.colsum + (long)b * J.nTot + col0, cs0);
                atomicAdd(J.colsum + (long)b * J.nTot + col0 + 1, cs1);
            }
        }
#pragma unroll
        for (int i = 0; i < 4; i++)
#pragma unroll
            for (int h = 0; h < 2; h++) {
                float v = rs[i][h];
                v += __shfl_xor_sync(0xffffffff, v, 1);
                v += __shfl_xor_sync(0xffffffff, v, 2);
                if (lc == 0) {
                    int r = bm + wm * 64 + i * 16 + lr + h * 8;
                    atomicAdd(J.rowsum + (long)b * mTot + r, v);
                }
            }
        float* stg = dynsm;
        __half* Ch = (__half*)J.C + (long)b * J.cStr;
#pragma unroll
        for (int h2 = 0; h2 < 2; h2++) {
            __syncthreads();
            if ((wn >> 1) == h2) {
                int snb = wn * 32 - h2 * 64;
#pragma unroll
                for (int j = 0; j < 4; j++) {
                    int sn = snb + j * 8 + lc * 2;
#pragma unroll
                    for (int i = 0; i < 4; i++) {
                        int ml = wm * 64 + i * 16 + lr;
                        stg[sn * 132 + ml]           = acc[i][j][0];
                        stg[(sn + 1) * 132 + ml]     = acc[i][j][1];
                        stg[sn * 132 + ml + 8]       = acc[i][j][2];
                        stg[(sn + 1) * 132 + ml + 8] = acc[i][j][3];
                    }
                }
            }
            __syncthreads();
#pragma unroll
            for (int it = 0; it < 8; it++) {
                int id = tid + (it << 8);
                int row = id >> 5, m4 = (id & 31) << 2;
                float4 v = *(float4*)&stg[row * 132 + m4];
                __half2 h0 = __floats2half2_rn(v.x, v.y);
                __half2 h1 = __floats2half2_rn(v.z, v.w);
                uint2 o;
                o.x = *(uint32_t*)&h0; o.y = *(uint32_t*)&h1;
                *(uint2*)(Ch + (long)(bn + h2 * 64 + row) * ldc + bm + m4) = o;
            }
        }
    } else if (EPI == 6) {
#pragma unroll
        for (int i = 0; i < 4; i++) {
#pragma unroll
            for (int h = 0; h < 2; h++) {
                int r = bm + wm * 64 + i * 16 + lr + h * 8;
                if (r >= mTot) continue;
                float* Crow = Cb + (long)r * ldc;
#pragma unroll
                for (int j = 0; j < 4; j++) {
                    int col0 = bn + wn * 32 + j * 8 + lc * 2;
                    atomicAdd(Crow + col0,     alpha * acc[i][j][h * 2 + 0]);
                    atomicAdd(Crow + col0 + 1, alpha * acc[i][j][h * 2 + 1]);
                }
            }
        }
    } else {
#pragma unroll
        for (int i = 0; i < 4; i++) {
#pragma unroll
            for (int h = 0; h < 2; h++) {
                int r = bm + wm * 64 + i * 16 + lr + h * 8;
                if (r >= mTot) continue;
                float* Crow = Cb + (long)r * ldc;
#pragma unroll
                for (int j = 0; j < 4; j++) {
                    int col0 = bn + wn * 32 + j * 8 + lc * 2;
                    float v0 = acc[i][j][h * 2 + 0];
                    float v1 = acc[i][j][h * 2 + 1];
                    if (EPI == 2) {
                        v0 = alpha * (v0 + bias[col0]);
                        v1 = alpha * (v1 + bias[col0 + 1]);
                    }
                    if (RND) { v0 = to_tf32(v0); v1 = to_tf32(v1); }
                    float2 o; o.x = v0; o.y = v1;
                    *(float2*)(Crow + col0) = o;
                }
            }
        }
    }
}

// ================= fp16 NT GEMM (BK=64, m16n8k16) =================
// EPI 1: exp -> fp16 Et (transposed) + stats   (normal grid decode)
// EPI 5: symmetric S-GEMM, triangular decode, split-K atomics (x mscale);
//        B-fragment *= kscale (fp16, per-k) when KSC.
// A/B/Et strides in HALF units.
template<int EPI, bool KSC>
__global__ void __launch_bounds__(256, 2) hgemm(Jobs jobs)
{
    extern __shared__ float dynsm[];

    int q = blockIdx.x;
    int ji = 0;
    if (q >= jobs.off[1]) ji = 1;
    if (q >= jobs.off[2]) ji = 2;
    q -= jobs.off[ji];
    const Job J = jobs.j[ji];

    const int b = blockIdx.z;
    const int Kc = J.kTot / J.splits;
    int sp, bxq, byq;
    if (EPI == 5) {
        sp = q / J.gx;
        int tri = q % J.gx;
        const int T = J.nTot >> 7;
        int by = 0;
        while (tri >= T - by) { tri -= (T - by); by++; }
        byq = by; bxq = by + tri;
    } else {
        const int gxy = J.gx * J.gy;
        sp = q / gxy;
        int r0q = q % gxy;
        bxq = r0q % J.gx; byq = r0q / J.gx;
    }
    const int kbase = sp * Kc;
    const int nt = Kc >> 6;
    const int bm = byq * 128;
    const int bn = bxq * 128;

    const __half* Ab = (const __half*)J.A + (long)b * J.aStr;
    const __half* Bb = (const __half*)J.Bm + (long)b * J.bStr;
    const __half2* ksc2 = KSC ? (const __half2*)((const __half*)J.kscale + (long)b * J.kTot) : nullptr;
    const int lda = J.lda, ldb = J.ldb;
    const int mTot = J.mTot;

    const int tid = threadIdx.x;
    const int wid = tid >> 5, lane = tid & 31;
    const int wm = wid & 1, wn = wid >> 1;
    const int lr = lane >> 2, lc = lane & 3;

    const uint32_t smBase = smem_u32(dynsm);
    const int g8 = lane >> 3;
    const int r8 = lane & 7;
    const uint32_t asBase = smBase +
        (uint32_t)(((wm * 64 + (g8 & 1) * 8 + r8) * 72 + (g8 >> 1) * 8) * 2);
    const uint32_t bsBase = smBase + BOFF +
        (uint32_t)(((wn * 32 + (g8 >> 1) * 8 + r8) * 72 + (g8 & 1) * 8) * 2);

    auto issue_copy = [&](int tt, uint32_t stOff) {
        const int k0 = kbase + (tt << 6);
        const uint32_t aS = smBase + stOff;
        const uint32_t bS = smBase + BOFF + stOff;
#pragma unroll
        for (int l = 0; l < 4; l++) {
            int c = tid + (l << 8);
            int row = c >> 3, kq = (c & 7) << 3;
            uint32_t off = (uint32_t)(row * 144 + kq * 2);
            cpa16(aS + off, Ab + (long)(bm + row) * lda + k0 + kq, true);
            cpa16(bS + off, Bb + (long)(bn + row) * ldb + k0 + kq, true);
        }
    };

    float acc[4][4][4];
#pragma unroll
    for (int i = 0; i < 4; i++)
#pragma unroll
        for (int j = 0; j < 4; j++)
#pragma unroll
            for (int r = 0; r < 4; r++) acc[i][j][r] = 0.0f;

    issue_copy(0, 0);        CP_COMMIT();
    if (nt > 1) { issue_copy(1, STAGEB); }
    CP_COMMIT();

    uint32_t curOff = 0, nxtOff = STAGEB, thrOff = 2 * STAGEB;

    for (int t = 0; t < nt; t++) {
        CP_WAIT1();
        __syncthreads();
        if (t + 2 < nt) issue_copy(t + 2, thrOff);
        CP_COMMIT();

        const uint32_t aCur = asBase + curOff;
        const uint32_t bCur = bsBase + curOff;
        const int kh = (kbase + (t << 6)) >> 1;
#pragma unroll
        for (int ks = 0; ks < 4; ks++) {
            uint32_t af[4][4];
#pragma unroll
            for (int i = 0; i < 4; i++)
                ldm_x4(af[i], aCur + i * 2304 + ks * 32);
            __half2 slo, shi;
            if (KSC) {
                slo = ksc2[kh + ks * 8 + lc];
                shi = ksc2[kh + ks * 8 + 4 + lc];
            }
            uint32_t bf[4][2];
#pragma unroll
            for (int j2 = 0; j2 < 2; j2++) {
                uint32_t r4[4];
                ldm_x4(r4, bCur + j2 * 2304 + ks * 32);
                if (KSC) {
                    r4[0] = h2mul(r4[0], slo);
                    r4[1] = h2mul(r4[1], shi);
                    r4[2] = h2mul(r4[2], slo);
                    r4[3] = h2mul(r4[3], shi);
                }
                bf[2 * j2][0] = r4[0]; bf[2 * j2][1] = r4[1];
                bf[2 * j2 + 1][0] = r4[2]; bf[2 * j2 + 1][1] = r4[3];
            }
#pragma unroll
            for (int i = 0; i < 4; i++)
#pragma unroll
                for (int j = 0; j < 4; j++)
                    mma_f16(acc[i][j], af[i], bf[j]);
        }
        uint32_t tmp = curOff; curOff = nxtOff; nxtOff = thrOff; thrOff = tmp;
    }
    __syncthreads();

    const int ldc = J.ldc;

    if (EPI == 1) {
        float rs[4][2];
#pragma unroll
        for (int i = 0; i < 4; i++) { rs[i][0] = 0.f; rs[i][1] = 0.f; }
#pragma unroll
        for (int j = 0; j < 4; j++) {
            int col0 = bn + wn * 32 + j * 8 + lc * 2;
            float cs0 = 0.f, cs1 = 0.f;
#pragma unroll
            for (int i = 0; i < 4; i++) {
                float e0 = __half2float(__float2half_rn(expf(acc[i][j][0])));
                float e1 = __half2float(__float2half_rn(expf(acc[i][j][1])));
                float e2 = __half2float(__float2half_rn(expf(acc[i][j][2])));
                float e3 = __half2float(__float2half_rn(expf(acc[i][j][3])));
                acc[i][j][0] = e0; acc[i][j][1] = e1;
                acc[i][j][2] = e2; acc[i][j][3] = e3;
                cs0 += e0 + e2; cs1 += e1 + e3;
                rs[i][0] += e0 + e1; rs[i][1] += e2 + e3;
            }
#pragma unroll
            for (int o = 4; o <= 16; o <<= 1) {
                cs0 += __shfl_xor_sync(0xffffffff, cs0, o);
                cs1 += __shfl_xor_sync(0xffffffff, cs1, o);
            }
            if (lane < 4) {
                atomicAdd(J.colsum + (long)b * J.nTot + col0, cs0);
                atomicAdd(J.colsum + (long)b * J.nTot + col0 + 1, cs1);
            }
        }
#pragma unroll
        for (int i = 0; i < 4; i++)
#pragma unroll
            for (int h = 0; h < 2; h++) {
                float v = rs[i][h];
                v += __shfl_xor_sync(0xffffffff, v, 1);
                v += __shfl_xor_sync(0xffffffff, v, 2);
                if (lc == 0) {
                    int r = bm + wm * 64 + i * 16 + lr + h * 8;
                    atomicAdd(J.rowsum + (long)b * mTot + r, v);
                }
            }
        float* stg = dynsm;
        __half* Ch = (__half*)J.C + (long)b * J.cStr;
#pragma unroll
        for (int h2 = 0; h2 < 2; h2++) {
            __syncthreads();
            if ((wn >> 1) == h2) {
                int snb = wn * 32 - h2 * 64;
#pragma unroll
                for (int j = 0; j < 4; j++) {
                    int sn = snb + j * 8 + lc * 2;
#pragma unroll
                    for (int i = 0; i < 4; i++) {
                        int ml = wm * 64 + i * 16 + lr;
                        stg[sn * 132 + ml]           = acc[i][j][0];
                        stg[(sn + 1) * 132 + ml]     = acc[i][j][1];
                        stg[sn * 132 + ml + 8]       = acc[i][j][2];
                        stg[(sn + 1) * 132 + ml + 8] = acc[i][j][3];
                    }
                }
            }
            __syncthreads();
#pragma unroll
            for (int it = 0; it < 8; it++) {
                int id = tid + (it << 8);
                int row = id >> 5, m4 = (id & 31) << 2;
                float4 v = *(float4*)&stg[row * 132 + m4];
                __half2 h0 = __floats2half2_rn(v.x, v.y);
                __half2 h1 = __floats2half2_rn(v.z, v.w);
                uint2 o;
                o.x = *(uint32_t*)&h0; o.y = *(uint32_t*)&h1;
                *(uint2*)(Ch + (long)(bn + h2 * 64 + row) * ldc + bm + m4) = o;
            }
        }
    } else {
        float* Cb = J.C + (long)b * J.cStr;
        const float* msc = J.mscale + (long)b * mTot;
#pragma unroll
        for (int i = 0; i < 4; i++) {
            int r0 = bm + wm * 64 + i * 16 + lr;
            float s0 = msc[r0];
            float s1 = msc[r0 + 8];
#pragma unroll
            for (int j = 0; j < 4; j++) {
                int col0 = bn + wn * 32 + j * 8 + lc * 2;
                atomicAdd(Cb + (long)r0 * ldc + col0,           acc[i][j][0] * s0);
                atomicAdd(Cb + (long)r0 * ldc + col0 + 1,       acc[i][j][1] * s0);
                atomicAdd(Cb + (long)(r0 + 8) * ldc + col0,     acc[i][j][2] * s1);
                atomicAdd(Cb + (long)(r0 + 8) * ldc + col0 + 1, acc[i][j][3] * s1);
            }
        }
        if (bxq != byq) {
#pragma unroll
            for (int j = 0; j < 4; j++) {
                int n0 = bn + wn * 32 + j * 8 + lc * 2;
                float sn0 = msc[n0];
                float sn1 = msc[n0 + 1];
#pragma unroll
                for (int i = 0; i < 4; i++) {
                    int r0 = bm + wm * 64 + i * 16 + lr;
                    atomicAdd(Cb + (long)n0 * ldc + r0,           acc[i][j][0] * sn0);
                    atomicAdd(Cb + (long)(n0 + 1) * ldc + r0,     acc[i][j][1] * sn1);
                    atomicAdd(Cb + (long)n0 * ldc + r0 + 8,       acc[i][j][2] * sn0);
                    atomicAdd(Cb + (long)(n0 + 1) * ldc + r0 + 8, acc[i][j][3] * sn1);
                }
            }
        }
    }
}

// ---------------- fused utility kernels ----------------
struct PrepArgs {
    const float* src[12];
    float* dst[12];
    long n[12];
    int typ[12];                 // 0 = tf32 round f32->f32 ; 1 = f32 -> fp16
    const float *W1, *W2, *b1, *b2;
    float *W12, *bsum, *zero;
    long zn;
};
// seg 0-11 typed copies; seg 12: zero; seg 13: W12 concat; seg 14: bsum
__global__ void prep(PrepArgs a) {
    int seg = blockIdx.y;
    long i0 = (long)blockIdx.x * blockDim.x + threadIdx.x;
    long stride = (long)gridDim.x * blockDim.x;
    if (seg < 12) {
        const float4* s = (const float4*)a.src[seg];
        long n4 = a.n[seg] >> 2;
        if (a.typ[seg] == 0) {
            float4* d = (float4*)a.dst[seg];
            for (long i = i0; i < n4; i += stride) d[i] = rnd4(s[i]);
        } else {
            __half* d = (__half*)a.dst[seg];
            for (long i = i0; i < n4; i += stride) {
                float4 v = s[i];
                __half2 h0 = __floats2half2_rn(v.x, v.y);
                __half2 h1 = __floats2half2_rn(v.z, v.w);
                uint2 o; o.x = *(uint32_t*)&h0; o.y = *(uint32_t*)&h1;
                *(uint2*)(d + (i << 2)) = o;
            }
        }
    } else if (seg == 12) {
        float4* z = (float4*)a.zero;
        long n4 = a.zn >> 2;
        float4 v = make_float4(0.f, 0.f, 0.f, 0.f);
        for (long i = i0; i < n4; i += stride) z[i] = v;
    } else if (seg == 13) {
        float4* d = (float4*)a.W12;
        for (long i = i0; i < 131072L; i += stride) {
            long base = i << 2;
            int n = (int)(base >> 10), k = (int)(base & 1023);
            float4 v = (k < 512) ? *(const float4*)(a.W1 + (long)n * 512 + k)
                                 : *(const float4*)(a.W2 + (long)n * 512 + k - 512);
            d[i] = rnd4(v);
        }
    } else {
        for (long i = i0; i < 512; i += stride) a.bsum[i] = a.b1[i] + a.b2[i];
    }
}

// seg0: stats recips (R->fp16*1024, C->fp32/1024); seg1: ATT prefill; seg2: A3 = bp3
__global__ void fuse2(float* stats,
                      __half* r1h, __half* r2h, __half* r4h,
                      const float* __restrict__ x3, const float* __restrict__ bsum,
                      const float* __restrict__ bp4, const float* __restrict__ wscal,
                      float* __restrict__ ATT,
                      const float* __restrict__ bp3, float* __restrict__ A3)
{
    int seg = blockIdx.y;
    long i0 = (long)blockIdx.x * blockDim.x + threadIdx.x;
    long stride = (long)gridDim.x * blockDim.x;
    if (seg == 0) {
        for (long i = i0; i < 88064; i += stride) {
            float r = 1.0f / stats[i];
            if (i < 36864)       r1h[i] = __float2half(r * 1024.0f);
            else if (i < 38912)  stats[i] = r * 0.0009765625f;
            else if (i < 48128)  r2h[i - 38912] = __float2half(r * 1024.0f);
            else if (i < 50176)  stats[i] = r * 0.0009765625f;
            else if (i < 87040)  r4h[i - 50176] = __float2half(r * 1024.0f);
            else                 stats[i] = r * 0.0009765625f;
        }
    } else if (seg == 1) {
        float f = 1.0f / (1.0f + expf(-wscal[0]));
        float other = (1.0f - f) * 0.5f;
        for (long i = i0; i < (long)BB * N3_ * D2_; i += stride) {
            int col = (int)(i & (D2_ - 1));
            ATT[i] = x3[i] + other * bsum[col] + f * bp4[col];
        }
    } else {
        for (long i = i0; i < (long)BB * N2_ * D1_; i += stride)
            A3[i] = bp3[(int)(i & (D1_ - 1))];
    }
}

// RA -> fp16 1024/x ; CA -> fp32 (1/x)/1024
__global__ void recip2(float* ra, __half* rah, int nr, float* ca, int nc) {
    int i = blockIdx.x * blockDim.x + threadIdx.x;
    if (i < nr) rah[i] = __float2half(1024.0f / ra[i]);
    else if (i < nr + nc) { int j = i - nr; ca[j] = (1.0f / ca[j]) * 0.0009765625f; }
}

// LN over last dim + fused out-prefill
__global__ void ln_rows(const float* __restrict__ X, const float* __restrict__ g,
                        const float* __restrict__ bb, float* __restrict__ Y, int C,
                        const float* __restrict__ bfc2, float* __restrict__ outp)
{
    long row = blockIdx.x;
    const float* x = X + row * C;
    float s = 0.f, s2 = 0.f;
    for (int c = threadIdx.x; c < C; c += blockDim.x) { float v = x[c]; s += v; s2 += v * v; }
    __shared__ float sh1[32], sh2[32];
    int lane = threadIdx.x & 31, wid = threadIdx.x >> 5;
#pragma unroll
    for (int o = 16; o; o >>= 1) {
        s  += __shfl_down_sync(0xffffffff, s,  o);
        s2 += __shfl_down_sync(0xffffffff, s2, o);
    }
    if (!lane) { sh1[wid] = s; sh2[wid] = s2; }
    __syncthreads();
    if (threadIdx.x == 0) {
        float a = 0.f, c2 = 0.f;
        int nw = blockDim.x >> 5;
        for (int i = 0; i < nw; i++) { a += sh1[i]; c2 += sh2[i]; }
        float mean = a / C;
        float var  = c2 / C - mean * mean;
        sh1[0] = mean; sh2[0] = rsqrtf(var + 1e-5f);
    }
    __syncthreads();
    float mean = sh1[0], rstd = sh2[0];
    for (int c = threadIdx.x; c < C; c += blockDim.x) {
        float v = x[c];
        Y[row * C + c] = to_tf32((v - mean) * rstd * g[c] + bb[c]);
        outp[row * C + c] = v + bfc2[c];
    }
}

__global__ void __launch_bounds__(256) dwconv_ln_gelu(
    const float* __restrict__ H, const float* __restrict__ Wdw,
    const float* __restrict__ bdw, const float* __restrict__ g,
    const float* __restrict__ bt, float* __restrict__ AX)
{
    const int n = blockIdx.x;
    const int b = blockIdx.y;
    const int y = n / 24, x = n % 24;
    const float* Hb = H + (long)b * 576 * 2048;
    const int tid = threadIdx.x;

    float v[8];
    float s = 0.f, s2 = 0.f;
#pragma unroll
    for (int it = 0; it < 8; it++) {
        int c = tid + it * 256;
        float a = Hb[(long)n * 2048 + c] + bdw[c];
#pragma unroll
        for (int ky = 0; ky < 3; ky++) {
            int yy = y + ky - 1;
            if (yy < 0 || yy > 23) continue;
#pragma unroll
            for (int kx = 0; kx < 3; kx++) {
                int xx = x + kx - 1;
                if (xx < 0 || xx > 23) continue;
                a += Wdw[c * 9 + ky * 3 + kx] * Hb[(long)(yy * 24 + xx) * 2048 + c];
            }
        }
        v[it] = a; s += a; s2 += a * a;
    }
    __shared__ float sh1[32], sh2[32];
    int lane = tid & 31, wid = tid >> 5;
#pragma unroll
    for (int o = 16; o; o >>= 1) {
        s  += __shfl_down_sync(0xffffffff, s,  o);
        s2 += __shfl_down_sync(0xffffffff, s2, o);
    }
    if (!lane) { sh1[wid] = s; sh2[wid] = s2; }
    __syncthreads();
    if (tid == 0) {
        float a = 0.f, c2 = 0.f;
        for (int i = 0; i < 8; i++) { a += sh1[i]; c2 += sh2[i]; }
        float mean = a / 2048.0f;
        float var  = c2 / 2048.0f - mean * mean;
        sh1[0] = mean; sh2[0] = rsqrtf(var + 1e-5f);
    }
    __syncthreads();
    float mean = sh1[0], rstd = sh2[0];
    float* out = AX + ((long)b * 576 + n) * 2048;
#pragma unroll
    for (int it = 0; it < 8; it++) {
        int c = tid + it * 256;
        float t = (v[it] - mean) * rstd * g[c] + bt[c];
        out[c] = to_tf32(0.5f * t * (1.0f + erff(t * 0.70710678118654752f)));
    }
}

// ---------------- host orchestration ----------------
#define SET_SMEM(k) cudaFuncSetAttribute(k, cudaFuncAttributeMaxDynamicSharedMemorySize, SMEM_DYN)

static Job mk_job(const float* A, long aStr, int lda,
                  const float* B, long bStr, int ldb,
                  float* C, long cStr, int ldc,
                  int m, int n, int k, int splits, int gx, int gy, int amode,
                  const float* ksc = nullptr, const float* msc = nullptr,
                  float* rsum = nullptr, float* csum = nullptr) {
    Job J;
    J.A = A; J.Bm = B; J.C = C;
    J.aStr = aStr; J.bStr = bStr; J.cStr = cStr;
    J.lda = lda; J.ldb = ldb; J.ldc = ldc;
    J.mTot = m; J.nTot = n; J.kTot = k; J.splits = splits; J.gx = gx; J.gy = gy;
    J.amode = amode;
    J.kscale = ksc; J.mscale = msc; J.rowsum = rsum; J.colsum = csum;
    return J;
}

extern "C" void kernel_launch(void* const* d_in, const int* in_sizes, int n_in,
                              void* d_out, int out_size)
{
    const float* x      = (const float*)d_in[0];
    const float* x2     = (const float*)d_in[1];
    const float* x3     = (const float*)d_in[2];
    const float* W_lin  = (const float*)d_in[3];
    const float* W_lin2 = (const float*)d_in[4];
    const float* W_lin3 = (const float*)d_in[5];
    const float* W_lin4 = (const float*)d_in[6];
    const float* w      = (const float*)d_in[7];
    const float* Wp1 = (const float*)d_in[8];  const float* bp1 = (const float*)d_in[9];
    const float* Wp2 = (const float*)d_in[10]; const float* bp2 = (const float*)d_in[11];
    const float* Wp3 = (const float*)d_in[12]; const float* bp3 = (const float*)d_in[13];
    const float* Wp4 = (const float*)d_in[14]; const float* bp4 = (const float*)d_in[15];
    const float* g_norm = (const float*)d_in[16]; const float* b_norm = (const float*)d_in[17];
    const float* Wfc1 = (const float*)d_in[18];   const float* bfc1  = (const float*)d_in[19];
    const float* Wdw  = (const float*)d_in[20];   const float* bdw   = (const float*)d_in[21];
    const float* g_ln1 = (const float*)d_in[22];  const float* b_ln1 = (const float*)d_in[23];
    const float* Wfc2 = (const float*)d_in[24];   const float* bfc2  = (const float*)d_in[25];

    float* pool = nullptr;
    cudaGetSymbolAddress((void**)&pool, g_pool);

    SET_SMEM((tgemm<1,false>));
    SET_SMEM((tgemm<0,true>));
    SET_SMEM((tgemm<2,false>));
    SET_SMEM((tgemm<6,false>));
    SET_SMEM((hgemm<1,false>));
    SET_SMEM((hgemm<5,true>));

    // 0) fused prologue (fp16 + tf32 copies, zero, W12, bsum)
    {
        PrepArgs pa;
        const float* srcs[12] = { x, x2, x2, x3, W_lin, W_lin2, W_lin3, W_lin4, Wp3, Wp4, Wfc1, Wfc2 };
        long offs[12] = { OFF_XH, OFF_X2H, OFF_X2R, OFF_X3R, OFF_WLH, OFF_WL2H, OFF_WL3H,
                          OFF_WL4, OFF_WP3R, OFF_WP4R, OFF_WF1, OFF_WF2 };
        long ns[12] = { (long)BB*N1_*D0_, (long)BB*N2_*D1_, (long)BB*N2_*D1_, (long)BB*N3_*D2_,
                        (long)D2_*D0_, (long)D2_*D1_, (long)D1_*D0_,
                        (long)D2_*D1_, (long)D1_*D1_, (long)D2_*D2_, (long)DH_*D2_, (long)D2_*DH_ };
        int typs[12] = { 1, 1, 0, 0, 1, 1, 1, 0, 0, 0, 0, 0 };
        for (int i = 0; i < 12; i++) {
            pa.src[i] = srcs[i]; pa.dst[i] = pool + offs[i]; pa.n[i] = ns[i]; pa.typ[i] = typs[i];
        }
        pa.W1 = Wp1; pa.W2 = Wp2; pa.b1 = bp1; pa.b2 = bp2;
        pa.W12 = pool + OFF_WP12; pa.bsum = pool + OFF_BSUM;
        pa.zero = pool; pa.zn = ZERO_CNT;
        prep<<<dim3(512, 15), 256>>>(pa);
    }
    const float* x2r = pool + OFF_X2R;
    const float* x3r = pool + OFF_X3R;

    // 1-3) Et1+Et2+Et4 (fp16 GEMM, EPI1: exp -> fp16 transposed; HALF strides)
    {
        Jobs js;
        js.j[0] = mk_job(pool+OFF_XH, (long)N1_*D0_, D0_, pool+OFF_WLH, 0L, D0_,
                         pool+OFF_ET1, (long)D2_*N1_, N1_, N1_, D2_, D0_, 1, 4, 72, 0,
                         nullptr, nullptr, pool+OFF_R1, pool+OFF_C1);
        js.j[1] = mk_job(pool+OFF_X2H, (long)N2_*D1_, D1_, pool+OFF_WL2H, 0L, D1_,
                         pool+OFF_ET2, (long)D2_*N2_, N2_, N2_, D2_, D1_, 1, 4, 18, 0,
                         nullptr, nullptr, pool+OFF_R2, pool+OFF_C2);
        js.j[2] = mk_job(pool+OFF_XH, (long)N1_*D0_, D0_, pool+OFF_WL3H, 0L, D0_,
                         pool+OFF_ET4, (long)D1_*N1_, N1_, N1_, D1_, D0_, 1, 2, 72, 0,
                         nullptr, nullptr, pool+OFF_R4, pool+OFF_C4);
        js.off[0] = 0; js.off[1] = 288; js.off[2] = 360; js.off[3] = 504;
        hgemm<1,false><<<dim3(504,1,BB), 256, SMEM_DYN>>>(js);
    }

    // 4) fused: recips + ATT prefill + A3 prefill
    fuse2<<<dim3(1024, 3), 256>>>(pool,
        (__half*)(pool + OFF_R1H), (__half*)(pool + OFF_R2H), (__half*)(pool + OFF_R4H),
        x3, pool+OFF_BSUM, bp4, w, pool+OFF_ATT, bp3, pool+OFF_A3);

    // 5-7) St1+St2+St3 (fp16 symmetric; halved split-K: 4/2/4)
    {
        Jobs js;
        js.j[0] = mk_job(pool+OFF_ET1, (long)D2_*N1_, N1_, pool+OFF_ET1, (long)D2_*N1_, N1_,
                         pool+OFF_ST12, (long)2*D2_*D2_, D2_, D2_, D2_, N1_, 4, 10, 1, 0,
                         (const float*)(pool+OFF_R1H), pool+OFF_C1);
        js.j[1] = mk_job(pool+OFF_ET2, (long)D2_*N2_, N2_, pool+OFF_ET2, (long)D2_*N2_, N2_,
                         pool+OFF_ST12 + (long)D2_*D2_, (long)2*D2_*D2_, D2_, D2_, D2_, N2_, 2, 10, 1, 0,
                         (const float*)(pool+OFF_R2H), pool+OFF_C2);
        js.j[2] = mk_job(pool+OFF_ET4, (long)D1_*N1_, N1_, pool+OFF_ET4, (long)D1_*N1_, N1_,
                         pool+OFF_ST3, (long)D1_*D1_, D1_, D1_, D1_, N1_, 4, 3, 1, 0,
                         (const float*)(pool+OFF_R4H), pool+OFF_C4);
        js.off[0] = 0; js.off[1] = 40; js.off[2] = 60; js.off[3] = 72;
        hgemm<5,true><<<dim3(72,1,BB), 256, SMEM_DYN>>>(js);
    }

    // 8+12) T12 and T3 (tf32, EPI0 RND)
    {
        Jobs js;
        js.j[0] = mk_job(x3r, (long)N3_*D2_, D2_, pool+OFF_ST12, (long)2*D2_*D2_, D2_,
                         pool+OFF_T12, (long)N3_*2*D2_, 2*D2_, N3_, 2*D2_, D2_, 1, 8, 5, 0);
        js.j[1] = mk_job(x2r, (long)N2_*D1_, D1_, pool+OFF_ST3, (long)D1_*D1_, D1_,
                         pool+OFF_T3, (long)N2_*D1_, D1_, N2_, D1_, D1_, 1, 2, 18, 0);
        js.j[2] = js.j[1];
        js.off[0] = 0; js.off[1] = 40; js.off[2] = 76; js.off[3] = 76;
        tgemm<0,true><<<dim3(76,1,BB), 256, SMEM_DYN>>>(js, nullptr, nullptr);
    }

    // 9+13) ATT += other*(T12@Wp12^T)  AND  A3 += T3@Wp3^T  (EPI6)
    {
        Jobs js;
        js.j[0] = mk_job(pool+OFF_T12, (long)N3_*2*D2_, 2*D2_, pool+OFF_WP12, 0L, 2*D2_,
                         pool+OFF_ATT, (long)N3_*D2_, D2_, N3_, D2_, 2*D2_, 2, 4, 5, 2);
        js.j[1] = mk_job(pool+OFF_T3, (long)N2_*D1_, D1_, pool+OFF_WP3R, 0L, D1_,
                         pool+OFF_A3, (long)N2_*D1_, D1_, N2_, D1_, D1_, 1, 2, 18, 0);
        js.j[2] = js.j[1];
        js.off[0] = 0; js.off[1] = 40; js.off[2] = 76; js.off[3] = 76;
        tgemm<6,false><<<dim3(76,1,BB), 256, SMEM_DYN>>>(js, nullptr, w);
    }

    // 14) EtA (tf32 EPI1 -> fp16; A3 fp32)
    {
        Jobs js;
        js.j[0] = mk_job(pool+OFF_A3, (long)N2_*D1_, D1_, pool+OFF_WL4, 0L, D1_,
                         pool+OFF_ETA, (long)D2_*N2_, N2_, N2_, D2_, D1_, 1, 4, 18, 0,
                         nullptr, nullptr, pool+OFF_RA, pool+OFF_CA);
        js.j[1] = js.j[0]; js.j[2] = js.j[0];
        js.off[0] = 0; js.off[1] = 72; js.off[2] = 72; js.off[3] = 72;
        tgemm<1,false><<<dim3(72,1,BB), 256, SMEM_DYN>>>(js, nullptr, nullptr);
    }
    // 15) RA->fp16*1024, CA->fp32/1024
    recip2<<<(11264 + 255) / 256, 256>>>(pool + OFF_RA, (__half*)(pool + OFF_RAH),
                                         BB * N2_, pool + OFF_CA, BB * D2_);
    // 16) St4 (fp16 symmetric, split-K 2)
    {
        Jobs js;
        js.j[0] = mk_job(pool+OFF_ETA, (long)D2_*N2_, N2_, pool+OFF_ETA, (long)D2_*N2_, N2_,
                         pool+OFF_ST4, (long)D2_*D2_, D2_, D2_, D2_, N2_, 2, 10, 1, 0,
                         (const float*)(pool+OFF_RAH), pool+OFF_CA);
        js.j[1] = js.j[0]; js.j[2] = js.j[0];
        js.off[0] = 0; js.off[1] = 20; js.off[2] = 20; js.off[3] = 20;
        hgemm<5,true><<<dim3(20,1,BB), 256, SMEM_DYN>>>(js);
    }
    // 17a) T = x3 @ St4
    {
        Jobs js;
        js.j[0] = mk_job(x3r, (long)N3_*D2_, D2_, pool+OFF_ST4, (long)D2_*D2_, D2_,
                         pool+OFF_T, (long)N3_*D2_, D2_, N3_, D2_, D2_, 1, 4, 5, 0);
        js.j[1] = js.j[0]; js.j[2] = js.j[0];
        js.off[0] = 0; js.off[1] = 20; js.off[2] = 20; js.off[3] = 20;
        tgemm<0,true><<<dim3(20,1,BB), 256, SMEM_DYN>>>(js, nullptr, nullptr);
    }
    // 17b) ATT += f*(T @ Wp4^T)  (EPI6, split-K 2)
    {
        Jobs js;
        js.j[0] = mk_job(pool+OFF_T, (long)N3_*D2_, D2_, pool+OFF_WP4R, 0L, D2_,
                         pool+OFF_ATT, (long)N3_*D2_, D2_, N3_, D2_, D2_, 2, 4, 5, 1);
        js.j[1] = js.j[0]; js.j[2] = js.j[0];
        js.off[0] = 0; js.off[1] = 40; js.off[2] = 40; js.off[3] = 40;
        tgemm<6,false><<<dim3(40,1,BB), 256, SMEM_DYN>>>(js, nullptr, w);
    }

    // 19) AN = tf32(LN(ATT)) + out prefill
    ln_rows<<<BB * N3_, 256>>>(pool + OFF_ATT, g_norm, b_norm, pool + OFF_AN, D2_,
                               bfc2, (float*)d_out);

    // 20) H = AN @ Wfc1^T + bfc1
    {
        Jobs js;
        js.j[0] = mk_job(pool+OFF_AN, (long)N3_*D2_, D2_, pool+OFF_WF1, 0L, D2_,
                         pool+OFF_H, (long)N3_*DH_, DH_, N3_, DH_, D2_, 1, 16, 5, 0);
        js.j[1] = js.j[0]; js.j[2] = js.j[0];
        js.off[0] = 0; js.off[1] = 80; js.off[2] = 80; js.off[3] = 80;
        tgemm<2,false><<<dim3(80,1,BB), 256, SMEM_DYN>>>(js, bfc1, nullptr);
    }

    // 21) AX = tf32(gelu(LN(dwconv(H)+bdw+H)))
    dwconv_ln_gelu<<<dim3(N3_, BB), 256>>>(pool + OFF_H, Wdw, bdw, g_ln1, b_ln1, pool + OFF_AX);

    // 22) out += AX @ Wfc2^T  (EPI6, split-K 4)
    {
        Jobs js;
        js.j[0] = mk_job(pool+OFF_AX, (long)N3_*DH_, DH_, pool+OFF_WF2, 0L, DH_,
                         (float*)d_out, (long)N3_*D2_, D2_, N3_, D2_, DH_, 4, 4, 5, 0);
        js.j[1] = js.j[0]; js.j[2] = js.j[0];
        js.off[0] = 0; js.off[1] = 80; js.off[2] = 80; js.off[3] = 80;
        tgemm<6,false><<<dim3(80,1,BB), 256, SMEM_DYN>>>(js, nullptr, nullptr);
    }
}

// round 16
// speedup vs baseline: 2.3518x; 1.0150x over previous
#include <cuda_runtime.h>
#include <cuda_fp16.h>
#include <math.h>
#include <stdint.h>

// ---------------- problem dims ----------------
#define BB   4
#define N1_  9216
#define N2_  2304
#define N3_  576
#define D0_  128
#define D1_  256
#define D2_  512
#define DH_  2048

// ---------------- scratch pool (floats) ----------------
#define OFF_R1   0L
#define OFF_C1   36864L
#define OFF_R2   38912L
#define OFF_C2   48128L
#define OFF_R4   50176L
#define OFF_C4   87040L
#define OFF_RA   88064L
#define OFF_CA   97280L
#define OFF_ST12 99328L            // [B][1024][512] fp32
#define OFF_ST3  2196480L          // [B][256][256]  fp32
#define OFF_ST4  2458624L          // [B][512][512]  fp32
#define ZERO_CNT 3507200L
#define OFF_ET1  3507200L          // fp16 [B][512][9216]
#define OFF_ET2  22381568L         // fp16
#define OFF_ET4  27100160L         // fp16
#define OFF_ETA  36537344L         // fp16; earlier reused as T12 [B][576][1024] fp32
#define OFF_T    41255936L         // Wp12+bsum early; T later
#define OFF_T3   42435584L
#define OFF_A3   44794880L
#define OFF_ATT  47154176L
#define OFF_AN   48333824L
#define OFF_H    49513472L
#define OFF_AX   54232064L
// fp16 operand copies + tf32 copies
#define OFF_XH   58950656L
#define OFF_X2H  61309952L
#define OFF_X2R  63669248L
#define OFF_X3R  66028544L
#define OFF_WLH  67208192L
#define OFF_WL2H 67273728L
#define OFF_WL3H 67404800L
#define OFF_WL4  67437568L
#define OFF_WP3R 67568640L
#define OFF_WP4R 67634176L
#define OFF_WF1  67896320L
#define OFF_WF2  68944896L
// fp16 scaled row-recip arrays
#define OFF_R1H  69993472L
#define OFF_R2H  70011904L
#define OFF_R4H  70016512L
#define OFF_RAH  70034944L
#define POOL_SZ  70039552L

#define OFF_T12   OFF_ETA
#define OFF_WP12  OFF_T
#define OFF_BSUM  (OFF_T + 524288L)

__device__ float g_pool[POOL_SZ];

#define STAGEB  18432u
#define BOFF    55296u
#define SMEM_DYN 110592

// ---------------- job table ----------------
struct Job {
    const float *A, *Bm;
    float *C;
    long aStr, bStr, cStr;   // element units of their respective dtypes
    int lda, ldb, ldc;
    int mTot, nTot, kTot, splits, gx, gy, amode;
    const float *kscale, *mscale;
    float *rowsum, *colsum;
};
struct Jobs { Job j[3]; int off[4]; };

// ---------------- helpers ----------------
__device__ __forceinline__ uint32_t smem_u32(const void* p) {
    uint32_t a;
    asm("{ .reg .u64 t; cvta.to.shared.u64 t, %1; cvt.u32.u64 %0, t; }" : "=r"(a) : "l"(p));
    return a;
}
__device__ __forceinline__ float to_tf32(float x) {
    float y;
    asm("cvt.rna.tf32.f32 %0, %1;" : "=f"(y) : "f"(x));
    return y;
}
__device__ __forceinline__ float4 rnd4(float4 v) {
    v.x = to_tf32(v.x); v.y = to_tf32(v.y); v.z = to_tf32(v.z); v.w = to_tf32(v.w);
    return v;
}
__device__ __forceinline__ void mma_tf32(float* d, const uint32_t* a, const uint32_t* bf) {
    asm volatile(
        "mma.sync.aligned.m16n8k8.row.col.f32.tf32.tf32.f32 "
        "{%0,%1,%2,%3}, {%4,%5,%6,%7}, {%8,%9}, {%0,%1,%2,%3};"
        : "+f"(d[0]), "+f"(d[1]), "+f"(d[2]), "+f"(d[3])
        : "r"(a[0]), "r"(a[1]), "r"(a[2]), "r"(a[3]), "r"(bf[0]), "r"(bf[1]));
}
__device__ __forceinline__ void mma_f16(float* d, const uint32_t* a, const uint32_t* bf) {
    asm volatile(
        "mma.sync.aligned.m16n8k16.row.col.f32.f16.f16.f32 "
        "{%0,%1,%2,%3}, {%4,%5,%6,%7}, {%8,%9}, {%0,%1,%2,%3};"
        : "+f"(d[0]), "+f"(d[1]), "+f"(d[2]), "+f"(d[3])
        : "r"(a[0]), "r"(a[1]), "r"(a[2]), "r"(a[3]), "r"(bf[0]), "r"(bf[1]));
}
__device__ __forceinline__ void ldm_x4(uint32_t* r, uint32_t addr) {
    asm volatile("ldmatrix.sync.aligned.m8n8.x4.shared.b16 {%0,%1,%2,%3}, [%4];"
        : "=r"(r[0]), "=r"(r[1]), "=r"(r[2]), "=r"(r[3]) : "r"(addr));
}
__device__ __forceinline__ void cpa16(uint32_t dst, const void* src, bool valid) {
    int sz = valid ? 16 : 0;
    asm volatile("cp.async.cg.shared.global [%0], [%1], 16, %2;"
        :: "r"(dst), "l"(src), "r"(sz) : "memory");
}
__device__ __forceinline__ uint32_t h2mul(uint32_t a, __half2 s) {
    __half2 v = __hmul2(*(__half2*)&a, s);
    return *(uint32_t*)&v;
}
#define CP_COMMIT() asm volatile("cp.async.commit_group;" ::: "memory")
#define CP_WAIT1()  asm volatile("cp.async.wait_group 1;" ::: "memory")

// ================= fp32/tf32 NT GEMM (job-batched, 3-stage cp.async, BK=32) ======
// EPI 0: C = acc (RND rounds)   EPI 1: exp -> fp16; Et (half; cStr HALF units)
// EPI 2: C = alpha*(acc+bias)   EPI 6: atomicAdd(C, alpha*acc)
template<int EPI, bool RND>
__global__ void __launch_bounds__(256, 2) tgemm(
    Jobs jobs, const float* __restrict__ bias, const float* __restrict__ wscal)
{
    extern __shared__ float dynsm[];

    int q = blockIdx.x;
    int ji = 0;
    if (q >= jobs.off[1]) ji = 1;
    if (q >= jobs.off[2]) ji = 2;
    q -= jobs.off[ji];
    const Job J = jobs.j[ji];

    const int b = blockIdx.z;
    const int Kc = J.kTot / J.splits;
    const int gxy = J.gx * J.gy;
    int sp = q / gxy;
    int r0q = q % gxy;
    int bxq = r0q % J.gx, byq = r0q / J.gx;
    const int kbase = sp * Kc;
    const int nt = Kc >> 5;
    const int bm = byq * 128;
    const int bn = bxq * 128;

    const float* Ab = J.A + (long)b * J.aStr;
    const float* Bb = J.Bm + (long)b * J.bStr;
    const int lda = J.lda, ldb = J.ldb;
    const int mTot = J.mTot;

    const int tid = threadIdx.x;
    const int wid = tid >> 5, lane = tid & 31;
    const int wm = wid & 1, wn = wid >> 1;
    const int lr = lane >> 2, lc = lane & 3;

    const uint32_t smBase = smem_u32(dynsm);
    const int g8 = lane >> 3;
    const int r8 = lane & 7;
    const uint32_t asBase = smBase +
        (uint32_t)(((wm * 64 + (g8 & 1) * 8 + r8) * 36 + (g8 >> 1) * 4) * 4);
    const uint32_t bsBase = smBase + BOFF +
        (uint32_t)(((wn * 32 + (g8 >> 1) * 8 + r8) * 36 + (g8 & 1) * 4) * 4);

    auto issue_copy = [&](int tt, uint32_t stOff) {
        const int k0 = kbase + (tt << 5);
        const uint32_t aS = smBase + stOff;
        const uint32_t bS = smBase + BOFF + stOff;
#pragma unroll
        for (int l = 0; l < 4; l++) {
            int c = tid + (l << 8);
            int row = c >> 3, kq = (c & 7) << 2;
            uint32_t off = (uint32_t)((row * 36 + kq) * 4);
            cpa16(aS + off, Ab + (long)(bm + row) * lda + k0 + kq, (bm + row) < mTot);
            cpa16(bS + off, Bb + (long)(bn + row) * ldb + k0 + kq, true);
        }
    };

    float acc[4][4][4];
#pragma unroll
    for (int i = 0; i < 4; i++)
#pragma unroll
        for (int j = 0; j < 4; j++)
#pragma unroll
            for (int r = 0; r < 4; r++) acc[i][j][r] = 0.0f;

    issue_copy(0, 0);        CP_COMMIT();
    if (nt > 1) { issue_copy(1, STAGEB); }
    CP_COMMIT();

    uint32_t curOff = 0, nxtOff = STAGEB, thrOff = 2 * STAGEB;

    for (int t = 0; t < nt; t++) {
        CP_WAIT1();
        __syncthreads();
        if (t + 2 < nt) issue_copy(t + 2, thrOff);
        CP_COMMIT();

        const uint32_t aCur = asBase + curOff;
        const uint32_t bCur = bsBase + curOff;
#pragma unroll
        for (int ks = 0; ks < 4; ks++) {
            uint32_t af[4][4];
#pragma unroll
            for (int i = 0; i < 4; i++)
                ldm_x4(af[i], aCur + i * 2304 + ks * 32);
            uint32_t bf[4][2];
#pragma unroll
            for (int j2 = 0; j2 < 2; j2++) {
                uint32_t r4[4];
                ldm_x4(r4, bCur + j2 * 2304 + ks * 32);
                bf[2 * j2][0] = r4[0]; bf[2 * j2][1] = r4[1];
                bf[2 * j2 + 1][0] = r4[2]; bf[2 * j2 + 1][1] = r4[3];
            }
#pragma unroll
            for (int i = 0; i < 4; i++)
#pragma unroll
                for (int j = 0; j < 4; j++)
                    mma_tf32(acc[i][j], af[i], bf[j]);
        }
        uint32_t tmp = curOff; curOff = nxtOff; nxtOff = thrOff; thrOff = tmp;
    }
    __syncthreads();

    float alpha = 1.0f;
    if (J.amode != 0) {
        float f = 1.0f / (1.0f + expf(-wscal[0]));
        alpha = (J.amode == 1) ? f : (1.0f - f) * 0.5f;
    }

    float* Cb = J.C + (long)b * J.cStr;
    const int ldc = J.ldc;

    if (EPI == 1) {
        float rs[4][2];
#pragma unroll
        for (int i = 0; i < 4; i++) { rs[i][0] = 0.f; rs[i][1] = 0.f; }
#pragma unroll
        for (int j = 0; j < 4; j++) {
            int col0 = bn + wn * 32 + j * 8 + lc * 2;
            float cs0 = 0.f, cs1 = 0.f;
#pragma unroll
            for (int i = 0; i < 4; i++) {
                float e0 = __half2float(__float2half_rn(expf(acc[i][j][0])));
                float e1 = __half2float(__float2half_rn(expf(acc[i][j][1])));
                float e2 = __half2float(__float2half_rn(expf(acc[i][j][2])));
                float e3 = __half2float(__float2half_rn(expf(acc[i][j][3])));
                acc[i][j][0] = e0; acc[i][j][1] = e1;
                acc[i][j][2] = e2; acc[i][j][3] = e3;
                cs0 += e0 + e2; cs1 += e1 + e3;
                rs[i][0] += e0 + e1; rs[i][1] += e2 + e3;
            }
#pragma unroll
            for (int o = 4; o <= 16; o <<= 1) {
                cs0 += __shfl_xor_sync(0xffffffff, cs0, o);
                cs1 += __shfl_xor_sync(0xffffffff, cs1, o);
            }
            if (lane < 4) {
                atomicAdd(J.colsum + (long)b * J.nTot + col0, cs0);
                atomicAdd(J.colsum + (long)b * J.nTot + col0 + 1, cs1);
            }
        }
#pragma unroll
        for (int i = 0; i < 4; i++)
#pragma unroll
            for (int h = 0; h < 2; h++) {
                float v = rs[i][h];
                v += __shfl_xor_sync(0xffffffff, v, 1);
                v += __shfl_xor_sync(0xffffffff, v, 2);
                if (lc == 0) {
                    int r = bm + wm * 64 + i * 16 + lr + h * 8;
                    atomicAdd(J.rowsum + (long)b * mTot + r, v);
                }
            }
        float* stg = dynsm;
        __half* Ch = (__half*)J.C + (long)b * J.cStr;
#pragma unroll
        for (int h2 = 0; h2 < 2; h2++) {
            __syncthreads();
            if ((wn >> 1) == h2) {
                int snb = wn * 32 - h2 * 64;
#pragma unroll
                for (int j = 0; j < 4; j++) {
                    int sn = snb + j * 8 + lc * 2;
#pragma unroll
                    for (int i = 0; i < 4; i++) {
                        int ml = wm * 64 + i * 16 + lr;
                        stg[sn * 132 + ml]           = acc[i][j][0];
                        stg[(sn + 1) * 132 + ml]     = acc[i][j][1];
                        stg[sn * 132 + ml + 8]       = acc[i][j][2];
                        stg[(sn + 1) * 132 + ml + 8] = acc[i][j][3];
                    }
                }
            }
            __syncthreads();
#pragma unroll
            for (int it = 0; it < 8; it++) {
                int id = tid + (it << 8);
                int row = id >> 5, m4 = (id & 31) << 2;
                float4 v = *(float4*)&stg[row * 132 + m4];
                __half2 h0 = __floats2half2_rn(v.x, v.y);
                __half2 h1 = __floats2half2_rn(v.z, v.w);
                uint2 o;
                o.x = *(uint32_t*)&h0; o.y = *(uint32_t*)&h1;
                *(uint2*)(Ch + (long)(bn + h2 * 64 + row) * ldc + bm + m4) = o;
            }
        }
    } else if (EPI == 6) {
#pragma unroll
        for (int i = 0; i < 4; i++) {
#pragma unroll
            for (int h = 0; h < 2; h++) {
                int r = bm + wm * 64 + i * 16 + lr + h * 8;
                if (r >= mTot) continue;
                float* Crow = Cb + (long)r * ldc;
#pragma unroll
                for (int j = 0; j < 4; j++) {
                    int col0 = bn + wn * 32 + j * 8 + lc * 2;
                    atomicAdd(Crow + col0,     alpha * acc[i][j][h * 2 + 0]);
                    atomicAdd(Crow + col0 + 1, alpha * acc[i][j][h * 2 + 1]);
                }
            }
        }
    } else {
#pragma unroll
        for (int i = 0; i < 4; i++) {
#pragma unroll
            for (int h = 0; h < 2; h++) {
                int r = bm + wm * 64 + i * 16 + lr + h * 8;
                if (r >= mTot) continue;
                float* Crow = Cb + (long)r * ldc;
#pragma unroll
                for (int j = 0; j < 4; j++) {
                    int col0 = bn + wn * 32 + j * 8 + lc * 2;
                    float v0 = acc[i][j][h * 2 + 0];
                    float v1 = acc[i][j][h * 2 + 1];
                    if (EPI == 2) {
                        v0 = alpha * (v0 + bias[col0]);
                        v1 = alpha * (v1 + bias[col0 + 1]);
                    }
                    if (RND) { v0 = to_tf32(v0); v1 = to_tf32(v1); }
                    float2 o; o.x = v0; o.y = v1;
                    *(float2*)(Crow + col0) = o;
                }
            }
        }
    }
}

// ================= fp16 NT GEMM (BK=64, m16n8k16) =================
// EPI 1: exp -> fp16 Et + stats (normal grid decode)
// EPI 5: symmetric S-GEMM (triangular decode, atomics x mscale; kscale on B)
template<int EPI, bool KSC>
__global__ void __launch_bounds__(256, 2) hgemm(Jobs jobs)
{
    extern __shared__ float dynsm[];

    int q = blockIdx.x;
    int ji = 0;
    if (q >= jobs.off[1]) ji = 1;
    if (q >= jobs.off[2]) ji = 2;
    q -= jobs.off[ji];
    const Job J = jobs.j[ji];

    const int b = blockIdx.z;
    const int Kc = J.kTot / J.splits;
    int sp, bxq, byq;
    if (EPI == 5) {
        sp = q / J.gx;
        int tri = q % J.gx;
        const int T = J.nTot >> 7;
        int by = 0;
        while (tri >= T - by) { tri -= (T - by); by++; }
        byq = by; bxq = by + tri;
    } else {
        const int gxy = J.gx * J.gy;
        sp = q / gxy;
        int r0q = q % gxy;
        bxq = r0q % J.gx; byq = r0q / J.gx;
    }
    const int kbase = sp * Kc;
    const int nt = Kc >> 6;
    const int bm = byq * 128;
    const int bn = bxq * 128;

    const __half* Ab = (const __half*)J.A + (long)b * J.aStr;
    const __half* Bb = (const __half*)J.Bm + (long)b * J.bStr;
    const __half2* ksc2 = KSC ? (const __half2*)((const __half*)J.kscale + (long)b * J.kTot) : nullptr;
    const int lda = J.lda, ldb = J.ldb;
    const int mTot = J.mTot;

    const int tid = threadIdx.x;
    const int wid = tid >> 5, lane = tid & 31;
    const int wm = wid & 1, wn = wid >> 1;
    const int lr = lane >> 2, lc = lane & 3;

    const uint32_t smBase = smem_u32(dynsm);
    const int g8 = lane >> 3;
    const int r8 = lane & 7;
    const uint32_t asBase = smBase +
        (uint32_t)(((wm * 64 + (g8 & 1) * 8 + r8) * 72 + (g8 >> 1) * 8) * 2);
    const uint32_t bsBase = smBase + BOFF +
        (uint32_t)(((wn * 32 + (g8 >> 1) * 8 + r8) * 72 + (g8 & 1) * 8) * 2);

    auto issue_copy = [&](int tt, uint32_t stOff) {
        const int k0 = kbase + (tt << 6);
        const uint32_t aS = smBase + stOff;
        const uint32_t bS = smBase + BOFF + stOff;
#pragma unroll
        for (int l = 0; l < 4; l++) {
            int c = tid + (l << 8);
            int row = c >> 3, kq = (c & 7) << 3;
            uint32_t off = (uint32_t)(row * 144 + kq * 2);
            cpa16(aS + off, Ab + (long)(bm + row) * lda + k0 + kq, true);
            cpa16(bS + off, Bb + (long)(bn + row) * ldb + k0 + kq, true);
        }
    };

    float acc[4][4][4];
#pragma unroll
    for (int i = 0; i < 4; i++)
#pragma unroll
        for (int j = 0; j < 4; j++)
#pragma unroll
            for (int r = 0; r < 4; r++) acc[i][j][r] = 0.0f;

    issue_copy(0, 0);        CP_COMMIT();
    if (nt > 1) { issue_copy(1, STAGEB); }
    CP_COMMIT();

    uint32_t curOff = 0, nxtOff = STAGEB, thrOff = 2 * STAGEB;

    for (int t = 0; t < nt; t++) {
        CP_WAIT1();
        __syncthreads();
        if (t + 2 < nt) issue_copy(t + 2, thrOff);
        CP_COMMIT();

        const uint32_t aCur = asBase + curOff;
        const uint32_t bCur = bsBase + curOff;
        const int kh = (kbase + (t << 6)) >> 1;
#pragma unroll
        for (int ks = 0; ks < 4; ks++) {
            uint32_t af[4][4];
#pragma unroll
            for (int i = 0; i < 4; i++)
                ldm_x4(af[i], aCur + i * 2304 + ks * 32);
            __half2 slo, shi;
            if (KSC) {
                slo = ksc2[kh + ks * 8 + lc];
                shi = ksc2[kh + ks * 8 + 4 + lc];
            }
            uint32_t bf[4][2];
#pragma unroll
            for (int j2 = 0; j2 < 2; j2++) {
                uint32_t r4[4];
                ldm_x4(r4, bCur + j2 * 2304 + ks * 32);
                if (KSC) {
                    r4[0] = h2mul(r4[0], slo);
                    r4[1] = h2mul(r4[1], shi);
                    r4[2] = h2mul(r4[2], slo);
                    r4[3] = h2mul(r4[3], shi);
                }
                bf[2 * j2][0] = r4[0]; bf[2 * j2][1] = r4[1];
                bf[2 * j2 + 1][0] = r4[2]; bf[2 * j2 + 1][1] = r4[3];
            }
#pragma unroll
            for (int i = 0; i < 4; i++)
#pragma unroll
                for (int j = 0; j < 4; j++)
                    mma_f16(acc[i][j], af[i], bf[j]);
        }
        uint32_t tmp = curOff; curOff = nxtOff; nxtOff = thrOff; thrOff = tmp;
    }
    __syncthreads();

    const int ldc = J.ldc;

    if (EPI == 1) {
        float rs[4][2];
#pragma unroll
        for (int i = 0; i < 4; i++) { rs[i][0] = 0.f; rs[i][1] = 0.f; }
#pragma unroll
        for (int j = 0; j < 4; j++) {
            int col0 = bn + wn * 32 + j * 8 + lc * 2;
            float cs0 = 0.f, cs1 = 0.f;
#pragma unroll
            for (int i = 0; i < 4; i++) {
                float e0 = __half2float(__float2half_rn(expf(acc[i][j][0])));
                float e1 = __half2float(__float2half_rn(expf(acc[i][j][1])));
                float e2 = __half2float(__float2half_rn(expf(acc[i][j][2])));
                float e3 = __half2float(__float2half_rn(expf(acc[i][j][3])));
                acc[i][j][0] = e0; acc[i][j][1] = e1;
                acc[i][j][2] = e2; acc[i][j][3] = e3;
                cs0 += e0 + e2; cs1 += e1 + e3;
                rs[i][0] += e0 + e1; rs[i][1] += e2 + e3;
            }
#pragma unroll
            for (int o = 4; o <= 16; o <<= 1) {
                cs0 += __shfl_xor_sync(0xffffffff, cs0, o);
                cs1 += __shfl_xor_sync(0xffffffff, cs1, o);
            }
            if (lane < 4) {
                atomicAdd(J.colsum + (long)b * J.nTot + col0, cs0);
                atomicAdd(J.colsum + (long)b * J.nTot + col0 + 1, cs1);
            }
        }
#pragma unroll
        for (int i = 0; i < 4; i++)
#pragma unroll
            for (int h = 0; h < 2; h++) {
                float v = rs[i][h];
                v += __shfl_xor_sync(0xffffffff, v, 1);
                v += __shfl_xor_sync(0xffffffff, v, 2);
                if (lc == 0) {
                    int r = bm + wm * 64 + i * 16 + lr + h * 8;
                    atomicAdd(J.rowsum + (long)b * mTot + r, v);
                }
            }
        float* stg = dynsm;
        __half* Ch = (__half*)J.C + (long)b * J.cStr;
#pragma unroll
        for (int h2 = 0; h2 < 2; h2++) {
            __syncthreads();
            if ((wn >> 1) == h2) {
                int snb = wn * 32 - h2 * 64;
#pragma unroll
                for (int j = 0; j < 4; j++) {
                    int sn = snb + j * 8 + lc * 2;
#pragma unroll
                    for (int i = 0; i < 4; i++) {
                        int ml = wm * 64 + i * 16 + lr;
                        stg[sn * 132 + ml]           = acc[i][j][0];
                        stg[(sn + 1) * 132 + ml]     = acc[i][j][1];
                        stg[sn * 132 + ml + 8]       = acc[i][j][2];
                        stg[(sn + 1) * 132 + ml + 8] = acc[i][j][3];
                    }
                }
            }
            __syncthreads();
#pragma unroll
            for (int it = 0; it < 8; it++) {
                int id = tid + (it << 8);
                int row = id >> 5, m4 = (id & 31) << 2;
                float4 v = *(float4*)&stg[row * 132 + m4];
                __half2 h0 = __floats2half2_rn(v.x, v.y);
                __half2 h1 = __floats2half2_rn(v.z, v.w);
                uint2 o;
                o.x = *(uint32_t*)&h0; o.y = *(uint32_t*)&h1;
                *(uint2*)(Ch + (long)(bn + h2 * 64 + row) * ldc + bm + m4) = o;
            }
        }
    } else {
        float* Cb = J.C + (long)b * J.cStr;
        const float* msc = J.mscale + (long)b * mTot;
#pragma unroll
        for (int i = 0; i < 4; i++) {
            int r0 = bm + wm * 64 + i * 16 + lr;
            float s0 = msc[r0];
            float s1 = msc[r0 + 8];
#pragma unroll
            for (int j = 0; j < 4; j++) {
                int col0 = bn + wn * 32 + j * 8 + lc * 2;
                atomicAdd(Cb + (long)r0 * ldc + col0,           acc[i][j][0] * s0);
                atomicAdd(Cb + (long)r0 * ldc + col0 + 1,       acc[i][j][1] * s0);
                atomicAdd(Cb + (long)(r0 + 8) * ldc + col0,     acc[i][j][2] * s1);
                atomicAdd(Cb + (long)(r0 + 8) * ldc + col0 + 1, acc[i][j][3] * s1);
            }
        }
        if (bxq != byq) {
#pragma unroll
            for (int j = 0; j < 4; j++) {
                int n0 = bn + wn * 32 + j * 8 + lc * 2;
                float sn0 = msc[n0];
                float sn1 = msc[n0 + 1];
#pragma unroll
                for (int i = 0; i < 4; i++) {
                    int r0 = bm + wm * 64 + i * 16 + lr;
                    atomicAdd(Cb + (long)n0 * ldc + r0,           acc[i][j][0] * sn0);
                    atomicAdd(Cb + (long)(n0 + 1) * ldc + r0,     acc[i][j][1] * sn1);
                    atomicAdd(Cb + (long)n0 * ldc + r0 + 8,       acc[i][j][2] * sn0);
                    atomicAdd(Cb + (long)(n0 + 1) * ldc + r0 + 8, acc[i][j][3] * sn1);
                }
            }
        }
    }
}

// ---------------- fused utility kernels ----------------
struct PrepArgs {
    const float* src[13];
    float* dst[13];
    long n[13];
    int typ[13];                 // 0 = tf32 round ; 1 = f32->fp16 ; 2 = zero
    const float *W1, *W2, *b1, *b2;
    float *W12, *bsum;
};
// seg = base + blockIdx.y: segs 0-12 typed ops; 13 = W12 concat; 14 = bsum
__global__ void prep(PrepArgs a, int base) {
    int seg = base + blockIdx.y;
    long i0 = (long)blockIdx.x * blockDim.x + threadIdx.x;
    long stride = (long)gridDim.x * blockDim.x;
    if (seg < 13) {
        int t = a.typ[seg];
        long n4 = a.n[seg] >> 2;
        if (t == 0) {
            const float4* s = (const float4*)a.src[seg];
            float4* d = (float4*)a.dst[seg];
            for (long i = i0; i < n4; i += stride) d[i] = rnd4(s[i]);
        } else if (t == 1) {
            const float4* s = (const float4*)a.src[seg];
            __half* d = (__half*)a.dst[seg];
            for (long i = i0; i < n4; i += stride) {
                float4 v = s[i];
                __half2 h0 = __floats2half2_rn(v.x, v.y);
                __half2 h1 = __floats2half2_rn(v.z, v.w);
                uint2 o; o.x = *(uint32_t*)&h0; o.y = *(uint32_t*)&h1;
                *(uint2*)(d + (i << 2)) = o;
            }
        } else {
            float4* z = (float4*)a.dst[seg];
            float4 v = make_float4(0.f, 0.f, 0.f, 0.f);
            for (long i = i0; i < n4; i += stride) z[i] = v;
        }
    } else if (seg == 13) {
        float4* d = (float4*)a.W12;
        for (long i = i0; i < 131072L; i += stride) {
            long bse = i << 2;
            int n = (int)(bse >> 10), k = (int)(bse & 1023);
            float4 v = (k < 512) ? *(const float4*)(a.W1 + (long)n * 512 + k)
                                 : *(const float4*)(a.W2 + (long)n * 512 + k - 512);
            d[i] = rnd4(v);
        }
    } else {
        for (long i = i0; i < 512; i += stride) a.bsum[i] = a.b1[i] + a.b2[i];
    }
}

// seg0: stats recips (R->fp16*1024, C->fp32/1024); seg1: ATT prefill; seg2: A3 = bp3
__global__ void fuse2(float* stats,
                      __half* r1h, __half* r2h, __half* r4h,
                      const float* __restrict__ x3, const float* __restrict__ bsum,
                      const float* __restrict__ bp4, const float* __restrict__ wscal,
                      float* __restrict__ ATT,
                      const float* __restrict__ bp3, float* __restrict__ A3)
{
    int seg = blockIdx.y;
    long i0 = (long)blockIdx.x * blockDim.x + threadIdx.x;
    long stride = (long)gridDim.x * blockDim.x;
    if (seg == 0) {
        for (long i = i0; i < 88064; i += stride) {
            float r = 1.0f / stats[i];
            if (i < 36864)       r1h[i] = __float2half(r * 1024.0f);
            else if (i < 38912)  stats[i] = r * 0.0009765625f;
            else if (i < 48128)  r2h[i - 38912] = __float2half(r * 1024.0f);
            else if (i < 50176)  stats[i] = r * 0.0009765625f;
            else if (i < 87040)  r4h[i - 50176] = __float2half(r * 1024.0f);
            else                 stats[i] = r * 0.0009765625f;
        }
    } else if (seg == 1) {
        float f = 1.0f / (1.0f + expf(-wscal[0]));
        float other = (1.0f - f) * 0.5f;
        for (long i = i0; i < (long)BB * N3_ * D2_; i += stride) {
            int col = (int)(i & (D2_ - 1));
            ATT[i] = x3[i] + other * bsum[col] + f * bp4[col];
        }
    } else {
        for (long i = i0; i < (long)BB * N2_ * D1_; i += stride)
            A3[i] = bp3[(int)(i & (D1_ - 1))];
    }
}

// RA -> fp16 1024/x ; CA -> fp32 (1/x)/1024
__global__ void recip2(float* ra, __half* rah, int nr, float* ca, int nc) {
    int i = blockIdx.x * blockDim.x + threadIdx.x;
    if (i < nr) rah[i] = __float2half(1024.0f / ra[i]);
    else if (i < nr + nc) { int j = i - nr; ca[j] = (1.0f / ca[j]) * 0.0009765625f; }
}

// LN over last dim + fused out-prefill
__global__ void ln_rows(const float* __restrict__ X, const float* __restrict__ g,
                        const float* __restrict__ bb, float* __restrict__ Y, int C,
                        const float* __restrict__ bfc2, float* __restrict__ outp)
{
    long row = blockIdx.x;
    const float* x = X + row * C;
    float s = 0.f, s2 = 0.f;
    for (int c = threadIdx.x; c < C; c += blockDim.x) { float v = x[c]; s += v; s2 += v * v; }
    __shared__ float sh1[32], sh2[32];
    int lane = threadIdx.x & 31, wid = threadIdx.x >> 5;
#pragma unroll
    for (int o = 16; o; o >>= 1) {
        s  += __shfl_down_sync(0xffffffff, s,  o);
        s2 += __shfl_down_sync(0xffffffff, s2, o);
    }
    if (!lane) { sh1[wid] = s; sh2[wid] = s2; }
    __syncthreads();
    if (threadIdx.x == 0) {
        float a = 0.f, c2 = 0.f;
        int nw = blockDim.x >> 5;
        for (int i = 0; i < nw; i++) { a += sh1[i]; c2 += sh2[i]; }
        float mean = a / C;
        float var  = c2 / C - mean * mean;
        sh1[0] = mean; sh2[0] = rsqrtf(var + 1e-5f);
    }
    __syncthreads();
    float mean = sh1[0], rstd = sh2[0];
    for (int c = threadIdx.x; c < C; c += blockDim.x) {
        float v = x[c];
        Y[row * C + c] = to_tf32((v - mean) * rstd * g[c] + bb[c]);
        outp[row * C + c] = v + bfc2[c];
    }
}

__global__ void __launch_bounds__(256) dwconv_ln_gelu(
    const float* __restrict__ H, const float* __restrict__ Wdw,
    const float* __restrict__ bdw, const float* __restrict__ g,
    const float* __restrict__ bt, float* __restrict__ AX)
{
    const int n = blockIdx.x;
    const int b = blockIdx.y;
    const int y = n / 24, x = n % 24;
    const float* Hb = H + (long)b * 576 * 2048;
    const int tid = threadIdx.x;

    float v[8];
    float s = 0.f, s2 = 0.f;
#pragma unroll
    for (int it = 0; it < 8; it++) {
        int c = tid + it * 256;
        float a = Hb[(long)n * 2048 + c] + bdw[c];
#pragma unroll
        for (int ky = 0; ky < 3; ky++) {
            int yy = y + ky - 1;
            if (yy < 0 || yy > 23) continue;
#pragma unroll
            for (int kx = 0; kx < 3; kx++) {
                int xx = x + kx - 1;
                if (xx < 0 || xx > 23) continue;
                a += Wdw[c * 9 + ky * 3 + kx] * Hb[(long)(yy * 24 + xx) * 2048 + c];
            }
        }
        v[it] = a; s += a; s2 += a * a;
    }
    __shared__ float sh1[32], sh2[32];
    int lane = tid & 31, wid = tid >> 5;
#pragma unroll
    for (int o = 16; o; o >>= 1) {
        s  += __shfl_down_sync(0xffffffff, s,  o);
        s2 += __shfl_down_sync(0xffffffff, s2, o);
    }
    if (!lane) { sh1[wid] = s; sh2[wid] = s2; }
    __syncthreads();
    if (tid == 0) {
        float a = 0.f, c2 = 0.f;
        for (int i = 0; i < 8; i++) { a += sh1[i]; c2 += sh2[i]; }
        float mean = a / 2048.0f;
        float var  = c2 / 2048.0f - mean * mean;
        sh1[0] = mean; sh2[0] = rsqrtf(var + 1e-5f);
    }
    __syncthreads();
    float mean = sh1[0], rstd = sh2[0];
    float* out = AX + ((long)b * 576 + n) * 2048;
#pragma unroll
    for (int it = 0; it < 8; it++) {
        int c = tid + it * 256;
        float t = (v[it] - mean) * rstd * g[c] + bt[c];
        out[c] = to_tf32(0.5f * t * (1.0f + erff(t * 0.70710678118654752f)));
    }
}

// ---------------- host orchestration ----------------
#define SET_SMEM(k) cudaFuncSetAttribute(k, cudaFuncAttributeMaxDynamicSharedMemorySize, SMEM_DYN)

static Job mk_job(const float* A, long aStr, int lda,
                  const float* B, long bStr, int ldb,
                  float* C, long cStr, int ldc,
                  int m, int n, int k, int splits, int gx, int gy, int amode,
                  const float* ksc = nullptr, const float* msc = nullptr,
                  float* rsum = nullptr, float* csum = nullptr) {
    Job J;
    J.A = A; J.Bm = B; J.C = C;
    J.aStr = aStr; J.bStr = bStr; J.cStr = cStr;
    J.lda = lda; J.ldb = ldb; J.ldc = ldc;
    J.mTot = m; J.nTot = n; J.kTot = k; J.splits = splits; J.gx = gx; J.gy = gy;
    J.amode = amode;
    J.kscale = ksc; J.mscale = msc; J.rowsum = rsum; J.colsum = csum;
    return J;
}

extern "C" void kernel_launch(void* const* d_in, const int* in_sizes, int n_in,
                              void* d_out, int out_size)
{
    const float* x      = (const float*)d_in[0];
    const float* x2     = (const float*)d_in[1];
    const float* x3     = (const float*)d_in[2];
    const float* W_lin  = (const float*)d_in[3];
    const float* W_lin2 = (const float*)d_in[4];
    const float* W_lin3 = (const float*)d_in[5];
    const float* W_lin4 = (const float*)d_in[6];
    const float* w      = (const float*)d_in[7];
    const float* Wp1 = (const float*)d_in[8];  const float* bp1 = (const float*)d_in[9];
    const float* Wp2 = (const float*)d_in[10]; const float* bp2 = (const float*)d_in[11];
    const float* Wp3 = (const float*)d_in[12]; const float* bp3 = (const float*)d_in[13];
    const float* Wp4 = (const float*)d_in[14]; const float* bp4 = (const float*)d_in[15];
    const float* g_norm = (const float*)d_in[16]; const float* b_norm = (const float*)d_in[17];
    const float* Wfc1 = (const float*)d_in[18];   const float* bfc1  = (const float*)d_in[19];
    const float* Wdw  = (const float*)d_in[20];   const float* bdw   = (const float*)d_in[21];
    const float* g_ln1 = (const float*)d_in[22];  const float* b_ln1 = (const float*)d_in[23];
    const float* Wfc2 = (const float*)d_in[24];   const float* bfc2  = (const float*)d_in[25];

    float* pool = nullptr;
    cudaGetSymbolAddress((void**)&pool, g_pool);

    SET_SMEM((tgemm<1,false>));
    SET_SMEM((tgemm<0,true>));
    SET_SMEM((tgemm<2,false>));
    SET_SMEM((tgemm<6,false>));
    SET_SMEM((hgemm<1,false>));
    SET_SMEM((hgemm<5,true>));

    // streams/events (created once; host code only runs during capture/correctness)
    static cudaStream_t s1 = nullptr;
    static cudaEvent_t evStart = nullptr, evB = nullptr, evS = nullptr, evP = nullptr;
    if (!s1) {
        cudaStreamCreateWithFlags(&s1, cudaStreamNonBlocking);
        cudaEventCreateWithFlags(&evStart, cudaEventDisableTiming);
        cudaEventCreateWithFlags(&evB, cudaEventDisableTiming);
        cudaEventCreateWithFlags(&evS, cudaEventDisableTiming);
        cudaEventCreateWithFlags(&evP, cudaEventDisableTiming);
    }

    // prep table: segs 0-4 E-critical copies, 5 zero, 6-12 later copies, 13 W12, 14 bsum
    PrepArgs pa;
    {
        const float* srcs[13] = { x, x2, W_lin, W_lin2, W_lin3, nullptr,
                                  x2, x3, W_lin4, Wp3, Wp4, Wfc1, Wfc2 };
        long offs[13] = { OFF_XH, OFF_X2H, OFF_WLH, OFF_WL2H, OFF_WL3H, 0L,
                          OFF_X2R, OFF_X3R, OFF_WL4, OFF_WP3R, OFF_WP4R, OFF_WF1, OFF_WF2 };
        long ns[13] = { (long)BB*N1_*D0_, (long)BB*N2_*D1_,
                        (long)D2_*D0_, (long)D2_*D1_, (long)D1_*D0_, ZERO_CNT,
                        (long)BB*N2_*D1_, (long)BB*N3_*D2_, (long)D2_*D1_,
                        (long)D1_*D1_, (long)D2_*D2_, (long)DH_*D2_, (long)D2_*DH_ };
        int typs[13] = { 1, 1, 1, 1, 1, 2, 0, 0, 0, 0, 0, 0, 0 };
        for (int i = 0; i < 13; i++) {
            pa.src[i] = srcs[i]; pa.dst[i] = pool + offs[i]; pa.n[i] = ns[i]; pa.typ[i] = typs[i];
        }
        pa.W1 = Wp1; pa.W2 = Wp2; pa.b1 = bp1; pa.b2 = bp2;
        pa.W12 = pool + OFF_WP12; pa.bsum = pool + OFF_BSUM;
    }
    const float* x2r = pool + OFF_X2R;
    const float* x3r = pool + OFF_X3R;

    // fork s1
    cudaEventRecord(evStart, 0);
    cudaStreamWaitEvent(s1, evStart, 0);

    // prepA (E-critical + zero) on s0; prepB (rest) on s1
    prep<<<dim3(512, 6), 256, 0, 0>>>(pa, 0);
    prep<<<dim3(512, 9), 256, 0, s1>>>(pa, 6);
    cudaEventRecord(evB, s1);

    // E-group on s0
    {
        Jobs js;
        js.j[0] = mk_job(pool+OFF_XH, (long)N1_*D0_, D0_, pool+OFF_WLH, 0L, D0_,
                         pool+OFF_ET1, (long)D2_*N1_, N1_, N1_, D2_, D0_, 1, 4, 72, 0,
                         nullptr, nullptr, pool+OFF_R1, pool+OFF_C1);
        js.j[1] = mk_job(pool+OFF_X2H, (long)N2_*D1_, D1_, pool+OFF_WL2H, 0L, D1_,
                         pool+OFF_ET2, (long)D2_*N2_, N2_, N2_, D2_, D1_, 1, 4, 18, 0,
                         nullptr, nullptr, pool+OFF_R2, pool+OFF_C2);
        js.j[2] = mk_job(pool+OFF_XH, (long)N1_*D0_, D0_, pool+OFF_WL3H, 0L, D0_,
                         pool+OFF_ET4, (long)D1_*N1_, N1_, N1_, D1_, D0_, 1, 2, 72, 0,
                         nullptr, nullptr, pool+OFF_R4, pool+OFF_C4);
        js.off[0] = 0; js.off[1] = 288; js.off[2] = 360; js.off[3] = 504;
        hgemm<1,false><<<dim3(504,1,BB), 256, SMEM_DYN, 0>>>(js);
    }

    // fuse2 needs bsum (prepB)
    cudaStreamWaitEvent(0, evB, 0);
    fuse2<<<dim3(1024, 3), 256, 0, 0>>>(pool,
        (__half*)(pool + OFF_R1H), (__half*)(pool + OFF_R2H), (__half*)(pool + OFF_R4H),
        x3, pool+OFF_BSUM, bp4, w, pool+OFF_ATT, bp3, pool+OFF_A3);

    // S-group (St1+St2+St3) on s0
    {
        Jobs js;
        js.j[0] = mk_job(pool+OFF_ET1, (long)D2_*N1_, N1_, pool+OFF_ET1, (long)D2_*N1_, N1_,
                         pool+OFF_ST12, (long)2*D2_*D2_, D2_, D2_, D2_, N1_, 4, 10, 1, 0,
                         (const float*)(pool+OFF_R1H), pool+OFF_C1);
        js.j[1] = mk_job(pool+OFF_ET2, (long)D2_*N2_, N2_, pool+OFF_ET2, (long)D2_*N2_, N2_,
                         pool+OFF_ST12 + (long)D2_*D2_, (long)2*D2_*D2_, D2_, D2_, D2_, N2_, 2, 10, 1, 0,
                         (const float*)(pool+OFF_R2H), pool+OFF_C2);
        js.j[2] = mk_job(pool+OFF_ET4, (long)D1_*N1_, N1_, pool+OFF_ET4, (long)D1_*N1_, N1_,
                         pool+OFF_ST3, (long)D1_*D1_, D1_, D1_, D1_, N1_, 4, 3, 1, 0,
                         (const float*)(pool+OFF_R4H), pool+OFF_C4);
        js.off[0] = 0; js.off[1] = 40; js.off[2] = 60; js.off[3] = 72;
        hgemm<5,true><<<dim3(72,1,BB), 256, SMEM_DYN, 0>>>(js);
    }
    cudaEventRecord(evS, 0);

    // ---- chain P on s1: T12 -> ATT += other*(T12@Wp12^T) ----
    cudaStreamWaitEvent(s1, evS, 0);
    {
        Jobs js;
        js.j[0] = mk_job(x3r, (long)N3_*D2_, D2_, pool+OFF_ST12, (long)2*D2_*D2_, D2_,
                         pool+OFF_T12, (long)N3_*2*D2_, 2*D2_, N3_, 2*D2_, D2_, 1, 8, 5, 0);
        js.j[1] = js.j[0]; js.j[2] = js.j[0];
        js.off[0] = 0; js.off[1] = 40; js.off[2] = 40; js.off[3] = 40;
        tgemm<0,true><<<dim3(40,1,BB), 256, SMEM_DYN, s1>>>(js, nullptr, nullptr);
    }
    {
        Jobs js;
        js.j[0] = mk_job(pool+OFF_T12, (long)N3_*2*D2_, 2*D2_, pool+OFF_WP12, 0L, 2*D2_,
                         pool+OFF_ATT, (long)N3_*D2_, D2_, N3_, D2_, 2*D2_, 2, 4, 5, 2);
        js.j[1] = js.j[0]; js.j[2] = js.j[0];
        js.off[0] = 0; js.off[1] = 40; js.off[2] = 40; js.off[3] = 40;
        tgemm<6,false><<<dim3(40,1,BB), 256, SMEM_DYN, s1>>>(js, nullptr, w);
    }
    cudaEventRecord(evP, s1);

    // ---- chain Q on s0 ----
    // T3 = x2 @ St3
    {
        Jobs js;
        js.j[0] = mk_job(x2r, (long)N2_*D1_, D1_, pool+OFF_ST3, (long)D1_*D1_, D1_,
                         pool+OFF_T3, (long)N2_*D1_, D1_, N2_, D1_, D1_, 1, 2, 18, 0);
        js.j[1] = js.j[0]; js.j[2] = js.j[0];
        js.off[0] = 0; js.off[1] = 36; js.off[2] = 36; js.off[3] = 36;
        tgemm<0,true><<<dim3(36,1,BB), 256, SMEM_DYN, 0>>>(js, nullptr, nullptr);
    }
    // A3 += T3 @ Wp3^T
    {
        Jobs js;
        js.j[0] = mk_job(pool+OFF_T3, (long)N2_*D1_, D1_, pool+OFF_WP3R, 0L, D1_,
                         pool+OFF_A3, (long)N2_*D1_, D1_, N2_, D1_, D1_, 1, 2, 18, 0);
        js.j[1] = js.j[0]; js.j[2] = js.j[0];
        js.off[0] = 0; js.off[1] = 36; js.off[2] = 36; js.off[3] = 36;
        tgemm<6,false><<<dim3(36,1,BB), 256, SMEM_DYN, 0>>>(js, nullptr, w);
    }
    // EtA (tf32 EPI1 -> fp16)
    {
        Jobs js;
        js.j[0] = mk_job(pool+OFF_A3, (long)N2_*D1_, D1_, pool+OFF_WL4, 0L, D1_,
                         pool+OFF_ETA, (long)D2_*N2_, N2_, N2_, D2_, D1_, 1, 4, 18, 0,
                         nullptr, nullptr, pool+OFF_RA, pool+OFF_CA);
        js.j[1] = js.j[0]; js.j[2] = js.j[0];
        js.off[0] = 0; js.off[1] = 72; js.off[2] = 72; js.off[3] = 72;
        tgemm<1,false><<<dim3(72,1,BB), 256, SMEM_DYN, 0>>>(js, nullptr, nullptr);
    }
    recip2<<<(11264 + 255) / 256, 256, 0, 0>>>(pool + OFF_RA, (__half*)(pool + OFF_RAH),
                                               BB * N2_, pool + OFF_CA, BB * D2_);
    // St4 (fp16 symmetric, split-K 2)
    {
        Jobs js;
        js.j[0] = mk_job(pool+OFF_ETA, (long)D2_*N2_, N2_, pool+OFF_ETA, (long)D2_*N2_, N2_,
                         pool+OFF_ST4, (long)D2_*D2_, D2_, D2_, D2_, N2_, 2, 10, 1, 0,
                         (const float*)(pool+OFF_RAH), pool+OFF_CA);
        js.j[1] = js.j[0]; js.j[2] = js.j[0];
        js.off[0] = 0; js.off[1] = 20; js.off[2] = 20; js.off[3] = 20;
        hgemm<5,true><<<dim3(20,1,BB), 256, SMEM_DYN, 0>>>(js);
    }
    // 17a) T = x3 @ St4
    {
        Jobs js;
        js.j[0] = mk_job(x3r, (long)N3_*D2_, D2_, pool+OFF_ST4, (long)D2_*D2_, D2_,
                         pool+OFF_T, (long)N3_*D2_, D2_, N3_, D2_, D2_, 1, 4, 5, 0);
        js.j[1] = js.j[0]; js.j[2] = js.j[0];
        js.off[0] = 0; js.off[1] = 20; js.off[2] = 20; js.off[3] = 20;
        tgemm<0,true><<<dim3(20,1,BB), 256, SMEM_DYN, 0>>>(js, nullptr, nullptr);
    }
    // 17b) ATT += f*(T @ Wp4^T)
    {
        Jobs js;
        js.j[0] = mk_job(pool+OFF_T, (long)N3_*D2_, D2_, pool+OFF_WP4R, 0L, D2_,
                         pool+OFF_ATT, (long)N3_*D2_, D2_, N3_, D2_, D2_, 2, 4, 5, 1);
        js.j[1] = js.j[0]; js.j[2] = js.j[0];
        js.off[0] = 0; js.off[1] = 40; js.off[2] = 40; js.off[3] = 40;
        tgemm<6,false><<<dim3(40,1,BB), 256, SMEM_DYN, 0>>>(js, nullptr, w);
    }

    // join chain P, then tail on s0
    cudaStreamWaitEvent(0, evP, 0);
    ln_rows<<<BB * N3_, 256, 0, 0>>>(pool + OFF_ATT, g_norm, b_norm, pool + OFF_AN, D2_,
                                     bfc2, (float*)d_out);
    {
        Jobs js;
        js.j[0] = mk_job(pool+OFF_AN, (long)N3_*D2_, D2_, pool+OFF_WF1, 0L, D2_,
                         pool+OFF_H, (long)N3_*DH_, DH_, N3_, DH_, D2_, 1, 16, 5, 0);
        js.j[1] = js.j[0]; js.j[2] = js.j[0];
        js.off[0] = 0; js.off[1] = 80; js.off[2] = 80; js.off[3] = 80;
        tgemm<2,false><<<dim3(80,1,BB), 256, SMEM_DYN, 0>>>(js, bfc1, nullptr);
    }
    dwconv_ln_gelu<<<dim3(N3_, BB), 256, 0, 0>>>(pool + OFF_H, Wdw, bdw, g_ln1, b_ln1, pool + OFF_AX);
    {
        Jobs js;
        js.j[0] = mk_job(pool+OFF_AX, (long)N3_*DH_, DH_, pool+OFF_WF2, 0L, DH_,
                         (float*)d_out, (long)N3_*D2_, D2_, N3_, D2_, DH_, 4, 4, 5, 0);
        js.j[1] = js.j[0]; js.j[2] = js.j[0];
        js.off[0] = 0; js.off[1] = 80; js.off[2] = 80; js.off[3] = 80;
        tgemm<6,false><<<dim3(80,1,BB), 256, SMEM_DYN, 0>>>(js, nullptr, nullptr);
    }
}

// round 17
// speedup vs baseline: 2.7721x; 1.1787x over previous
#include <cuda_runtime.h>
#include <cuda_fp16.h>
#include <math.h>
#include <stdint.h>

// ---------------- problem dims ----------------
#define BB   4
#define N1_  9216
#define N2_  2304
#define N3_  576
#define D0_  128
#define D1_  256
#define D2_  512
#define DH_  2048

// ---------------- scratch pool (floats) ----------------
#define OFF_R1   0L
#define OFF_C1   36864L
#define OFF_R2   38912L
#define OFF_C2   48128L
#define OFF_R4   50176L
#define OFF_C4   87040L
#define OFF_RA   88064L
#define OFF_CA   97280L
#define OFF_ST12 99328L            // [B][1024][512] fp32 (atomic target)
#define OFF_ST3  2196480L          // [B][256][256]  fp32
#define OFF_ST4  2458624L          // [B][512][512]  fp32
#define ZERO_CNT 3507200L
#define OFF_ET1  3507200L          // fp16 [B][512][9216]
#define OFF_ET2  22381568L         // fp16
#define OFF_ET4  27100160L         // fp16
#define OFF_ETA  36537344L         // fp16 [B][512][2304]
#define OFF_T    41255936L         // (spare)
#define OFF_A3   44794880L         // fp32
#define OFF_ATT  47154176L         // fp32
#define OFF_AN   48333824L         // fp16 now (slot large enough)
#define OFF_H    49513472L         // fp32
#define OFF_AX   54232064L         // fp16 now
#define OFF_XH   58950656L         // fp16 x
#define OFF_X2H  61309952L         // fp16 x2
#define OFF_WLH  67208192L
#define OFF_WL2H 67273728L
#define OFF_WL3H 67404800L
#define OFF_WL4  67437568L         // tf32 (EtA path)
// fp16 scaled row-recips
#define OFF_R1H  69993472L
#define OFF_R2H  70011904L
#define OFF_R4H  70016512L
#define OFF_RAH  70034944L
// new fp16 buffers
#define OFF_X3H   70039552L
#define OFF_WP12H 70629376L
#define OFF_WP3H  70891520L
#define OFF_WP4H  70924288L
#define OFF_WF1H  71055360L
#define OFF_WF2H  71579648L
#define OFF_ST12H 72103936L
#define OFF_ST3H  73152512L
#define OFF_ST4H  73283584L
#define OFF_T12H  73807872L
#define OFF_T3H   74987520L
#define OFF_TH    76167168L
#define POOL_SZ   76756992L

#define OFF_BSUM  (OFF_T + 524288L)

__device__ float g_pool[POOL_SZ];

#define STAGEB  18432u
#define BOFF    55296u
#define SMEM_DYN 110592

// ---------------- job table ----------------
struct Job {
    const float *A, *Bm;
    float *C;
    long aStr, bStr, cStr;   // element units of their respective dtypes
    int lda, ldb, ldc;
    int mTot, nTot, kTot, splits, gx, gy, amode;
    const float *kscale, *mscale;
    float *rowsum, *colsum;
};
struct Jobs { Job j[3]; int off[4]; };

// ---------------- helpers ----------------
__device__ __forceinline__ uint32_t smem_u32(const void* p) {
    uint32_t a;
    asm("{ .reg .u64 t; cvta.to.shared.u64 t, %1; cvt.u32.u64 %0, t; }" : "=r"(a) : "l"(p));
    return a;
}
__device__ __forceinline__ float to_tf32(float x) {
    float y;
    asm("cvt.rna.tf32.f32 %0, %1;" : "=f"(y) : "f"(x));
    return y;
}
__device__ __forceinline__ float4 rnd4(float4 v) {
    v.x = to_tf32(v.x); v.y = to_tf32(v.y); v.z = to_tf32(v.z); v.w = to_tf32(v.w);
    return v;
}
__device__ __forceinline__ void mma_tf32(float* d, const uint32_t* a, const uint32_t* bf) {
    asm volatile(
        "mma.sync.aligned.m16n8k8.row.col.f32.tf32.tf32.f32 "
        "{%0,%1,%2,%3}, {%4,%5,%6,%7}, {%8,%9}, {%0,%1,%2,%3};"
        : "+f"(d[0]), "+f"(d[1]), "+f"(d[2]), "+f"(d[3])
        : "r"(a[0]), "r"(a[1]), "r"(a[2]), "r"(a[3]), "r"(bf[0]), "r"(bf[1]));
}
__device__ __forceinline__ void mma_f16(float* d, const uint32_t* a, const uint32_t* bf) {
    asm volatile(
        "mma.sync.aligned.m16n8k16.row.col.f32.f16.f16.f32 "
        "{%0,%1,%2,%3}, {%4,%5,%6,%7}, {%8,%9}, {%0,%1,%2,%3};"
        : "+f"(d[0]), "+f"(d[1]), "+f"(d[2]), "+f"(d[3])
        : "r"(a[0]), "r"(a[1]), "r"(a[2]), "r"(a[3]), "r"(bf[0]), "r"(bf[1]));
}
__device__ __forceinline__ void ldm_x4(uint32_t* r, uint32_t addr) {
    asm volatile("ldmatrix.sync.aligned.m8n8.x4.shared.b16 {%0,%1,%2,%3}, [%4];"
        : "=r"(r[0]), "=r"(r[1]), "=r"(r[2]), "=r"(r[3]) : "r"(addr));
}
__device__ __forceinline__ void cpa16(uint32_t dst, const void* src, bool valid) {
    int sz = valid ? 16 : 0;
    asm volatile("cp.async.cg.shared.global [%0], [%1], 16, %2;"
        :: "r"(dst), "l"(src), "r"(sz) : "memory");
}
__device__ __forceinline__ uint32_t h2mul(uint32_t a, __half2 s) {
    __half2 v = __hmul2(*(__half2*)&a, s);
    return *(uint32_t*)&v;
}
#define CP_COMMIT() asm volatile("cp.async.commit_group;" ::: "memory")
#define CP_WAIT1()  asm volatile("cp.async.wait_group 1;" ::: "memory")

// ================= fp32/tf32 NT GEMM (BK=32) — only EtA uses this now ======
// EPI 1: exp -> fp16 Et (cStr HALF units) + stats
template<int EPI>
__global__ void __launch_bounds__(256, 2) tgemm(
    Jobs jobs, const float* __restrict__ bias, const float* __restrict__ wscal)
{
    extern __shared__ float dynsm[];

    int q = blockIdx.x;
    int ji = 0;
    if (q >= jobs.off[1]) ji = 1;
    if (q >= jobs.off[2]) ji = 2;
    q -= jobs.off[ji];
    const Job J = jobs.j[ji];

    const int b = blockIdx.z;
    const int Kc = J.kTot / J.splits;
    const int gxy = J.gx * J.gy;
    int sp = q / gxy;
    int r0q = q % gxy;
    int bxq = r0q % J.gx, byq = r0q / J.gx;
    const int kbase = sp * Kc;
    const int nt = Kc >> 5;
    const int bm = byq * 128;
    const int bn = bxq * 128;

    const float* Ab = J.A + (long)b * J.aStr;
    const float* Bb = J.Bm + (long)b * J.bStr;
    const int lda = J.lda, ldb = J.ldb;
    const int mTot = J.mTot;

    const int tid = threadIdx.x;
    const int wid = tid >> 5, lane = tid & 31;
    const int wm = wid & 1, wn = wid >> 1;
    const int lr = lane >> 2, lc = lane & 3;

    const uint32_t smBase = smem_u32(dynsm);
    const int g8 = lane >> 3;
    const int r8 = lane & 7;
    const uint32_t asBase = smBase +
        (uint32_t)(((wm * 64 + (g8 & 1) * 8 + r8) * 36 + (g8 >> 1) * 4) * 4);
    const uint32_t bsBase = smBase + BOFF +
        (uint32_t)(((wn * 32 + (g8 >> 1) * 8 + r8) * 36 + (g8 & 1) * 4) * 4);

    auto issue_copy = [&](int tt, uint32_t stOff) {
        const int k0 = kbase + (tt << 5);
        const uint32_t aS = smBase + stOff;
        const uint32_t bS = smBase + BOFF + stOff;
#pragma unroll
        for (int l = 0; l < 4; l++) {
            int c = tid + (l << 8);
            int row = c >> 3, kq = (c & 7) << 2;
            uint32_t off = (uint32_t)((row * 36 + kq) * 4);
            cpa16(aS + off, Ab + (long)(bm + row) * lda + k0 + kq, (bm + row) < mTot);
            cpa16(bS + off, Bb + (long)(bn + row) * ldb + k0 + kq, true);
        }
    };

    float acc[4][4][4];
#pragma unroll
    for (int i = 0; i < 4; i++)
#pragma unroll
        for (int j = 0; j < 4; j++)
#pragma unroll
            for (int r = 0; r < 4; r++) acc[i][j][r] = 0.0f;

    issue_copy(0, 0);        CP_COMMIT();
    if (nt > 1) { issue_copy(1, STAGEB); }
    CP_COMMIT();

    uint32_t curOff = 0, nxtOff = STAGEB, thrOff = 2 * STAGEB;

    for (int t = 0; t < nt; t++) {
        CP_WAIT1();
        __syncthreads();
        if (t + 2 < nt) issue_copy(t + 2, thrOff);
        CP_COMMIT();

        const uint32_t aCur = asBase + curOff;
        const uint32_t bCur = bsBase + curOff;
#pragma unroll
        for (int ks = 0; ks < 4; ks++) {
            uint32_t af[4][4];
#pragma unroll
            for (int i = 0; i < 4; i++)
                ldm_x4(af[i], aCur + i * 2304 + ks * 32);
            uint32_t bf[4][2];
#pragma unroll
            for (int j2 = 0; j2 < 2; j2++) {
                uint32_t r4[4];
                ldm_x4(r4, bCur + j2 * 2304 + ks * 32);
                bf[2 * j2][0] = r4[0]; bf[2 * j2][1] = r4[1];
                bf[2 * j2 + 1][0] = r4[2]; bf[2 * j2 + 1][1] = r4[3];
            }
#pragma unroll
            for (int i = 0; i < 4; i++)
#pragma unroll
                for (int j = 0; j < 4; j++)
                    mma_tf32(acc[i][j], af[i], bf[j]);
        }
        uint32_t tmp = curOff; curOff = nxtOff; nxtOff = thrOff; thrOff = tmp;
    }
    __syncthreads();

    const int ldc = J.ldc;

    // EPI 1 only
    float rs[4][2];
#pragma unroll
    for (int i = 0; i < 4; i++) { rs[i][0] = 0.f; rs[i][1] = 0.f; }
#pragma unroll
    for (int j = 0; j < 4; j++) {
        int col0 = bn + wn * 32 + j * 8 + lc * 2;
        float cs0 = 0.f, cs1 = 0.f;
#pragma unroll
        for (int i = 0; i < 4; i++) {
            float e0 = __half2float(__float2half_rn(expf(acc[i][j][0])));
            float e1 = __half2float(__float2half_rn(expf(acc[i][j][1])));
            float e2 = __half2float(__float2half_rn(expf(acc[i][j][2])));
            float e3 = __half2float(__float2half_rn(expf(acc[i][j][3])));
            acc[i][j][0] = e0; acc[i][j][1] = e1;
            acc[i][j][2] = e2; acc[i][j][3] = e3;
            cs0 += e0 + e2; cs1 += e1 + e3;
            rs[i][0] += e0 + e1; rs[i][1] += e2 + e3;
        }
#pragma unroll
        for (int o = 4; o <= 16; o <<= 1) {
            cs0 += __shfl_xor_sync(0xffffffff, cs0, o);
            cs1 += __shfl_xor_sync(0xffffffff, cs1, o);
        }
        if (lane < 4) {
            atomicAdd(J.colsum + (long)b * J.nTot + col0, cs0);
            atomicAdd(J.colsum + (long)b * J.nTot + col0 + 1, cs1);
        }
    }
#pragma unroll
    for (int i = 0; i < 4; i++)
#pragma unroll
        for (int h = 0; h < 2; h++) {
            float v = rs[i][h];
            v += __shfl_xor_sync(0xffffffff, v, 1);
            v += __shfl_xor_sync(0xffffffff, v, 2);
            if (lc == 0) {
                int r = bm + wm * 64 + i * 16 + lr + h * 8;
                atomicAdd(J.rowsum + (long)b * mTot + r, v);
            }
        }
    float* stg = dynsm;
    __half* Ch = (__half*)J.C + (long)b * J.cStr;
#pragma unroll
    for (int h2 = 0; h2 < 2; h2++) {
        __syncthreads();
        if ((wn >> 1) == h2) {
            int snb = wn * 32 - h2 * 64;
#pragma unroll
            for (int j = 0; j < 4; j++) {
                int sn = snb + j * 8 + lc * 2;
#pragma unroll
                for (int i = 0; i < 4; i++) {
                    int ml = wm * 64 + i * 16 + lr;
                    stg[sn * 132 + ml]           = acc[i][j][0];
                    stg[(sn + 1) * 132 + ml]     = acc[i][j][1];
                    stg[sn * 132 + ml + 8]       = acc[i][j][2];
                    stg[(sn + 1) * 132 + ml + 8] = acc[i][j][3];
                }
            }
        }
        __syncthreads();
#pragma unroll
        for (int it = 0; it < 8; it++) {
            int id = tid + (it << 8);
            int row = id >> 5, m4 = (id & 31) << 2;
            float4 v = *(float4*)&stg[row * 132 + m4];
            __half2 h0 = __floats2half2_rn(v.x, v.y);
            __half2 h1 = __floats2half2_rn(v.z, v.w);
            uint2 o;
            o.x = *(uint32_t*)&h0; o.y = *(uint32_t*)&h1;
            *(uint2*)(Ch + (long)(bn + h2 * 64 + row) * ldc + bm + m4) = o;
        }
    }
}

// ================= fp16 NT GEMM (BK=64, m16n8k16) =================
// EPI 0: C(fp16) = acc                 EPI 1: exp -> fp16 Et + stats
// EPI 2: C(fp32) = acc + bias[col]     EPI 5: symmetric S atomics (x mscale)
// EPI 6: atomicAdd(C fp32, alpha*acc)  amode: 0=1, 1=sigmoid, 2=(1-sig)/2
template<int EPI, bool KSC>
__global__ void __launch_bounds__(256, 2) hgemm(
    Jobs jobs, const float* __restrict__ bias, const float* __restrict__ wscal)
{
    extern __shared__ float dynsm[];

    int q = blockIdx.x;
    int ji = 0;
    if (q >= jobs.off[1]) ji = 1;
    if (q >= jobs.off[2]) ji = 2;
    q -= jobs.off[ji];
    const Job J = jobs.j[ji];

    const int b = blockIdx.z;
    const int Kc = J.kTot / J.splits;
    int sp, bxq, byq;
    if (EPI == 5) {
        sp = q / J.gx;
        int tri = q % J.gx;
        const int T = J.nTot >> 7;
        int by = 0;
        while (tri >= T - by) { tri -= (T - by); by++; }
        byq = by; bxq = by + tri;
    } else {
        const int gxy = J.gx * J.gy;
        sp = q / gxy;
        int r0q = q % gxy;
        bxq = r0q % J.gx; byq = r0q / J.gx;
    }
    const int kbase = sp * Kc;
    const int nt = Kc >> 6;
    const int bm = byq * 128;
    const int bn = bxq * 128;

    const __half* Ab = (const __half*)J.A + (long)b * J.aStr;
    const __half* Bb = (const __half*)J.Bm + (long)b * J.bStr;
    const __half2* ksc2 = KSC ? (const __half2*)((const __half*)J.kscale + (long)b * J.kTot) : nullptr;
    const int lda = J.lda, ldb = J.ldb;
    const int mTot = J.mTot;

    const int tid = threadIdx.x;
    const int wid = tid >> 5, lane = tid & 31;
    const int wm = wid & 1, wn = wid >> 1;
    const int lr = lane >> 2, lc = lane & 3;

    const uint32_t smBase = smem_u32(dynsm);
    const int g8 = lane >> 3;
    const int r8 = lane & 7;
    const uint32_t asBase = smBase +
        (uint32_t)(((wm * 64 + (g8 & 1) * 8 + r8) * 72 + (g8 >> 1) * 8) * 2);
    const uint32_t bsBase = smBase + BOFF +
        (uint32_t)(((wn * 32 + (g8 >> 1) * 8 + r8) * 72 + (g8 & 1) * 8) * 2);

    auto issue_copy = [&](int tt, uint32_t stOff) {
        const int k0 = kbase + (tt << 6);
        const uint32_t aS = smBase + stOff;
        const uint32_t bS = smBase + BOFF + stOff;
#pragma unroll
        for (int l = 0; l < 4; l++) {
            int c = tid + (l << 8);
            int row = c >> 3, kq = (c & 7) << 3;
            uint32_t off = (uint32_t)(row * 144 + kq * 2);
            cpa16(aS + off, Ab + (long)(bm + row) * lda + k0 + kq, (bm + row) < mTot);
            cpa16(bS + off, Bb + (long)(bn + row) * ldb + k0 + kq, true);
        }
    };

    float acc[4][4][4];
#pragma unroll
    for (int i = 0; i < 4; i++)
#pragma unroll
        for (int j = 0; j < 4; j++)
#pragma unroll
            for (int r = 0; r < 4; r++) acc[i][j][r] = 0.0f;

    issue_copy(0, 0);        CP_COMMIT();
    if (nt > 1) { issue_copy(1, STAGEB); }
    CP_COMMIT();

    uint32_t curOff = 0, nxtOff = STAGEB, thrOff = 2 * STAGEB;

    for (int t = 0; t < nt; t++) {
        CP_WAIT1();
        __syncthreads();
        if (t + 2 < nt) issue_copy(t + 2, thrOff);
        CP_COMMIT();

        const uint32_t aCur = asBase + curOff;
        const uint32_t bCur = bsBase + curOff;
        const int kh = (kbase + (t << 6)) >> 1;
#pragma unroll
        for (int ks = 0; ks < 4; ks++) {
            uint32_t af[4][4];
#pragma unroll
            for (int i = 0; i < 4; i++)
                ldm_x4(af[i], aCur + i * 2304 + ks * 32);
            __half2 slo, shi;
            if (KSC) {
                slo = ksc2[kh + ks * 8 + lc];
                shi = ksc2[kh + ks * 8 + 4 + lc];
            }
            uint32_t bf[4][2];
#pragma unroll
            for (int j2 = 0; j2 < 2; j2++) {
                uint32_t r4[4];
                ldm_x4(r4, bCur + j2 * 2304 + ks * 32);
                if (KSC) {
                    r4[0] = h2mul(r4[0], slo);
                    r4[1] = h2mul(r4[1], shi);
                    r4[2] = h2mul(r4[2], slo);
                    r4[3] = h2mul(r4[3], shi);
                }
                bf[2 * j2][0] = r4[0]; bf[2 * j2][1] = r4[1];
                bf[2 * j2 + 1][0] = r4[2]; bf[2 * j2 + 1][1] = r4[3];
            }
#pragma unroll
            for (int i = 0; i < 4; i++)
#pragma unroll
                for (int j = 0; j < 4; j++)
                    mma_f16(acc[i][j], af[i], bf[j]);
        }
        uint32_t tmp = curOff; curOff = nxtOff; nxtOff = thrOff; thrOff = tmp;
    }
    __syncthreads();

    const int ldc = J.ldc;

    if (EPI == 1) {
        float rs[4][2];
#pragma unroll
        for (int i = 0; i < 4; i++) { rs[i][0] = 0.f; rs[i][1] = 0.f; }
#pragma unroll
        for (int j = 0; j < 4; j++) {
            int col0 = bn + wn * 32 + j * 8 + lc * 2;
            float cs0 = 0.f, cs1 = 0.f;
#pragma unroll
            for (int i = 0; i < 4; i++) {
                float e0 = __half2float(__float2half_rn(expf(acc[i][j][0])));
                float e1 = __half2float(__float2half_rn(expf(acc[i][j][1])));
                float e2 = __half2float(__float2half_rn(expf(acc[i][j][2])));
                float e3 = __half2float(__float2half_rn(expf(acc[i][j][3])));
                acc[i][j][0] = e0; acc[i][j][1] = e1;
                acc[i][j][2] = e2; acc[i][j][3] = e3;
                cs0 += e0 + e2; cs1 += e1 + e3;
                rs[i][0] += e0 + e1; rs[i][1] += e2 + e3;
            }
#pragma unroll
            for (int o = 4; o <= 16; o <<= 1) {
                cs0 += __shfl_xor_sync(0xffffffff, cs0, o);
                cs1 += __shfl_xor_sync(0xffffffff, cs1, o);
            }
            if (lane < 4) {
                atomicAdd(J.colsum + (long)b * J.nTot + col0, cs0);
                atomicAdd(J.colsum + (long)b * J.nTot + col0 + 1, cs1);
            }
        }
#pragma unroll
        for (int i = 0; i < 4; i++)
#pragma unroll
            for (int h = 0; h < 2; h++) {
                float v = rs[i][h];
                v += __shfl_xor_sync(0xffffffff, v, 1);
                v += __shfl_xor_sync(0xffffffff, v, 2);
                if (lc == 0) {
                    int r = bm + wm * 64 + i * 16 + lr + h * 8;
                    atomicAdd(J.rowsum + (long)b * mTot + r, v);
                }
            }
        float* stg = dynsm;
        __half* Ch = (__half*)J.C + (long)b * J.cStr;
#pragma unroll
        for (int h2 = 0; h2 < 2; h2++) {
            __syncthreads();
            if ((wn >> 1) == h2) {
                int snb = wn * 32 - h2 * 64;
#pragma unroll
                for (int j = 0; j < 4; j++) {
                    int sn = snb + j * 8 + lc * 2;
#pragma unroll
                    for (int i = 0; i < 4; i++) {
                        int ml = wm * 64 + i * 16 + lr;
                        stg[sn * 132 + ml]           = acc[i][j][0];
                        stg[(sn + 1) * 132 + ml]     = acc[i][j][1];
                        stg[sn * 132 + ml + 8]       = acc[i][j][2];
                        stg[(sn + 1) * 132 + ml + 8] = acc[i][j][3];
                    }
                }
            }
            __syncthreads();
#pragma unroll
            for (int it = 0; it < 8; it++) {
                int id = tid + (it << 8);
                int row = id >> 5, m4 = (id & 31) << 2;
                float4 v = *(float4*)&stg[row * 132 + m4];
                __half2 h0 = __floats2half2_rn(v.x, v.y);
                __half2 h1 = __floats2half2_rn(v.z, v.w);
                uint2 o;
                o.x = *(uint32_t*)&h0; o.y = *(uint32_t*)&h1;
                *(uint2*)(Ch + (long)(bn + h2 * 64 + row) * ldc + bm + m4) = o;
            }
        }
    } else if (EPI == 5) {
        float* Cb = J.C + (long)b * J.cStr;
        const float* msc = J.mscale + (long)b * mTot;
#pragma unroll
        for (int i = 0; i < 4; i++) {
            int r0 = bm + wm * 64 + i * 16 + lr;
            float s0 = msc[r0];
            float s1 = msc[r0 + 8];
#pragma unroll
            for (int j = 0; j < 4; j++) {
                int col0 = bn + wn * 32 + j * 8 + lc * 2;
                atomicAdd(Cb + (long)r0 * ldc + col0,           acc[i][j][0] * s0);
                atomicAdd(Cb + (long)r0 * ldc + col0 + 1,       acc[i][j][1] * s0);
                atomicAdd(Cb + (long)(r0 + 8) * ldc + col0,     acc[i][j][2] * s1);
                atomicAdd(Cb + (long)(r0 + 8) * ldc + col0 + 1, acc[i][j][3] * s1);
            }
        }
        if (bxq != byq) {
#pragma unroll
            for (int j = 0; j < 4; j++) {
                int n0 = bn + wn * 32 + j * 8 + lc * 2;
                float sn0 = msc[n0];
                float sn1 = msc[n0 + 1];
#pragma unroll
                for (int i = 0; i < 4; i++) {
                    int r0 = bm + wm * 64 + i * 16 + lr;
                    atomicAdd(Cb + (long)n0 * ldc + r0,           acc[i][j][0] * sn0);
                    atomicAdd(Cb + (long)(n0 + 1) * ldc + r0,     acc[i][j][1] * sn1);
                    atomicAdd(Cb + (long)n0 * ldc + r0 + 8,       acc[i][j][2] * sn0);
                    atomicAdd(Cb + (long)(n0 + 1) * ldc + r0 + 8, acc[i][j][3] * sn1);
                }
            }
        }
    } else if (EPI == 0) {
        __half* Ch = (__half*)J.C + (long)b * J.cStr;
#pragma unroll
        for (int i = 0; i < 4; i++) {
#pragma unroll
            for (int h = 0; h < 2; h++) {
                int r = bm + wm * 64 + i * 16 + lr + h * 8;
                if (r >= mTot) continue;
                __half* Crow = Ch + (long)r * ldc;
#pragma unroll
                for (int j = 0; j < 4; j++) {
                    int col0 = bn + wn * 32 + j * 8 + lc * 2;
                    __half2 o = __floats2half2_rn(acc[i][j][h * 2 + 0], acc[i][j][h * 2 + 1]);
                    *(__half2*)(Crow + col0) = o;
                }
            }
        }
    } else if (EPI == 2) {
        float* Cb = J.C + (long)b * J.cStr;
#pragma unroll
        for (int i = 0; i < 4; i++) {
#pragma unroll
            for (int h = 0; h < 2; h++) {
                int r = bm + wm * 64 + i * 16 + lr + h * 8;
                if (r >= mTot) continue;
                float* Crow = Cb + (long)r * ldc;
#pragma unroll
                for (int j = 0; j < 4; j++) {
                    int col0 = bn + wn * 32 + j * 8 + lc * 2;
                    float2 o;
                    o.x = acc[i][j][h * 2 + 0] + bias[col0];
                    o.y = acc[i][j][h * 2 + 1] + bias[col0 + 1];
                    *(float2*)(Crow + col0) = o;
                }
            }
        }
    } else { // EPI 6
        float alpha = 1.0f;
        if (J.amode != 0) {
            float f = 1.0f / (1.0f + expf(-wscal[0]));
            alpha = (J.amode == 1) ? f : (1.0f - f) * 0.5f;
        }
        float* Cb = J.C + (long)b * J.cStr;
#pragma unroll
        for (int i = 0; i < 4; i++) {
#pragma unroll
            for (int h = 0; h < 2; h++) {
                int r = bm + wm * 64 + i * 16 + lr + h * 8;
                if (r >= mTot) continue;
                float* Crow = Cb + (long)r * ldc;
#pragma unroll
                for (int j = 0; j < 4; j++) {
                    int col0 = bn + wn * 32 + j * 8 + lc * 2;
                    atomicAdd(Crow + col0,     alpha * acc[i][j][h * 2 + 0]);
                    atomicAdd(Crow + col0 + 1, alpha * acc[i][j][h * 2 + 1]);
                }
            }
        }
    }
}

// ---------------- fused utility kernels ----------------
struct PrepArgs {
    const float* src[13];
    float* dst[13];
    long n[13];
    int typ[13];                 // 0 = tf32 round ; 1 = f32->fp16 ; 2 = zero
    const float *W1, *W2, *b1, *b2;
    float *W12h, *bsum;
};
// seg = base + blockIdx.y: 0-12 typed; 13 = W12 fp16 concat; 14 = bsum
__global__ void prep(PrepArgs a, int base) {
    int seg = base + blockIdx.y;
    long i0 = (long)blockIdx.x * blockDim.x + threadIdx.x;
    long stride = (long)gridDim.x * blockDim.x;
    if (seg < 13) {
        int t = a.typ[seg];
        long n4 = a.n[seg] >> 2;
        if (t == 0) {
            const float4* s = (const float4*)a.src[seg];
            float4* d = (float4*)a.dst[seg];
            for (long i = i0; i < n4; i += stride) d[i] = rnd4(s[i]);
        } else if (t == 1) {
            const float4* s = (const float4*)a.src[seg];
            __half* d = (__half*)a.dst[seg];
            for (long i = i0; i < n4; i += stride) {
                float4 v = s[i];
                __half2 h0 = __floats2half2_rn(v.x, v.y);
                __half2 h1 = __floats2half2_rn(v.z, v.w);
                uint2 o; o.x = *(uint32_t*)&h0; o.y = *(uint32_t*)&h1;
                *(uint2*)(d + (i << 2)) = o;
            }
        } else {
            float4* z = (float4*)a.dst[seg];
            float4 v = make_float4(0.f, 0.f, 0.f, 0.f);
            for (long i = i0; i < n4; i += stride) z[i] = v;
        }
    } else if (seg == 13) {
        __half* d = (__half*)a.W12h;
        for (long i = i0; i < 131072L; i += stride) {
            long bse = i << 2;
            int n = (int)(bse >> 10), k = (int)(bse & 1023);
            const float* s = (k < 512) ? (a.W1 + (long)n * 512 + k)
                                       : (a.W2 + (long)n * 512 + k - 512);
            float4 v = *(const float4*)s;
            __half2 h0 = __floats2half2_rn(v.x, v.y);
            __half2 h1 = __floats2half2_rn(v.z, v.w);
            uint2 o; o.x = *(uint32_t*)&h0; o.y = *(uint32_t*)&h1;
            *(uint2*)(d + bse) = o;
        }
    } else {
        for (long i = i0; i < 512; i += stride) a.bsum[i] = a.b1[i] + a.b2[i];
    }
}

// fp32 -> fp16 converter, up to 3 segments
struct CvtArgs { const float* src[3]; float* dst[3]; long n[3]; };
__global__ void f2h(CvtArgs a) {
    int seg = blockIdx.y;
    long i0 = (long)blockIdx.x * blockDim.x + threadIdx.x;
    long stride = (long)gridDim.x * blockDim.x;
    const float4* s = (const float4*)a.src[seg];
    __half* d = (__half*)a.dst[seg];
    long n4 = a.n[seg] >> 2;
    for (long i = i0; i < n4; i += stride) {
        float4 v = s[i];
        __half2 h0 = __floats2half2_rn(v.x, v.y);
        __half2 h1 = __floats2half2_rn(v.z, v.w);
        uint2 o; o.x = *(uint32_t*)&h0; o.y = *(uint32_t*)&h1;
        *(uint2*)(d + (i << 2)) = o;
    }
}

// seg0: stats recips (R->fp16*1024, C->fp32/1024); seg1: ATT prefill; seg2: A3 = bp3
__global__ void fuse2(float* stats,
                      __half* r1h, __half* r2h, __half* r4h,
                      const float* __restrict__ x3, const float* __restrict__ bsum,
                      const float* __restrict__ bp4, const float* __restrict__ wscal,
                      float* __restrict__ ATT,
                      const float* __restrict__ bp3, float* __restrict__ A3)
{
    int seg = blockIdx.y;
    long i0 = (long)blockIdx.x * blockDim.x + threadIdx.x;
    long stride = (long)gridDim.x * blockDim.x;
    if (seg == 0) {
        for (long i = i0; i < 88064; i += stride) {
            float r = 1.0f / stats[i];
            if (i < 36864)       r1h[i] = __float2half(r * 1024.0f);
            else if (i < 38912)  stats[i] = r * 0.0009765625f;
            else if (i < 48128)  r2h[i - 38912] = __float2half(r * 1024.0f);
            else if (i < 50176)  stats[i] = r * 0.0009765625f;
            else if (i < 87040)  r4h[i - 50176] = __float2half(r * 1024.0f);
            else                 stats[i] = r * 0.0009765625f;
        }
    } else if (seg == 1) {
        float f = 1.0f / (1.0f + expf(-wscal[0]));
        float other = (1.0f - f) * 0.5f;
        for (long i = i0; i < (long)BB * N3_ * D2_; i += stride) {
            int col = (int)(i & (D2_ - 1));
            ATT[i] = x3[i] + other * bsum[col] + f * bp4[col];
        }
    } else {
        for (long i = i0; i < (long)BB * N2_ * D1_; i += stride)
            A3[i] = bp3[(int)(i & (D1_ - 1))];
    }
}

// RA -> fp16 1024/x ; CA -> fp32 (1/x)/1024
__global__ void recip2(float* ra, __half* rah, int nr, float* ca, int nc) {
    int i = blockIdx.x * blockDim.x + threadIdx.x;
    if (i < nr) rah[i] = __float2half(1024.0f / ra[i]);
    else if (i < nr + nc) { int j = i - nr; ca[j] = (1.0f / ca[j]) * 0.0009765625f; }
}

// LN over last dim -> fp16 Y + fused out-prefill (fp32)
__global__ void ln_rows(const float* __restrict__ X, const float* __restrict__ g,
                        const float* __restrict__ bb, __half* __restrict__ Y, int C,
                        const float* __restrict__ bfc2, float* __restrict__ outp)
{
    long row = blockIdx.x;
    const float* x = X + row * C;
    float s = 0.f, s2 = 0.f;
    for (int c = threadIdx.x; c < C; c += blockDim.x) { float v = x[c]; s += v; s2 += v * v; }
    __shared__ float sh1[32], sh2[32];
    int lane = threadIdx.x & 31, wid = threadIdx.x >> 5;
#pragma unroll
    for (int o = 16; o; o >>= 1) {
        s  += __shfl_down_sync(0xffffffff, s,  o);
        s2 += __shfl_down_sync(0xffffffff, s2, o);
    }
    if (!lane) { sh1[wid] = s; sh2[wid] = s2; }
    __syncthreads();
    if (threadIdx.x == 0) {
        float a = 0.f, c2 = 0.f;
        int nw = blockDim.x >> 5;
        for (int i = 0; i < nw; i++) { a += sh1[i]; c2 += sh2[i]; }
        float mean = a / C;
        float var  = c2 / C - mean * mean;
        sh1[0] = mean; sh2[0] = rsqrtf(var + 1e-5f);
    }
    __syncthreads();
    float mean = sh1[0], rstd = sh2[0];
    for (int c = threadIdx.x; c < C; c += blockDim.x) {
        float v = x[c];
        Y[row * C + c] = __float2half_rn((v - mean) * rstd * g[c] + bb[c]);
        outp[row * C + c] = v + bfc2[c];
    }
}

__global__ void __launch_bounds__(256) dwconv_ln_gelu(
    const float* __restrict__ H, const float* __restrict__ Wdw,
    const float* __restrict__ bdw, const float* __restrict__ g,
    const float* __restrict__ bt, __half* __restrict__ AX)
{
    const int n = blockIdx.x;
    const int b = blockIdx.y;
    const int y = n / 24, x = n % 24;
    const float* Hb = H + (long)b * 576 * 2048;
    const int tid = threadIdx.x;

    float v[8];
    float s = 0.f, s2 = 0.f;
#pragma unroll
    for (int it = 0; it < 8; it++) {
        int c = tid + it * 256;
        float a = Hb[(long)n * 2048 + c] + bdw[c];
#pragma unroll
        for (int ky = 0; ky < 3; ky++) {
            int yy = y + ky - 1;
            if (yy < 0 || yy > 23) continue;
#pragma unroll
            for (int kx = 0; kx < 3; kx++) {
                int xx = x + kx - 1;
                if (xx < 0 || xx > 23) continue;
                a += Wdw[c * 9 + ky * 3 + kx] * Hb[(long)(yy * 24 + xx) * 2048 + c];
            }
        }
        v[it] = a; s += a; s2 += a * a;
    }
    __shared__ float sh1[32], sh2[32];
    int lane = tid & 31, wid = tid >> 5;
#pragma unroll
    for (int o = 16; o; o >>= 1) {
        s  += __shfl_down_sync(0xffffffff, s,  o);
        s2 += __shfl_down_sync(0xffffffff, s2, o);
    }
    if (!lane) { sh1[wid] = s; sh2[wid] = s2; }
    __syncthreads();
    if (tid == 0) {
        float a = 0.f, c2 = 0.f;
        for (int i = 0; i < 8; i++) { a += sh1[i]; c2 += sh2[i]; }
        float mean = a / 2048.0f;
        float var  = c2 / 2048.0f - mean * mean;
        sh1[0] = mean; sh2[0] = rsqrtf(var + 1e-5f);
    }
    __syncthreads();
    float mean = sh1[0], rstd = sh2[0];
    __half* out = AX + ((long)b * 576 + n) * 2048;
#pragma unroll
    for (int it = 0; it < 8; it++) {
        int c = tid + it * 256;
        float t = (v[it] - mean) * rstd * g[c] + bt[c];
        out[c] = __float2half_rn(0.5f * t * (1.0f + erff(t * 0.70710678118654752f)));
    }
}

// ---------------- host orchestration ----------------
#define SET_SMEM(k) cudaFuncSetAttribute(k, cudaFuncAttributeMaxDynamicSharedMemorySize, SMEM_DYN)

static Job mk_job(const float* A, long aStr, int lda,
                  const float* B, long bStr, int ldb,
                  float* C, long cStr, int ldc,
                  int m, int n, int k, int splits, int gx, int gy, int amode,
                  const float* ksc = nullptr, const float* msc = nullptr,
                  float* rsum = nullptr, float* csum = nullptr) {
    Job J;
    J.A = A; J.Bm = B; J.C = C;
    J.aStr = aStr; J.bStr = bStr; J.cStr = cStr;
    J.lda = lda; J.ldb = ldb; J.ldc = ldc;
    J.mTot = m; J.nTot = n; J.kTot = k; J.splits = splits; J.gx = gx; J.gy = gy;
    J.amode = amode;
    J.kscale = ksc; J.mscale = msc; J.rowsum = rsum; J.colsum = csum;
    return J;
}

extern "C" void kernel_launch(void* const* d_in, const int* in_sizes, int n_in,
                              void* d_out, int out_size)
{
    const float* x      = (const float*)d_in[0];
    const float* x2     = (const float*)d_in[1];
    const float* x3     = (const float*)d_in[2];
    const float* W_lin  = (const float*)d_in[3];
    const float* W_lin2 = (const float*)d_in[4];
    const float* W_lin3 = (const float*)d_in[5];
    const float* W_lin4 = (const float*)d_in[6];
    const float* w      = (const float*)d_in[7];
    const float* Wp1 = (const float*)d_in[8];  const float* bp1 = (const float*)d_in[9];
    const float* Wp2 = (const float*)d_in[10]; const float* bp2 = (const float*)d_in[11];
    const float* Wp3 = (const float*)d_in[12]; const float* bp3 = (const float*)d_in[13];
    const float* Wp4 = (const float*)d_in[14]; const float* bp4 = (const float*)d_in[15];
    const float* g_norm = (const float*)d_in[16]; const float* b_norm = (const float*)d_in[17];
    const float* Wfc1 = (const float*)d_in[18];   const float* bfc1  = (const float*)d_in[19];
    const float* Wdw  = (const float*)d_in[20];   const float* bdw   = (const float*)d_in[21];
    const float* g_ln1 = (const float*)d_in[22];  const float* b_ln1 = (const float*)d_in[23];
    const float* Wfc2 = (const float*)d_in[24];   const float* bfc2  = (const float*)d_in[25];

    float* pool = nullptr;
    cudaGetSymbolAddress((void**)&pool, g_pool);

    SET_SMEM((tgemm<1>));
    SET_SMEM((hgemm<0,false>));
    SET_SMEM((hgemm<1,false>));
    SET_SMEM((hgemm<2,false>));
    SET_SMEM((hgemm<5,true>));
    SET_SMEM((hgemm<6,false>));

    static cudaStream_t s1 = nullptr;
    static cudaEvent_t evStart = nullptr, evB = nullptr, evS = nullptr, evP = nullptr;
    if (!s1) {
        cudaStreamCreateWithFlags(&s1, cudaStreamNonBlocking);
        cudaEventCreateWithFlags(&evStart, cudaEventDisableTiming);
        cudaEventCreateWithFlags(&evB, cudaEventDisableTiming);
        cudaEventCreateWithFlags(&evS, cudaEventDisableTiming);
        cudaEventCreateWithFlags(&evP, cudaEventDisableTiming);
    }

    // prep table: segs 0-4 E-critical, 5 zero, 6-12 later, 13 W12h, 14 bsum
    PrepArgs pa;
    {
        const float* srcs[13] = { x, x2, W_lin, W_lin2, W_lin3, nullptr,
                                  x3, W_lin4, Wp3, Wp4, Wfc1, Wfc2, nullptr };
        long offs[13] = { OFF_XH, OFF_X2H, OFF_WLH, OFF_WL2H, OFF_WL3H, 0L,
                          OFF_X3H, OFF_WL4, OFF_WP3H, OFF_WP4H, OFF_WF1H, OFF_WF2H, 0L };
        long ns[13] = { (long)BB*N1_*D0_, (long)BB*N2_*D1_,
                        (long)D2_*D0_, (long)D2_*D1_, (long)D1_*D0_, ZERO_CNT,
                        (long)BB*N3_*D2_, (long)D2_*D1_, (long)D1_*D1_,
                        (long)D2_*D2_, (long)DH_*D2_, (long)D2_*DH_, 0L };
        int typs[13] = { 1, 1, 1, 1, 1, 2, 1, 0, 1, 1, 1, 1, 2 };
        for (int i = 0; i < 13; i++) {
            pa.src[i] = srcs[i]; pa.dst[i] = pool + offs[i]; pa.n[i] = ns[i]; pa.typ[i] = typs[i];
        }
        pa.W1 = Wp1; pa.W2 = Wp2; pa.b1 = bp1; pa.b2 = bp2;
        pa.W12h = pool + OFF_WP12H; pa.bsum = pool + OFF_BSUM;
    }

    // fork s1
    cudaEventRecord(evStart, 0);
    cudaStreamWaitEvent(s1, evStart, 0);

    prep<<<dim3(512, 6), 256, 0, 0>>>(pa, 0);       // E-critical + zero
    prep<<<dim3(512, 9), 256, 0, s1>>>(pa, 6);      // later copies + W12h + bsum
    cudaEventRecord(evB, s1);

    // E-group on s0
    {
        Jobs js;
        js.j[0] = mk_job(pool+OFF_XH, (long)N1_*D0_, D0_, pool+OFF_WLH, 0L, D0_,
                         pool+OFF_ET1, (long)D2_*N1_, N1_, N1_, D2_, D0_, 1, 4, 72, 0,
                         nullptr, nullptr, pool+OFF_R1, pool+OFF_C1);
        js.j[1] = mk_job(pool+OFF_X2H, (long)N2_*D1_, D1_, pool+OFF_WL2H, 0L, D1_,
                         pool+OFF_ET2, (long)D2_*N2_, N2_, N2_, D2_, D1_, 1, 4, 18, 0,
                         nullptr, nullptr, pool+OFF_R2, pool+OFF_C2);
        js.j[2] = mk_job(pool+OFF_XH, (long)N1_*D0_, D0_, pool+OFF_WL3H, 0L, D0_,
                         pool+OFF_ET4, (long)D1_*N1_, N1_, N1_, D1_, D0_, 1, 2, 72, 0,
                         nullptr, nullptr, pool+OFF_R4, pool+OFF_C4);
        js.off[0] = 0; js.off[1] = 288; js.off[2] = 360; js.off[3] = 504;
        hgemm<1,false><<<dim3(504,1,BB), 256, SMEM_DYN, 0>>>(js, nullptr, nullptr);
    }

    cudaStreamWaitEvent(0, evB, 0);
    fuse2<<<dim3(1024, 3), 256, 0, 0>>>(pool,
        (__half*)(pool + OFF_R1H), (__half*)(pool + OFF_R2H), (__half*)(pool + OFF_R4H),
        x3, pool+OFF_BSUM, bp4, w, pool+OFF_ATT, bp3, pool+OFF_A3);

    // S-group (St1+St2+St3) on s0
    {
        Jobs js;
        js.j[0] = mk_job(pool+OFF_ET1, (long)D2_*N1_, N1_, pool+OFF_ET1, (long)D2_*N1_, N1_,
                         pool+OFF_ST12, (long)2*D2_*D2_, D2_, D2_, D2_, N1_, 4, 10, 1, 0,
                         (const float*)(pool+OFF_R1H), pool+OFF_C1);
        js.j[1] = mk_job(pool+OFF_ET2, (long)D2_*N2_, N2_, pool+OFF_ET2, (long)D2_*N2_, N2_,
                         pool+OFF_ST12 + (long)D2_*D2_, (long)2*D2_*D2_, D2_, D2_, D2_, N2_, 2, 10, 1, 0,
                         (const float*)(pool+OFF_R2H), pool+OFF_C2);
        js.j[2] = mk_job(pool+OFF_ET4, (long)D1_*N1_, N1_, pool+OFF_ET4, (long)D1_*N1_, N1_,
                         pool+OFF_ST3, (long)D1_*D1_, D1_, D1_, D1_, N1_, 4, 3, 1, 0,
                         (const float*)(pool+OFF_R4H), pool+OFF_C4);
        js.off[0] = 0; js.off[1] = 40; js.off[2] = 60; js.off[3] = 72;
        hgemm<5,true><<<dim3(72,1,BB), 256, SMEM_DYN, 0>>>(js, nullptr, nullptr);
    }
    // convert St12 + St3 to fp16
    {
        CvtArgs ca;
        ca.src[0] = pool + OFF_ST12; ca.dst[0] = pool + OFF_ST12H; ca.n[0] = (long)BB*2*D2_*D2_;
        ca.src[1] = pool + OFF_ST3;  ca.dst[1] = pool + OFF_ST3H;  ca.n[1] = (long)BB*D1_*D1_;
        ca.src[2] = ca.src[1]; ca.dst[2] = ca.dst[1]; ca.n[2] = 0;
        f2h<<<dim3(256, 2), 256, 0, 0>>>(ca);
    }
    cudaEventRecord(evS, 0);

    // ---- chain P on s1: T12h -> ATT += other*(T12h@Wp12h^T) ----
    cudaStreamWaitEvent(s1, evS, 0);
    {
        Jobs js;
        js.j[0] = mk_job(pool+OFF_X3H, (long)N3_*D2_, D2_, pool+OFF_ST12H, (long)2*D2_*D2_, D2_,
                         pool+OFF_T12H, (long)N3_*2*D2_, 2*D2_, N3_, 2*D2_, D2_, 1, 8, 5, 0);
        js.j[1] = js.j[0]; js.j[2] = js.j[0];
        js.off[0] = 0; js.off[1] = 40; js.off[2] = 40; js.off[3] = 40;
        hgemm<0,false><<<dim3(40,1,BB), 256, SMEM_DYN, s1>>>(js, nullptr, nullptr);
    }
    {
        Jobs js;
        js.j[0] = mk_job(pool+OFF_T12H, (long)N3_*2*D2_, 2*D2_, pool+OFF_WP12H, 0L, 2*D2_,
                         pool+OFF_ATT, (long)N3_*D2_, D2_, N3_, D2_, 2*D2_, 2, 4, 5, 2);
        js.j[1] = js.j[0]; js.j[2] = js.j[0];
        js.off[0] = 0; js.off[1] = 40; js.off[2] = 40; js.off[3] = 40;
        hgemm<6,false><<<dim3(40,1,BB), 256, SMEM_DYN, s1>>>(js, nullptr, w);
    }
    cudaEventRecord(evP, s1);

    // ---- chain Q on s0 ----
    // T3h = x2h @ St3h
    {
        Jobs js;
        js.j[0] = mk_job(pool+OFF_X2H, (long)N2_*D1_, D1_, pool+OFF_ST3H, (long)D1_*D1_, D1_,
                         pool+OFF_T3H, (long)N2_*D1_, D1_, N2_, D1_, D1_, 1, 2, 18, 0);
        js.j[1] = js.j[0]; js.j[2] = js.j[0];
        js.off[0] = 0; js.off[1] = 36; js.off[2] = 36; js.off[3] = 36;
        hgemm<0,false><<<dim3(36,1,BB), 256, SMEM_DYN, 0>>>(js, nullptr, nullptr);
    }
    // A3 += T3h @ Wp3h^T
    {
        Jobs js;
        js.j[0] = mk_job(pool+OFF_T3H, (long)N2_*D1_, D1_, pool+OFF_WP3H, 0L, D1_,
                         pool+OFF_A3, (long)N2_*D1_, D1_, N2_, D1_, D1_, 1, 2, 18, 0);
        js.j[1] = js.j[0]; js.j[2] = js.j[0];
        js.off[0] = 0; js.off[1] = 36; js.off[2] = 36; js.off[3] = 36;
        hgemm<6,false><<<dim3(36,1,BB), 256, SMEM_DYN, 0>>>(js, nullptr, w);
    }
    // EtA (tf32: A3 fp32 x WL4 tf32 -> fp16 EtA)
    {
        Jobs js;
        js.j[0] = mk_job(pool+OFF_A3, (long)N2_*D1_, D1_, pool+OFF_WL4, 0L, D1_,
                         pool+OFF_ETA, (long)D2_*N2_, N2_, N2_, D2_, D1_, 1, 4, 18, 0,
                         nullptr, nullptr, pool+OFF_RA, pool+OFF_CA);
        js.j[1] = js.j[0]; js.j[2] = js.j[0];
        js.off[0] = 0; js.off[1] = 72; js.off[2] = 72; js.off[3] = 72;
        tgemm<1><<<dim3(72,1,BB), 256, SMEM_DYN, 0>>>(js, nullptr, nullptr);
    }
    recip2<<<(11264 + 255) / 256, 256, 0, 0>>>(pool + OFF_RA, (__half*)(pool + OFF_RAH),
                                               BB * N2_, pool + OFF_CA, BB * D2_);
    // St4 (fp16 symmetric, split-K 2)
    {
        Jobs js;
        js.j[0] = mk_job(pool+OFF_ETA, (long)D2_*N2_, N2_, pool+OFF_ETA, (long)D2_*N2_, N2_,
                         pool+OFF_ST4, (long)D2_*D2_, D2_, D2_, D2_, N2_, 2, 10, 1, 0,
                         (const float*)(pool+OFF_RAH), pool+OFF_CA);
        js.j[1] = js.j[0]; js.j[2] = js.j[0];
        js.off[0] = 0; js.off[1] = 20; js.off[2] = 20; js.off[3] = 20;
        hgemm<5,true><<<dim3(20,1,BB), 256, SMEM_DYN, 0>>>(js, nullptr, nullptr);
    }
    // convert St4 -> fp16
    {
        CvtArgs ca;
        ca.src[0] = pool + OFF_ST4; ca.dst[0] = pool + OFF_ST4H; ca.n[0] = (long)BB*D2_*D2_;
        ca.src[1] = ca.src[0]; ca.dst[1] = ca.dst[0]; ca.n[1] = 0;
        ca.src[2] = ca.src[0]; ca.dst[2] = ca.dst[0]; ca.n[2] = 0;
        f2h<<<dim3(256, 1), 256, 0, 0>>>(ca);
    }
    // 17a) Th = x3h @ St4h
    {
        Jobs js;
        js.j[0] = mk_job(pool+OFF_X3H, (long)N3_*D2_, D2_, pool+OFF_ST4H, (long)D2_*D2_, D2_,
                         pool+OFF_TH, (long)N3_*D2_, D2_, N3_, D2_, D2_, 1, 4, 5, 0);
        js.j[1] = js.j[0]; js.j[2] = js.j[0];
        js.off[0] = 0; js.off[1] = 20; js.off[2] = 20; js.off[3] = 20;
        hgemm<0,false><<<dim3(20,1,BB), 256, SMEM_DYN, 0>>>(js, nullptr, nullptr);
    }
    // 17b) ATT += f*(Th @ Wp4h^T)
    {
        Jobs js;
        js.j[0] = mk_job(pool+OFF_TH, (long)N3_*D2_, D2_, pool+OFF_WP4H, 0L, D2_,
                         pool+OFF_ATT, (long)N3_*D2_, D2_, N3_, D2_, D2_, 2, 4, 5, 1);
        js.j[1] = js.j[0]; js.j[2] = js.j[0];
        js.off[0] = 0; js.off[1] = 40; js.off[2] = 40; js.off[3] = 40;
        hgemm<6,false><<<dim3(40,1,BB), 256, SMEM_DYN, 0>>>(js, nullptr, w);
    }

    // join chain P; tail on s0
    cudaStreamWaitEvent(0, evP, 0);
    ln_rows<<<BB * N3_, 256, 0, 0>>>(pool + OFF_ATT, g_norm, b_norm,
                                     (__half*)(pool + OFF_AN), D2_, bfc2, (float*)d_out);
    // H = ANh @ Wfc1h^T + bfc1 (fp32 out)
    {
        Jobs js;
        js.j[0] = mk_job(pool+OFF_AN, (long)N3_*D2_, D2_, pool+OFF_WF1H, 0L, D2_,
                         pool+OFF_H, (long)N3_*DH_, DH_, N3_, DH_, D2_, 1, 16, 5, 0);
        js.j[1] = js.j[0]; js.j[2] = js.j[0];
        js.off[0] = 0; js.off[1] = 80; js.off[2] = 80; js.off[3] = 80;
        hgemm<2,false><<<dim3(80,1,BB), 256, SMEM_DYN, 0>>>(js, bfc1, nullptr);
    }
    dwconv_ln_gelu<<<dim3(N3_, BB), 256, 0, 0>>>(pool + OFF_H, Wdw, bdw, g_ln1, b_ln1,
                                                 (__half*)(pool + OFF_AX));
    // out += AXh @ Wfc2h^T (split-K 4)
    {
        Jobs js;
        js.j[0] = mk_job(pool+OFF_AX, (long)N3_*DH_, DH_, pool+OFF_WF2H, 0L, DH_,
                         (float*)d_out, (long)N3_*D2_, D2_, N3_, D2_, DH_, 4, 4, 5, 0);
        js.j[1] = js.j[0]; js.j[2] = js.j[0];
        js.off[0] = 0; js.off[1] = 80; js.off[2] = 80; js.off[3] = 80;
        hgemm<6,false><<<dim3(80,1,BB), 256, SMEM_DYN, 0>>>(js, nullptr, nullptr);
    }
}